// round 1
// baseline (speedup 1.0000x reference)
#include <cuda_runtime.h>
#include <math.h>

// ---------------------------------------------------------------------------
// Problem constants
// ---------------------------------------------------------------------------
namespace {
constexpr int Bz   = 2;
constexpr int Sq   = 2048;
constexpr int Dm   = 1024;
constexpr int Hn   = 16;
constexpr int HDm  = 64;
constexpr int FFNm = 2048;
constexpr int En   = 8;
constexpr int Tn   = Bz * Sq;     // 4096 tokens
constexpr int NA   = Tn * 2;      // 8192 flat assignments (top-2)
constexpr int CAPn = 1280;        // ceil(2*2048*2*1.25/8)
}

// ---------------------------------------------------------------------------
// Static scratch (no allocations allowed)
// ---------------------------------------------------------------------------
__device__ float g_xn  [Tn * Dm];
__device__ float g_qkv [Tn * 3 * Dm];
__device__ float g_q   [Tn * Dm];
__device__ float g_k   [Tn * Dm];
__device__ float g_v   [Tn * Dm];
__device__ float g_attn[Tn * Dm];
__device__ float g_x1  [Tn * Dm];
__device__ float g_cos [Sq * (HDm / 2)];
__device__ float g_sin [Sq * (HDm / 2)];
__device__ float g_fg  [NA];
__device__ int   g_fe  [NA];
__device__ int   g_slot[NA];
__device__ int   g_etok [En * CAPn];
__device__ float g_egate[En * CAPn];
__device__ float g_h [En * CAPn * FFNm];  // 83.9 MB
__device__ float g_ye[En * CAPn * Dm];    // 41.9 MB

// ---------------------------------------------------------------------------
// RMSNorm: one block per row, 256 threads x float4 == 1024 elems
// ---------------------------------------------------------------------------
__global__ void __launch_bounds__(256) rmsnorm_k(const float* __restrict__ x,
                                                 const float* __restrict__ g,
                                                 float* __restrict__ y) {
    int row = blockIdx.x;
    int i = threadIdx.x;
    const float4* xr = (const float4*)(x + (size_t)row * Dm);
    float4 xv = xr[i];
    float ss = xv.x * xv.x + xv.y * xv.y + xv.z * xv.z + xv.w * xv.w;
#pragma unroll
    for (int off = 16; off; off >>= 1) ss += __shfl_down_sync(0xffffffffu, ss, off);
    __shared__ float red[8];
    __shared__ float srms;
    if ((i & 31) == 0) red[i >> 5] = ss;
    __syncthreads();
    if (i == 0) {
        float t = 0.f;
#pragma unroll
        for (int w = 0; w < 8; w++) t += red[w];
        srms = rsqrtf(t * (1.0f / Dm) + 1e-6f);
    }
    __syncthreads();
    float r = srms;
    float4 gv = ((const float4*)g)[i];
    float4 o;
    o.x = gv.x * xv.x * r; o.y = gv.y * xv.y * r;
    o.z = gv.z * xv.z * r; o.w = gv.w * xv.w * r;
    ((float4*)(y + (size_t)row * Dm))[i] = o;
}

// ---------------------------------------------------------------------------
// RoPE cos/sin table (double-precision angle, rounded like f32 pipeline)
// ---------------------------------------------------------------------------
__global__ void rope_table_k(float* __restrict__ ct, float* __restrict__ st) {
    int idx = blockIdx.x * blockDim.x + threadIdx.x;
    if (idx >= Sq * (HDm / 2)) return;
    int s = idx >> 5, j = idx & 31;
    float th = (float)pow(10000.0, -2.0 * (double)j / (double)HDm);
    double f = (double)s * (double)th;
    ct[idx] = (float)cos(f);
    st[idx] = (float)sin(f);
}

// ---------------------------------------------------------------------------
// Split QKV [T,3D] -> q,k,v in [B,H,S,HD] with RoPE on q,k
// ---------------------------------------------------------------------------
__global__ void __launch_bounds__(256) split_rope_k(const float* __restrict__ qkv,
                                                    const float* __restrict__ ct,
                                                    const float* __restrict__ st,
                                                    float* __restrict__ q,
                                                    float* __restrict__ k,
                                                    float* __restrict__ v) {
    int t = blockIdx.x;
    int b = t / Sq, s = t % Sq;
    const float* row = qkv + (size_t)t * (3 * Dm);
    for (int idx = threadIdx.x; idx < Hn * (HDm / 2); idx += blockDim.x) {
        int h = idx >> 5, j = idx & 31;
        float c = ct[s * 32 + j], sn = st[s * 32 + j];
        size_t o = ((size_t)(b * Hn + h) * Sq + s) * HDm;
        float qr = row[h * HDm + 2 * j], qi = row[h * HDm + 2 * j + 1];
        q[o + 2 * j]     = qr * c - qi * sn;
        q[o + 2 * j + 1] = qr * sn + qi * c;
        float kr = row[Dm + h * HDm + 2 * j], ki = row[Dm + h * HDm + 2 * j + 1];
        k[o + 2 * j]     = kr * c - ki * sn;
        k[o + 2 * j + 1] = kr * sn + ki * c;
    }
    for (int idx = threadIdx.x; idx < Dm; idx += blockDim.x) {
        int h = idx >> 6, d = idx & 63;
        v[((size_t)(b * Hn + h) * Sq + s) * HDm + d] = row[2 * Dm + idx];
    }
}

// ---------------------------------------------------------------------------
// Flash-style causal attention. 1 thread == 1 query row (full online softmax
// state in registers, no cross-thread reduction). K/V tiles (32x64) in smem,
// all threads read the same smem address per step -> broadcast, conflict-free.
// Output written in [B,S,H,HD] layout == [T,D] rows for the out-proj GEMM.
// ---------------------------------------------------------------------------
__global__ void __launch_bounds__(128) attn_k(const float* __restrict__ Q,
                                              const float* __restrict__ Kt,
                                              const float* __restrict__ Vt,
                                              float* __restrict__ Out) {
    int qt = blockIdx.x * 128;
    int h = blockIdx.y, b = blockIdx.z;
    int tid = threadIdx.x;
    int myq = qt + tid;
    const size_t base = ((size_t)(b * Hn + h)) * Sq * HDm;

    float4 q4[16];
    {
        const float4* qrow = (const float4*)(Q + base + (size_t)myq * HDm);
#pragma unroll
        for (int i = 0; i < 16; i++) q4[i] = qrow[i];
    }
    float4 a4[16];
#pragma unroll
    for (int i = 0; i < 16; i++) a4[i] = make_float4(0.f, 0.f, 0.f, 0.f);
    float m = -1e30f, l = 0.f;

    __shared__ float Ks[32][64];
    __shared__ float Vs[32][64];

    int kend = qt + 128;
    for (int kt = 0; kt < kend; kt += 32) {
        __syncthreads();
#pragma unroll
        for (int r = 0; r < 4; r++) {
            int fi = tid + r * 128;          // 0..511
            int row = fi >> 4, c4 = fi & 15;
            ((float4*)&Ks[row][0])[c4] = ((const float4*)(Kt + base + (size_t)(kt + row) * HDm))[c4];
            ((float4*)&Vs[row][0])[c4] = ((const float4*)(Vt + base + (size_t)(kt + row) * HDm))[c4];
        }
        __syncthreads();

        float sreg[32];
        float mt = m;
        int lim = myq - kt;                  // keys j valid iff j <= lim
#pragma unroll
        for (int j = 0; j < 32; j++) {
            float s0 = 0.f, s1 = 0.f, s2 = 0.f, s3 = 0.f;
#pragma unroll
            for (int d4 = 0; d4 < 16; d4++) {
                float4 kk = ((const float4*)&Ks[j][0])[d4];
                s0 = fmaf(q4[d4].x, kk.x, s0);
                s1 = fmaf(q4[d4].y, kk.y, s1);
                s2 = fmaf(q4[d4].z, kk.z, s2);
                s3 = fmaf(q4[d4].w, kk.w, s3);
            }
            float sj = ((s0 + s1) + (s2 + s3)) * 0.125f;
            sreg[j] = sj;
            mt = (j <= lim) ? fmaxf(mt, sj) : mt;
        }
        if (mt > m) {
            float corr = __expf(m - mt);
            l *= corr;
#pragma unroll
            for (int i = 0; i < 16; i++) {
                a4[i].x *= corr; a4[i].y *= corr; a4[i].z *= corr; a4[i].w *= corr;
            }
            m = mt;
        }
#pragma unroll
        for (int j = 0; j < 32; j++) {
            if (j <= lim) {
                float p = __expf(sreg[j] - m);
                l += p;
#pragma unroll
                for (int d4 = 0; d4 < 16; d4++) {
                    float4 vv = ((const float4*)&Vs[j][0])[d4];
                    a4[d4].x = fmaf(p, vv.x, a4[d4].x);
                    a4[d4].y = fmaf(p, vv.y, a4[d4].y);
                    a4[d4].z = fmaf(p, vv.z, a4[d4].z);
                    a4[d4].w = fmaf(p, vv.w, a4[d4].w);
                }
            }
        }
    }
    float inv = 1.f / l;
    float* orow = Out + ((size_t)(b * Sq + myq)) * Dm + h * HDm;
#pragma unroll
    for (int i = 0; i < 16; i++) {
        float4 o;
        o.x = a4[i].x * inv; o.y = a4[i].y * inv;
        o.z = a4[i].z * inv; o.w = a4[i].w * inv;
        ((float4*)orow)[i] = o;
    }
}

// ---------------------------------------------------------------------------
// Generic tiled SGEMM: 128x128 block tile, BK=16, 256 threads, 8x8 per thread.
// MODE 0: C = A@B        MODE 1: C = A@B + resid
// MODE 2: C = relu(A@B)  MODE 3: C = (A@B) * gates[row]
// GATHER: A row r comes from A[tok[r]] (tok<0 -> zero row).
// blockIdx.z selects expert via the sA/sB/sC/sTok/sG strides.
// ---------------------------------------------------------------------------
template <int MODE, bool GATHER>
__global__ void __launch_bounds__(256) sgemm_k(const float* __restrict__ A,
                                               const float* __restrict__ Bm,
                                               float* __restrict__ C,
                                               int M, int N, int K,
                                               const float* __restrict__ resid,
                                               const int* __restrict__ tok,
                                               const float* __restrict__ gates,
                                               long sA, long sB, long sC,
                                               int sTok, int sG) {
    int e = blockIdx.z;
    A  += (size_t)e * sA;
    Bm += (size_t)e * sB;
    C  += (size_t)e * sC;
    if (GATHER) tok += e * sTok;
    if (MODE == 3) gates += e * sG;

    __shared__ float As[16][128];
    __shared__ float Bs[16][128];

    int tid = threadIdx.x;
    int m0 = blockIdx.y * 128, n0 = blockIdx.x * 128;

    int a_row = tid >> 1;
    int a_k   = (tid & 1) * 8;
    const float* Ap = nullptr;
    if (GATHER) {
        int t = tok[m0 + a_row];
        if (t >= 0) Ap = A + (size_t)t * K + a_k;
    } else {
        Ap = A + (size_t)(m0 + a_row) * K + a_k;
    }
    int b_r = tid >> 5;
    int b_c = (tid & 31) * 4;
    const float* Bp = Bm + (size_t)b_r * N + n0 + b_c;

    float acc[8][8];
#pragma unroll
    for (int i = 0; i < 8; i++)
#pragma unroll
        for (int j = 0; j < 8; j++) acc[i][j] = 0.f;

    int ty = tid >> 4, tx = tid & 15;

    for (int k0 = 0; k0 < K; k0 += 16) {
        float4 av0, av1;
        if (Ap) {
            av0 = *(const float4*)(Ap + k0);
            av1 = *(const float4*)(Ap + k0 + 4);
        } else {
            av0 = make_float4(0.f, 0.f, 0.f, 0.f);
            av1 = av0;
        }
        float4 bv0 = *(const float4*)(Bp + (size_t)k0 * N);
        float4 bv1 = *(const float4*)(Bp + (size_t)(k0 + 8) * N);
        __syncthreads();
        As[a_k + 0][a_row] = av0.x; As[a_k + 1][a_row] = av0.y;
        As[a_k + 2][a_row] = av0.z; As[a_k + 3][a_row] = av0.w;
        As[a_k + 4][a_row] = av1.x; As[a_k + 5][a_row] = av1.y;
        As[a_k + 6][a_row] = av1.z; As[a_k + 7][a_row] = av1.w;
        *(float4*)&Bs[b_r][b_c]     = bv0;
        *(float4*)&Bs[b_r + 8][b_c] = bv1;
        __syncthreads();
#pragma unroll
        for (int kk = 0; kk < 16; kk++) {
            float a[8], bb[8];
            *(float4*)&a[0]  = *(const float4*)&As[kk][ty * 8];
            *(float4*)&a[4]  = *(const float4*)&As[kk][ty * 8 + 4];
            *(float4*)&bb[0] = *(const float4*)&Bs[kk][tx * 8];
            *(float4*)&bb[4] = *(const float4*)&Bs[kk][tx * 8 + 4];
#pragma unroll
            for (int i = 0; i < 8; i++)
#pragma unroll
                for (int j = 0; j < 8; j++)
                    acc[i][j] = fmaf(a[i], bb[j], acc[i][j]);
        }
    }

#pragma unroll
    for (int i = 0; i < 8; i++) {
        int gm = m0 + ty * 8 + i;
        float gate = 1.f;
        if (MODE == 3) gate = gates[gm];
#pragma unroll
        for (int j4 = 0; j4 < 2; j4++) {
            float4 v;
            v.x = acc[i][j4 * 4 + 0]; v.y = acc[i][j4 * 4 + 1];
            v.z = acc[i][j4 * 4 + 2]; v.w = acc[i][j4 * 4 + 3];
            size_t off = (size_t)gm * N + n0 + tx * 8 + j4 * 4;
            if (MODE == 1) {
                float4 rr = *(const float4*)(resid + off);
                v.x += rr.x; v.y += rr.y; v.z += rr.z; v.w += rr.w;
            }
            if (MODE == 2) {
                v.x = fmaxf(v.x, 0.f); v.y = fmaxf(v.y, 0.f);
                v.z = fmaxf(v.z, 0.f); v.w = fmaxf(v.w, 0.f);
            }
            if (MODE == 3) {
                v.x *= gate; v.y *= gate; v.z *= gate; v.w *= gate;
            }
            *(float4*)(C + off) = v;
        }
    }
}

// ---------------------------------------------------------------------------
// Router: 1 warp per token. 8 logits -> softmax -> top-2 (ties: lower index,
// matching jax.lax.top_k).
// ---------------------------------------------------------------------------
__global__ void __launch_bounds__(256) router_k(const float* __restrict__ xn,
                                                const float* __restrict__ wr,
                                                float* __restrict__ fg,
                                                int* __restrict__ fe) {
    int warp = threadIdx.x >> 5, lane = threadIdx.x & 31;
    int t = blockIdx.x * 8 + warp;
    float acc[8];
#pragma unroll
    for (int e2 = 0; e2 < 8; e2++) acc[e2] = 0.f;
    const float* xr = xn + (size_t)t * Dm;
    for (int d = lane; d < Dm; d += 32) {
        float xv = xr[d];
        const float4* w = (const float4*)(wr + d * En);
        float4 w0 = w[0], w1 = w[1];
        acc[0] = fmaf(xv, w0.x, acc[0]); acc[1] = fmaf(xv, w0.y, acc[1]);
        acc[2] = fmaf(xv, w0.z, acc[2]); acc[3] = fmaf(xv, w0.w, acc[3]);
        acc[4] = fmaf(xv, w1.x, acc[4]); acc[5] = fmaf(xv, w1.y, acc[5]);
        acc[6] = fmaf(xv, w1.z, acc[6]); acc[7] = fmaf(xv, w1.w, acc[7]);
    }
#pragma unroll
    for (int e2 = 0; e2 < 8; e2++)
#pragma unroll
        for (int off = 16; off; off >>= 1)
            acc[e2] += __shfl_down_sync(0xffffffffu, acc[e2], off);
    if (lane == 0) {
        float mx = acc[0];
#pragma unroll
        for (int e2 = 1; e2 < 8; e2++) mx = fmaxf(mx, acc[e2]);
        float p[8], sum = 0.f;
#pragma unroll
        for (int e2 = 0; e2 < 8; e2++) { p[e2] = expf(acc[e2] - mx); sum += p[e2]; }
        float inv = 1.f / sum;
#pragma unroll
        for (int e2 = 0; e2 < 8; e2++) p[e2] *= inv;
        int e0 = 0; float p0 = p[0];
#pragma unroll
        for (int e2 = 1; e2 < 8; e2++) if (p[e2] > p0) { p0 = p[e2]; e0 = e2; }
        int e1 = -1; float p1 = -1.f;
#pragma unroll
        for (int e2 = 0; e2 < 8; e2++)
            if (e2 != e0 && p[e2] > p1) { p1 = p[e2]; e1 = e2; }
        fg[2 * t]     = p0; fe[2 * t]     = e0;
        fg[2 * t + 1] = p1; fe[2 * t + 1] = e1;
    }
}

__global__ void init_etok_k(int* __restrict__ etok) {
    int i = blockIdx.x * blockDim.x + threadIdx.x;
    if (i < En * CAPn) etok[i] = -1;
}

// ---------------------------------------------------------------------------
// Exact capacity routing: rank of each assignment within its expert
// (value desc, tie -> lower flat index) == its capacity slot. Matches
// jax.lax.top_k(masked, CAP) exactly, deterministic, no atomics.
// ---------------------------------------------------------------------------
__global__ void __launch_bounds__(256) rank_k(const float* __restrict__ fg,
                                              const int* __restrict__ fe,
                                              int* __restrict__ slot,
                                              int* __restrict__ etok,
                                              float* __restrict__ egate) {
    __shared__ float sg[NA];
    __shared__ unsigned char se[NA];
    for (int i = threadIdx.x; i < NA; i += 256) {
        sg[i] = fg[i];
        se[i] = (unsigned char)fe[i];
    }
    __syncthreads();
    int i = blockIdx.x * 256 + threadIdx.x;
    float gi = sg[i];
    unsigned char ei = se[i];
    int r = 0;
    for (int j = 0; j < NA; j++) {
        bool c = (se[j] == ei) && ((sg[j] > gi) || (sg[j] == gi && j < i));
        r += (int)c;
    }
    if (r < CAPn) {
        slot[i] = r;
        etok[(int)ei * CAPn + r] = i >> 1;
        egate[(int)ei * CAPn + r] = gi;
    } else {
        slot[i] = -1;
    }
}

// ---------------------------------------------------------------------------
// Final combine: out = x1 + sum over the token's kept assignments of its
// (already gate-scaled) expert output row. No atomics -> deterministic.
// ---------------------------------------------------------------------------
__global__ void __launch_bounds__(256) combine_k(const float* __restrict__ x1,
                                                 const float* __restrict__ ye,
                                                 const int* __restrict__ fe,
                                                 const int* __restrict__ slot,
                                                 float* __restrict__ out) {
    int t = blockIdx.x;
    int d = threadIdx.x;  // float4 index, 256 * 4 = 1024
    float4 v = ((const float4*)(x1 + (size_t)t * Dm))[d];
#pragma unroll
    for (int kk = 0; kk < 2; kk++) {
        int i = 2 * t + kk;
        int sl = slot[i];
        if (sl >= 0) {
            int e = fe[i];
            float4 w = ((const float4*)(ye + ((size_t)e * CAPn + sl) * Dm))[d];
            v.x += w.x; v.y += w.y; v.z += w.z; v.w += w.w;
        }
    }
    ((float4*)(out + (size_t)t * Dm))[d] = v;
}

// ---------------------------------------------------------------------------
// Launch
// ---------------------------------------------------------------------------
extern "C" void kernel_launch(void* const* d_in, const int* in_sizes, int n_in,
                              void* d_out, int out_size) {
    (void)in_sizes; (void)n_in; (void)out_size;
    const float* x        = (const float*)d_in[0];
    const float* g1       = (const float*)d_in[1];
    const float* w_qkv    = (const float*)d_in[2];
    const float* w_o      = (const float*)d_in[3];
    const float* g2       = (const float*)d_in[4];
    const float* w_router = (const float*)d_in[5];
    const float* w1       = (const float*)d_in[6];
    const float* w2       = (const float*)d_in[7];
    float* out = (float*)d_out;

    float *p_xn, *p_qkv, *p_q, *p_k, *p_v, *p_attn, *p_x1, *p_cos, *p_sin;
    float *p_fg, *p_egate, *p_h, *p_ye;
    int *p_fe, *p_slot, *p_etok;
    cudaGetSymbolAddress((void**)&p_xn,   g_xn);
    cudaGetSymbolAddress((void**)&p_qkv,  g_qkv);
    cudaGetSymbolAddress((void**)&p_q,    g_q);
    cudaGetSymbolAddress((void**)&p_k,    g_k);
    cudaGetSymbolAddress((void**)&p_v,    g_v);
    cudaGetSymbolAddress((void**)&p_attn, g_attn);
    cudaGetSymbolAddress((void**)&p_x1,   g_x1);
    cudaGetSymbolAddress((void**)&p_cos,  g_cos);
    cudaGetSymbolAddress((void**)&p_sin,  g_sin);
    cudaGetSymbolAddress((void**)&p_fg,   g_fg);
    cudaGetSymbolAddress((void**)&p_fe,   g_fe);
    cudaGetSymbolAddress((void**)&p_slot, g_slot);
    cudaGetSymbolAddress((void**)&p_etok, g_etok);
    cudaGetSymbolAddress((void**)&p_egate,g_egate);
    cudaGetSymbolAddress((void**)&p_h,    g_h);
    cudaGetSymbolAddress((void**)&p_ye,   g_ye);

    // cos/sin table (independent; overlaps nothing it shouldn't)
    rope_table_k<<<(Sq * 32 + 255) / 256, 256>>>(p_cos, p_sin);

    // xn1 = rmsnorm(x, g1)
    rmsnorm_k<<<Tn, 256>>>(x, g1, p_xn);

    // qkv = xn1 @ w_qkv   [4096,1024]@[1024,3072]
    sgemm_k<0, false><<<dim3(3 * Dm / 128, Tn / 128, 1), 256>>>(
        p_xn, w_qkv, p_qkv, Tn, 3 * Dm, Dm, nullptr, nullptr, nullptr, 0, 0, 0, 0, 0);

    // split + rope -> q,k,v in [B,H,S,HD]
    split_rope_k<<<Tn, 256>>>(p_qkv, p_cos, p_sin, p_q, p_k, p_v);

    // causal attention -> [T, D] (head-major within row)
    attn_k<<<dim3(Sq / 128, Hn, Bz), 128>>>(p_q, p_k, p_v, p_attn);

    // x1 = x + attn @ w_o
    sgemm_k<1, false><<<dim3(Dm / 128, Tn / 128, 1), 256>>>(
        p_attn, w_o, p_x1, Tn, Dm, Dm, x, nullptr, nullptr, 0, 0, 0, 0, 0);

    // xn2 = rmsnorm(x1, g2)
    rmsnorm_k<<<Tn, 256>>>(p_x1, g2, p_xn);

    // routing
    router_k<<<Tn / 8, 256>>>(p_xn, w_router, p_fg, p_fe);
    init_etok_k<<<(En * CAPn + 255) / 256, 256>>>(p_etok);
    rank_k<<<NA / 256, 256>>>(p_fg, p_fe, p_slot, p_etok, p_egate);

    // h[e] = relu(gather(xn2, etok[e]) @ w1[e])   [1280,1024]@[1024,2048] x8
    sgemm_k<2, true><<<dim3(FFNm / 128, CAPn / 128, En), 256>>>(
        p_xn, w1, p_h, CAPn, FFNm, Dm, nullptr, p_etok, nullptr,
        0, (long)Dm * FFNm, (long)CAPn * FFNm, CAPn, 0);

    // ye[e] = (h[e] @ w2[e]) * gate   [1280,2048]@[2048,1024] x8
    sgemm_k<3, false><<<dim3(Dm / 128, CAPn / 128, En), 256>>>(
        p_h, w2, p_ye, CAPn, Dm, FFNm, nullptr, nullptr, p_egate,
        (long)CAPn * FFNm, (long)FFNm * Dm, (long)CAPn * Dm, 0, CAPn);

    // out = x1 + gathered moe contributions
    combine_k<<<Tn, 256>>>(p_x1, p_ye, p_fe, p_slot, out);
}

// round 2
// speedup vs baseline: 1.6256x; 1.6256x over previous
#include <cuda_runtime.h>
#include <math.h>

// ---------------------------------------------------------------------------
// Problem constants
// ---------------------------------------------------------------------------
namespace {
constexpr int Bz   = 2;
constexpr int Sq   = 2048;
constexpr int Dm   = 1024;
constexpr int Hn   = 16;
constexpr int HDm  = 64;
constexpr int FFNm = 2048;
constexpr int En   = 8;
constexpr int Tn   = Bz * Sq;     // 4096 tokens
constexpr int NA   = Tn * 2;      // 8192 flat assignments (top-2)
constexpr int CAPn = 1280;        // ceil(2*2048*2*1.25/8)
}

// ---------------------------------------------------------------------------
// Static scratch (no allocations allowed)
// ---------------------------------------------------------------------------
__device__ float g_xn  [Tn * Dm];
__device__ float g_qkv [Tn * 3 * Dm];
__device__ float g_q   [Tn * Dm];
__device__ float g_k   [Tn * Dm];
__device__ float g_v   [Tn * Dm];
__device__ float g_attn[Tn * Dm];
__device__ float g_x1  [Tn * Dm];
__device__ float g_cos [Sq * (HDm / 2)];
__device__ float g_sin [Sq * (HDm / 2)];
__device__ float g_fg  [NA];
__device__ int   g_fe  [NA];
__device__ int   g_slot[NA];
__device__ int   g_etok [En * CAPn];
__device__ float g_egate[En * CAPn];
__device__ float g_h [En * CAPn * FFNm];  // 83.9 MB
__device__ float g_ye[En * CAPn * Dm];    // 41.9 MB

// ---------------------------------------------------------------------------
// RMSNorm: one block per row, 256 threads x float4 == 1024 elems
// ---------------------------------------------------------------------------
__global__ void __launch_bounds__(256) rmsnorm_k(const float* __restrict__ x,
                                                 const float* __restrict__ g,
                                                 float* __restrict__ y) {
    int row = blockIdx.x;
    int i = threadIdx.x;
    const float4* xr = (const float4*)(x + (size_t)row * Dm);
    float4 xv = xr[i];
    float ss = xv.x * xv.x + xv.y * xv.y + xv.z * xv.z + xv.w * xv.w;
#pragma unroll
    for (int off = 16; off; off >>= 1) ss += __shfl_down_sync(0xffffffffu, ss, off);
    __shared__ float red[8];
    __shared__ float srms;
    if ((i & 31) == 0) red[i >> 5] = ss;
    __syncthreads();
    if (i == 0) {
        float t = 0.f;
#pragma unroll
        for (int w = 0; w < 8; w++) t += red[w];
        srms = rsqrtf(t * (1.0f / Dm) + 1e-6f);
    }
    __syncthreads();
    float r = srms;
    float4 gv = ((const float4*)g)[i];
    float4 o;
    o.x = gv.x * xv.x * r; o.y = gv.y * xv.y * r;
    o.z = gv.z * xv.z * r; o.w = gv.w * xv.w * r;
    ((float4*)(y + (size_t)row * Dm))[i] = o;
}

// ---------------------------------------------------------------------------
// RoPE cos/sin table (double-precision angle, rounded like f32 pipeline)
// ---------------------------------------------------------------------------
__global__ void rope_table_k(float* __restrict__ ct, float* __restrict__ st) {
    int idx = blockIdx.x * blockDim.x + threadIdx.x;
    if (idx >= Sq * (HDm / 2)) return;
    int s = idx >> 5, j = idx & 31;
    float th = (float)pow(10000.0, -2.0 * (double)j / (double)HDm);
    double f = (double)s * (double)th;
    ct[idx] = (float)cos(f);
    st[idx] = (float)sin(f);
}

// ---------------------------------------------------------------------------
// Split QKV [T,3D] -> q,k,v in [B,H,S,HD] with RoPE on q,k
// ---------------------------------------------------------------------------
__global__ void __launch_bounds__(256) split_rope_k(const float* __restrict__ qkv,
                                                    const float* __restrict__ ct,
                                                    const float* __restrict__ st,
                                                    float* __restrict__ q,
                                                    float* __restrict__ k,
                                                    float* __restrict__ v) {
    int t = blockIdx.x;
    int b = t / Sq, s = t % Sq;
    const float* row = qkv + (size_t)t * (3 * Dm);
    for (int idx = threadIdx.x; idx < Hn * (HDm / 2); idx += blockDim.x) {
        int h = idx >> 5, j = idx & 31;
        float c = ct[s * 32 + j], sn = st[s * 32 + j];
        size_t o = ((size_t)(b * Hn + h) * Sq + s) * HDm;
        float qr = row[h * HDm + 2 * j], qi = row[h * HDm + 2 * j + 1];
        q[o + 2 * j]     = qr * c - qi * sn;
        q[o + 2 * j + 1] = qr * sn + qi * c;
        float kr = row[Dm + h * HDm + 2 * j], ki = row[Dm + h * HDm + 2 * j + 1];
        k[o + 2 * j]     = kr * c - ki * sn;
        k[o + 2 * j + 1] = kr * sn + ki * c;
    }
    for (int idx = threadIdx.x; idx < Dm; idx += blockDim.x) {
        int h = idx >> 6, d = idx & 63;
        v[((size_t)(b * Hn + h) * Sq + s) * HDm + d] = row[2 * Dm + idx];
    }
}

// ---------------------------------------------------------------------------
// Flash-style causal attention. 1 thread == 1 query row (full online softmax
// state in registers, no cross-thread reduction). K/V tiles (32x64) in smem,
// all threads read the same smem address per step -> broadcast, conflict-free.
// Output written in [B,S,H,HD] layout == [T,D] rows for the out-proj GEMM.
// ---------------------------------------------------------------------------
__global__ void __launch_bounds__(128) attn_k(const float* __restrict__ Q,
                                              const float* __restrict__ Kt,
                                              const float* __restrict__ Vt,
                                              float* __restrict__ Out) {
    int qt = blockIdx.x * 128;
    int h = blockIdx.y, b = blockIdx.z;
    int tid = threadIdx.x;
    int myq = qt + tid;
    const size_t base = ((size_t)(b * Hn + h)) * Sq * HDm;

    float4 q4[16];
    {
        const float4* qrow = (const float4*)(Q + base + (size_t)myq * HDm);
#pragma unroll
        for (int i = 0; i < 16; i++) q4[i] = qrow[i];
    }
    float4 a4[16];
#pragma unroll
    for (int i = 0; i < 16; i++) a4[i] = make_float4(0.f, 0.f, 0.f, 0.f);
    float m = -1e30f, l = 0.f;

    __shared__ float Ks[32][64];
    __shared__ float Vs[32][64];

    int kend = qt + 128;
    for (int kt = 0; kt < kend; kt += 32) {
        __syncthreads();
#pragma unroll
        for (int r = 0; r < 4; r++) {
            int fi = tid + r * 128;          // 0..511
            int row = fi >> 4, c4 = fi & 15;
            ((float4*)&Ks[row][0])[c4] = ((const float4*)(Kt + base + (size_t)(kt + row) * HDm))[c4];
            ((float4*)&Vs[row][0])[c4] = ((const float4*)(Vt + base + (size_t)(kt + row) * HDm))[c4];
        }
        __syncthreads();

        float sreg[32];
        float mt = m;
        int lim = myq - kt;                  // keys j valid iff j <= lim
#pragma unroll
        for (int j = 0; j < 32; j++) {
            float s0 = 0.f, s1 = 0.f, s2 = 0.f, s3 = 0.f;
#pragma unroll
            for (int d4 = 0; d4 < 16; d4++) {
                float4 kk = ((const float4*)&Ks[j][0])[d4];
                s0 = fmaf(q4[d4].x, kk.x, s0);
                s1 = fmaf(q4[d4].y, kk.y, s1);
                s2 = fmaf(q4[d4].z, kk.z, s2);
                s3 = fmaf(q4[d4].w, kk.w, s3);
            }
            float sj = ((s0 + s1) + (s2 + s3)) * 0.125f;
            sreg[j] = sj;
            mt = (j <= lim) ? fmaxf(mt, sj) : mt;
        }
        if (mt > m) {
            float corr = __expf(m - mt);
            l *= corr;
#pragma unroll
            for (int i = 0; i < 16; i++) {
                a4[i].x *= corr; a4[i].y *= corr; a4[i].z *= corr; a4[i].w *= corr;
            }
            m = mt;
        }
#pragma unroll
        for (int j = 0; j < 32; j++) {
            if (j <= lim) {
                float p = __expf(sreg[j] - m);
                l += p;
#pragma unroll
                for (int d4 = 0; d4 < 16; d4++) {
                    float4 vv = ((const float4*)&Vs[j][0])[d4];
                    a4[d4].x = fmaf(p, vv.x, a4[d4].x);
                    a4[d4].y = fmaf(p, vv.y, a4[d4].y);
                    a4[d4].z = fmaf(p, vv.z, a4[d4].z);
                    a4[d4].w = fmaf(p, vv.w, a4[d4].w);
                }
            }
        }
    }
    float inv = 1.f / l;
    float* orow = Out + ((size_t)(b * Sq + myq)) * Dm + h * HDm;
#pragma unroll
    for (int i = 0; i < 16; i++) {
        float4 o;
        o.x = a4[i].x * inv; o.y = a4[i].y * inv;
        o.z = a4[i].z * inv; o.w = a4[i].w * inv;
        ((float4*)orow)[i] = o;
    }
}

// ---------------------------------------------------------------------------
// Generic tiled SGEMM: 128x128 block tile, BK=16, 256 threads, 8x8 per thread.
// MODE 0: C = A@B        MODE 1: C = A@B + resid
// MODE 2: C = relu(A@B)  MODE 3: C = (A@B) * gates[row]
// GATHER: A row r comes from A[tok[r]] (tok<0 -> zero row).
// blockIdx.z selects expert via the sA/sB/sC/sTok/sG strides.
// ---------------------------------------------------------------------------
template <int MODE, bool GATHER>
__global__ void __launch_bounds__(256) sgemm_k(const float* __restrict__ A,
                                               const float* __restrict__ Bm,
                                               float* __restrict__ C,
                                               int M, int N, int K,
                                               const float* __restrict__ resid,
                                               const int* __restrict__ tok,
                                               const float* __restrict__ gates,
                                               long sA, long sB, long sC,
                                               int sTok, int sG) {
    int e = blockIdx.z;
    A  += (size_t)e * sA;
    Bm += (size_t)e * sB;
    C  += (size_t)e * sC;
    if (GATHER) tok += e * sTok;
    if (MODE == 3) gates += e * sG;

    __shared__ float As[16][128];
    __shared__ float Bs[16][128];

    int tid = threadIdx.x;
    int m0 = blockIdx.y * 128, n0 = blockIdx.x * 128;

    int a_row = tid >> 1;
    int a_k   = (tid & 1) * 8;
    const float* Ap = nullptr;
    if (GATHER) {
        int t = tok[m0 + a_row];
        if (t >= 0) Ap = A + (size_t)t * K + a_k;
    } else {
        Ap = A + (size_t)(m0 + a_row) * K + a_k;
    }
    int b_r = tid >> 5;
    int b_c = (tid & 31) * 4;
    const float* Bp = Bm + (size_t)b_r * N + n0 + b_c;

    float acc[8][8];
#pragma unroll
    for (int i = 0; i < 8; i++)
#pragma unroll
        for (int j = 0; j < 8; j++) acc[i][j] = 0.f;

    int ty = tid >> 4, tx = tid & 15;

    for (int k0 = 0; k0 < K; k0 += 16) {
        float4 av0, av1;
        if (Ap) {
            av0 = *(const float4*)(Ap + k0);
            av1 = *(const float4*)(Ap + k0 + 4);
        } else {
            av0 = make_float4(0.f, 0.f, 0.f, 0.f);
            av1 = av0;
        }
        float4 bv0 = *(const float4*)(Bp + (size_t)k0 * N);
        float4 bv1 = *(const float4*)(Bp + (size_t)(k0 + 8) * N);
        __syncthreads();
        As[a_k + 0][a_row] = av0.x; As[a_k + 1][a_row] = av0.y;
        As[a_k + 2][a_row] = av0.z; As[a_k + 3][a_row] = av0.w;
        As[a_k + 4][a_row] = av1.x; As[a_k + 5][a_row] = av1.y;
        As[a_k + 6][a_row] = av1.z; As[a_k + 7][a_row] = av1.w;
        *(float4*)&Bs[b_r][b_c]     = bv0;
        *(float4*)&Bs[b_r + 8][b_c] = bv1;
        __syncthreads();
#pragma unroll
        for (int kk = 0; kk < 16; kk++) {
            float a[8], bb[8];
            *(float4*)&a[0]  = *(const float4*)&As[kk][ty * 8];
            *(float4*)&a[4]  = *(const float4*)&As[kk][ty * 8 + 4];
            *(float4*)&bb[0] = *(const float4*)&Bs[kk][tx * 8];
            *(float4*)&bb[4] = *(const float4*)&Bs[kk][tx * 8 + 4];
#pragma unroll
            for (int i = 0; i < 8; i++)
#pragma unroll
                for (int j = 0; j < 8; j++)
                    acc[i][j] = fmaf(a[i], bb[j], acc[i][j]);
        }
    }

#pragma unroll
    for (int i = 0; i < 8; i++) {
        int gm = m0 + ty * 8 + i;
        float gate = 1.f;
        if (MODE == 3) gate = gates[gm];
#pragma unroll
        for (int j4 = 0; j4 < 2; j4++) {
            float4 v;
            v.x = acc[i][j4 * 4 + 0]; v.y = acc[i][j4 * 4 + 1];
            v.z = acc[i][j4 * 4 + 2]; v.w = acc[i][j4 * 4 + 3];
            size_t off = (size_t)gm * N + n0 + tx * 8 + j4 * 4;
            if (MODE == 1) {
                float4 rr = *(const float4*)(resid + off);
                v.x += rr.x; v.y += rr.y; v.z += rr.z; v.w += rr.w;
            }
            if (MODE == 2) {
                v.x = fmaxf(v.x, 0.f); v.y = fmaxf(v.y, 0.f);
                v.z = fmaxf(v.z, 0.f); v.w = fmaxf(v.w, 0.f);
            }
            if (MODE == 3) {
                v.x *= gate; v.y *= gate; v.z *= gate; v.w *= gate;
            }
            *(float4*)(C + off) = v;
        }
    }
}

// ---------------------------------------------------------------------------
// Router: 1 warp per token. 8 logits -> softmax -> top-2 (ties: lower index,
// matching jax.lax.top_k).
// ---------------------------------------------------------------------------
__global__ void __launch_bounds__(256) router_k(const float* __restrict__ xn,
                                                const float* __restrict__ wr,
                                                float* __restrict__ fg,
                                                int* __restrict__ fe) {
    int warp = threadIdx.x >> 5, lane = threadIdx.x & 31;
    int t = blockIdx.x * 8 + warp;
    float acc[8];
#pragma unroll
    for (int e2 = 0; e2 < 8; e2++) acc[e2] = 0.f;
    const float* xr = xn + (size_t)t * Dm;
    for (int d = lane; d < Dm; d += 32) {
        float xv = xr[d];
        const float4* w = (const float4*)(wr + d * En);
        float4 w0 = w[0], w1 = w[1];
        acc[0] = fmaf(xv, w0.x, acc[0]); acc[1] = fmaf(xv, w0.y, acc[1]);
        acc[2] = fmaf(xv, w0.z, acc[2]); acc[3] = fmaf(xv, w0.w, acc[3]);
        acc[4] = fmaf(xv, w1.x, acc[4]); acc[5] = fmaf(xv, w1.y, acc[5]);
        acc[6] = fmaf(xv, w1.z, acc[6]); acc[7] = fmaf(xv, w1.w, acc[7]);
    }
#pragma unroll
    for (int e2 = 0; e2 < 8; e2++)
#pragma unroll
        for (int off = 16; off; off >>= 1)
            acc[e2] += __shfl_down_sync(0xffffffffu, acc[e2], off);
    if (lane == 0) {
        float mx = acc[0];
#pragma unroll
        for (int e2 = 1; e2 < 8; e2++) mx = fmaxf(mx, acc[e2]);
        float p[8], sum = 0.f;
#pragma unroll
        for (int e2 = 0; e2 < 8; e2++) { p[e2] = expf(acc[e2] - mx); sum += p[e2]; }
        float inv = 1.f / sum;
#pragma unroll
        for (int e2 = 0; e2 < 8; e2++) p[e2] *= inv;
        int e0 = 0; float p0 = p[0];
#pragma unroll
        for (int e2 = 1; e2 < 8; e2++) if (p[e2] > p0) { p0 = p[e2]; e0 = e2; }
        int e1 = -1; float p1 = -1.f;
#pragma unroll
        for (int e2 = 0; e2 < 8; e2++)
            if (e2 != e0 && p[e2] > p1) { p1 = p[e2]; e1 = e2; }
        fg[2 * t]     = p0; fe[2 * t]     = e0;
        fg[2 * t + 1] = p1; fe[2 * t + 1] = e1;
    }
}

__global__ void init_etok_k(int* __restrict__ etok) {
    int i = blockIdx.x * blockDim.x + threadIdx.x;
    if (i < En * CAPn) etok[i] = -1;
}

// ---------------------------------------------------------------------------
// Exact capacity routing: rank of each assignment within its expert
// (value desc, tie -> lower flat index) == its capacity slot. Matches
// jax.lax.top_k(masked, CAP) exactly, deterministic, no atomics.
// ---------------------------------------------------------------------------
__global__ void __launch_bounds__(256) rank_k(const float* __restrict__ fg,
                                              const int* __restrict__ fe,
                                              int* __restrict__ slot,
                                              int* __restrict__ etok,
                                              float* __restrict__ egate) {
    __shared__ float sg[NA];
    __shared__ unsigned char se[NA];
    for (int i = threadIdx.x; i < NA; i += 256) {
        sg[i] = fg[i];
        se[i] = (unsigned char)fe[i];
    }
    __syncthreads();
    int i = blockIdx.x * 256 + threadIdx.x;
    float gi = sg[i];
    unsigned char ei = se[i];
    int r = 0;
    for (int j = 0; j < NA; j++) {
        bool c = (se[j] == ei) && ((sg[j] > gi) || (sg[j] == gi && j < i));
        r += (int)c;
    }
    if (r < CAPn) {
        slot[i] = r;
        etok[(int)ei * CAPn + r] = i >> 1;
        egate[(int)ei * CAPn + r] = gi;
    } else {
        slot[i] = -1;
    }
}

// ---------------------------------------------------------------------------
// Final combine: out = x1 + sum over the token's kept assignments of its
// (already gate-scaled) expert output row. No atomics -> deterministic.
// ---------------------------------------------------------------------------
__global__ void __launch_bounds__(256) combine_k(const float* __restrict__ x1,
                                                 const float* __restrict__ ye,
                                                 const int* __restrict__ fe,
                                                 const int* __restrict__ slot,
                                                 float* __restrict__ out) {
    int t = blockIdx.x;
    int d = threadIdx.x;  // float4 index, 256 * 4 = 1024
    float4 v = ((const float4*)(x1 + (size_t)t * Dm))[d];
#pragma unroll
    for (int kk = 0; kk < 2; kk++) {
        int i = 2 * t + kk;
        int sl = slot[i];
        if (sl >= 0) {
            int e = fe[i];
            float4 w = ((const float4*)(ye + ((size_t)e * CAPn + sl) * Dm))[d];
            v.x += w.x; v.y += w.y; v.z += w.z; v.w += w.w;
        }
    }
    ((float4*)(out + (size_t)t * Dm))[d] = v;
}

// ---------------------------------------------------------------------------
// Launch
// ---------------------------------------------------------------------------
extern "C" void kernel_launch(void* const* d_in, const int* in_sizes, int n_in,
                              void* d_out, int out_size) {
    (void)in_sizes; (void)n_in; (void)out_size;
    const float* x        = (const float*)d_in[0];
    const float* g1       = (const float*)d_in[1];
    const float* w_qkv    = (const float*)d_in[2];
    const float* w_o      = (const float*)d_in[3];
    const float* g2       = (const float*)d_in[4];
    const float* w_router = (const float*)d_in[5];
    const float* w1       = (const float*)d_in[6];
    const float* w2       = (const float*)d_in[7];
    float* out = (float*)d_out;

    float *p_xn, *p_qkv, *p_q, *p_k, *p_v, *p_attn, *p_x1, *p_cos, *p_sin;
    float *p_fg, *p_egate, *p_h, *p_ye;
    int *p_fe, *p_slot, *p_etok;
    cudaGetSymbolAddress((void**)&p_xn,   g_xn);
    cudaGetSymbolAddress((void**)&p_qkv,  g_qkv);
    cudaGetSymbolAddress((void**)&p_q,    g_q);
    cudaGetSymbolAddress((void**)&p_k,    g_k);
    cudaGetSymbolAddress((void**)&p_v,    g_v);
    cudaGetSymbolAddress((void**)&p_attn, g_attn);
    cudaGetSymbolAddress((void**)&p_x1,   g_x1);
    cudaGetSymbolAddress((void**)&p_cos,  g_cos);
    cudaGetSymbolAddress((void**)&p_sin,  g_sin);
    cudaGetSymbolAddress((void**)&p_fg,   g_fg);
    cudaGetSymbolAddress((void**)&p_fe,   g_fe);
    cudaGetSymbolAddress((void**)&p_slot, g_slot);
    cudaGetSymbolAddress((void**)&p_etok, g_etok);
    cudaGetSymbolAddress((void**)&p_egate,g_egate);
    cudaGetSymbolAddress((void**)&p_h,    g_h);
    cudaGetSymbolAddress((void**)&p_ye,   g_ye);

    // cos/sin table (independent; overlaps nothing it shouldn't)
    rope_table_k<<<(Sq * 32 + 255) / 256, 256>>>(p_cos, p_sin);

    // xn1 = rmsnorm(x, g1)
    rmsnorm_k<<<Tn, 256>>>(x, g1, p_xn);

    // qkv = xn1 @ w_qkv   [4096,1024]@[1024,3072]
    sgemm_k<0, false><<<dim3(3 * Dm / 128, Tn / 128, 1), 256>>>(
        p_xn, w_qkv, p_qkv, Tn, 3 * Dm, Dm, nullptr, nullptr, nullptr, 0, 0, 0, 0, 0);

    // split + rope -> q,k,v in [B,H,S,HD]
    split_rope_k<<<Tn, 256>>>(p_qkv, p_cos, p_sin, p_q, p_k, p_v);

    // causal attention -> [T, D] (head-major within row)
    attn_k<<<dim3(Sq / 128, Hn, Bz), 128>>>(p_q, p_k, p_v, p_attn);

    // x1 = x + attn @ w_o
    sgemm_k<1, false><<<dim3(Dm / 128, Tn / 128, 1), 256>>>(
        p_attn, w_o, p_x1, Tn, Dm, Dm, x, nullptr, nullptr, 0, 0, 0, 0, 0);

    // xn2 = rmsnorm(x1, g2)
    rmsnorm_k<<<Tn, 256>>>(p_x1, g2, p_xn);

    // routing
    router_k<<<Tn / 8, 256>>>(p_xn, w_router, p_fg, p_fe);
    init_etok_k<<<(En * CAPn + 255) / 256, 256>>>(p_etok);
    rank_k<<<NA / 256, 256>>>(p_fg, p_fe, p_slot, p_etok, p_egate);

    // h[e] = relu(gather(xn2, etok[e]) @ w1[e])   [1280,1024]@[1024,2048] x8
    sgemm_k<2, true><<<dim3(FFNm / 128, CAPn / 128, En), 256>>>(
        p_xn, w1, p_h, CAPn, FFNm, Dm, nullptr, p_etok, nullptr,
        0, (long)Dm * FFNm, (long)CAPn * FFNm, CAPn, 0);

    // ye[e] = (h[e] @ w2[e]) * gate   [1280,2048]@[2048,1024] x8
    sgemm_k<3, false><<<dim3(Dm / 128, CAPn / 128, En), 256>>>(
        p_h, w2, p_ye, CAPn, Dm, FFNm, nullptr, nullptr, p_egate,
        (long)CAPn * FFNm, (long)FFNm * Dm, (long)CAPn * Dm, 0, CAPn);

    // out = x1 + gathered moe contributions
    combine_k<<<Tn, 256>>>(p_x1, p_ye, p_fe, p_slot, out);
}

// round 4
// speedup vs baseline: 1.9305x; 1.1876x over previous
#include <cuda_runtime.h>
#include <math.h>
#include <stdint.h>

// ---------------------------------------------------------------------------
// Problem constants
// ---------------------------------------------------------------------------
namespace {
constexpr int Bz   = 2;
constexpr int Sq   = 2048;
constexpr int Dm   = 1024;
constexpr int Hn   = 16;
constexpr int HDm  = 64;
constexpr int FFNm = 2048;
constexpr int En   = 8;
constexpr int Tn   = Bz * Sq;     // 4096 tokens
constexpr int NA   = Tn * 2;      // 8192 flat assignments (top-2)
constexpr int CAPn = 1280;        // ceil(2*2048*2*1.25/8)
}

// ---------------------------------------------------------------------------
// Static scratch (no allocations allowed)
// ---------------------------------------------------------------------------
__device__ float g_xn  [Tn * Dm];
__device__ float g_qkv [Tn * 3 * Dm];
__device__ float g_q   [Tn * Dm];
__device__ float g_k   [Tn * Dm];
__device__ float g_v   [Tn * Dm];
__device__ float g_attn[Tn * Dm];
__device__ float g_x1  [Tn * Dm];
__device__ float g_cos [Sq * (HDm / 2)];
__device__ float g_sin [Sq * (HDm / 2)];
__device__ float g_fg  [NA];
__device__ int   g_fe  [NA];
__device__ int   g_slot[NA];
__device__ int   g_etok [En * CAPn];
__device__ float g_egate[En * CAPn];
__device__ float g_xe[En * CAPn * Dm];    // gathered tokens, tf32-rounded
__device__ float g_h [En * CAPn * FFNm];  // relu output, tf32-rounded
__device__ float g_ye[En * CAPn * Dm];

// ---------------------------------------------------------------------------
// Helpers
// ---------------------------------------------------------------------------
__device__ __forceinline__ float rnd_tf32(float x) {
    uint32_t u = __float_as_uint(x);
    u = (u + 0x1000u) & 0xFFFFE000u;   // round-to-nearest to tf32 (10-bit mantissa)
    return __uint_as_float(u);
}

// m16n8k8 tf32 MMA (Ampere-era PTX, compiles for plain sm_103 target)
__device__ __forceinline__ void mma_tf32(float* d, const uint32_t* a, const uint32_t* b) {
    asm volatile(
        "mma.sync.aligned.m16n8k8.row.col.f32.tf32.tf32.f32 "
        "{%0,%1,%2,%3}, {%4,%5,%6,%7}, {%8,%9}, {%0,%1,%2,%3};"
        : "+f"(d[0]), "+f"(d[1]), "+f"(d[2]), "+f"(d[3])
        : "r"(a[0]), "r"(a[1]), "r"(a[2]), "r"(a[3]), "r"(b[0]), "r"(b[1]));
}

// ---------------------------------------------------------------------------
// RMSNorm
// ---------------------------------------------------------------------------
__global__ void __launch_bounds__(256) rmsnorm_k(const float* __restrict__ x,
                                                 const float* __restrict__ g,
                                                 float* __restrict__ y) {
    int row = blockIdx.x;
    int i = threadIdx.x;
    const float4* xr = (const float4*)(x + (size_t)row * Dm);
    float4 xv = xr[i];
    float ss = xv.x * xv.x + xv.y * xv.y + xv.z * xv.z + xv.w * xv.w;
#pragma unroll
    for (int off = 16; off; off >>= 1) ss += __shfl_down_sync(0xffffffffu, ss, off);
    __shared__ float red[8];
    __shared__ float srms;
    if ((i & 31) == 0) red[i >> 5] = ss;
    __syncthreads();
    if (i == 0) {
        float t = 0.f;
#pragma unroll
        for (int w = 0; w < 8; w++) t += red[w];
        srms = rsqrtf(t * (1.0f / Dm) + 1e-6f);
    }
    __syncthreads();
    float r = srms;
    float4 gv = ((const float4*)g)[i];
    float4 o;
    o.x = gv.x * xv.x * r; o.y = gv.y * xv.y * r;
    o.z = gv.z * xv.z * r; o.w = gv.w * xv.w * r;
    ((float4*)(y + (size_t)row * Dm))[i] = o;
}

// ---------------------------------------------------------------------------
// RoPE table
// ---------------------------------------------------------------------------
__global__ void rope_table_k(float* __restrict__ ct, float* __restrict__ st) {
    int idx = blockIdx.x * blockDim.x + threadIdx.x;
    if (idx >= Sq * (HDm / 2)) return;
    int s = idx >> 5, j = idx & 31;
    float th = (float)pow(10000.0, -2.0 * (double)j / (double)HDm);
    double f = (double)s * (double)th;
    ct[idx] = (float)cos(f);
    st[idx] = (float)sin(f);
}

// ---------------------------------------------------------------------------
// Split QKV + RoPE
// ---------------------------------------------------------------------------
__global__ void __launch_bounds__(256) split_rope_k(const float* __restrict__ qkv,
                                                    const float* __restrict__ ct,
                                                    const float* __restrict__ st,
                                                    float* __restrict__ q,
                                                    float* __restrict__ k,
                                                    float* __restrict__ v) {
    int t = blockIdx.x;
    int b = t / Sq, s = t % Sq;
    const float* row = qkv + (size_t)t * (3 * Dm);
    for (int idx = threadIdx.x; idx < Hn * (HDm / 2); idx += blockDim.x) {
        int h = idx >> 5, j = idx & 31;
        float c = ct[s * 32 + j], sn = st[s * 32 + j];
        size_t o = ((size_t)(b * Hn + h) * Sq + s) * HDm;
        float qr = row[h * HDm + 2 * j], qi = row[h * HDm + 2 * j + 1];
        q[o + 2 * j]     = qr * c - qi * sn;
        q[o + 2 * j + 1] = qr * sn + qi * c;
        float kr = row[Dm + h * HDm + 2 * j], ki = row[Dm + h * HDm + 2 * j + 1];
        k[o + 2 * j]     = kr * c - ki * sn;
        k[o + 2 * j + 1] = kr * sn + ki * c;
    }
    for (int idx = threadIdx.x; idx < Dm; idx += blockDim.x) {
        int h = idx >> 6, d = idx & 63;
        v[((size_t)(b * Hn + h) * Sq + s) * HDm + d] = row[2 * Dm + idx];
    }
}

// ---------------------------------------------------------------------------
// Flash-style causal attention (fp32, exact path — protects routing)
// ---------------------------------------------------------------------------
__global__ void __launch_bounds__(128) attn_k(const float* __restrict__ Q,
                                              const float* __restrict__ Kt,
                                              const float* __restrict__ Vt,
                                              float* __restrict__ Out) {
    int qt = blockIdx.x * 128;
    int h = blockIdx.y, b = blockIdx.z;
    int tid = threadIdx.x;
    int myq = qt + tid;
    const size_t base = ((size_t)(b * Hn + h)) * Sq * HDm;

    float4 q4[16];
    {
        const float4* qrow = (const float4*)(Q + base + (size_t)myq * HDm);
#pragma unroll
        for (int i = 0; i < 16; i++) q4[i] = qrow[i];
    }
    float4 a4[16];
#pragma unroll
    for (int i = 0; i < 16; i++) a4[i] = make_float4(0.f, 0.f, 0.f, 0.f);
    float m = -1e30f, l = 0.f;

    __shared__ float Ks[32][64];
    __shared__ float Vs[32][64];

    int kend = qt + 128;
    for (int kt = 0; kt < kend; kt += 32) {
        __syncthreads();
#pragma unroll
        for (int r = 0; r < 4; r++) {
            int fi = tid + r * 128;
            int row = fi >> 4, c4 = fi & 15;
            ((float4*)&Ks[row][0])[c4] = ((const float4*)(Kt + base + (size_t)(kt + row) * HDm))[c4];
            ((float4*)&Vs[row][0])[c4] = ((const float4*)(Vt + base + (size_t)(kt + row) * HDm))[c4];
        }
        __syncthreads();

        float sreg[32];
        float mt = m;
        int lim = myq - kt;
#pragma unroll
        for (int j = 0; j < 32; j++) {
            float s0 = 0.f, s1 = 0.f, s2 = 0.f, s3 = 0.f;
#pragma unroll
            for (int d4 = 0; d4 < 16; d4++) {
                float4 kk = ((const float4*)&Ks[j][0])[d4];
                s0 = fmaf(q4[d4].x, kk.x, s0);
                s1 = fmaf(q4[d4].y, kk.y, s1);
                s2 = fmaf(q4[d4].z, kk.z, s2);
                s3 = fmaf(q4[d4].w, kk.w, s3);
            }
            float sj = ((s0 + s1) + (s2 + s3)) * 0.125f;
            sreg[j] = sj;
            mt = (j <= lim) ? fmaxf(mt, sj) : mt;
        }
        if (mt > m) {
            float corr = __expf(m - mt);
            l *= corr;
#pragma unroll
            for (int i = 0; i < 16; i++) {
                a4[i].x *= corr; a4[i].y *= corr; a4[i].z *= corr; a4[i].w *= corr;
            }
            m = mt;
        }
#pragma unroll
        for (int j = 0; j < 32; j++) {
            if (j <= lim) {
                float p = __expf(sreg[j] - m);
                l += p;
#pragma unroll
                for (int d4 = 0; d4 < 16; d4++) {
                    float4 vv = ((const float4*)&Vs[j][0])[d4];
                    a4[d4].x = fmaf(p, vv.x, a4[d4].x);
                    a4[d4].y = fmaf(p, vv.y, a4[d4].y);
                    a4[d4].z = fmaf(p, vv.z, a4[d4].z);
                    a4[d4].w = fmaf(p, vv.w, a4[d4].w);
                }
            }
        }
    }
    float inv = 1.f / l;
    float* orow = Out + ((size_t)(b * Sq + myq)) * Dm + h * HDm;
#pragma unroll
    for (int i = 0; i < 16; i++) {
        float4 o;
        o.x = a4[i].x * inv; o.y = a4[i].y * inv;
        o.z = a4[i].z * inv; o.w = a4[i].w * inv;
        ((float4*)orow)[i] = o;
    }
}

// ---------------------------------------------------------------------------
// fp32 SGEMM (qkv + o projections; MODE 0 plain, 1 +resid)
// ---------------------------------------------------------------------------
template <int MODE>
__global__ void __launch_bounds__(256) sgemm_k(const float* __restrict__ A,
                                               const float* __restrict__ Bm,
                                               float* __restrict__ C,
                                               int M, int N, int K,
                                               const float* __restrict__ resid) {
    __shared__ float As[16][128];
    __shared__ float Bs[16][128];

    int tid = threadIdx.x;
    int m0 = blockIdx.y * 128, n0 = blockIdx.x * 128;

    int a_row = tid >> 1;
    int a_k   = (tid & 1) * 8;
    const float* Ap = A + (size_t)(m0 + a_row) * K + a_k;
    int b_r = tid >> 5;
    int b_c = (tid & 31) * 4;
    const float* Bp = Bm + (size_t)b_r * N + n0 + b_c;

    float acc[8][8];
#pragma unroll
    for (int i = 0; i < 8; i++)
#pragma unroll
        for (int j = 0; j < 8; j++) acc[i][j] = 0.f;

    int ty = tid >> 4, tx = tid & 15;

    for (int k0 = 0; k0 < K; k0 += 16) {
        float4 av0 = *(const float4*)(Ap + k0);
        float4 av1 = *(const float4*)(Ap + k0 + 4);
        float4 bv0 = *(const float4*)(Bp + (size_t)k0 * N);
        float4 bv1 = *(const float4*)(Bp + (size_t)(k0 + 8) * N);
        __syncthreads();
        As[a_k + 0][a_row] = av0.x; As[a_k + 1][a_row] = av0.y;
        As[a_k + 2][a_row] = av0.z; As[a_k + 3][a_row] = av0.w;
        As[a_k + 4][a_row] = av1.x; As[a_k + 5][a_row] = av1.y;
        As[a_k + 6][a_row] = av1.z; As[a_k + 7][a_row] = av1.w;
        *(float4*)&Bs[b_r][b_c]     = bv0;
        *(float4*)&Bs[b_r + 8][b_c] = bv1;
        __syncthreads();
#pragma unroll
        for (int kk = 0; kk < 16; kk++) {
            float a[8], bb[8];
            *(float4*)&a[0]  = *(const float4*)&As[kk][ty * 8];
            *(float4*)&a[4]  = *(const float4*)&As[kk][ty * 8 + 4];
            *(float4*)&bb[0] = *(const float4*)&Bs[kk][tx * 8];
            *(float4*)&bb[4] = *(const float4*)&Bs[kk][tx * 8 + 4];
#pragma unroll
            for (int i = 0; i < 8; i++)
#pragma unroll
                for (int j = 0; j < 8; j++)
                    acc[i][j] = fmaf(a[i], bb[j], acc[i][j]);
        }
    }

#pragma unroll
    for (int i = 0; i < 8; i++) {
        int gm = m0 + ty * 8 + i;
#pragma unroll
        for (int j4 = 0; j4 < 2; j4++) {
            float4 v;
            v.x = acc[i][j4 * 4 + 0]; v.y = acc[i][j4 * 4 + 1];
            v.z = acc[i][j4 * 4 + 2]; v.w = acc[i][j4 * 4 + 3];
            size_t off = (size_t)gm * N + n0 + tx * 8 + j4 * 4;
            if (MODE == 1) {
                float4 rr = *(const float4*)(resid + off);
                v.x += rr.x; v.y += rr.y; v.z += rr.z; v.w += rr.w;
            }
            *(float4*)(C + off) = v;
        }
    }
}

// ---------------------------------------------------------------------------
// Router (fp32, exact)
// ---------------------------------------------------------------------------
__global__ void __launch_bounds__(256) router_k(const float* __restrict__ xn,
                                                const float* __restrict__ wr,
                                                float* __restrict__ fg,
                                                int* __restrict__ fe) {
    int warp = threadIdx.x >> 5, lane = threadIdx.x & 31;
    int t = blockIdx.x * 8 + warp;
    float acc[8];
#pragma unroll
    for (int e2 = 0; e2 < 8; e2++) acc[e2] = 0.f;
    const float* xr = xn + (size_t)t * Dm;
    for (int d = lane; d < Dm; d += 32) {
        float xv = xr[d];
        const float4* w = (const float4*)(wr + d * En);
        float4 w0 = w[0], w1 = w[1];
        acc[0] = fmaf(xv, w0.x, acc[0]); acc[1] = fmaf(xv, w0.y, acc[1]);
        acc[2] = fmaf(xv, w0.z, acc[2]); acc[3] = fmaf(xv, w0.w, acc[3]);
        acc[4] = fmaf(xv, w1.x, acc[4]); acc[5] = fmaf(xv, w1.y, acc[5]);
        acc[6] = fmaf(xv, w1.z, acc[6]); acc[7] = fmaf(xv, w1.w, acc[7]);
    }
#pragma unroll
    for (int e2 = 0; e2 < 8; e2++)
#pragma unroll
        for (int off = 16; off; off >>= 1)
            acc[e2] += __shfl_down_sync(0xffffffffu, acc[e2], off);
    if (lane == 0) {
        float mx = acc[0];
#pragma unroll
        for (int e2 = 1; e2 < 8; e2++) mx = fmaxf(mx, acc[e2]);
        float p[8], sum = 0.f;
#pragma unroll
        for (int e2 = 0; e2 < 8; e2++) { p[e2] = expf(acc[e2] - mx); sum += p[e2]; }
        float inv = 1.f / sum;
#pragma unroll
        for (int e2 = 0; e2 < 8; e2++) p[e2] *= inv;
        int e0 = 0; float p0 = p[0];
#pragma unroll
        for (int e2 = 1; e2 < 8; e2++) if (p[e2] > p0) { p0 = p[e2]; e0 = e2; }
        int e1 = -1; float p1 = -1.f;
#pragma unroll
        for (int e2 = 0; e2 < 8; e2++)
            if (e2 != e0 && p[e2] > p1) { p1 = p[e2]; e1 = e2; }
        fg[2 * t]     = p0; fe[2 * t]     = e0;
        fg[2 * t + 1] = p1; fe[2 * t + 1] = e1;
    }
}

__global__ void init_etok_k(int* __restrict__ etok) {
    int i = blockIdx.x * blockDim.x + threadIdx.x;
    if (i < En * CAPn) etok[i] = -1;
}

__global__ void __launch_bounds__(256) rank_k(const float* __restrict__ fg,
                                              const int* __restrict__ fe,
                                              int* __restrict__ slot,
                                              int* __restrict__ etok,
                                              float* __restrict__ egate) {
    __shared__ float sg[NA];
    __shared__ unsigned char se[NA];
    for (int i = threadIdx.x; i < NA; i += 256) {
        sg[i] = fg[i];
        se[i] = (unsigned char)fe[i];
    }
    __syncthreads();
    int i = blockIdx.x * 256 + threadIdx.x;
    float gi = sg[i];
    unsigned char ei = se[i];
    int r = 0;
    for (int j = 0; j < NA; j++) {
        bool c = (se[j] == ei) && ((sg[j] > gi) || (sg[j] == gi && j < i));
        r += (int)c;
    }
    if (r < CAPn) {
        slot[i] = r;
        etok[(int)ei * CAPn + r] = i >> 1;
        egate[(int)ei * CAPn + r] = gi;
    } else {
        slot[i] = -1;
    }
}

// ---------------------------------------------------------------------------
// Gather expert inputs (plain row-major, tf32-rounded; tok<0 -> zeros)
// ---------------------------------------------------------------------------
__global__ void __launch_bounds__(256) xepack_k(const float* __restrict__ xn,
                                                const int* __restrict__ etok,
                                                float* __restrict__ xe) {
    int row = blockIdx.x;                 // e*CAPn + r
    int tok = etok[row];
    int i = threadIdx.x;
    float4 v = make_float4(0.f, 0.f, 0.f, 0.f);
    if (tok >= 0) v = ((const float4*)(xn + (size_t)tok * Dm))[i];
    v.x = rnd_tf32(v.x); v.y = rnd_tf32(v.y); v.z = rnd_tf32(v.z); v.w = rnd_tf32(v.w);
    ((float4*)(xe + (size_t)row * Dm))[i] = v;
}

// ---------------------------------------------------------------------------
// tf32 tensor-core GEMM via mma.sync.m16n8k8 (arch-portable HMMA path).
// CTA tile 128x128, BK=32, 8 warps in 4x2 (warp tile 32x64), reg prefetch.
// MODE 2: C = tf32_round(relu(A@B))   (feeds GEMM-2 as A)
// MODE 3: C = (A@B) * gates[row]
// blockIdx.z = expert; A/B/C/gates offset by per-expert strides.
// Inputs in global are already tf32-rounded (xe, h); B (weights) are rounded
// at smem-store time.
// ---------------------------------------------------------------------------
template <int MODE, bool ROUND_B>
__global__ void __launch_bounds__(256, 1) gemm_mma(const float* __restrict__ A,
                                                   const float* __restrict__ Bm,
                                                   float* __restrict__ C,
                                                   int N, int K,
                                                   const float* __restrict__ gates,
                                                   long sA, long sB, long sC) {
    // A-frag LDS conflict-free: stride 36 -> bank = (4*g + t) is a bijection.
    __shared__ float As[128][36];
    __shared__ float Bs[32][132];

    int e = blockIdx.z;
    A  += (size_t)e * sA;
    Bm += (size_t)e * sB;
    C  += (size_t)e * sC;
    if (MODE == 3) gates += (size_t)e * CAPn;

    int tid = threadIdx.x;
    int warp = tid >> 5, lane = tid & 31;
    int gq = lane >> 2, tq = lane & 3;       // groupID, threadID_in_group
    int wm = (warp >> 1) * 32, wn = (warp & 1) * 64;
    int m0 = blockIdx.y * 128, n0 = blockIdx.x * 128;

    int ar = tid >> 1, ac = (tid & 1) * 16;  // A fill: row, col base
    int br = tid >> 3, bc = (tid & 7) * 16;  // B fill: k-row, n-col base
    const float* Ap = A + (size_t)(m0 + ar) * K + ac;
    const float* Bp = Bm + (size_t)br * N + n0 + bc;

    float d[2][8][4];
#pragma unroll
    for (int i = 0; i < 2; i++)
#pragma unroll
        for (int j = 0; j < 8; j++)
#pragma unroll
            for (int c = 0; c < 4; c++) d[i][j][c] = 0.f;

    for (int k0 = 0; k0 < K; k0 += 32) {
        float4 av[4], bv[4];
#pragma unroll
        for (int i = 0; i < 4; i++) av[i] = *(const float4*)(Ap + k0 + i * 4);
#pragma unroll
        for (int i = 0; i < 4; i++) bv[i] = *(const float4*)(Bp + (size_t)k0 * N + i * 4);
        __syncthreads();
#pragma unroll
        for (int i = 0; i < 4; i++) {
            *(float4*)&As[ar][ac + i * 4] = av[i];
            if (ROUND_B) {
                bv[i].x = rnd_tf32(bv[i].x); bv[i].y = rnd_tf32(bv[i].y);
                bv[i].z = rnd_tf32(bv[i].z); bv[i].w = rnd_tf32(bv[i].w);
            }
            *(float4*)&Bs[br][bc + i * 4] = bv[i];
        }
        __syncthreads();
#pragma unroll
        for (int kk = 0; kk < 4; kk++) {
            uint32_t a[2][4], b[8][2];
#pragma unroll
            for (int mt = 0; mt < 2; mt++) {
                int row = wm + mt * 16 + gq;
                int col = kk * 8 + tq;
                a[mt][0] = __float_as_uint(As[row][col]);
                a[mt][1] = __float_as_uint(As[row + 8][col]);
                a[mt][2] = __float_as_uint(As[row][col + 4]);
                a[mt][3] = __float_as_uint(As[row + 8][col + 4]);
            }
#pragma unroll
            for (int nt = 0; nt < 8; nt++) {
                int col = wn + nt * 8 + gq;
                b[nt][0] = __float_as_uint(Bs[kk * 8 + tq][col]);
                b[nt][1] = __float_as_uint(Bs[kk * 8 + tq + 4][col]);
            }
#pragma unroll
            for (int mt = 0; mt < 2; mt++)
#pragma unroll
                for (int nt = 0; nt < 8; nt++)
                    mma_tf32(d[mt][nt], a[mt], b[nt]);
        }
    }

    // Epilogue. D frag (thread gq,tq): c0,c1 at (row gq, cols 2t,2t+1),
    // c2,c3 at (row gq+8).
#pragma unroll
    for (int mt = 0; mt < 2; mt++) {
        int mrow = m0 + wm + mt * 16 + gq;
        float g0 = 1.f, g1 = 1.f;
        if (MODE == 3) { g0 = gates[mrow]; g1 = gates[mrow + 8]; }
#pragma unroll
        for (int nt = 0; nt < 8; nt++) {
            int col = n0 + wn + nt * 8 + 2 * tq;
            float2 v01, v23;
            if (MODE == 2) {
                v01.x = rnd_tf32(fmaxf(d[mt][nt][0], 0.f));
                v01.y = rnd_tf32(fmaxf(d[mt][nt][1], 0.f));
                v23.x = rnd_tf32(fmaxf(d[mt][nt][2], 0.f));
                v23.y = rnd_tf32(fmaxf(d[mt][nt][3], 0.f));
            } else {
                v01.x = d[mt][nt][0] * g0;
                v01.y = d[mt][nt][1] * g0;
                v23.x = d[mt][nt][2] * g1;
                v23.y = d[mt][nt][3] * g1;
            }
            *(float2*)(C + (size_t)mrow * N + col) = v01;
            *(float2*)(C + (size_t)(mrow + 8) * N + col) = v23;
        }
    }
}

// ---------------------------------------------------------------------------
// Final combine
// ---------------------------------------------------------------------------
__global__ void __launch_bounds__(256) combine_k(const float* __restrict__ x1,
                                                 const float* __restrict__ ye,
                                                 const int* __restrict__ fe,
                                                 const int* __restrict__ slot,
                                                 float* __restrict__ out) {
    int t = blockIdx.x;
    int d = threadIdx.x;
    float4 v = ((const float4*)(x1 + (size_t)t * Dm))[d];
#pragma unroll
    for (int kk = 0; kk < 2; kk++) {
        int i = 2 * t + kk;
        int sl = slot[i];
        if (sl >= 0) {
            int e = fe[i];
            float4 w = ((const float4*)(ye + ((size_t)e * CAPn + sl) * Dm))[d];
            v.x += w.x; v.y += w.y; v.z += w.z; v.w += w.w;
        }
    }
    ((float4*)(out + (size_t)t * Dm))[d] = v;
}

// ---------------------------------------------------------------------------
// Launch
// ---------------------------------------------------------------------------
extern "C" void kernel_launch(void* const* d_in, const int* in_sizes, int n_in,
                              void* d_out, int out_size) {
    (void)in_sizes; (void)n_in; (void)out_size;
    const float* x        = (const float*)d_in[0];
    const float* g1       = (const float*)d_in[1];
    const float* w_qkv    = (const float*)d_in[2];
    const float* w_o      = (const float*)d_in[3];
    const float* g2       = (const float*)d_in[4];
    const float* w_router = (const float*)d_in[5];
    const float* w1       = (const float*)d_in[6];
    const float* w2       = (const float*)d_in[7];
    float* out = (float*)d_out;

    float *p_xn, *p_qkv, *p_q, *p_k, *p_v, *p_attn, *p_x1, *p_cos, *p_sin;
    float *p_fg, *p_egate, *p_h, *p_ye, *p_xe;
    int *p_fe, *p_slot, *p_etok;
    cudaGetSymbolAddress((void**)&p_xn,   g_xn);
    cudaGetSymbolAddress((void**)&p_qkv,  g_qkv);
    cudaGetSymbolAddress((void**)&p_q,    g_q);
    cudaGetSymbolAddress((void**)&p_k,    g_k);
    cudaGetSymbolAddress((void**)&p_v,    g_v);
    cudaGetSymbolAddress((void**)&p_attn, g_attn);
    cudaGetSymbolAddress((void**)&p_x1,   g_x1);
    cudaGetSymbolAddress((void**)&p_cos,  g_cos);
    cudaGetSymbolAddress((void**)&p_sin,  g_sin);
    cudaGetSymbolAddress((void**)&p_fg,   g_fg);
    cudaGetSymbolAddress((void**)&p_fe,   g_fe);
    cudaGetSymbolAddress((void**)&p_slot, g_slot);
    cudaGetSymbolAddress((void**)&p_etok, g_etok);
    cudaGetSymbolAddress((void**)&p_egate,g_egate);
    cudaGetSymbolAddress((void**)&p_h,    g_h);
    cudaGetSymbolAddress((void**)&p_ye,   g_ye);
    cudaGetSymbolAddress((void**)&p_xe,   g_xe);

    // Independent precomputation
    rope_table_k<<<(Sq * 32 + 255) / 256, 256>>>(p_cos, p_sin);

    // Attention branch (fp32 exact path — protects routing decisions)
    rmsnorm_k<<<Tn, 256>>>(x, g1, p_xn);
    sgemm_k<0><<<dim3(3 * Dm / 128, Tn / 128, 1), 256>>>(
        p_xn, w_qkv, p_qkv, Tn, 3 * Dm, Dm, nullptr);
    split_rope_k<<<Tn, 256>>>(p_qkv, p_cos, p_sin, p_q, p_k, p_v);
    attn_k<<<dim3(Sq / 128, Hn, Bz), 128>>>(p_q, p_k, p_v, p_attn);
    sgemm_k<1><<<dim3(Dm / 128, Tn / 128, 1), 256>>>(
        p_attn, w_o, p_x1, Tn, Dm, Dm, x);
    rmsnorm_k<<<Tn, 256>>>(p_x1, g2, p_xn);

    // Routing (fp32 exact)
    router_k<<<Tn / 8, 256>>>(p_xn, w_router, p_fg, p_fe);
    init_etok_k<<<(En * CAPn + 255) / 256, 256>>>(p_etok);
    rank_k<<<NA / 256, 256>>>(p_fg, p_fe, p_slot, p_etok, p_egate);
    xepack_k<<<En * CAPn, 256>>>(p_xn, p_etok, p_xe);

    // MoE expert GEMMs on tf32 mma.sync tensor cores
    // h = relu(xe @ w1)  [1280,1024]@[1024,2048] x8
    gemm_mma<2, true><<<dim3(FFNm / 128, CAPn / 128, En), 256>>>(
        p_xe, w1, p_h, FFNm, Dm, nullptr,
        (long)CAPn * Dm, (long)Dm * FFNm, (long)CAPn * FFNm);
    // ye = (h @ w2) * gate  [1280,2048]@[2048,1024] x8
    gemm_mma<3, true><<<dim3(Dm / 128, CAPn / 128, En), 256>>>(
        p_h, w2, p_ye, Dm, FFNm, p_egate,
        (long)CAPn * FFNm, (long)FFNm * Dm, (long)CAPn * Dm);

    // out = x1 + moe
    combine_k<<<Tn, 256>>>(p_x1, p_ye, p_fe, p_slot, out);
}

// round 5
// speedup vs baseline: 2.7543x; 1.4267x over previous
#include <cuda_runtime.h>
#include <math.h>
#include <stdint.h>

// ---------------------------------------------------------------------------
// Problem constants
// ---------------------------------------------------------------------------
namespace {
constexpr int Bz   = 2;
constexpr int Sq   = 2048;
constexpr int Dm   = 1024;
constexpr int Hn   = 16;
constexpr int HDm  = 64;
constexpr int FFNm = 2048;
constexpr int En   = 8;
constexpr int Tn   = Bz * Sq;     // 4096 tokens
constexpr int NA   = Tn * 2;      // 8192 flat assignments (top-2)
constexpr int CAPn = 1280;        // ceil(2*2048*2*1.25/8)
}

// ---------------------------------------------------------------------------
// Static scratch (no allocations allowed)
// ---------------------------------------------------------------------------
__device__ float g_xn  [Tn * Dm];
__device__ float g_qkv [Tn * 3 * Dm];
__device__ float g_q   [Tn * Dm];
__device__ float g_k   [Tn * Dm];
__device__ float g_v   [Tn * Dm];
__device__ float g_attn[Tn * Dm];
__device__ float g_x1  [Tn * Dm];
__device__ float g_cos [Sq * (HDm / 2)];
__device__ float g_sin [Sq * (HDm / 2)];
__device__ float g_fg  [NA];
__device__ int   g_fe  [NA];
__device__ int   g_slot[NA];
__device__ int   g_etok [En * CAPn];
__device__ float g_egate[En * CAPn];
__device__ float g_xe[En * CAPn * Dm];    // gathered tokens, tf32-rounded
__device__ float g_h [En * CAPn * FFNm];  // relu output, tf32-rounded
__device__ float g_ye[En * CAPn * Dm];
// tf32-rounded weight copies
__device__ float g_wqkvr[Dm * 3 * Dm];
__device__ float g_wor  [Dm * Dm];
__device__ float g_w1r  [En * Dm * FFNm];
__device__ float g_w2r  [En * FFNm * Dm];

// ---------------------------------------------------------------------------
// Helpers
// ---------------------------------------------------------------------------
__device__ __forceinline__ float rnd_tf32(float x) {
    uint32_t u = __float_as_uint(x);
    u = (u + 0x1000u) & 0xFFFFE000u;   // RN to tf32 (10-bit mantissa)
    return __uint_as_float(u);
}

__device__ __forceinline__ uint32_t smem_u32(const void* p) {
    uint32_t a;
    asm("{ .reg .u64 t; cvta.to.shared.u64 t, %1; cvt.u32.u64 %0, t; }"
        : "=r"(a) : "l"(p));
    return a;
}

__device__ __forceinline__ void cpasync16(uint32_t dst, const float* src) {
    asm volatile("cp.async.cg.shared.global [%0], [%1], 16;" :: "r"(dst), "l"(src));
}
__device__ __forceinline__ void cp_commit() {
    asm volatile("cp.async.commit_group;" ::: "memory");
}
template <int N>
__device__ __forceinline__ void cp_wait() {
    asm volatile("cp.async.wait_group %0;" :: "n"(N) : "memory");
}

// m16n8k8 tf32 MMA (arch-portable; compiles for plain sm_103 target)
__device__ __forceinline__ void mma_tf32(float* d, const uint32_t* a, const uint32_t* b) {
    asm volatile(
        "mma.sync.aligned.m16n8k8.row.col.f32.tf32.tf32.f32 "
        "{%0,%1,%2,%3}, {%4,%5,%6,%7}, {%8,%9}, {%0,%1,%2,%3};"
        : "+f"(d[0]), "+f"(d[1]), "+f"(d[2]), "+f"(d[3])
        : "r"(a[0]), "r"(a[1]), "r"(a[2]), "r"(a[3]), "r"(b[0]), "r"(b[1]));
}

// ---------------------------------------------------------------------------
// Weight tf32 pre-round (grid-stride float4)
// ---------------------------------------------------------------------------
__global__ void wround_k(const float* __restrict__ in, float* __restrict__ out, int n4) {
    int i = blockIdx.x * blockDim.x + threadIdx.x;
    int stride = gridDim.x * blockDim.x;
    for (; i < n4; i += stride) {
        float4 v = ((const float4*)in)[i];
        v.x = rnd_tf32(v.x); v.y = rnd_tf32(v.y);
        v.z = rnd_tf32(v.z); v.w = rnd_tf32(v.w);
        ((float4*)out)[i] = v;
    }
}

// ---------------------------------------------------------------------------
// RMSNorm (RND: tf32-round the output — used when it feeds a tf32 GEMM only)
// ---------------------------------------------------------------------------
template <bool RND>
__global__ void __launch_bounds__(256) rmsnorm_k(const float* __restrict__ x,
                                                 const float* __restrict__ g,
                                                 float* __restrict__ y) {
    int row = blockIdx.x;
    int i = threadIdx.x;
    const float4* xr = (const float4*)(x + (size_t)row * Dm);
    float4 xv = xr[i];
    float ss = xv.x * xv.x + xv.y * xv.y + xv.z * xv.z + xv.w * xv.w;
#pragma unroll
    for (int off = 16; off; off >>= 1) ss += __shfl_down_sync(0xffffffffu, ss, off);
    __shared__ float red[8];
    __shared__ float srms;
    if ((i & 31) == 0) red[i >> 5] = ss;
    __syncthreads();
    if (i == 0) {
        float t = 0.f;
#pragma unroll
        for (int w = 0; w < 8; w++) t += red[w];
        srms = rsqrtf(t * (1.0f / Dm) + 1e-6f);
    }
    __syncthreads();
    float r = srms;
    float4 gv = ((const float4*)g)[i];
    float4 o;
    o.x = gv.x * xv.x * r; o.y = gv.y * xv.y * r;
    o.z = gv.z * xv.z * r; o.w = gv.w * xv.w * r;
    if (RND) {
        o.x = rnd_tf32(o.x); o.y = rnd_tf32(o.y);
        o.z = rnd_tf32(o.z); o.w = rnd_tf32(o.w);
    }
    ((float4*)(y + (size_t)row * Dm))[i] = o;
}

// ---------------------------------------------------------------------------
// RoPE table
// ---------------------------------------------------------------------------
__global__ void rope_table_k(float* __restrict__ ct, float* __restrict__ st) {
    int idx = blockIdx.x * blockDim.x + threadIdx.x;
    if (idx >= Sq * (HDm / 2)) return;
    int s = idx >> 5, j = idx & 31;
    float th = (float)pow(10000.0, -2.0 * (double)j / (double)HDm);
    double f = (double)s * (double)th;
    ct[idx] = (float)cos(f);
    st[idx] = (float)sin(f);
}

// ---------------------------------------------------------------------------
// Split QKV + RoPE
// ---------------------------------------------------------------------------
__global__ void __launch_bounds__(256) split_rope_k(const float* __restrict__ qkv,
                                                    const float* __restrict__ ct,
                                                    const float* __restrict__ st,
                                                    float* __restrict__ q,
                                                    float* __restrict__ k,
                                                    float* __restrict__ v) {
    int t = blockIdx.x;
    int b = t / Sq, s = t % Sq;
    const float* row = qkv + (size_t)t * (3 * Dm);
    for (int idx = threadIdx.x; idx < Hn * (HDm / 2); idx += blockDim.x) {
        int h = idx >> 5, j = idx & 31;
        float c = ct[s * 32 + j], sn = st[s * 32 + j];
        size_t o = ((size_t)(b * Hn + h) * Sq + s) * HDm;
        float qr = row[h * HDm + 2 * j], qi = row[h * HDm + 2 * j + 1];
        q[o + 2 * j]     = qr * c - qi * sn;
        q[o + 2 * j + 1] = qr * sn + qi * c;
        float kr = row[Dm + h * HDm + 2 * j], ki = row[Dm + h * HDm + 2 * j + 1];
        k[o + 2 * j]     = kr * c - ki * sn;
        k[o + 2 * j + 1] = kr * sn + ki * c;
    }
    for (int idx = threadIdx.x; idx < Dm; idx += blockDim.x) {
        int h = idx >> 6, d = idx & 63;
        v[((size_t)(b * Hn + h) * Sq + s) * HDm + d] = row[2 * Dm + idx];
    }
}

// ---------------------------------------------------------------------------
// Flash-style causal attention (fp32 math; tf32-rounded output for o-GEMM)
// ---------------------------------------------------------------------------
__global__ void __launch_bounds__(128) attn_k(const float* __restrict__ Q,
                                              const float* __restrict__ Kt,
                                              const float* __restrict__ Vt,
                                              float* __restrict__ Out) {
    int qt = blockIdx.x * 128;
    int h = blockIdx.y, b = blockIdx.z;
    int tid = threadIdx.x;
    int myq = qt + tid;
    const size_t base = ((size_t)(b * Hn + h)) * Sq * HDm;

    float4 q4[16];
    {
        const float4* qrow = (const float4*)(Q + base + (size_t)myq * HDm);
#pragma unroll
        for (int i = 0; i < 16; i++) q4[i] = qrow[i];
    }
    float4 a4[16];
#pragma unroll
    for (int i = 0; i < 16; i++) a4[i] = make_float4(0.f, 0.f, 0.f, 0.f);
    float m = -1e30f, l = 0.f;

    __shared__ float Ks[32][64];
    __shared__ float Vs[32][64];

    int kend = qt + 128;
    for (int kt = 0; kt < kend; kt += 32) {
        __syncthreads();
#pragma unroll
        for (int r = 0; r < 4; r++) {
            int fi = tid + r * 128;
            int row = fi >> 4, c4 = fi & 15;
            ((float4*)&Ks[row][0])[c4] = ((const float4*)(Kt + base + (size_t)(kt + row) * HDm))[c4];
            ((float4*)&Vs[row][0])[c4] = ((const float4*)(Vt + base + (size_t)(kt + row) * HDm))[c4];
        }
        __syncthreads();

        float sreg[32];
        float mt = m;
        int lim = myq - kt;
#pragma unroll
        for (int j = 0; j < 32; j++) {
            float s0 = 0.f, s1 = 0.f, s2 = 0.f, s3 = 0.f;
#pragma unroll
            for (int d4 = 0; d4 < 16; d4++) {
                float4 kk = ((const float4*)&Ks[j][0])[d4];
                s0 = fmaf(q4[d4].x, kk.x, s0);
                s1 = fmaf(q4[d4].y, kk.y, s1);
                s2 = fmaf(q4[d4].z, kk.z, s2);
                s3 = fmaf(q4[d4].w, kk.w, s3);
            }
            float sj = ((s0 + s1) + (s2 + s3)) * 0.125f;
            sreg[j] = sj;
            mt = (j <= lim) ? fmaxf(mt, sj) : mt;
        }
        if (mt > m) {
            float corr = __expf(m - mt);
            l *= corr;
#pragma unroll
            for (int i = 0; i < 16; i++) {
                a4[i].x *= corr; a4[i].y *= corr; a4[i].z *= corr; a4[i].w *= corr;
            }
            m = mt;
        }
#pragma unroll
        for (int j = 0; j < 32; j++) {
            if (j <= lim) {
                float p = __expf(sreg[j] - m);
                l += p;
#pragma unroll
                for (int d4 = 0; d4 < 16; d4++) {
                    float4 vv = ((const float4*)&Vs[j][0])[d4];
                    a4[d4].x = fmaf(p, vv.x, a4[d4].x);
                    a4[d4].y = fmaf(p, vv.y, a4[d4].y);
                    a4[d4].z = fmaf(p, vv.z, a4[d4].z);
                    a4[d4].w = fmaf(p, vv.w, a4[d4].w);
                }
            }
        }
    }
    float inv = 1.f / l;
    float* orow = Out + ((size_t)(b * Sq + myq)) * Dm + h * HDm;
#pragma unroll
    for (int i = 0; i < 16; i++) {
        float4 o;
        o.x = rnd_tf32(a4[i].x * inv); o.y = rnd_tf32(a4[i].y * inv);
        o.z = rnd_tf32(a4[i].z * inv); o.w = rnd_tf32(a4[i].w * inv);
        ((float4*)orow)[i] = o;
    }
}

// ---------------------------------------------------------------------------
// tf32 tensor-core GEMM v2: CTA 128x256, warp tile 64x64 (2x4 warps), BK=32,
// 3-stage cp.async pipeline. Inputs must be tf32-pre-rounded.
// MODE 0: C = A@B             MODE 1: C = A@B + extra(resid)
// MODE 2: C = rnd(relu(A@B))  MODE 3: C = (A@B) * extra(gates)[row]
// blockIdx.z = expert (strides sA/sB/sC, gates stride gstride).
// smem per stage: A 128x36 floats (18432B) + B 32x260 floats (33280B) = 51712B
// ---------------------------------------------------------------------------
template <int MODE>
__global__ void __launch_bounds__(256, 1)
gemm2_k(const float* __restrict__ A, const float* __restrict__ Bm,
        float* __restrict__ C, int N, int K,
        const float* __restrict__ extra,
        long sA, long sB, long sC, int gstride) {
    extern __shared__ __align__(16) float sm[];
    const uint32_t sb = smem_u32(sm);
    constexpr int STGF = 12928;           // floats per stage
    constexpr int STGB = STGF * 4;        // bytes per stage

    int tid = threadIdx.x, warp = tid >> 5, lane = tid & 31;
    int gq = lane >> 2, tq = lane & 3;
    int e = blockIdx.z;
    A  += (size_t)e * sA;
    Bm += (size_t)e * sB;
    C  += (size_t)e * sC;
    const float* gates = extra;
    if (MODE == 3) gates += (size_t)e * gstride;

    int m0 = blockIdx.y * 128, n0 = blockIdx.x * 256;
    int wm = (warp & 1) * 64, wn = (warp >> 1) * 64;

    // fill assignments
    int ar = tid >> 1;                     // 0..127 A row
    int acf = (tid & 1) * 16;              // A col float base (16 floats/thread)
    int br = tid >> 3;                     // 0..31 B k-row
    int bcf = (tid & 7) * 4;               // B col float base; chunks +32 floats
    const float* aSrc = A + (size_t)(m0 + ar) * K + acf;
    const float* bSrc = Bm + (size_t)br * N + n0 + bcf;
    uint32_t aDst = sb + (uint32_t)(ar * 144 + acf * 4);
    uint32_t bDst = sb + 18432u + (uint32_t)(br * 1040 + bcf * 4);

    auto fetch = [&](int stage, int k0) {
        uint32_t so = (uint32_t)stage * STGB;
        const float* as = aSrc + k0;
#pragma unroll
        for (int i = 0; i < 4; i++) cpasync16(aDst + so + 16u * i, as + 4 * i);
        const float* bs = bSrc + (size_t)k0 * N;
#pragma unroll
        for (int j = 0; j < 8; j++) cpasync16(bDst + so + 128u * j, bs + 32 * j);
    };

    float d[4][8][4];
#pragma unroll
    for (int i = 0; i < 4; i++)
#pragma unroll
        for (int j = 0; j < 8; j++)
#pragma unroll
            for (int c = 0; c < 4; c++) d[i][j][c] = 0.f;

    fetch(0, 0);  cp_commit();
    fetch(1, 32); cp_commit();
    fetch(2, 64); cp_commit();

    int KB = K >> 5;
    int stg = 0;
    for (int it = 0; it < KB; ++it) {
        cp_wait<2>();
        __syncthreads();
        const float* As = sm + stg * STGF;
        const float* Bs = As + 4608;
#pragma unroll
        for (int kk = 0; kk < 4; kk++) {
            uint32_t a[4][4], b[8][2];
#pragma unroll
            for (int mt = 0; mt < 4; mt++) {
                int row = wm + mt * 16 + gq;
                int col = kk * 8 + tq;
                a[mt][0] = __float_as_uint(As[row * 36 + col]);
                a[mt][1] = __float_as_uint(As[(row + 8) * 36 + col]);
                a[mt][2] = __float_as_uint(As[row * 36 + col + 4]);
                a[mt][3] = __float_as_uint(As[(row + 8) * 36 + col + 4]);
            }
#pragma unroll
            for (int nt = 0; nt < 8; nt++) {
                int col = wn + nt * 8 + gq;
                b[nt][0] = __float_as_uint(Bs[(kk * 8 + tq) * 260 + col]);
                b[nt][1] = __float_as_uint(Bs[(kk * 8 + tq + 4) * 260 + col]);
            }
#pragma unroll
            for (int mt = 0; mt < 4; mt++)
#pragma unroll
                for (int nt = 0; nt < 8; nt++)
                    mma_tf32(d[mt][nt], a[mt], b[nt]);
        }
        __syncthreads();
        if (it + 3 < KB) fetch(stg, (it + 3) * 32);
        cp_commit();
        stg = (stg == 2) ? 0 : stg + 1;
    }

    // Epilogue: frag (gq,tq): c0,c1 at (row gq, cols 2tq,2tq+1), c2,c3 at row gq+8
#pragma unroll
    for (int mt = 0; mt < 4; mt++) {
        int r0 = m0 + wm + mt * 16 + gq;
        int r1 = r0 + 8;
        float g0 = 1.f, g1 = 1.f;
        if (MODE == 3) { g0 = gates[r0]; g1 = gates[r1]; }
#pragma unroll
        for (int nt = 0; nt < 8; nt++) {
            int c = n0 + wn + nt * 8 + 2 * tq;
            float2 v01, v23;
            v01.x = d[mt][nt][0]; v01.y = d[mt][nt][1];
            v23.x = d[mt][nt][2]; v23.y = d[mt][nt][3];
            if (MODE == 1) {
                float2 ra = *(const float2*)(extra + (size_t)r0 * N + c);
                float2 rb = *(const float2*)(extra + (size_t)r1 * N + c);
                v01.x += ra.x; v01.y += ra.y;
                v23.x += rb.x; v23.y += rb.y;
            }
            if (MODE == 2) {
                v01.x = rnd_tf32(fmaxf(v01.x, 0.f));
                v01.y = rnd_tf32(fmaxf(v01.y, 0.f));
                v23.x = rnd_tf32(fmaxf(v23.x, 0.f));
                v23.y = rnd_tf32(fmaxf(v23.y, 0.f));
            }
            if (MODE == 3) {
                v01.x *= g0; v01.y *= g0;
                v23.x *= g1; v23.y *= g1;
            }
            *(float2*)(C + (size_t)r0 * N + c) = v01;
            *(float2*)(C + (size_t)r1 * N + c) = v23;
        }
    }
}

// ---------------------------------------------------------------------------
// Router (fp32, exact)
// ---------------------------------------------------------------------------
__global__ void __launch_bounds__(256) router_k(const float* __restrict__ xn,
                                                const float* __restrict__ wr,
                                                float* __restrict__ fg,
                                                int* __restrict__ fe) {
    int warp = threadIdx.x >> 5, lane = threadIdx.x & 31;
    int t = blockIdx.x * 8 + warp;
    float acc[8];
#pragma unroll
    for (int e2 = 0; e2 < 8; e2++) acc[e2] = 0.f;
    const float* xr = xn + (size_t)t * Dm;
    for (int d = lane; d < Dm; d += 32) {
        float xv = xr[d];
        const float4* w = (const float4*)(wr + d * En);
        float4 w0 = w[0], w1 = w[1];
        acc[0] = fmaf(xv, w0.x, acc[0]); acc[1] = fmaf(xv, w0.y, acc[1]);
        acc[2] = fmaf(xv, w0.z, acc[2]); acc[3] = fmaf(xv, w0.w, acc[3]);
        acc[4] = fmaf(xv, w1.x, acc[4]); acc[5] = fmaf(xv, w1.y, acc[5]);
        acc[6] = fmaf(xv, w1.z, acc[6]); acc[7] = fmaf(xv, w1.w, acc[7]);
    }
#pragma unroll
    for (int e2 = 0; e2 < 8; e2++)
#pragma unroll
        for (int off = 16; off; off >>= 1)
            acc[e2] += __shfl_down_sync(0xffffffffu, acc[e2], off);
    if (lane == 0) {
        float mx = acc[0];
#pragma unroll
        for (int e2 = 1; e2 < 8; e2++) mx = fmaxf(mx, acc[e2]);
        float p[8], sum = 0.f;
#pragma unroll
        for (int e2 = 0; e2 < 8; e2++) { p[e2] = expf(acc[e2] - mx); sum += p[e2]; }
        float inv = 1.f / sum;
#pragma unroll
        for (int e2 = 0; e2 < 8; e2++) p[e2] *= inv;
        int e0 = 0; float p0 = p[0];
#pragma unroll
        for (int e2 = 1; e2 < 8; e2++) if (p[e2] > p0) { p0 = p[e2]; e0 = e2; }
        int e1 = -1; float p1 = -1.f;
#pragma unroll
        for (int e2 = 0; e2 < 8; e2++)
            if (e2 != e0 && p[e2] > p1) { p1 = p[e2]; e1 = e2; }
        fg[2 * t]     = p0; fe[2 * t]     = e0;
        fg[2 * t + 1] = p1; fe[2 * t + 1] = e1;
    }
}

__global__ void init_etok_k(int* __restrict__ etok) {
    int i = blockIdx.x * blockDim.x + threadIdx.x;
    if (i < En * CAPn) etok[i] = -1;
}

__global__ void __launch_bounds__(256) rank_k(const float* __restrict__ fg,
                                              const int* __restrict__ fe,
                                              int* __restrict__ slot,
                                              int* __restrict__ etok,
                                              float* __restrict__ egate) {
    __shared__ float sg[NA];
    __shared__ unsigned char se[NA];
    for (int i = threadIdx.x; i < NA; i += 256) {
        sg[i] = fg[i];
        se[i] = (unsigned char)fe[i];
    }
    __syncthreads();
    int i = blockIdx.x * 256 + threadIdx.x;
    float gi = sg[i];
    unsigned char ei = se[i];
    int r = 0;
    for (int j = 0; j < NA; j++) {
        bool c = (se[j] == ei) && ((sg[j] > gi) || (sg[j] == gi && j < i));
        r += (int)c;
    }
    if (r < CAPn) {
        slot[i] = r;
        etok[(int)ei * CAPn + r] = i >> 1;
        egate[(int)ei * CAPn + r] = gi;
    } else {
        slot[i] = -1;
    }
}

// ---------------------------------------------------------------------------
// Gather expert inputs (row-major, tf32-rounded; tok<0 -> zeros)
// ---------------------------------------------------------------------------
__global__ void __launch_bounds__(256) xepack_k(const float* __restrict__ xn,
                                                const int* __restrict__ etok,
                                                float* __restrict__ xe) {
    int row = blockIdx.x;                 // e*CAPn + r
    int tok = etok[row];
    int i = threadIdx.x;
    float4 v = make_float4(0.f, 0.f, 0.f, 0.f);
    if (tok >= 0) v = ((const float4*)(xn + (size_t)tok * Dm))[i];
    v.x = rnd_tf32(v.x); v.y = rnd_tf32(v.y); v.z = rnd_tf32(v.z); v.w = rnd_tf32(v.w);
    ((float4*)(xe + (size_t)row * Dm))[i] = v;
}

// ---------------------------------------------------------------------------
// Final combine
// ---------------------------------------------------------------------------
__global__ void __launch_bounds__(256) combine_k(const float* __restrict__ x1,
                                                 const float* __restrict__ ye,
                                                 const int* __restrict__ fe,
                                                 const int* __restrict__ slot,
                                                 float* __restrict__ out) {
    int t = blockIdx.x;
    int d = threadIdx.x;
    float4 v = ((const float4*)(x1 + (size_t)t * Dm))[d];
#pragma unroll
    for (int kk = 0; kk < 2; kk++) {
        int i = 2 * t + kk;
        int sl = slot[i];
        if (sl >= 0) {
            int e = fe[i];
            float4 w = ((const float4*)(ye + ((size_t)e * CAPn + sl) * Dm))[d];
            v.x += w.x; v.y += w.y; v.z += w.z; v.w += w.w;
        }
    }
    ((float4*)(out + (size_t)t * Dm))[d] = v;
}

// ---------------------------------------------------------------------------
// Launch
// ---------------------------------------------------------------------------
extern "C" void kernel_launch(void* const* d_in, const int* in_sizes, int n_in,
                              void* d_out, int out_size) {
    (void)in_sizes; (void)n_in; (void)out_size;
    const float* x        = (const float*)d_in[0];
    const float* g1       = (const float*)d_in[1];
    const float* w_qkv    = (const float*)d_in[2];
    const float* w_o      = (const float*)d_in[3];
    const float* g2       = (const float*)d_in[4];
    const float* w_router = (const float*)d_in[5];
    const float* w1       = (const float*)d_in[6];
    const float* w2       = (const float*)d_in[7];
    float* out = (float*)d_out;

    float *p_xn, *p_qkv, *p_q, *p_k, *p_v, *p_attn, *p_x1, *p_cos, *p_sin;
    float *p_fg, *p_egate, *p_h, *p_ye, *p_xe;
    float *p_wqkvr, *p_wor, *p_w1r, *p_w2r;
    int *p_fe, *p_slot, *p_etok;
    cudaGetSymbolAddress((void**)&p_xn,   g_xn);
    cudaGetSymbolAddress((void**)&p_qkv,  g_qkv);
    cudaGetSymbolAddress((void**)&p_q,    g_q);
    cudaGetSymbolAddress((void**)&p_k,    g_k);
    cudaGetSymbolAddress((void**)&p_v,    g_v);
    cudaGetSymbolAddress((void**)&p_attn, g_attn);
    cudaGetSymbolAddress((void**)&p_x1,   g_x1);
    cudaGetSymbolAddress((void**)&p_cos,  g_cos);
    cudaGetSymbolAddress((void**)&p_sin,  g_sin);
    cudaGetSymbolAddress((void**)&p_fg,   g_fg);
    cudaGetSymbolAddress((void**)&p_fe,   g_fe);
    cudaGetSymbolAddress((void**)&p_slot, g_slot);
    cudaGetSymbolAddress((void**)&p_etok, g_etok);
    cudaGetSymbolAddress((void**)&p_egate,g_egate);
    cudaGetSymbolAddress((void**)&p_h,    g_h);
    cudaGetSymbolAddress((void**)&p_ye,   g_ye);
    cudaGetSymbolAddress((void**)&p_xe,   g_xe);
    cudaGetSymbolAddress((void**)&p_wqkvr,g_wqkvr);
    cudaGetSymbolAddress((void**)&p_wor,  g_wor);
    cudaGetSymbolAddress((void**)&p_w1r,  g_w1r);
    cudaGetSymbolAddress((void**)&p_w2r,  g_w2r);

    constexpr int GEMM_SMEM = 3 * 51712;  // 155136 bytes
    cudaFuncSetAttribute(gemm2_k<0>, cudaFuncAttributeMaxDynamicSharedMemorySize, GEMM_SMEM);
    cudaFuncSetAttribute(gemm2_k<1>, cudaFuncAttributeMaxDynamicSharedMemorySize, GEMM_SMEM);
    cudaFuncSetAttribute(gemm2_k<2>, cudaFuncAttributeMaxDynamicSharedMemorySize, GEMM_SMEM);
    cudaFuncSetAttribute(gemm2_k<3>, cudaFuncAttributeMaxDynamicSharedMemorySize, GEMM_SMEM);

    // Independent precomputation
    rope_table_k<<<(Sq * 32 + 255) / 256, 256>>>(p_cos, p_sin);
    wround_k<<<592, 256>>>(w_qkv, p_wqkvr, Dm * 3 * Dm / 4);
    wround_k<<<592, 256>>>(w_o,   p_wor,   Dm * Dm / 4);
    wround_k<<<592, 256>>>(w1,    p_w1r,   En * Dm * FFNm / 4);
    wround_k<<<592, 256>>>(w2,    p_w2r,   En * FFNm * Dm / 4);

    // Attention branch
    rmsnorm_k<true><<<Tn, 256>>>(x, g1, p_xn);
    // qkv = xn1 @ w_qkv  [4096,1024]@[1024,3072]  tf32
    gemm2_k<0><<<dim3(3 * Dm / 256, Tn / 128, 1), 256, GEMM_SMEM>>>(
        p_xn, p_wqkvr, p_qkv, 3 * Dm, Dm, nullptr, 0, 0, 0, 0);
    split_rope_k<<<Tn, 256>>>(p_qkv, p_cos, p_sin, p_q, p_k, p_v);
    attn_k<<<dim3(Sq / 128, Hn, Bz), 128>>>(p_q, p_k, p_v, p_attn);
    // x1 = x + attn @ w_o  tf32 + fp32 residual
    gemm2_k<1><<<dim3(Dm / 256, Tn / 128, 1), 256, GEMM_SMEM>>>(
        p_attn, p_wor, p_x1, Dm, Dm, x, 0, 0, 0, 0);
    rmsnorm_k<false><<<Tn, 256>>>(p_x1, g2, p_xn);

    // Routing (fp32 exact)
    router_k<<<Tn / 8, 256>>>(p_xn, w_router, p_fg, p_fe);
    init_etok_k<<<(En * CAPn + 255) / 256, 256>>>(p_etok);
    rank_k<<<NA / 256, 256>>>(p_fg, p_fe, p_slot, p_etok, p_egate);
    xepack_k<<<En * CAPn, 256>>>(p_xn, p_etok, p_xe);

    // MoE expert GEMMs (tf32)
    // h = rnd(relu(xe @ w1))  [1280,1024]@[1024,2048] x8
    gemm2_k<2><<<dim3(FFNm / 256, CAPn / 128, En), 256, GEMM_SMEM>>>(
        p_xe, p_w1r, p_h, FFNm, Dm, nullptr,
        (long)CAPn * Dm, (long)Dm * FFNm, (long)CAPn * FFNm, 0);
    // ye = (h @ w2) * gate  [1280,2048]@[2048,1024] x8
    gemm2_k<3><<<dim3(Dm / 256, CAPn / 128, En), 256, GEMM_SMEM>>>(
        p_h, p_w2r, p_ye, Dm, FFNm, p_egate,
        (long)CAPn * FFNm, (long)FFNm * Dm, (long)CAPn * Dm, CAPn);

    // out = x1 + moe
    combine_k<<<Tn, 256>>>(p_x1, p_ye, p_fe, p_slot, out);
}

// round 6
// speedup vs baseline: 3.8803x; 1.4088x over previous
#include <cuda_runtime.h>
#include <math.h>
#include <stdint.h>

// ---------------------------------------------------------------------------
// Problem constants
// ---------------------------------------------------------------------------
namespace {
constexpr int Bz   = 2;
constexpr int Sq   = 2048;
constexpr int Dm   = 1024;
constexpr int Hn   = 16;
constexpr int HDm  = 64;
constexpr int FFNm = 2048;
constexpr int En   = 8;
constexpr int Tn   = Bz * Sq;     // 4096 tokens
constexpr int NA   = Tn * 2;      // 8192 flat assignments (top-2)
constexpr int CAPn = 1280;        // ceil(2*2048*2*1.25/8)
}

// ---------------------------------------------------------------------------
// Static scratch (no allocations allowed)
// ---------------------------------------------------------------------------
__device__ float g_xn  [Tn * Dm];
__device__ float g_qkv [Tn * 3 * Dm];
__device__ float g_q   [Tn * Dm];
__device__ float g_k   [Tn * Dm];
__device__ float g_v   [Tn * Dm];
__device__ float g_attn[Tn * Dm];
__device__ float g_x1  [Tn * Dm];
__device__ float g_cos [Sq * (HDm / 2)];
__device__ float g_sin [Sq * (HDm / 2)];
__device__ float g_fg  [NA];
__device__ int   g_fe  [NA];
__device__ int   g_slot[NA];
__device__ int   g_etok [En * CAPn];
__device__ float g_egate[En * CAPn];
__device__ float g_xe[En * CAPn * Dm];    // gathered tokens, tf32-rounded
__device__ float g_h [En * CAPn * FFNm];  // relu output, tf32-rounded
__device__ float g_ye[En * CAPn * Dm];
// tf32-rounded weight copies
__device__ float g_wqkvr[Dm * 3 * Dm];
__device__ float g_wor  [Dm * Dm];
__device__ float g_w1r  [En * Dm * FFNm];
__device__ float g_w2r  [En * FFNm * Dm];

// ---------------------------------------------------------------------------
// Helpers
// ---------------------------------------------------------------------------
__device__ __forceinline__ float rnd_tf32(float x) {
    uint32_t u = __float_as_uint(x);
    u = (u + 0x1000u) & 0xFFFFE000u;   // RN to tf32 (10-bit mantissa)
    return __uint_as_float(u);
}

__device__ __forceinline__ uint32_t smem_u32(const void* p) {
    uint32_t a;
    asm("{ .reg .u64 t; cvta.to.shared.u64 t, %1; cvt.u32.u64 %0, t; }"
        : "=r"(a) : "l"(p));
    return a;
}

__device__ __forceinline__ void cpasync16(uint32_t dst, const float* src) {
    asm volatile("cp.async.cg.shared.global [%0], [%1], 16;" :: "r"(dst), "l"(src));
}
__device__ __forceinline__ void cp_commit() {
    asm volatile("cp.async.commit_group;" ::: "memory");
}
template <int N>
__device__ __forceinline__ void cp_wait() {
    asm volatile("cp.async.wait_group %0;" :: "n"(N) : "memory");
}

// m16n8k8 tf32 MMA (arch-portable; compiles for plain sm_103 target)
__device__ __forceinline__ void mma_tf32(float* d, const uint32_t* a, const uint32_t* b) {
    asm volatile(
        "mma.sync.aligned.m16n8k8.row.col.f32.tf32.tf32.f32 "
        "{%0,%1,%2,%3}, {%4,%5,%6,%7}, {%8,%9}, {%0,%1,%2,%3};"
        : "+f"(d[0]), "+f"(d[1]), "+f"(d[2]), "+f"(d[3])
        : "r"(a[0]), "r"(a[1]), "r"(a[2]), "r"(a[3]), "r"(b[0]), "r"(b[1]));
}

// 2^x for x <= 0, FMA-pipe only (no MUFU). Magic-constant RN split, deg-6 poly
// on f in [-0.5, 0.5]. Handles -inf via clamp (returns ~2^-126 ~= 0).
__device__ __forceinline__ float exp2p(float x) {
    float t = fmaxf(x, -126.f);
    float z = t + 12582912.f;          // 1.5 * 2^23 : RN to integer
    float n = z - 12582912.f;
    float f = t - n;
    float p =         1.5353e-4f;
    p = fmaf(p, f, 1.3398886e-3f);
    p = fmaf(p, f, 9.6184372e-3f);
    p = fmaf(p, f, 5.5503327e-2f);
    p = fmaf(p, f, 2.4022648e-1f);
    p = fmaf(p, f, 6.9314718e-1f);
    p = fmaf(p, f, 1.0f);
    int iz = __float_as_int(z) - 0x4B400000;      // = (int)n
    return p * __int_as_float((iz + 127) << 23);  // * 2^n (n >= -126: normal)
}

// ---------------------------------------------------------------------------
// Weight tf32 pre-round (grid-stride float4)
// ---------------------------------------------------------------------------
__global__ void wround_k(const float* __restrict__ in, float* __restrict__ out, int n4) {
    int i = blockIdx.x * blockDim.x + threadIdx.x;
    int stride = gridDim.x * blockDim.x;
    for (; i < n4; i += stride) {
        float4 v = ((const float4*)in)[i];
        v.x = rnd_tf32(v.x); v.y = rnd_tf32(v.y);
        v.z = rnd_tf32(v.z); v.w = rnd_tf32(v.w);
        ((float4*)out)[i] = v;
    }
}

// ---------------------------------------------------------------------------
// RMSNorm (RND: tf32-round output when it only feeds a tf32 GEMM)
// ---------------------------------------------------------------------------
template <bool RND>
__global__ void __launch_bounds__(256) rmsnorm_k(const float* __restrict__ x,
                                                 const float* __restrict__ g,
                                                 float* __restrict__ y) {
    int row = blockIdx.x;
    int i = threadIdx.x;
    const float4* xr = (const float4*)(x + (size_t)row * Dm);
    float4 xv = xr[i];
    float ss = xv.x * xv.x + xv.y * xv.y + xv.z * xv.z + xv.w * xv.w;
#pragma unroll
    for (int off = 16; off; off >>= 1) ss += __shfl_down_sync(0xffffffffu, ss, off);
    __shared__ float red[8];
    __shared__ float srms;
    if ((i & 31) == 0) red[i >> 5] = ss;
    __syncthreads();
    if (i == 0) {
        float t = 0.f;
#pragma unroll
        for (int w = 0; w < 8; w++) t += red[w];
        srms = rsqrtf(t * (1.0f / Dm) + 1e-6f);
    }
    __syncthreads();
    float r = srms;
    float4 gv = ((const float4*)g)[i];
    float4 o;
    o.x = gv.x * xv.x * r; o.y = gv.y * xv.y * r;
    o.z = gv.z * xv.z * r; o.w = gv.w * xv.w * r;
    if (RND) {
        o.x = rnd_tf32(o.x); o.y = rnd_tf32(o.y);
        o.z = rnd_tf32(o.z); o.w = rnd_tf32(o.w);
    }
    ((float4*)(y + (size_t)row * Dm))[i] = o;
}

// ---------------------------------------------------------------------------
// RoPE table
// ---------------------------------------------------------------------------
__global__ void rope_table_k(float* __restrict__ ct, float* __restrict__ st) {
    int idx = blockIdx.x * blockDim.x + threadIdx.x;
    if (idx >= Sq * (HDm / 2)) return;
    int s = idx >> 5, j = idx & 31;
    float th = (float)pow(10000.0, -2.0 * (double)j / (double)HDm);
    double f = (double)s * (double)th;
    ct[idx] = (float)cos(f);
    st[idx] = (float)sin(f);
}

// ---------------------------------------------------------------------------
// Split QKV + RoPE
// ---------------------------------------------------------------------------
__global__ void __launch_bounds__(256) split_rope_k(const float* __restrict__ qkv,
                                                    const float* __restrict__ ct,
                                                    const float* __restrict__ st,
                                                    float* __restrict__ q,
                                                    float* __restrict__ k,
                                                    float* __restrict__ v) {
    int t = blockIdx.x;
    int b = t / Sq, s = t % Sq;
    const float* row = qkv + (size_t)t * (3 * Dm);
    for (int idx = threadIdx.x; idx < Hn * (HDm / 2); idx += blockDim.x) {
        int h = idx >> 5, j = idx & 31;
        float c = ct[s * 32 + j], sn = st[s * 32 + j];
        size_t o = ((size_t)(b * Hn + h) * Sq + s) * HDm;
        float qr = row[h * HDm + 2 * j], qi = row[h * HDm + 2 * j + 1];
        q[o + 2 * j]     = qr * c - qi * sn;
        q[o + 2 * j + 1] = qr * sn + qi * c;
        float kr = row[Dm + h * HDm + 2 * j], ki = row[Dm + h * HDm + 2 * j + 1];
        k[o + 2 * j]     = kr * c - ki * sn;
        k[o + 2 * j + 1] = kr * sn + ki * c;
    }
    for (int idx = threadIdx.x; idx < Dm; idx += blockDim.x) {
        int h = idx >> 6, d = idx & 63;
        v[((size_t)(b * Hn + h) * Sq + s) * HDm + d] = row[2 * Dm + idx];
    }
}

// ---------------------------------------------------------------------------
// Tensor-core causal flash attention.
// CTA: 128 queries of one (b,h). 8 warps x 16 query rows each (warp-local
// online softmax). Key tiles 64 wide, 2-stage cp.async double buffer.
// K smem stride 68 / V stride 72 -> both b-frag LDS patterns conflict-free.
// exp on FMA pipe (exp2p), P re-fragmented via shfl.idx (no smem roundtrip).
// Output tf32-rounded (feeds the o-projection tf32 GEMM).
// ---------------------------------------------------------------------------
__global__ void __launch_bounds__(256) attn_tc_k(const float* __restrict__ Q,
                                                 const float* __restrict__ Kt,
                                                 const float* __restrict__ Vt,
                                                 float* __restrict__ Out) {
    extern __shared__ __align__(16) float sm[];
    constexpr float LOG2E = 1.4426950408889634f;
    constexpr int STG = 64 * 68 + 64 * 72;   // 8960 floats per stage

    int bx = blockIdx.x, h = blockIdx.y, b = blockIdx.z;
    int qt = bx * 128;
    int tid = threadIdx.x, warp = tid >> 5, lane = tid & 31;
    int gq = lane >> 2, tq = lane & 3;
    int wq = qt + warp * 16;
    const size_t base = ((size_t)(b * Hn + h)) * Sq * HDm;
    const float* Qg = Q + base;
    const float* Kg = Kt + base;
    const float* Vg = Vt + base;

    const uint32_t sb = smem_u32(sm);

    // Q fragments, pre-scaled by 1/8 and tf32-rounded
    uint32_t qf[8][4];
#pragma unroll
    for (int kk = 0; kk < 8; kk++) {
        int c = kk * 8 + tq;
        qf[kk][0] = __float_as_uint(rnd_tf32(Qg[(size_t)(wq + gq) * 64 + c] * 0.125f));
        qf[kk][1] = __float_as_uint(rnd_tf32(Qg[(size_t)(wq + gq + 8) * 64 + c] * 0.125f));
        qf[kk][2] = __float_as_uint(rnd_tf32(Qg[(size_t)(wq + gq) * 64 + c + 4] * 0.125f));
        qf[kk][3] = __float_as_uint(rnd_tf32(Qg[(size_t)(wq + gq + 8) * 64 + c + 4] * 0.125f));
    }

    float O[8][4];
#pragma unroll
    for (int nt = 0; nt < 8; nt++)
#pragma unroll
        for (int c = 0; c < 4; c++) O[nt][c] = 0.f;
    float m0 = -1e30f, m1 = -1e30f, l0 = 0.f, l1 = 0.f;

    // fill: 256 threads load K,V 64x64 tiles into stage's smem
    int fr = tid >> 2, fs = (tid & 3) * 16;
    auto fill = [&](int stage, int kt) {
        uint32_t kDst = sb + (uint32_t)(stage * STG + fr * 68 + fs) * 4u;
        uint32_t vDst = sb + (uint32_t)(stage * STG + 64 * 68 + fr * 72 + fs) * 4u;
        const float* ks = Kg + (size_t)(kt + fr) * 64 + fs;
        const float* vs = Vg + (size_t)(kt + fr) * 64 + fs;
#pragma unroll
        for (int c = 0; c < 4; c++) {
            cpasync16(kDst + 16u * c, ks + 4 * c);
            cpasync16(vDst + 16u * c, vs + 4 * c);
        }
    };

    int ntiles = 2 * bx + 2;
    fill(0, 0);
    cp_commit();

    for (int it = 0; it < ntiles; it++) {
        if (it + 1 < ntiles) fill((it + 1) & 1, (it + 1) * 64);
        cp_commit();
        cp_wait<1>();
        __syncthreads();

        int kt = it * 64;
        if (kt <= wq + 15) {
            const float* Ks = sm + (it & 1) * STG;
            const float* Vs = Ks + 64 * 68;

            // ---- S = Q K^T (scaled) ----
            float s[8][4];
#pragma unroll
            for (int nt = 0; nt < 8; nt++)
#pragma unroll
                for (int c = 0; c < 4; c++) s[nt][c] = 0.f;
#pragma unroll
            for (int kk = 0; kk < 8; kk++) {
                uint32_t bf[8][2];
#pragma unroll
                for (int nt = 0; nt < 8; nt++) {
                    int krow = nt * 8 + gq;
                    bf[nt][0] = __float_as_uint(Ks[krow * 68 + kk * 8 + tq]);
                    bf[nt][1] = __float_as_uint(Ks[krow * 68 + kk * 8 + tq + 4]);
                }
#pragma unroll
                for (int nt = 0; nt < 8; nt++) mma_tf32(s[nt], qf[kk], bf[nt]);
            }

            // ---- causal mask (only diagonal-straddling tiles) ----
            if (kt + 63 > wq) {
                int r0 = wq + gq, r1 = wq + gq + 8;
#pragma unroll
                for (int nt = 0; nt < 8; nt++) {
                    int c0 = kt + nt * 8 + 2 * tq;
                    if (c0 > r0)     s[nt][0] = -3.4e38f;
                    if (c0 + 1 > r0) s[nt][1] = -3.4e38f;
                    if (c0 > r1)     s[nt][2] = -3.4e38f;
                    if (c0 + 1 > r1) s[nt][3] = -3.4e38f;
                }
            }

            // ---- row maxes (replicated over the 4 tq lanes) ----
            float mx0 = -3.4e38f, mx1 = -3.4e38f;
#pragma unroll
            for (int nt = 0; nt < 8; nt++) {
                mx0 = fmaxf(mx0, fmaxf(s[nt][0], s[nt][1]));
                mx1 = fmaxf(mx1, fmaxf(s[nt][2], s[nt][3]));
            }
            mx0 = fmaxf(mx0, __shfl_xor_sync(0xffffffffu, mx0, 1));
            mx0 = fmaxf(mx0, __shfl_xor_sync(0xffffffffu, mx0, 2));
            mx1 = fmaxf(mx1, __shfl_xor_sync(0xffffffffu, mx1, 1));
            mx1 = fmaxf(mx1, __shfl_xor_sync(0xffffffffu, mx1, 2));
            float mn0 = fmaxf(m0, mx0), mn1 = fmaxf(m1, mx1);
            float cr0 = exp2p((m0 - mn0) * LOG2E);
            float cr1 = exp2p((m1 - mn1) * LOG2E);
            float nm0 = mn0 * LOG2E, nm1 = mn1 * LOG2E;

            // ---- P = exp(S - m), tf32-rounded; row sums ----
            float sum0 = 0.f, sum1 = 0.f;
#pragma unroll
            for (int nt = 0; nt < 8; nt++) {
                float p0 = rnd_tf32(exp2p(fmaf(s[nt][0], LOG2E, -nm0)));
                float p1 = rnd_tf32(exp2p(fmaf(s[nt][1], LOG2E, -nm0)));
                float p2 = rnd_tf32(exp2p(fmaf(s[nt][2], LOG2E, -nm1)));
                float p3 = rnd_tf32(exp2p(fmaf(s[nt][3], LOG2E, -nm1)));
                s[nt][0] = p0; s[nt][1] = p1; s[nt][2] = p2; s[nt][3] = p3;
                sum0 += p0 + p1; sum1 += p2 + p3;
            }
            sum0 += __shfl_xor_sync(0xffffffffu, sum0, 1);
            sum0 += __shfl_xor_sync(0xffffffffu, sum0, 2);
            sum1 += __shfl_xor_sync(0xffffffffu, sum1, 1);
            sum1 += __shfl_xor_sync(0xffffffffu, sum1, 2);
            l0 = l0 * cr0 + sum0;
            l1 = l1 * cr1 + sum1;
#pragma unroll
            for (int nt = 0; nt < 8; nt++) {
                O[nt][0] *= cr0; O[nt][1] *= cr0;
                O[nt][2] *= cr1; O[nt][3] *= cr1;
            }
            m0 = mn0; m1 = mn1;

            // ---- O += P V ----
            int sl1 = gq * 4 + (tq >> 1);
            int sl2 = sl1 + 2;
            bool odd = (tq & 1);
#pragma unroll
            for (int kk = 0; kk < 8; kk++) {
                float v00 = __shfl_sync(0xffffffffu, s[kk][0], sl1);
                float v01 = __shfl_sync(0xffffffffu, s[kk][1], sl1);
                float v10 = __shfl_sync(0xffffffffu, s[kk][0], sl2);
                float v11 = __shfl_sync(0xffffffffu, s[kk][1], sl2);
                float w00 = __shfl_sync(0xffffffffu, s[kk][2], sl1);
                float w01 = __shfl_sync(0xffffffffu, s[kk][3], sl1);
                float w10 = __shfl_sync(0xffffffffu, s[kk][2], sl2);
                float w11 = __shfl_sync(0xffffffffu, s[kk][3], sl2);
                uint32_t a[4];
                a[0] = __float_as_uint(odd ? v01 : v00);
                a[1] = __float_as_uint(odd ? w01 : w00);
                a[2] = __float_as_uint(odd ? v11 : v10);
                a[3] = __float_as_uint(odd ? w11 : w10);
                uint32_t bf[8][2];
#pragma unroll
                for (int nt = 0; nt < 8; nt++) {
                    int krow = kk * 8 + tq;
                    bf[nt][0] = __float_as_uint(Vs[krow * 72 + nt * 8 + gq]);
                    bf[nt][1] = __float_as_uint(Vs[(krow + 4) * 72 + nt * 8 + gq]);
                }
#pragma unroll
                for (int nt = 0; nt < 8; nt++) mma_tf32(O[nt], a, bf[nt]);
            }
        }
        __syncthreads();
    }

    // ---- epilogue: O / l, tf32-rounded, [T, D] head-major layout ----
    float i0 = 1.f / l0, i1 = 1.f / l1;
    int r0 = wq + gq, r1 = wq + gq + 8;
    float* o0 = Out + ((size_t)(b * Sq + r0)) * Dm + h * 64 + 2 * tq;
    float* o1 = Out + ((size_t)(b * Sq + r1)) * Dm + h * 64 + 2 * tq;
#pragma unroll
    for (int nt = 0; nt < 8; nt++) {
        float2 u, w;
        u.x = rnd_tf32(O[nt][0] * i0); u.y = rnd_tf32(O[nt][1] * i0);
        w.x = rnd_tf32(O[nt][2] * i1); w.y = rnd_tf32(O[nt][3] * i1);
        *(float2*)(o0 + nt * 8) = u;
        *(float2*)(o1 + nt * 8) = w;
    }
}

// ---------------------------------------------------------------------------
// tf32 tensor-core GEMM v2: CTA 128x256, warp tile 64x64 (2x4 warps), BK=32,
// 3-stage cp.async pipeline. Inputs must be tf32-pre-rounded.
// MODE 0: C = A@B             MODE 1: C = A@B + extra(resid)
// MODE 2: C = rnd(relu(A@B))  MODE 3: C = (A@B) * extra(gates)[row]
// ---------------------------------------------------------------------------
template <int MODE>
__global__ void __launch_bounds__(256, 1)
gemm2_k(const float* __restrict__ A, const float* __restrict__ Bm,
        float* __restrict__ C, int N, int K,
        const float* __restrict__ extra,
        long sA, long sB, long sC, int gstride) {
    extern __shared__ __align__(16) float sm[];
    const uint32_t sb = smem_u32(sm);
    constexpr int STGF = 12928;           // floats per stage
    constexpr int STGB = STGF * 4;        // bytes per stage

    int tid = threadIdx.x, warp = tid >> 5, lane = tid & 31;
    int gq = lane >> 2, tq = lane & 3;
    int e = blockIdx.z;
    A  += (size_t)e * sA;
    Bm += (size_t)e * sB;
    C  += (size_t)e * sC;
    const float* gates = extra;
    if (MODE == 3) gates += (size_t)e * gstride;

    int m0 = blockIdx.y * 128, n0 = blockIdx.x * 256;
    int wm = (warp & 1) * 64, wn = (warp >> 1) * 64;

    int ar = tid >> 1;
    int acf = (tid & 1) * 16;
    int br = tid >> 3;
    int bcf = (tid & 7) * 4;
    const float* aSrc = A + (size_t)(m0 + ar) * K + acf;
    const float* bSrc = Bm + (size_t)br * N + n0 + bcf;
    uint32_t aDst = sb + (uint32_t)(ar * 144 + acf * 4);
    uint32_t bDst = sb + 18432u + (uint32_t)(br * 1040 + bcf * 4);

    auto fetch = [&](int stage, int k0) {
        uint32_t so = (uint32_t)stage * STGB;
        const float* as = aSrc + k0;
#pragma unroll
        for (int i = 0; i < 4; i++) cpasync16(aDst + so + 16u * i, as + 4 * i);
        const float* bs = bSrc + (size_t)k0 * N;
#pragma unroll
        for (int j = 0; j < 8; j++) cpasync16(bDst + so + 128u * j, bs + 32 * j);
    };

    float d[4][8][4];
#pragma unroll
    for (int i = 0; i < 4; i++)
#pragma unroll
        for (int j = 0; j < 8; j++)
#pragma unroll
            for (int c = 0; c < 4; c++) d[i][j][c] = 0.f;

    fetch(0, 0);  cp_commit();
    fetch(1, 32); cp_commit();
    fetch(2, 64); cp_commit();

    int KB = K >> 5;
    int stg = 0;
    for (int it = 0; it < KB; ++it) {
        cp_wait<2>();
        __syncthreads();
        const float* As = sm + stg * STGF;
        const float* Bs = As + 4608;
#pragma unroll
        for (int kk = 0; kk < 4; kk++) {
            uint32_t a[4][4], b[8][2];
#pragma unroll
            for (int mt = 0; mt < 4; mt++) {
                int row = wm + mt * 16 + gq;
                int col = kk * 8 + tq;
                a[mt][0] = __float_as_uint(As[row * 36 + col]);
                a[mt][1] = __float_as_uint(As[(row + 8) * 36 + col]);
                a[mt][2] = __float_as_uint(As[row * 36 + col + 4]);
                a[mt][3] = __float_as_uint(As[(row + 8) * 36 + col + 4]);
            }
#pragma unroll
            for (int nt = 0; nt < 8; nt++) {
                int col = wn + nt * 8 + gq;
                b[nt][0] = __float_as_uint(Bs[(kk * 8 + tq) * 260 + col]);
                b[nt][1] = __float_as_uint(Bs[(kk * 8 + tq + 4) * 260 + col]);
            }
#pragma unroll
            for (int mt = 0; mt < 4; mt++)
#pragma unroll
                for (int nt = 0; nt < 8; nt++)
                    mma_tf32(d[mt][nt], a[mt], b[nt]);
        }
        __syncthreads();
        if (it + 3 < KB) fetch(stg, (it + 3) * 32);
        cp_commit();
        stg = (stg == 2) ? 0 : stg + 1;
    }

#pragma unroll
    for (int mt = 0; mt < 4; mt++) {
        int r0 = m0 + wm + mt * 16 + gq;
        int r1 = r0 + 8;
        float g0 = 1.f, g1 = 1.f;
        if (MODE == 3) { g0 = gates[r0]; g1 = gates[r1]; }
#pragma unroll
        for (int nt = 0; nt < 8; nt++) {
            int c = n0 + wn + nt * 8 + 2 * tq;
            float2 v01, v23;
            v01.x = d[mt][nt][0]; v01.y = d[mt][nt][1];
            v23.x = d[mt][nt][2]; v23.y = d[mt][nt][3];
            if (MODE == 1) {
                float2 ra = *(const float2*)(extra + (size_t)r0 * N + c);
                float2 rb = *(const float2*)(extra + (size_t)r1 * N + c);
                v01.x += ra.x; v01.y += ra.y;
                v23.x += rb.x; v23.y += rb.y;
            }
            if (MODE == 2) {
                v01.x = rnd_tf32(fmaxf(v01.x, 0.f));
                v01.y = rnd_tf32(fmaxf(v01.y, 0.f));
                v23.x = rnd_tf32(fmaxf(v23.x, 0.f));
                v23.y = rnd_tf32(fmaxf(v23.y, 0.f));
            }
            if (MODE == 3) {
                v01.x *= g0; v01.y *= g0;
                v23.x *= g1; v23.y *= g1;
            }
            *(float2*)(C + (size_t)r0 * N + c) = v01;
            *(float2*)(C + (size_t)r1 * N + c) = v23;
        }
    }
}

// ---------------------------------------------------------------------------
// Router (fp32, exact)
// ---------------------------------------------------------------------------
__global__ void __launch_bounds__(256) router_k(const float* __restrict__ xn,
                                                const float* __restrict__ wr,
                                                float* __restrict__ fg,
                                                int* __restrict__ fe) {
    int warp = threadIdx.x >> 5, lane = threadIdx.x & 31;
    int t = blockIdx.x * 8 + warp;
    float acc[8];
#pragma unroll
    for (int e2 = 0; e2 < 8; e2++) acc[e2] = 0.f;
    const float* xr = xn + (size_t)t * Dm;
    for (int d = lane; d < Dm; d += 32) {
        float xv = xr[d];
        const float4* w = (const float4*)(wr + d * En);
        float4 w0 = w[0], w1 = w[1];
        acc[0] = fmaf(xv, w0.x, acc[0]); acc[1] = fmaf(xv, w0.y, acc[1]);
        acc[2] = fmaf(xv, w0.z, acc[2]); acc[3] = fmaf(xv, w0.w, acc[3]);
        acc[4] = fmaf(xv, w1.x, acc[4]); acc[5] = fmaf(xv, w1.y, acc[5]);
        acc[6] = fmaf(xv, w1.z, acc[6]); acc[7] = fmaf(xv, w1.w, acc[7]);
    }
#pragma unroll
    for (int e2 = 0; e2 < 8; e2++)
#pragma unroll
        for (int off = 16; off; off >>= 1)
            acc[e2] += __shfl_down_sync(0xffffffffu, acc[e2], off);
    if (lane == 0) {
        float mx = acc[0];
#pragma unroll
        for (int e2 = 1; e2 < 8; e2++) mx = fmaxf(mx, acc[e2]);
        float p[8], sum = 0.f;
#pragma unroll
        for (int e2 = 0; e2 < 8; e2++) { p[e2] = expf(acc[e2] - mx); sum += p[e2]; }
        float inv = 1.f / sum;
#pragma unroll
        for (int e2 = 0; e2 < 8; e2++) p[e2] *= inv;
        int e0 = 0; float p0 = p[0];
#pragma unroll
        for (int e2 = 1; e2 < 8; e2++) if (p[e2] > p0) { p0 = p[e2]; e0 = e2; }
        int e1 = -1; float p1 = -1.f;
#pragma unroll
        for (int e2 = 0; e2 < 8; e2++)
            if (e2 != e0 && p[e2] > p1) { p1 = p[e2]; e1 = e2; }
        fg[2 * t]     = p0; fe[2 * t]     = e0;
        fg[2 * t + 1] = p1; fe[2 * t + 1] = e1;
    }
}

__global__ void init_etok_k(int* __restrict__ etok) {
    int i = blockIdx.x * blockDim.x + threadIdx.x;
    if (i < En * CAPn) etok[i] = -1;
}

__global__ void __launch_bounds__(256) rank_k(const float* __restrict__ fg,
                                              const int* __restrict__ fe,
                                              int* __restrict__ slot,
                                              int* __restrict__ etok,
                                              float* __restrict__ egate) {
    __shared__ float sg[NA];
    __shared__ unsigned char se[NA];
    for (int i = threadIdx.x; i < NA; i += 256) {
        sg[i] = fg[i];
        se[i] = (unsigned char)fe[i];
    }
    __syncthreads();
    int i = blockIdx.x * 256 + threadIdx.x;
    float gi = sg[i];
    unsigned char ei = se[i];
    int r = 0;
    for (int j = 0; j < NA; j++) {
        bool c = (se[j] == ei) && ((sg[j] > gi) || (sg[j] == gi && j < i));
        r += (int)c;
    }
    if (r < CAPn) {
        slot[i] = r;
        etok[(int)ei * CAPn + r] = i >> 1;
        egate[(int)ei * CAPn + r] = gi;
    } else {
        slot[i] = -1;
    }
}

// ---------------------------------------------------------------------------
// Gather expert inputs (row-major, tf32-rounded; tok<0 -> zeros)
// ---------------------------------------------------------------------------
__global__ void __launch_bounds__(256) xepack_k(const float* __restrict__ xn,
                                                const int* __restrict__ etok,
                                                float* __restrict__ xe) {
    int row = blockIdx.x;
    int tok = etok[row];
    int i = threadIdx.x;
    float4 v = make_float4(0.f, 0.f, 0.f, 0.f);
    if (tok >= 0) v = ((const float4*)(xn + (size_t)tok * Dm))[i];
    v.x = rnd_tf32(v.x); v.y = rnd_tf32(v.y); v.z = rnd_tf32(v.z); v.w = rnd_tf32(v.w);
    ((float4*)(xe + (size_t)row * Dm))[i] = v;
}

// ---------------------------------------------------------------------------
// Final combine
// ---------------------------------------------------------------------------
__global__ void __launch_bounds__(256) combine_k(const float* __restrict__ x1,
                                                 const float* __restrict__ ye,
                                                 const int* __restrict__ fe,
                                                 const int* __restrict__ slot,
                                                 float* __restrict__ out) {
    int t = blockIdx.x;
    int d = threadIdx.x;
    float4 v = ((const float4*)(x1 + (size_t)t * Dm))[d];
#pragma unroll
    for (int kk = 0; kk < 2; kk++) {
        int i = 2 * t + kk;
        int sl = slot[i];
        if (sl >= 0) {
            int e = fe[i];
            float4 w = ((const float4*)(ye + ((size_t)e * CAPn + sl) * Dm))[d];
            v.x += w.x; v.y += w.y; v.z += w.z; v.w += w.w;
        }
    }
    ((float4*)(out + (size_t)t * Dm))[d] = v;
}

// ---------------------------------------------------------------------------
// Launch
// ---------------------------------------------------------------------------
extern "C" void kernel_launch(void* const* d_in, const int* in_sizes, int n_in,
                              void* d_out, int out_size) {
    (void)in_sizes; (void)n_in; (void)out_size;
    const float* x        = (const float*)d_in[0];
    const float* g1       = (const float*)d_in[1];
    const float* w_qkv    = (const float*)d_in[2];
    const float* w_o      = (const float*)d_in[3];
    const float* g2       = (const float*)d_in[4];
    const float* w_router = (const float*)d_in[5];
    const float* w1       = (const float*)d_in[6];
    const float* w2       = (const float*)d_in[7];
    float* out = (float*)d_out;

    float *p_xn, *p_qkv, *p_q, *p_k, *p_v, *p_attn, *p_x1, *p_cos, *p_sin;
    float *p_fg, *p_egate, *p_h, *p_ye, *p_xe;
    float *p_wqkvr, *p_wor, *p_w1r, *p_w2r;
    int *p_fe, *p_slot, *p_etok;
    cudaGetSymbolAddress((void**)&p_xn,   g_xn);
    cudaGetSymbolAddress((void**)&p_qkv,  g_qkv);
    cudaGetSymbolAddress((void**)&p_q,    g_q);
    cudaGetSymbolAddress((void**)&p_k,    g_k);
    cudaGetSymbolAddress((void**)&p_v,    g_v);
    cudaGetSymbolAddress((void**)&p_attn, g_attn);
    cudaGetSymbolAddress((void**)&p_x1,   g_x1);
    cudaGetSymbolAddress((void**)&p_cos,  g_cos);
    cudaGetSymbolAddress((void**)&p_sin,  g_sin);
    cudaGetSymbolAddress((void**)&p_fg,   g_fg);
    cudaGetSymbolAddress((void**)&p_fe,   g_fe);
    cudaGetSymbolAddress((void**)&p_slot, g_slot);
    cudaGetSymbolAddress((void**)&p_etok, g_etok);
    cudaGetSymbolAddress((void**)&p_egate,g_egate);
    cudaGetSymbolAddress((void**)&p_h,    g_h);
    cudaGetSymbolAddress((void**)&p_ye,   g_ye);
    cudaGetSymbolAddress((void**)&p_xe,   g_xe);
    cudaGetSymbolAddress((void**)&p_wqkvr,g_wqkvr);
    cudaGetSymbolAddress((void**)&p_wor,  g_wor);
    cudaGetSymbolAddress((void**)&p_w1r,  g_w1r);
    cudaGetSymbolAddress((void**)&p_w2r,  g_w2r);

    constexpr int GEMM_SMEM = 3 * 51712;         // 155136 bytes
    constexpr int ATTN_SMEM = 2 * 8960 * 4;      // 71680 bytes
    cudaFuncSetAttribute(gemm2_k<0>, cudaFuncAttributeMaxDynamicSharedMemorySize, GEMM_SMEM);
    cudaFuncSetAttribute(gemm2_k<1>, cudaFuncAttributeMaxDynamicSharedMemorySize, GEMM_SMEM);
    cudaFuncSetAttribute(gemm2_k<2>, cudaFuncAttributeMaxDynamicSharedMemorySize, GEMM_SMEM);
    cudaFuncSetAttribute(gemm2_k<3>, cudaFuncAttributeMaxDynamicSharedMemorySize, GEMM_SMEM);
    cudaFuncSetAttribute(attn_tc_k,  cudaFuncAttributeMaxDynamicSharedMemorySize, ATTN_SMEM);

    // Independent precomputation
    rope_table_k<<<(Sq * 32 + 255) / 256, 256>>>(p_cos, p_sin);
    wround_k<<<592, 256>>>(w_qkv, p_wqkvr, Dm * 3 * Dm / 4);
    wround_k<<<592, 256>>>(w_o,   p_wor,   Dm * Dm / 4);
    wround_k<<<592, 256>>>(w1,    p_w1r,   En * Dm * FFNm / 4);
    wround_k<<<592, 256>>>(w2,    p_w2r,   En * FFNm * Dm / 4);

    // Attention branch
    rmsnorm_k<true><<<Tn, 256>>>(x, g1, p_xn);
    gemm2_k<0><<<dim3(3 * Dm / 256, Tn / 128, 1), 256, GEMM_SMEM>>>(
        p_xn, p_wqkvr, p_qkv, 3 * Dm, Dm, nullptr, 0, 0, 0, 0);
    split_rope_k<<<Tn, 256>>>(p_qkv, p_cos, p_sin, p_q, p_k, p_v);
    attn_tc_k<<<dim3(Sq / 128, Hn, Bz), 256, ATTN_SMEM>>>(p_q, p_k, p_v, p_attn);
    gemm2_k<1><<<dim3(Dm / 256, Tn / 128, 1), 256, GEMM_SMEM>>>(
        p_attn, p_wor, p_x1, Dm, Dm, x, 0, 0, 0, 0);
    rmsnorm_k<false><<<Tn, 256>>>(p_x1, g2, p_xn);

    // Routing (fp32 exact)
    router_k<<<Tn / 8, 256>>>(p_xn, w_router, p_fg, p_fe);
    init_etok_k<<<(En * CAPn + 255) / 256, 256>>>(p_etok);
    rank_k<<<NA / 256, 256>>>(p_fg, p_fe, p_slot, p_etok, p_egate);
    xepack_k<<<En * CAPn, 256>>>(p_xn, p_etok, p_xe);

    // MoE expert GEMMs (tf32)
    gemm2_k<2><<<dim3(FFNm / 256, CAPn / 128, En), 256, GEMM_SMEM>>>(
        p_xe, p_w1r, p_h, FFNm, Dm, nullptr,
        (long)CAPn * Dm, (long)Dm * FFNm, (long)CAPn * FFNm, 0);
    gemm2_k<3><<<dim3(Dm / 256, CAPn / 128, En), 256, GEMM_SMEM>>>(
        p_h, p_w2r, p_ye, Dm, FFNm, p_egate,
        (long)CAPn * FFNm, (long)FFNm * Dm, (long)CAPn * Dm, CAPn);

    // out = x1 + moe
    combine_k<<<Tn, 256>>>(p_x1, p_ye, p_fe, p_slot, out);
}

// round 7
// speedup vs baseline: 4.8249x; 1.2435x over previous
#include <cuda_runtime.h>
#include <cuda_bf16.h>
#include <math.h>
#include <stdint.h>

// ---------------------------------------------------------------------------
// Problem constants
// ---------------------------------------------------------------------------
namespace {
constexpr int Bz   = 2;
constexpr int Sq   = 2048;
constexpr int Dm   = 1024;
constexpr int Hn   = 16;
constexpr int HDm  = 64;
constexpr int FFNm = 2048;
constexpr int En   = 8;
constexpr int Tn   = Bz * Sq;     // 4096 tokens
constexpr int NA   = Tn * 2;      // 8192 flat assignments (top-2)
constexpr int CAPn = 1280;        // ceil(2*2048*2*1.25/8)
}

// ---------------------------------------------------------------------------
// Static scratch (no allocations allowed)
// ---------------------------------------------------------------------------
__device__ float g_xn  [Tn * Dm];
__device__ float g_qkv [Tn * 3 * Dm];
__device__ float g_q   [Tn * Dm];
__device__ float g_k   [Tn * Dm];
__device__ float g_v   [Tn * Dm];
__device__ float g_attn[Tn * Dm];
__device__ float g_x1  [Tn * Dm];
__device__ float g_cos [Sq * (HDm / 2)];
__device__ float g_sin [Sq * (HDm / 2)];
__device__ float g_fg  [NA];
__device__ int   g_fe  [NA];
__device__ int   g_slot[NA];
__device__ int   g_etok [En * CAPn];
__device__ float g_egate[En * CAPn];
__device__ float g_ye[En * CAPn * Dm];
// tf32-rounded weight copies (attention branch)
__device__ float g_wqkvr[Dm * 3 * Dm];
__device__ float g_wor  [Dm * Dm];
// bf16 MoE data
__device__ __nv_bfloat16 g_xeb[En * CAPn * Dm];
__device__ __nv_bfloat16 g_hb [En * CAPn * FFNm];
__device__ __nv_bfloat16 g_w1b[En * Dm * FFNm];
__device__ __nv_bfloat16 g_w2b[En * FFNm * Dm];

// ---------------------------------------------------------------------------
// Helpers
// ---------------------------------------------------------------------------
__device__ __forceinline__ float rnd_tf32(float x) {
    uint32_t u = __float_as_uint(x);
    u = (u + 0x1000u) & 0xFFFFE000u;
    return __uint_as_float(u);
}

__device__ __forceinline__ uint32_t smem_u32(const void* p) {
    uint32_t a;
    asm("{ .reg .u64 t; cvta.to.shared.u64 t, %1; cvt.u32.u64 %0, t; }"
        : "=r"(a) : "l"(p));
    return a;
}

__device__ __forceinline__ void cpasync16(uint32_t dst, const void* src) {
    asm volatile("cp.async.cg.shared.global [%0], [%1], 16;" :: "r"(dst), "l"(src));
}
__device__ __forceinline__ void cp_commit() {
    asm volatile("cp.async.commit_group;" ::: "memory");
}
template <int N>
__device__ __forceinline__ void cp_wait() {
    asm volatile("cp.async.wait_group %0;" :: "n"(N) : "memory");
}

// tf32 m16n8k8 MMA
__device__ __forceinline__ void mma_tf32(float* d, const uint32_t* a, const uint32_t* b) {
    asm volatile(
        "mma.sync.aligned.m16n8k8.row.col.f32.tf32.tf32.f32 "
        "{%0,%1,%2,%3}, {%4,%5,%6,%7}, {%8,%9}, {%0,%1,%2,%3};"
        : "+f"(d[0]), "+f"(d[1]), "+f"(d[2]), "+f"(d[3])
        : "r"(a[0]), "r"(a[1]), "r"(a[2]), "r"(a[3]), "r"(b[0]), "r"(b[1]));
}

// bf16 m16n8k16 MMA
__device__ __forceinline__ void mma_bf16(float* d, const uint32_t* a, const uint32_t* b) {
    asm volatile(
        "mma.sync.aligned.m16n8k16.row.col.f32.bf16.bf16.f32 "
        "{%0,%1,%2,%3}, {%4,%5,%6,%7}, {%8,%9}, {%0,%1,%2,%3};"
        : "+f"(d[0]), "+f"(d[1]), "+f"(d[2]), "+f"(d[3])
        : "r"(a[0]), "r"(a[1]), "r"(a[2]), "r"(a[3]), "r"(b[0]), "r"(b[1]));
}

__device__ __forceinline__ void ldsm_x4(uint32_t* r, uint32_t addr) {
    asm volatile("ldmatrix.sync.aligned.m8n8.x4.shared.b16 {%0,%1,%2,%3}, [%4];"
                 : "=r"(r[0]), "=r"(r[1]), "=r"(r[2]), "=r"(r[3]) : "r"(addr));
}
__device__ __forceinline__ void ldsm_x4_t(uint32_t* r, uint32_t addr) {
    asm volatile("ldmatrix.sync.aligned.m8n8.x4.trans.shared.b16 {%0,%1,%2,%3}, [%4];"
                 : "=r"(r[0]), "=r"(r[1]), "=r"(r[2]), "=r"(r[3]) : "r"(addr));
}

// 2^x for x <= 0, FMA-pipe only.
__device__ __forceinline__ float exp2p(float x) {
    float t = fmaxf(x, -126.f);
    float z = t + 12582912.f;
    float n = z - 12582912.f;
    float f = t - n;
    float p =         1.5353e-4f;
    p = fmaf(p, f, 1.3398886e-3f);
    p = fmaf(p, f, 9.6184372e-3f);
    p = fmaf(p, f, 5.5503327e-2f);
    p = fmaf(p, f, 2.4022648e-1f);
    p = fmaf(p, f, 6.9314718e-1f);
    p = fmaf(p, f, 1.0f);
    int iz = __float_as_int(z) - 0x4B400000;
    return p * __int_as_float((iz + 127) << 23);
}

// ---------------------------------------------------------------------------
// Weight pre-conversion kernels
// ---------------------------------------------------------------------------
__global__ void wround_k(const float* __restrict__ in, float* __restrict__ out, int n4) {
    int i = blockIdx.x * blockDim.x + threadIdx.x;
    int stride = gridDim.x * blockDim.x;
    for (; i < n4; i += stride) {
        float4 v = ((const float4*)in)[i];
        v.x = rnd_tf32(v.x); v.y = rnd_tf32(v.y);
        v.z = rnd_tf32(v.z); v.w = rnd_tf32(v.w);
        ((float4*)out)[i] = v;
    }
}

__global__ void wbf16_k(const float* __restrict__ in, __nv_bfloat16* __restrict__ out, int n4) {
    int i = blockIdx.x * blockDim.x + threadIdx.x;
    int stride = gridDim.x * blockDim.x;
    for (; i < n4; i += stride) {
        float4 v = ((const float4*)in)[i];
        __nv_bfloat162 lo = __float22bfloat162_rn(make_float2(v.x, v.y));
        __nv_bfloat162 hi = __float22bfloat162_rn(make_float2(v.z, v.w));
        ((uint2*)out)[i] = make_uint2(*(uint32_t*)&lo, *(uint32_t*)&hi);
    }
}

// ---------------------------------------------------------------------------
// RMSNorm
// ---------------------------------------------------------------------------
template <bool RND>
__global__ void __launch_bounds__(256) rmsnorm_k(const float* __restrict__ x,
                                                 const float* __restrict__ g,
                                                 float* __restrict__ y) {
    int row = blockIdx.x;
    int i = threadIdx.x;
    const float4* xr = (const float4*)(x + (size_t)row * Dm);
    float4 xv = xr[i];
    float ss = xv.x * xv.x + xv.y * xv.y + xv.z * xv.z + xv.w * xv.w;
#pragma unroll
    for (int off = 16; off; off >>= 1) ss += __shfl_down_sync(0xffffffffu, ss, off);
    __shared__ float red[8];
    __shared__ float srms;
    if ((i & 31) == 0) red[i >> 5] = ss;
    __syncthreads();
    if (i == 0) {
        float t = 0.f;
#pragma unroll
        for (int w = 0; w < 8; w++) t += red[w];
        srms = rsqrtf(t * (1.0f / Dm) + 1e-6f);
    }
    __syncthreads();
    float r = srms;
    float4 gv = ((const float4*)g)[i];
    float4 o;
    o.x = gv.x * xv.x * r; o.y = gv.y * xv.y * r;
    o.z = gv.z * xv.z * r; o.w = gv.w * xv.w * r;
    if (RND) {
        o.x = rnd_tf32(o.x); o.y = rnd_tf32(o.y);
        o.z = rnd_tf32(o.z); o.w = rnd_tf32(o.w);
    }
    ((float4*)(y + (size_t)row * Dm))[i] = o;
}

// ---------------------------------------------------------------------------
// RoPE table
// ---------------------------------------------------------------------------
__global__ void rope_table_k(float* __restrict__ ct, float* __restrict__ st) {
    int idx = blockIdx.x * blockDim.x + threadIdx.x;
    if (idx >= Sq * (HDm / 2)) return;
    int s = idx >> 5, j = idx & 31;
    float th = (float)pow(10000.0, -2.0 * (double)j / (double)HDm);
    double f = (double)s * (double)th;
    ct[idx] = (float)cos(f);
    st[idx] = (float)sin(f);
}

// ---------------------------------------------------------------------------
// Split QKV + RoPE
// ---------------------------------------------------------------------------
__global__ void __launch_bounds__(256) split_rope_k(const float* __restrict__ qkv,
                                                    const float* __restrict__ ct,
                                                    const float* __restrict__ st,
                                                    float* __restrict__ q,
                                                    float* __restrict__ k,
                                                    float* __restrict__ v) {
    int t = blockIdx.x;
    int b = t / Sq, s = t % Sq;
    const float* row = qkv + (size_t)t * (3 * Dm);
    for (int idx = threadIdx.x; idx < Hn * (HDm / 2); idx += blockDim.x) {
        int h = idx >> 5, j = idx & 31;
        float c = ct[s * 32 + j], sn = st[s * 32 + j];
        size_t o = ((size_t)(b * Hn + h) * Sq + s) * HDm;
        float qr = row[h * HDm + 2 * j], qi = row[h * HDm + 2 * j + 1];
        q[o + 2 * j]     = qr * c - qi * sn;
        q[o + 2 * j + 1] = qr * sn + qi * c;
        float kr = row[Dm + h * HDm + 2 * j], ki = row[Dm + h * HDm + 2 * j + 1];
        k[o + 2 * j]     = kr * c - ki * sn;
        k[o + 2 * j + 1] = kr * sn + ki * c;
    }
    for (int idx = threadIdx.x; idx < Dm; idx += blockDim.x) {
        int h = idx >> 6, d = idx & 63;
        v[((size_t)(b * Hn + h) * Sq + s) * HDm + d] = row[2 * Dm + idx];
    }
}

// ---------------------------------------------------------------------------
// Tensor-core causal flash attention (unchanged from R6)
// ---------------------------------------------------------------------------
__global__ void __launch_bounds__(256) attn_tc_k(const float* __restrict__ Q,
                                                 const float* __restrict__ Kt,
                                                 const float* __restrict__ Vt,
                                                 float* __restrict__ Out) {
    extern __shared__ __align__(16) float sm[];
    constexpr float LOG2E = 1.4426950408889634f;
    constexpr int STG = 64 * 68 + 64 * 72;   // 8960 floats per stage

    int bx = blockIdx.x, h = blockIdx.y, b = blockIdx.z;
    int qt = bx * 128;
    int tid = threadIdx.x, warp = tid >> 5, lane = tid & 31;
    int gq = lane >> 2, tq = lane & 3;
    int wq = qt + warp * 16;
    const size_t base = ((size_t)(b * Hn + h)) * Sq * HDm;
    const float* Qg = Q + base;
    const float* Kg = Kt + base;
    const float* Vg = Vt + base;

    const uint32_t sb = smem_u32(sm);

    uint32_t qf[8][4];
#pragma unroll
    for (int kk = 0; kk < 8; kk++) {
        int c = kk * 8 + tq;
        qf[kk][0] = __float_as_uint(rnd_tf32(Qg[(size_t)(wq + gq) * 64 + c] * 0.125f));
        qf[kk][1] = __float_as_uint(rnd_tf32(Qg[(size_t)(wq + gq + 8) * 64 + c] * 0.125f));
        qf[kk][2] = __float_as_uint(rnd_tf32(Qg[(size_t)(wq + gq) * 64 + c + 4] * 0.125f));
        qf[kk][3] = __float_as_uint(rnd_tf32(Qg[(size_t)(wq + gq + 8) * 64 + c + 4] * 0.125f));
    }

    float O[8][4];
#pragma unroll
    for (int nt = 0; nt < 8; nt++)
#pragma unroll
        for (int c = 0; c < 4; c++) O[nt][c] = 0.f;
    float m0 = -1e30f, m1 = -1e30f, l0 = 0.f, l1 = 0.f;

    int fr = tid >> 2, fs = (tid & 3) * 16;
    auto fill = [&](int stage, int kt) {
        uint32_t kDst = sb + (uint32_t)(stage * STG + fr * 68 + fs) * 4u;
        uint32_t vDst = sb + (uint32_t)(stage * STG + 64 * 68 + fr * 72 + fs) * 4u;
        const float* ks = Kg + (size_t)(kt + fr) * 64 + fs;
        const float* vs = Vg + (size_t)(kt + fr) * 64 + fs;
#pragma unroll
        for (int c = 0; c < 4; c++) {
            cpasync16(kDst + 16u * c, ks + 4 * c);
            cpasync16(vDst + 16u * c, vs + 4 * c);
        }
    };

    int ntiles = 2 * bx + 2;
    fill(0, 0);
    cp_commit();

    for (int it = 0; it < ntiles; it++) {
        if (it + 1 < ntiles) fill((it + 1) & 1, (it + 1) * 64);
        cp_commit();
        cp_wait<1>();
        __syncthreads();

        int kt = it * 64;
        if (kt <= wq + 15) {
            const float* Ks = sm + (it & 1) * STG;
            const float* Vs = Ks + 64 * 68;

            float s[8][4];
#pragma unroll
            for (int nt = 0; nt < 8; nt++)
#pragma unroll
                for (int c = 0; c < 4; c++) s[nt][c] = 0.f;
#pragma unroll
            for (int kk = 0; kk < 8; kk++) {
                uint32_t bf[8][2];
#pragma unroll
                for (int nt = 0; nt < 8; nt++) {
                    int krow = nt * 8 + gq;
                    bf[nt][0] = __float_as_uint(Ks[krow * 68 + kk * 8 + tq]);
                    bf[nt][1] = __float_as_uint(Ks[krow * 68 + kk * 8 + tq + 4]);
                }
#pragma unroll
                for (int nt = 0; nt < 8; nt++) mma_tf32(s[nt], qf[kk], bf[nt]);
            }

            if (kt + 63 > wq) {
                int r0 = wq + gq, r1 = wq + gq + 8;
#pragma unroll
                for (int nt = 0; nt < 8; nt++) {
                    int c0 = kt + nt * 8 + 2 * tq;
                    if (c0 > r0)     s[nt][0] = -3.4e38f;
                    if (c0 + 1 > r0) s[nt][1] = -3.4e38f;
                    if (c0 > r1)     s[nt][2] = -3.4e38f;
                    if (c0 + 1 > r1) s[nt][3] = -3.4e38f;
                }
            }

            float mx0 = -3.4e38f, mx1 = -3.4e38f;
#pragma unroll
            for (int nt = 0; nt < 8; nt++) {
                mx0 = fmaxf(mx0, fmaxf(s[nt][0], s[nt][1]));
                mx1 = fmaxf(mx1, fmaxf(s[nt][2], s[nt][3]));
            }
            mx0 = fmaxf(mx0, __shfl_xor_sync(0xffffffffu, mx0, 1));
            mx0 = fmaxf(mx0, __shfl_xor_sync(0xffffffffu, mx0, 2));
            mx1 = fmaxf(mx1, __shfl_xor_sync(0xffffffffu, mx1, 1));
            mx1 = fmaxf(mx1, __shfl_xor_sync(0xffffffffu, mx1, 2));
            float mn0 = fmaxf(m0, mx0), mn1 = fmaxf(m1, mx1);
            float cr0 = exp2p((m0 - mn0) * LOG2E);
            float cr1 = exp2p((m1 - mn1) * LOG2E);
            float nm0 = mn0 * LOG2E, nm1 = mn1 * LOG2E;

            float sum0 = 0.f, sum1 = 0.f;
#pragma unroll
            for (int nt = 0; nt < 8; nt++) {
                float p0 = rnd_tf32(exp2p(fmaf(s[nt][0], LOG2E, -nm0)));
                float p1 = rnd_tf32(exp2p(fmaf(s[nt][1], LOG2E, -nm0)));
                float p2 = rnd_tf32(exp2p(fmaf(s[nt][2], LOG2E, -nm1)));
                float p3 = rnd_tf32(exp2p(fmaf(s[nt][3], LOG2E, -nm1)));
                s[nt][0] = p0; s[nt][1] = p1; s[nt][2] = p2; s[nt][3] = p3;
                sum0 += p0 + p1; sum1 += p2 + p3;
            }
            sum0 += __shfl_xor_sync(0xffffffffu, sum0, 1);
            sum0 += __shfl_xor_sync(0xffffffffu, sum0, 2);
            sum1 += __shfl_xor_sync(0xffffffffu, sum1, 1);
            sum1 += __shfl_xor_sync(0xffffffffu, sum1, 2);
            l0 = l0 * cr0 + sum0;
            l1 = l1 * cr1 + sum1;
#pragma unroll
            for (int nt = 0; nt < 8; nt++) {
                O[nt][0] *= cr0; O[nt][1] *= cr0;
                O[nt][2] *= cr1; O[nt][3] *= cr1;
            }
            m0 = mn0; m1 = mn1;

            int sl1 = gq * 4 + (tq >> 1);
            int sl2 = sl1 + 2;
            bool odd = (tq & 1);
#pragma unroll
            for (int kk = 0; kk < 8; kk++) {
                float v00 = __shfl_sync(0xffffffffu, s[kk][0], sl1);
                float v01 = __shfl_sync(0xffffffffu, s[kk][1], sl1);
                float v10 = __shfl_sync(0xffffffffu, s[kk][0], sl2);
                float v11 = __shfl_sync(0xffffffffu, s[kk][1], sl2);
                float w00 = __shfl_sync(0xffffffffu, s[kk][2], sl1);
                float w01 = __shfl_sync(0xffffffffu, s[kk][3], sl1);
                float w10 = __shfl_sync(0xffffffffu, s[kk][2], sl2);
                float w11 = __shfl_sync(0xffffffffu, s[kk][3], sl2);
                uint32_t a[4];
                a[0] = __float_as_uint(odd ? v01 : v00);
                a[1] = __float_as_uint(odd ? w01 : w00);
                a[2] = __float_as_uint(odd ? v11 : v10);
                a[3] = __float_as_uint(odd ? w11 : w10);
                uint32_t bf[8][2];
#pragma unroll
                for (int nt = 0; nt < 8; nt++) {
                    int krow = kk * 8 + tq;
                    bf[nt][0] = __float_as_uint(Vs[krow * 72 + nt * 8 + gq]);
                    bf[nt][1] = __float_as_uint(Vs[(krow + 4) * 72 + nt * 8 + gq]);
                }
#pragma unroll
                for (int nt = 0; nt < 8; nt++) mma_tf32(O[nt], a, bf[nt]);
            }
        }
        __syncthreads();
    }

    float i0 = 1.f / l0, i1 = 1.f / l1;
    int r0 = wq + gq, r1 = wq + gq + 8;
    float* o0 = Out + ((size_t)(b * Sq + r0)) * Dm + h * 64 + 2 * tq;
    float* o1 = Out + ((size_t)(b * Sq + r1)) * Dm + h * 64 + 2 * tq;
#pragma unroll
    for (int nt = 0; nt < 8; nt++) {
        float2 u, w;
        u.x = rnd_tf32(O[nt][0] * i0); u.y = rnd_tf32(O[nt][1] * i0);
        w.x = rnd_tf32(O[nt][2] * i1); w.y = rnd_tf32(O[nt][3] * i1);
        *(float2*)(o0 + nt * 8) = u;
        *(float2*)(o1 + nt * 8) = w;
    }
}

// ---------------------------------------------------------------------------
// tf32 GEMM (qkv + o projections; MODE 0 plain, 1 +resid) — unchanged
// ---------------------------------------------------------------------------
template <int MODE>
__global__ void __launch_bounds__(256, 1)
gemm2_k(const float* __restrict__ A, const float* __restrict__ Bm,
        float* __restrict__ C, int N, int K,
        const float* __restrict__ extra) {
    extern __shared__ __align__(16) float sm[];
    const uint32_t sb = smem_u32(sm);
    constexpr int STGF = 12928;
    constexpr int STGB = STGF * 4;

    int tid = threadIdx.x, warp = tid >> 5, lane = tid & 31;
    int gq = lane >> 2, tq = lane & 3;

    int m0 = blockIdx.y * 128, n0 = blockIdx.x * 256;
    int wm = (warp & 1) * 64, wn = (warp >> 1) * 64;

    int ar = tid >> 1;
    int acf = (tid & 1) * 16;
    int br = tid >> 3;
    int bcf = (tid & 7) * 4;
    const float* aSrc = A + (size_t)(m0 + ar) * K + acf;
    const float* bSrc = Bm + (size_t)br * N + n0 + bcf;
    uint32_t aDst = sb + (uint32_t)(ar * 144 + acf * 4);
    uint32_t bDst = sb + 18432u + (uint32_t)(br * 1040 + bcf * 4);

    auto fetch = [&](int stage, int k0) {
        uint32_t so = (uint32_t)stage * STGB;
        const float* as = aSrc + k0;
#pragma unroll
        for (int i = 0; i < 4; i++) cpasync16(aDst + so + 16u * i, as + 4 * i);
        const float* bs = bSrc + (size_t)k0 * N;
#pragma unroll
        for (int j = 0; j < 8; j++) cpasync16(bDst + so + 128u * j, bs + 32 * j);
    };

    float d[4][8][4];
#pragma unroll
    for (int i = 0; i < 4; i++)
#pragma unroll
        for (int j = 0; j < 8; j++)
#pragma unroll
            for (int c = 0; c < 4; c++) d[i][j][c] = 0.f;

    fetch(0, 0);  cp_commit();
    fetch(1, 32); cp_commit();
    fetch(2, 64); cp_commit();

    int KB = K >> 5;
    int stg = 0;
    for (int it = 0; it < KB; ++it) {
        cp_wait<2>();
        __syncthreads();
        const float* As = sm + stg * STGF;
        const float* Bs = As + 4608;
#pragma unroll
        for (int kk = 0; kk < 4; kk++) {
            uint32_t a[4][4], b[8][2];
#pragma unroll
            for (int mt = 0; mt < 4; mt++) {
                int row = wm + mt * 16 + gq;
                int col = kk * 8 + tq;
                a[mt][0] = __float_as_uint(As[row * 36 + col]);
                a[mt][1] = __float_as_uint(As[(row + 8) * 36 + col]);
                a[mt][2] = __float_as_uint(As[row * 36 + col + 4]);
                a[mt][3] = __float_as_uint(As[(row + 8) * 36 + col + 4]);
            }
#pragma unroll
            for (int nt = 0; nt < 8; nt++) {
                int col = wn + nt * 8 + gq;
                b[nt][0] = __float_as_uint(Bs[(kk * 8 + tq) * 260 + col]);
                b[nt][1] = __float_as_uint(Bs[(kk * 8 + tq + 4) * 260 + col]);
            }
#pragma unroll
            for (int mt = 0; mt < 4; mt++)
#pragma unroll
                for (int nt = 0; nt < 8; nt++)
                    mma_tf32(d[mt][nt], a[mt], b[nt]);
        }
        __syncthreads();
        if (it + 3 < KB) fetch(stg, (it + 3) * 32);
        cp_commit();
        stg = (stg == 2) ? 0 : stg + 1;
    }

#pragma unroll
    for (int mt = 0; mt < 4; mt++) {
        int r0 = m0 + wm + mt * 16 + gq;
        int r1 = r0 + 8;
#pragma unroll
        for (int nt = 0; nt < 8; nt++) {
            int c = n0 + wn + nt * 8 + 2 * tq;
            float2 v01, v23;
            v01.x = d[mt][nt][0]; v01.y = d[mt][nt][1];
            v23.x = d[mt][nt][2]; v23.y = d[mt][nt][3];
            if (MODE == 1) {
                float2 ra = *(const float2*)(extra + (size_t)r0 * N + c);
                float2 rb = *(const float2*)(extra + (size_t)r1 * N + c);
                v01.x += ra.x; v01.y += ra.y;
                v23.x += rb.x; v23.y += rb.y;
            }
            *(float2*)(C + (size_t)r0 * N + c) = v01;
            *(float2*)(C + (size_t)r1 * N + c) = v23;
        }
    }
}

// ---------------------------------------------------------------------------
// bf16 tensor-core GEMM (MoE experts): CTA 128x256, warp 64x64, BK=32,
// 4-stage cp.async pipeline, ldmatrix fragment loads, m16n8k16 MMA.
// Smem: A 128x32 bf16 (64B rows, chunk swizzle c^((r>>1)&3)),
//       B 32x256 bf16 (512B rows, chunk swizzle c^(r&7)).  24KB/stage.
// MODE 0: C(bf16) = bf16(relu(A@B))   MODE 1: C(f32) = (A@B)*gates[row]
// ---------------------------------------------------------------------------
template <int MODE>
__global__ void __launch_bounds__(256, 1)
gemm_bf16_k(const __nv_bfloat16* __restrict__ A, const __nv_bfloat16* __restrict__ Bm,
            void* __restrict__ Cp, int N, int K,
            const float* __restrict__ gates,
            long sA, long sB, long sC, int gstride) {
    extern __shared__ __align__(16) float smf[];
    const uint32_t sb = smem_u32(smf);
    constexpr uint32_t STGB = 24576;

    int tid = threadIdx.x, warp = tid >> 5, lane = tid & 31;
    int gq = lane >> 2, tq = lane & 3;
    int e = blockIdx.z;
    A  += (size_t)e * sA;
    Bm += (size_t)e * sB;
    if (MODE == 1) gates += (size_t)e * gstride;

    int m0 = blockIdx.y * 128, n0 = blockIdx.x * 256;
    int wm = (warp & 1) * 64, wn = (warp >> 1) * 64;

    // fill assignments
    int ar = tid >> 1, ah = tid & 1;        // A: row, 16-elem half
    int br2 = tid >> 3, bc0 = (tid & 7) * 4; // B: k-row, chunk base (4 chunks)
    const __nv_bfloat16* aSrc = A + (size_t)(m0 + ar) * K + ah * 16;
    const __nv_bfloat16* bSrc = Bm + (size_t)br2 * N + n0 + bc0 * 8;
    uint32_t aS = (ar >> 1) & 3;
    uint32_t aBase = sb + (uint32_t)ar * 64u;
    uint32_t bBase = sb + 8192u + (uint32_t)br2 * 512u;

    auto fetch = [&](int stage, int k0) {
        uint32_t so = (uint32_t)stage * STGB;
        const __nv_bfloat16* as = aSrc + k0;
        uint32_t c0 = 2u * ah;
        cpasync16(aBase + so + ((c0 ^ aS) * 16u), as);
        cpasync16(aBase + so + (((c0 + 1) ^ aS) * 16u), as + 8);
        const __nv_bfloat16* bs = bSrc + (size_t)k0 * N;
#pragma unroll
        for (int j = 0; j < 4; j++) {
            uint32_t c = bc0 + j;
            cpasync16(bBase + so + ((c ^ (br2 & 7)) * 16u), bs + j * 8);
        }
    };

    float d[4][8][4];
#pragma unroll
    for (int i = 0; i < 4; i++)
#pragma unroll
        for (int j = 0; j < 8; j++)
#pragma unroll
            for (int c = 0; c < 4; c++) d[i][j][c] = 0.f;

    fetch(0, 0);  cp_commit();
    fetch(1, 32); cp_commit();
    fetch(2, 64); cp_commit();

    // ldmatrix per-thread address components
    int lrow = lane & 7, selb = (lane >> 3) & 1, selc = lane >> 4;
    uint32_t aRow = (uint32_t)(wm + lrow + 8 * selb) * 64u;
    uint32_t aSw  = (uint32_t)((lrow >> 1) & 3);
    uint32_t bRow = (uint32_t)(lrow + 8 * selb) * 512u;
    uint32_t bCb  = (uint32_t)((wn >> 3) + selc);

    int KB = K >> 5;
    for (int it = 0; it < KB; ++it) {
        cp_wait<2>();
        __syncthreads();
        if (it + 3 < KB) fetch((it + 3) & 3, (it + 3) * 32);
        cp_commit();

        uint32_t As = sb + (uint32_t)(it & 3) * STGB;
        uint32_t Bs = As + 8192u;
#pragma unroll
        for (int kk = 0; kk < 2; kk++) {
            uint32_t a[4][4], b[8][2];
#pragma unroll
            for (int mt = 0; mt < 4; mt++) {
                uint32_t addr = As + aRow + (uint32_t)mt * 1024u
                              + ((((uint32_t)(2 * kk) + (uint32_t)selc) ^ aSw) * 16u);
                ldsm_x4(a[mt], addr);
            }
#pragma unroll
            for (int np = 0; np < 4; np++) {
                uint32_t q[4];
                uint32_t addr = Bs + bRow + (uint32_t)kk * 8192u
                              + (((bCb + 2u * np) ^ (uint32_t)lrow) * 16u);
                ldsm_x4_t(q, addr);
                b[2 * np][0]     = q[0]; b[2 * np][1]     = q[1];
                b[2 * np + 1][0] = q[2]; b[2 * np + 1][1] = q[3];
            }
#pragma unroll
            for (int mt = 0; mt < 4; mt++)
#pragma unroll
                for (int nt = 0; nt < 8; nt++)
                    mma_bf16(d[mt][nt], a[mt], b[nt]);
        }
        __syncthreads();
    }

    // Epilogue
#pragma unroll
    for (int mt = 0; mt < 4; mt++) {
        int r0 = m0 + wm + mt * 16 + gq;
        int r1 = r0 + 8;
        if (MODE == 0) {
            __nv_bfloat16* Cb = (__nv_bfloat16*)Cp + (size_t)e * sC;
#pragma unroll
            for (int nt = 0; nt < 8; nt++) {
                int c = n0 + wn + nt * 8 + 2 * tq;
                __nv_bfloat162 u = __float22bfloat162_rn(
                    make_float2(fmaxf(d[mt][nt][0], 0.f), fmaxf(d[mt][nt][1], 0.f)));
                __nv_bfloat162 w = __float22bfloat162_rn(
                    make_float2(fmaxf(d[mt][nt][2], 0.f), fmaxf(d[mt][nt][3], 0.f)));
                *(__nv_bfloat162*)(Cb + (size_t)r0 * N + c) = u;
                *(__nv_bfloat162*)(Cb + (size_t)r1 * N + c) = w;
            }
        } else {
            float* Cf = (float*)Cp + (size_t)e * sC;
            float g0 = gates[r0], g1 = gates[r1];
#pragma unroll
            for (int nt = 0; nt < 8; nt++) {
                int c = n0 + wn + nt * 8 + 2 * tq;
                float2 u, w;
                u.x = d[mt][nt][0] * g0; u.y = d[mt][nt][1] * g0;
                w.x = d[mt][nt][2] * g1; w.y = d[mt][nt][3] * g1;
                *(float2*)(Cf + (size_t)r0 * N + c) = u;
                *(float2*)(Cf + (size_t)r1 * N + c) = w;
            }
        }
    }
}

// ---------------------------------------------------------------------------
// Router (fp32, exact)
// ---------------------------------------------------------------------------
__global__ void __launch_bounds__(256) router_k(const float* __restrict__ xn,
                                                const float* __restrict__ wr,
                                                float* __restrict__ fg,
                                                int* __restrict__ fe) {
    int warp = threadIdx.x >> 5, lane = threadIdx.x & 31;
    int t = blockIdx.x * 8 + warp;
    float acc[8];
#pragma unroll
    for (int e2 = 0; e2 < 8; e2++) acc[e2] = 0.f;
    const float* xr = xn + (size_t)t * Dm;
    for (int d = lane; d < Dm; d += 32) {
        float xv = xr[d];
        const float4* w = (const float4*)(wr + d * En);
        float4 w0 = w[0], w1 = w[1];
        acc[0] = fmaf(xv, w0.x, acc[0]); acc[1] = fmaf(xv, w0.y, acc[1]);
        acc[2] = fmaf(xv, w0.z, acc[2]); acc[3] = fmaf(xv, w0.w, acc[3]);
        acc[4] = fmaf(xv, w1.x, acc[4]); acc[5] = fmaf(xv, w1.y, acc[5]);
        acc[6] = fmaf(xv, w1.z, acc[6]); acc[7] = fmaf(xv, w1.w, acc[7]);
    }
#pragma unroll
    for (int e2 = 0; e2 < 8; e2++)
#pragma unroll
        for (int off = 16; off; off >>= 1)
            acc[e2] += __shfl_down_sync(0xffffffffu, acc[e2], off);
    if (lane == 0) {
        float mx = acc[0];
#pragma unroll
        for (int e2 = 1; e2 < 8; e2++) mx = fmaxf(mx, acc[e2]);
        float p[8], sum = 0.f;
#pragma unroll
        for (int e2 = 0; e2 < 8; e2++) { p[e2] = expf(acc[e2] - mx); sum += p[e2]; }
        float inv = 1.f / sum;
#pragma unroll
        for (int e2 = 0; e2 < 8; e2++) p[e2] *= inv;
        int e0 = 0; float p0 = p[0];
#pragma unroll
        for (int e2 = 1; e2 < 8; e2++) if (p[e2] > p0) { p0 = p[e2]; e0 = e2; }
        int e1 = -1; float p1 = -1.f;
#pragma unroll
        for (int e2 = 0; e2 < 8; e2++)
            if (e2 != e0 && p[e2] > p1) { p1 = p[e2]; e1 = e2; }
        fg[2 * t]     = p0; fe[2 * t]     = e0;
        fg[2 * t + 1] = p1; fe[2 * t + 1] = e1;
    }
}

__global__ void init_etok_k(int* __restrict__ etok) {
    int i = blockIdx.x * blockDim.x + threadIdx.x;
    if (i < En * CAPn) etok[i] = -1;
}

__global__ void __launch_bounds__(256) rank_k(const float* __restrict__ fg,
                                              const int* __restrict__ fe,
                                              int* __restrict__ slot,
                                              int* __restrict__ etok,
                                              float* __restrict__ egate) {
    __shared__ float sg[NA];
    __shared__ unsigned char se[NA];
    for (int i = threadIdx.x; i < NA; i += 256) {
        sg[i] = fg[i];
        se[i] = (unsigned char)fe[i];
    }
    __syncthreads();
    int i = blockIdx.x * 256 + threadIdx.x;
    float gi = sg[i];
    unsigned char ei = se[i];
    int r = 0;
    for (int j = 0; j < NA; j++) {
        bool c = (se[j] == ei) && ((sg[j] > gi) || (sg[j] == gi && j < i));
        r += (int)c;
    }
    if (r < CAPn) {
        slot[i] = r;
        etok[(int)ei * CAPn + r] = i >> 1;
        egate[(int)ei * CAPn + r] = gi;
    } else {
        slot[i] = -1;
    }
}

// ---------------------------------------------------------------------------
// Gather expert inputs -> bf16 (tok<0 -> zeros)
// ---------------------------------------------------------------------------
__global__ void __launch_bounds__(256) xepack_k(const float* __restrict__ xn,
                                                const int* __restrict__ etok,
                                                __nv_bfloat16* __restrict__ xe) {
    int row = blockIdx.x;
    int tok = etok[row];
    int i = threadIdx.x;
    float4 v = make_float4(0.f, 0.f, 0.f, 0.f);
    if (tok >= 0) v = ((const float4*)(xn + (size_t)tok * Dm))[i];
    __nv_bfloat162 lo = __float22bfloat162_rn(make_float2(v.x, v.y));
    __nv_bfloat162 hi = __float22bfloat162_rn(make_float2(v.z, v.w));
    ((uint2*)(xe + (size_t)row * Dm))[i] = make_uint2(*(uint32_t*)&lo, *(uint32_t*)&hi);
}

// ---------------------------------------------------------------------------
// Final combine
// ---------------------------------------------------------------------------
__global__ void __launch_bounds__(256) combine_k(const float* __restrict__ x1,
                                                 const float* __restrict__ ye,
                                                 const int* __restrict__ fe,
                                                 const int* __restrict__ slot,
                                                 float* __restrict__ out) {
    int t = blockIdx.x;
    int d = threadIdx.x;
    float4 v = ((const float4*)(x1 + (size_t)t * Dm))[d];
#pragma unroll
    for (int kk = 0; kk < 2; kk++) {
        int i = 2 * t + kk;
        int sl = slot[i];
        if (sl >= 0) {
            int e = fe[i];
            float4 w = ((const float4*)(ye + ((size_t)e * CAPn + sl) * Dm))[d];
            v.x += w.x; v.y += w.y; v.z += w.z; v.w += w.w;
        }
    }
    ((float4*)(out + (size_t)t * Dm))[d] = v;
}

// ---------------------------------------------------------------------------
// Launch
// ---------------------------------------------------------------------------
extern "C" void kernel_launch(void* const* d_in, const int* in_sizes, int n_in,
                              void* d_out, int out_size) {
    (void)in_sizes; (void)n_in; (void)out_size;
    const float* x        = (const float*)d_in[0];
    const float* g1       = (const float*)d_in[1];
    const float* w_qkv    = (const float*)d_in[2];
    const float* w_o      = (const float*)d_in[3];
    const float* g2       = (const float*)d_in[4];
    const float* w_router = (const float*)d_in[5];
    const float* w1       = (const float*)d_in[6];
    const float* w2       = (const float*)d_in[7];
    float* out = (float*)d_out;

    float *p_xn, *p_qkv, *p_q, *p_k, *p_v, *p_attn, *p_x1, *p_cos, *p_sin;
    float *p_fg, *p_egate, *p_ye, *p_wqkvr, *p_wor;
    __nv_bfloat16 *p_xeb, *p_hb, *p_w1b, *p_w2b;
    int *p_fe, *p_slot, *p_etok;
    cudaGetSymbolAddress((void**)&p_xn,   g_xn);
    cudaGetSymbolAddress((void**)&p_qkv,  g_qkv);
    cudaGetSymbolAddress((void**)&p_q,    g_q);
    cudaGetSymbolAddress((void**)&p_k,    g_k);
    cudaGetSymbolAddress((void**)&p_v,    g_v);
    cudaGetSymbolAddress((void**)&p_attn, g_attn);
    cudaGetSymbolAddress((void**)&p_x1,   g_x1);
    cudaGetSymbolAddress((void**)&p_cos,  g_cos);
    cudaGetSymbolAddress((void**)&p_sin,  g_sin);
    cudaGetSymbolAddress((void**)&p_fg,   g_fg);
    cudaGetSymbolAddress((void**)&p_fe,   g_fe);
    cudaGetSymbolAddress((void**)&p_slot, g_slot);
    cudaGetSymbolAddress((void**)&p_etok, g_etok);
    cudaGetSymbolAddress((void**)&p_egate,g_egate);
    cudaGetSymbolAddress((void**)&p_ye,   g_ye);
    cudaGetSymbolAddress((void**)&p_wqkvr,g_wqkvr);
    cudaGetSymbolAddress((void**)&p_wor,  g_wor);
    cudaGetSymbolAddress((void**)&p_xeb,  g_xeb);
    cudaGetSymbolAddress((void**)&p_hb,   g_hb);
    cudaGetSymbolAddress((void**)&p_w1b,  g_w1b);
    cudaGetSymbolAddress((void**)&p_w2b,  g_w2b);

    constexpr int GEMM_SMEM = 3 * 51712;         // tf32 gemm: 155136 bytes
    constexpr int BF16_SMEM = 4 * 24576;         // bf16 gemm: 98304 bytes
    constexpr int ATTN_SMEM = 2 * 8960 * 4;      // 71680 bytes
    cudaFuncSetAttribute(gemm2_k<0>, cudaFuncAttributeMaxDynamicSharedMemorySize, GEMM_SMEM);
    cudaFuncSetAttribute(gemm2_k<1>, cudaFuncAttributeMaxDynamicSharedMemorySize, GEMM_SMEM);
    cudaFuncSetAttribute(gemm_bf16_k<0>, cudaFuncAttributeMaxDynamicSharedMemorySize, BF16_SMEM);
    cudaFuncSetAttribute(gemm_bf16_k<1>, cudaFuncAttributeMaxDynamicSharedMemorySize, BF16_SMEM);
    cudaFuncSetAttribute(attn_tc_k,  cudaFuncAttributeMaxDynamicSharedMemorySize, ATTN_SMEM);

    // Independent precomputation
    rope_table_k<<<(Sq * 32 + 255) / 256, 256>>>(p_cos, p_sin);
    wround_k<<<592, 256>>>(w_qkv, p_wqkvr, Dm * 3 * Dm / 4);
    wround_k<<<592, 256>>>(w_o,   p_wor,   Dm * Dm / 4);
    wbf16_k<<<592, 256>>>(w1, p_w1b, En * Dm * FFNm / 4);
    wbf16_k<<<592, 256>>>(w2, p_w2b, En * FFNm * Dm / 4);

    // Attention branch (tf32 — protects routing)
    rmsnorm_k<true><<<Tn, 256>>>(x, g1, p_xn);
    gemm2_k<0><<<dim3(3 * Dm / 256, Tn / 128, 1), 256, GEMM_SMEM>>>(
        p_xn, p_wqkvr, p_qkv, 3 * Dm, Dm, nullptr);
    split_rope_k<<<Tn, 256>>>(p_qkv, p_cos, p_sin, p_q, p_k, p_v);
    attn_tc_k<<<dim3(Sq / 128, Hn, Bz), 256, ATTN_SMEM>>>(p_q, p_k, p_v, p_attn);
    gemm2_k<1><<<dim3(Dm / 256, Tn / 128, 1), 256, GEMM_SMEM>>>(
        p_attn, p_wor, p_x1, Dm, Dm, x);
    rmsnorm_k<false><<<Tn, 256>>>(p_x1, g2, p_xn);

    // Routing (fp32 exact)
    router_k<<<Tn / 8, 256>>>(p_xn, w_router, p_fg, p_fe);
    init_etok_k<<<(En * CAPn + 255) / 256, 256>>>(p_etok);
    rank_k<<<NA / 256, 256>>>(p_fg, p_fe, p_slot, p_etok, p_egate);
    xepack_k<<<En * CAPn, 256>>>(p_xn, p_etok, p_xeb);

    // MoE expert GEMMs (bf16 tensor cores + ldmatrix)
    gemm_bf16_k<0><<<dim3(FFNm / 256, CAPn / 128, En), 256, BF16_SMEM>>>(
        p_xeb, p_w1b, p_hb, FFNm, Dm, nullptr,
        (long)CAPn * Dm, (long)Dm * FFNm, (long)CAPn * FFNm, 0);
    gemm_bf16_k<1><<<dim3(Dm / 256, CAPn / 128, En), 256, BF16_SMEM>>>(
        p_hb, p_w2b, p_ye, Dm, FFNm, p_egate,
        (long)CAPn * FFNm, (long)FFNm * Dm, (long)CAPn * Dm, CAPn);

    // out = x1 + moe
    combine_k<<<Tn, 256>>>(p_x1, p_ye, p_fe, p_slot, out);
}

// round 9
// speedup vs baseline: 4.8706x; 1.0095x over previous
#include <cuda_runtime.h>
#include <cuda_bf16.h>
#include <math.h>
#include <stdint.h>

// ---------------------------------------------------------------------------
// Problem constants
// ---------------------------------------------------------------------------
namespace {
constexpr int Bz   = 2;
constexpr int Sq   = 2048;
constexpr int Dm   = 1024;
constexpr int Hn   = 16;
constexpr int HDm  = 64;
constexpr int FFNm = 2048;
constexpr int En   = 8;
constexpr int Tn   = Bz * Sq;     // 4096 tokens
constexpr int NA   = Tn * 2;      // 8192 flat assignments (top-2)
constexpr int CAPn = 1280;        // ceil(2*2048*2*1.25/8)
// prep_k region sizes (float4 units except rope)
constexpr int NQ4  = Dm * 3 * Dm / 4;        // 786432
constexpr int NO4  = Dm * Dm / 4;            // 262144
constexpr int NW14 = En * Dm * FFNm / 4;     // 4194304
constexpr int NW24 = En * FFNm * Dm / 4;     // 4194304
constexpr int NRP  = Sq * (HDm / 2);         // 65536
}

// ---------------------------------------------------------------------------
// Static scratch (no allocations allowed)
// ---------------------------------------------------------------------------
__device__ float g_xn  [Tn * Dm];
__device__ float g_qkv [Tn * 3 * Dm];
__device__ float g_q   [Tn * Dm];
__device__ float g_k   [Tn * Dm];
__device__ float g_v   [Tn * Dm];
__device__ float g_attn[Tn * Dm];
__device__ float g_x1  [Tn * Dm];
__device__ float g_cos [Sq * (HDm / 2)];
__device__ float g_sin [Sq * (HDm / 2)];
__device__ float g_fg  [NA];
__device__ int   g_fe  [NA];
__device__ int   g_slot[NA];
__device__ int   g_etok [En * CAPn];
__device__ float g_egate[En * CAPn];
__device__ float g_ye[En * CAPn * Dm];
// tf32-rounded weight copies (attention branch)
__device__ float g_wqkvr[Dm * 3 * Dm];
__device__ float g_wor  [Dm * Dm];
// bf16 MoE data
__device__ __nv_bfloat16 g_xeb[En * CAPn * Dm];
__device__ __nv_bfloat16 g_hb [En * CAPn * FFNm];
__device__ __nv_bfloat16 g_w1b[En * Dm * FFNm];
__device__ __nv_bfloat16 g_w2b[En * FFNm * Dm];

// ---------------------------------------------------------------------------
// Helpers
// ---------------------------------------------------------------------------
__device__ __forceinline__ float rnd_tf32(float x) {
    uint32_t u = __float_as_uint(x);
    u = (u + 0x1000u) & 0xFFFFE000u;
    return __uint_as_float(u);
}

__device__ __forceinline__ uint32_t smem_u32(const void* p) {
    uint32_t a;
    asm("{ .reg .u64 t; cvta.to.shared.u64 t, %1; cvt.u32.u64 %0, t; }"
        : "=r"(a) : "l"(p));
    return a;
}

__device__ __forceinline__ void cpasync16(uint32_t dst, const void* src) {
    asm volatile("cp.async.cg.shared.global [%0], [%1], 16;" :: "r"(dst), "l"(src));
}
__device__ __forceinline__ void cp_commit() {
    asm volatile("cp.async.commit_group;" ::: "memory");
}
template <int N>
__device__ __forceinline__ void cp_wait() {
    asm volatile("cp.async.wait_group %0;" :: "n"(N) : "memory");
}

// tf32 m16n8k8 MMA
__device__ __forceinline__ void mma_tf32(float* d, const uint32_t* a, const uint32_t* b) {
    asm volatile(
        "mma.sync.aligned.m16n8k8.row.col.f32.tf32.tf32.f32 "
        "{%0,%1,%2,%3}, {%4,%5,%6,%7}, {%8,%9}, {%0,%1,%2,%3};"
        : "+f"(d[0]), "+f"(d[1]), "+f"(d[2]), "+f"(d[3])
        : "r"(a[0]), "r"(a[1]), "r"(a[2]), "r"(a[3]), "r"(b[0]), "r"(b[1]));
}

// bf16 m16n8k16 MMA
__device__ __forceinline__ void mma_bf16(float* d, const uint32_t* a, const uint32_t* b) {
    asm volatile(
        "mma.sync.aligned.m16n8k16.row.col.f32.bf16.bf16.f32 "
        "{%0,%1,%2,%3}, {%4,%5,%6,%7}, {%8,%9}, {%0,%1,%2,%3};"
        : "+f"(d[0]), "+f"(d[1]), "+f"(d[2]), "+f"(d[3])
        : "r"(a[0]), "r"(a[1]), "r"(a[2]), "r"(a[3]), "r"(b[0]), "r"(b[1]));
}

__device__ __forceinline__ void ldsm_x4(uint32_t* r, uint32_t addr) {
    asm volatile("ldmatrix.sync.aligned.m8n8.x4.shared.b16 {%0,%1,%2,%3}, [%4];"
                 : "=r"(r[0]), "=r"(r[1]), "=r"(r[2]), "=r"(r[3]) : "r"(addr));
}
__device__ __forceinline__ void ldsm_x4_t(uint32_t* r, uint32_t addr) {
    asm volatile("ldmatrix.sync.aligned.m8n8.x4.trans.shared.b16 {%0,%1,%2,%3}, [%4];"
                 : "=r"(r[0]), "=r"(r[1]), "=r"(r[2]), "=r"(r[3]) : "r"(addr));
}

// 2^x for x <= 0, FMA-pipe only.
__device__ __forceinline__ float exp2p(float x) {
    float t = fmaxf(x, -126.f);
    float z = t + 12582912.f;
    float n = z - 12582912.f;
    float f = t - n;
    float p =         1.5353e-4f;
    p = fmaf(p, f, 1.3398886e-3f);
    p = fmaf(p, f, 9.6184372e-3f);
    p = fmaf(p, f, 5.5503327e-2f);
    p = fmaf(p, f, 2.4022648e-1f);
    p = fmaf(p, f, 6.9314718e-1f);
    p = fmaf(p, f, 1.0f);
    int iz = __float_as_int(z) - 0x4B400000;
    return p * __int_as_float((iz + 127) << 23);
}

// ---------------------------------------------------------------------------
// Fused prep: tf32-round w_qkv+w_o, bf16-convert w1+w2, rope table.
// One launch, grid-stride over a virtual index space of all five regions.
// ---------------------------------------------------------------------------
__global__ void prep_k(const float* __restrict__ wqkv, float* __restrict__ wqkvr,
                       const float* __restrict__ wo,   float* __restrict__ wor,
                       const float* __restrict__ w1,   __nv_bfloat16* __restrict__ w1b,
                       const float* __restrict__ w2,   __nv_bfloat16* __restrict__ w2b,
                       float* __restrict__ ct, float* __restrict__ st) {
    const int total = NQ4 + NO4 + NW14 + NW24 + NRP;
    int stride = gridDim.x * blockDim.x;
    for (int i = blockIdx.x * blockDim.x + threadIdx.x; i < total; i += stride) {
        int r = i;
        if (r < NQ4) {
            float4 v = ((const float4*)wqkv)[r];
            v.x = rnd_tf32(v.x); v.y = rnd_tf32(v.y);
            v.z = rnd_tf32(v.z); v.w = rnd_tf32(v.w);
            ((float4*)wqkvr)[r] = v;
            continue;
        }
        r -= NQ4;
        if (r < NO4) {
            float4 v = ((const float4*)wo)[r];
            v.x = rnd_tf32(v.x); v.y = rnd_tf32(v.y);
            v.z = rnd_tf32(v.z); v.w = rnd_tf32(v.w);
            ((float4*)wor)[r] = v;
            continue;
        }
        r -= NO4;
        if (r < NW14) {
            float4 v = ((const float4*)w1)[r];
            __nv_bfloat162 lo = __float22bfloat162_rn(make_float2(v.x, v.y));
            __nv_bfloat162 hi = __float22bfloat162_rn(make_float2(v.z, v.w));
            ((uint2*)w1b)[r] = make_uint2(*(uint32_t*)&lo, *(uint32_t*)&hi);
            continue;
        }
        r -= NW14;
        if (r < NW24) {
            float4 v = ((const float4*)w2)[r];
            __nv_bfloat162 lo = __float22bfloat162_rn(make_float2(v.x, v.y));
            __nv_bfloat162 hi = __float22bfloat162_rn(make_float2(v.z, v.w));
            ((uint2*)w2b)[r] = make_uint2(*(uint32_t*)&lo, *(uint32_t*)&hi);
            continue;
        }
        r -= NW24;
        {
            int s = r >> 5, j = r & 31;
            float th = (float)pow(10000.0, -2.0 * (double)j / (double)HDm);
            double f = (double)s * (double)th;
            ct[r] = (float)cos(f);
            st[r] = (float)sin(f);
        }
    }
}

// ---------------------------------------------------------------------------
// RMSNorm
// ---------------------------------------------------------------------------
template <bool RND>
__global__ void __launch_bounds__(256) rmsnorm_k(const float* __restrict__ x,
                                                 const float* __restrict__ g,
                                                 float* __restrict__ y) {
    int row = blockIdx.x;
    int i = threadIdx.x;
    const float4* xr = (const float4*)(x + (size_t)row * Dm);
    float4 xv = xr[i];
    float ss = xv.x * xv.x + xv.y * xv.y + xv.z * xv.z + xv.w * xv.w;
#pragma unroll
    for (int off = 16; off; off >>= 1) ss += __shfl_down_sync(0xffffffffu, ss, off);
    __shared__ float red[8];
    __shared__ float srms;
    if ((i & 31) == 0) red[i >> 5] = ss;
    __syncthreads();
    if (i == 0) {
        float t = 0.f;
#pragma unroll
        for (int w = 0; w < 8; w++) t += red[w];
        srms = rsqrtf(t * (1.0f / Dm) + 1e-6f);
    }
    __syncthreads();
    float r = srms;
    float4 gv = ((const float4*)g)[i];
    float4 o;
    o.x = gv.x * xv.x * r; o.y = gv.y * xv.y * r;
    o.z = gv.z * xv.z * r; o.w = gv.w * xv.w * r;
    if (RND) {
        o.x = rnd_tf32(o.x); o.y = rnd_tf32(o.y);
        o.z = rnd_tf32(o.z); o.w = rnd_tf32(o.w);
    }
    ((float4*)(y + (size_t)row * Dm))[i] = o;
}

// ---------------------------------------------------------------------------
// Split QKV + RoPE
// ---------------------------------------------------------------------------
__global__ void __launch_bounds__(256) split_rope_k(const float* __restrict__ qkv,
                                                    const float* __restrict__ ct,
                                                    const float* __restrict__ st,
                                                    float* __restrict__ q,
                                                    float* __restrict__ k,
                                                    float* __restrict__ v) {
    int t = blockIdx.x;
    int b = t / Sq, s = t % Sq;
    const float* row = qkv + (size_t)t * (3 * Dm);
    for (int idx = threadIdx.x; idx < Hn * (HDm / 2); idx += blockDim.x) {
        int h = idx >> 5, j = idx & 31;
        float c = ct[s * 32 + j], sn = st[s * 32 + j];
        size_t o = ((size_t)(b * Hn + h) * Sq + s) * HDm;
        float qr = row[h * HDm + 2 * j], qi = row[h * HDm + 2 * j + 1];
        q[o + 2 * j]     = qr * c - qi * sn;
        q[o + 2 * j + 1] = qr * sn + qi * c;
        float kr = row[Dm + h * HDm + 2 * j], ki = row[Dm + h * HDm + 2 * j + 1];
        k[o + 2 * j]     = kr * c - ki * sn;
        k[o + 2 * j + 1] = kr * sn + ki * c;
    }
    for (int idx = threadIdx.x; idx < Dm; idx += blockDim.x) {
        int h = idx >> 6, d = idx & 63;
        v[((size_t)(b * Hn + h) * Sq + s) * HDm + d] = row[2 * Dm + idx];
    }
}

// ---------------------------------------------------------------------------
// Tensor-core causal flash attention (unchanged from R7)
// ---------------------------------------------------------------------------
__global__ void __launch_bounds__(256) attn_tc_k(const float* __restrict__ Q,
                                                 const float* __restrict__ Kt,
                                                 const float* __restrict__ Vt,
                                                 float* __restrict__ Out) {
    extern __shared__ __align__(16) float sm[];
    constexpr float LOG2E = 1.4426950408889634f;
    constexpr int STG = 64 * 68 + 64 * 72;

    int bx = blockIdx.x, h = blockIdx.y, b = blockIdx.z;
    int qt = bx * 128;
    int tid = threadIdx.x, warp = tid >> 5, lane = tid & 31;
    int gq = lane >> 2, tq = lane & 3;
    int wq = qt + warp * 16;
    const size_t base = ((size_t)(b * Hn + h)) * Sq * HDm;
    const float* Qg = Q + base;
    const float* Kg = Kt + base;
    const float* Vg = Vt + base;

    const uint32_t sb = smem_u32(sm);

    uint32_t qf[8][4];
#pragma unroll
    for (int kk = 0; kk < 8; kk++) {
        int c = kk * 8 + tq;
        qf[kk][0] = __float_as_uint(rnd_tf32(Qg[(size_t)(wq + gq) * 64 + c] * 0.125f));
        qf[kk][1] = __float_as_uint(rnd_tf32(Qg[(size_t)(wq + gq + 8) * 64 + c] * 0.125f));
        qf[kk][2] = __float_as_uint(rnd_tf32(Qg[(size_t)(wq + gq) * 64 + c + 4] * 0.125f));
        qf[kk][3] = __float_as_uint(rnd_tf32(Qg[(size_t)(wq + gq + 8) * 64 + c + 4] * 0.125f));
    }

    float O[8][4];
#pragma unroll
    for (int nt = 0; nt < 8; nt++)
#pragma unroll
        for (int c = 0; c < 4; c++) O[nt][c] = 0.f;
    float m0 = -1e30f, m1 = -1e30f, l0 = 0.f, l1 = 0.f;

    int fr = tid >> 2, fs = (tid & 3) * 16;
    auto fill = [&](int stage, int kt) {
        uint32_t kDst = sb + (uint32_t)(stage * STG + fr * 68 + fs) * 4u;
        uint32_t vDst = sb + (uint32_t)(stage * STG + 64 * 68 + fr * 72 + fs) * 4u;
        const float* ks = Kg + (size_t)(kt + fr) * 64 + fs;
        const float* vs = Vg + (size_t)(kt + fr) * 64 + fs;
#pragma unroll
        for (int c = 0; c < 4; c++) {
            cpasync16(kDst + 16u * c, ks + 4 * c);
            cpasync16(vDst + 16u * c, vs + 4 * c);
        }
    };

    int ntiles = 2 * bx + 2;
    fill(0, 0);
    cp_commit();

    for (int it = 0; it < ntiles; it++) {
        if (it + 1 < ntiles) fill((it + 1) & 1, (it + 1) * 64);
        cp_commit();
        cp_wait<1>();
        __syncthreads();

        int kt = it * 64;
        if (kt <= wq + 15) {
            const float* Ks = sm + (it & 1) * STG;
            const float* Vs = Ks + 64 * 68;

            float s[8][4];
#pragma unroll
            for (int nt = 0; nt < 8; nt++)
#pragma unroll
                for (int c = 0; c < 4; c++) s[nt][c] = 0.f;
#pragma unroll
            for (int kk = 0; kk < 8; kk++) {
                uint32_t bf[8][2];
#pragma unroll
                for (int nt = 0; nt < 8; nt++) {
                    int krow = nt * 8 + gq;
                    bf[nt][0] = __float_as_uint(Ks[krow * 68 + kk * 8 + tq]);
                    bf[nt][1] = __float_as_uint(Ks[krow * 68 + kk * 8 + tq + 4]);
                }
#pragma unroll
                for (int nt = 0; nt < 8; nt++) mma_tf32(s[nt], qf[kk], bf[nt]);
            }

            if (kt + 63 > wq) {
                int r0 = wq + gq, r1 = wq + gq + 8;
#pragma unroll
                for (int nt = 0; nt < 8; nt++) {
                    int c0 = kt + nt * 8 + 2 * tq;
                    if (c0 > r0)     s[nt][0] = -3.4e38f;
                    if (c0 + 1 > r0) s[nt][1] = -3.4e38f;
                    if (c0 > r1)     s[nt][2] = -3.4e38f;
                    if (c0 + 1 > r1) s[nt][3] = -3.4e38f;
                }
            }

            float mx0 = -3.4e38f, mx1 = -3.4e38f;
#pragma unroll
            for (int nt = 0; nt < 8; nt++) {
                mx0 = fmaxf(mx0, fmaxf(s[nt][0], s[nt][1]));
                mx1 = fmaxf(mx1, fmaxf(s[nt][2], s[nt][3]));
            }
            mx0 = fmaxf(mx0, __shfl_xor_sync(0xffffffffu, mx0, 1));
            mx0 = fmaxf(mx0, __shfl_xor_sync(0xffffffffu, mx0, 2));
            mx1 = fmaxf(mx1, __shfl_xor_sync(0xffffffffu, mx1, 1));
            mx1 = fmaxf(mx1, __shfl_xor_sync(0xffffffffu, mx1, 2));
            float mn0 = fmaxf(m0, mx0), mn1 = fmaxf(m1, mx1);
            float cr0 = exp2p((m0 - mn0) * LOG2E);
            float cr1 = exp2p((m1 - mn1) * LOG2E);
            float nm0 = mn0 * LOG2E, nm1 = mn1 * LOG2E;

            float sum0 = 0.f, sum1 = 0.f;
#pragma unroll
            for (int nt = 0; nt < 8; nt++) {
                float p0 = rnd_tf32(exp2p(fmaf(s[nt][0], LOG2E, -nm0)));
                float p1 = rnd_tf32(exp2p(fmaf(s[nt][1], LOG2E, -nm0)));
                float p2 = rnd_tf32(exp2p(fmaf(s[nt][2], LOG2E, -nm1)));
                float p3 = rnd_tf32(exp2p(fmaf(s[nt][3], LOG2E, -nm1)));
                s[nt][0] = p0; s[nt][1] = p1; s[nt][2] = p2; s[nt][3] = p3;
                sum0 += p0 + p1; sum1 += p2 + p3;
            }
            sum0 += __shfl_xor_sync(0xffffffffu, sum0, 1);
            sum0 += __shfl_xor_sync(0xffffffffu, sum0, 2);
            sum1 += __shfl_xor_sync(0xffffffffu, sum1, 1);
            sum1 += __shfl_xor_sync(0xffffffffu, sum1, 2);
            l0 = l0 * cr0 + sum0;
            l1 = l1 * cr1 + sum1;
#pragma unroll
            for (int nt = 0; nt < 8; nt++) {
                O[nt][0] *= cr0; O[nt][1] *= cr0;
                O[nt][2] *= cr1; O[nt][3] *= cr1;
            }
            m0 = mn0; m1 = mn1;

            int sl1 = gq * 4 + (tq >> 1);
            int sl2 = sl1 + 2;
            bool odd = (tq & 1);
#pragma unroll
            for (int kk = 0; kk < 8; kk++) {
                float v00 = __shfl_sync(0xffffffffu, s[kk][0], sl1);
                float v01 = __shfl_sync(0xffffffffu, s[kk][1], sl1);
                float v10 = __shfl_sync(0xffffffffu, s[kk][0], sl2);
                float v11 = __shfl_sync(0xffffffffu, s[kk][1], sl2);
                float w00 = __shfl_sync(0xffffffffu, s[kk][2], sl1);
                float w01 = __shfl_sync(0xffffffffu, s[kk][3], sl1);
                float w10 = __shfl_sync(0xffffffffu, s[kk][2], sl2);
                float w11 = __shfl_sync(0xffffffffu, s[kk][3], sl2);
                uint32_t a[4];
                a[0] = __float_as_uint(odd ? v01 : v00);
                a[1] = __float_as_uint(odd ? w01 : w00);
                a[2] = __float_as_uint(odd ? v11 : v10);
                a[3] = __float_as_uint(odd ? w11 : w10);
                uint32_t bf[8][2];
#pragma unroll
                for (int nt = 0; nt < 8; nt++) {
                    int krow = kk * 8 + tq;
                    bf[nt][0] = __float_as_uint(Vs[krow * 72 + nt * 8 + gq]);
                    bf[nt][1] = __float_as_uint(Vs[(krow + 4) * 72 + nt * 8 + gq]);
                }
#pragma unroll
                for (int nt = 0; nt < 8; nt++) mma_tf32(O[nt], a, bf[nt]);
            }
        }
        __syncthreads();
    }

    float i0 = 1.f / l0, i1 = 1.f / l1;
    int r0 = wq + gq, r1 = wq + gq + 8;
    float* o0 = Out + ((size_t)(b * Sq + r0)) * Dm + h * 64 + 2 * tq;
    float* o1 = Out + ((size_t)(b * Sq + r1)) * Dm + h * 64 + 2 * tq;
#pragma unroll
    for (int nt = 0; nt < 8; nt++) {
        float2 u, w;
        u.x = rnd_tf32(O[nt][0] * i0); u.y = rnd_tf32(O[nt][1] * i0);
        w.x = rnd_tf32(O[nt][2] * i1); w.y = rnd_tf32(O[nt][3] * i1);
        *(float2*)(o0 + nt * 8) = u;
        *(float2*)(o1 + nt * 8) = w;
    }
}

// ---------------------------------------------------------------------------
// tf32 GEMM v2b: CTA 128x256, warp 64x64, BK=32, 4-stage cp.async pipeline,
// ONE barrier per K-iter. MODE 0: C = A@B   MODE 1: C = A@B + extra(resid)
// ---------------------------------------------------------------------------
template <int MODE>
__global__ void __launch_bounds__(256, 1)
gemm2_k(const float* __restrict__ A, const float* __restrict__ Bm,
        float* __restrict__ C, int N, int K,
        const float* __restrict__ extra) {
    extern __shared__ __align__(16) float sm[];
    const uint32_t sb = smem_u32(sm);
    constexpr int STGF = 12928;
    constexpr int STGB = STGF * 4;

    int tid = threadIdx.x, warp = tid >> 5, lane = tid & 31;
    int gq = lane >> 2, tq = lane & 3;

    int m0 = blockIdx.y * 128, n0 = blockIdx.x * 256;
    int wm = (warp & 1) * 64, wn = (warp >> 1) * 64;

    int ar = tid >> 1;
    int acf = (tid & 1) * 16;
    int br = tid >> 3;
    int bcf = (tid & 7) * 4;
    const float* aSrc = A + (size_t)(m0 + ar) * K + acf;
    const float* bSrc = Bm + (size_t)br * N + n0 + bcf;
    uint32_t aDst = sb + (uint32_t)(ar * 144 + acf * 4);
    uint32_t bDst = sb + 18432u + (uint32_t)(br * 1040 + bcf * 4);

    auto fetch = [&](int stage, int k0) {
        uint32_t so = (uint32_t)stage * STGB;
        const float* as = aSrc + k0;
#pragma unroll
        for (int i = 0; i < 4; i++) cpasync16(aDst + so + 16u * i, as + 4 * i);
        const float* bs = bSrc + (size_t)k0 * N;
#pragma unroll
        for (int j = 0; j < 8; j++) cpasync16(bDst + so + 128u * j, bs + 32 * j);
    };

    float d[4][8][4];
#pragma unroll
    for (int i = 0; i < 4; i++)
#pragma unroll
        for (int j = 0; j < 8; j++)
#pragma unroll
            for (int c = 0; c < 4; c++) d[i][j][c] = 0.f;

    fetch(0, 0);  cp_commit();
    fetch(1, 32); cp_commit();
    fetch(2, 64); cp_commit();

    int KB = K >> 5;
    for (int it = 0; it < KB; ++it) {
        cp_wait<2>();
        __syncthreads();
        if (it + 3 < KB) fetch((it + 3) & 3, (it + 3) * 32);
        cp_commit();
        const float* As = sm + (it & 3) * STGF;
        const float* Bs = As + 4608;
#pragma unroll
        for (int kk = 0; kk < 4; kk++) {
            uint32_t a[4][4], b[8][2];
#pragma unroll
            for (int mt = 0; mt < 4; mt++) {
                int row = wm + mt * 16 + gq;
                int col = kk * 8 + tq;
                a[mt][0] = __float_as_uint(As[row * 36 + col]);
                a[mt][1] = __float_as_uint(As[(row + 8) * 36 + col]);
                a[mt][2] = __float_as_uint(As[row * 36 + col + 4]);
                a[mt][3] = __float_as_uint(As[(row + 8) * 36 + col + 4]);
            }
#pragma unroll
            for (int nt = 0; nt < 8; nt++) {
                int col = wn + nt * 8 + gq;
                b[nt][0] = __float_as_uint(Bs[(kk * 8 + tq) * 260 + col]);
                b[nt][1] = __float_as_uint(Bs[(kk * 8 + tq + 4) * 260 + col]);
            }
#pragma unroll
            for (int mt = 0; mt < 4; mt++)
#pragma unroll
                for (int nt = 0; nt < 8; nt++)
                    mma_tf32(d[mt][nt], a[mt], b[nt]);
        }
    }

#pragma unroll
    for (int mt = 0; mt < 4; mt++) {
        int r0 = m0 + wm + mt * 16 + gq;
        int r1 = r0 + 8;
#pragma unroll
        for (int nt = 0; nt < 8; nt++) {
            int c = n0 + wn + nt * 8 + 2 * tq;
            float2 v01, v23;
            v01.x = d[mt][nt][0]; v01.y = d[mt][nt][1];
            v23.x = d[mt][nt][2]; v23.y = d[mt][nt][3];
            if (MODE == 1) {
                float2 ra = *(const float2*)(extra + (size_t)r0 * N + c);
                float2 rb = *(const float2*)(extra + (size_t)r1 * N + c);
                v01.x += ra.x; v01.y += ra.y;
                v23.x += rb.x; v23.y += rb.y;
            }
            *(float2*)(C + (size_t)r0 * N + c) = v01;
            *(float2*)(C + (size_t)r1 * N + c) = v23;
        }
    }
}

// ---------------------------------------------------------------------------
// bf16 tensor-core GEMM (MoE experts, grid.z = expert): CTA 128x256,
// warp 64x64, BK=32, 4-stage cp.async, ldmatrix, m16n8k16, ONE barrier/iter.
// MODE 0: C(bf16) = bf16(relu(A@B))   MODE 1: C(f32) = (A@B)*gates[row]
// ---------------------------------------------------------------------------
template <int MODE>
__global__ void __launch_bounds__(256, 1)
gemm_bf16_k(const __nv_bfloat16* __restrict__ A, const __nv_bfloat16* __restrict__ Bm,
            void* __restrict__ Cp, int N, int K,
            const float* __restrict__ gates,
            long sA, long sB, long sC, int gstride) {
    extern __shared__ __align__(16) float smf[];
    const uint32_t sb = smem_u32(smf);
    constexpr uint32_t STGB = 24576;

    int tid = threadIdx.x, warp = tid >> 5, lane = tid & 31;
    int gq = lane >> 2, tq = lane & 3;
    int e = blockIdx.z;
    A  += (size_t)e * sA;
    Bm += (size_t)e * sB;
    if (MODE == 1) gates += (size_t)e * gstride;

    int m0 = blockIdx.y * 128, n0 = blockIdx.x * 256;
    int wm = (warp & 1) * 64, wn = (warp >> 1) * 64;

    int ar = tid >> 1, ah = tid & 1;
    int br2 = tid >> 3, bc0 = (tid & 7) * 4;
    const __nv_bfloat16* aSrc = A + (size_t)(m0 + ar) * K + ah * 16;
    const __nv_bfloat16* bSrc = Bm + (size_t)br2 * N + n0 + bc0 * 8;
    uint32_t aS = (ar >> 1) & 3;
    uint32_t aBase = sb + (uint32_t)ar * 64u;
    uint32_t bBase = sb + 8192u + (uint32_t)br2 * 512u;

    auto fetch = [&](int stage, int k0) {
        uint32_t so = (uint32_t)stage * STGB;
        const __nv_bfloat16* as = aSrc + k0;
        uint32_t c0 = 2u * ah;
        cpasync16(aBase + so + ((c0 ^ aS) * 16u), as);
        cpasync16(aBase + so + (((c0 + 1) ^ aS) * 16u), as + 8);
        const __nv_bfloat16* bs = bSrc + (size_t)k0 * N;
#pragma unroll
        for (int j = 0; j < 4; j++) {
            uint32_t c = bc0 + j;
            cpasync16(bBase + so + ((c ^ (br2 & 7)) * 16u), bs + j * 8);
        }
    };

    float d[4][8][4];
#pragma unroll
    for (int i = 0; i < 4; i++)
#pragma unroll
        for (int j = 0; j < 8; j++)
#pragma unroll
            for (int c = 0; c < 4; c++) d[i][j][c] = 0.f;

    fetch(0, 0);  cp_commit();
    fetch(1, 32); cp_commit();
    fetch(2, 64); cp_commit();

    int lrow = lane & 7, selb = (lane >> 3) & 1, selc = lane >> 4;
    uint32_t aRow = (uint32_t)(wm + lrow + 8 * selb) * 64u;
    uint32_t aSw  = (uint32_t)((lrow >> 1) & 3);
    uint32_t bRow = (uint32_t)(lrow + 8 * selb) * 512u;
    uint32_t bCb  = (uint32_t)((wn >> 3) + selc);

    int KB = K >> 5;
    for (int it = 0; it < KB; ++it) {
        cp_wait<2>();
        __syncthreads();
        if (it + 3 < KB) fetch((it + 3) & 3, (it + 3) * 32);
        cp_commit();

        uint32_t As = sb + (uint32_t)(it & 3) * STGB;
        uint32_t Bs = As + 8192u;
#pragma unroll
        for (int kk = 0; kk < 2; kk++) {
            uint32_t a[4][4], b[8][2];
#pragma unroll
            for (int mt = 0; mt < 4; mt++) {
                uint32_t addr = As + aRow + (uint32_t)mt * 1024u
                              + ((((uint32_t)(2 * kk) + (uint32_t)selc) ^ aSw) * 16u);
                ldsm_x4(a[mt], addr);
            }
#pragma unroll
            for (int np = 0; np < 4; np++) {
                uint32_t q[4];
                uint32_t addr = Bs + bRow + (uint32_t)kk * 8192u
                              + (((bCb + 2u * np) ^ (uint32_t)lrow) * 16u);
                ldsm_x4_t(q, addr);
                b[2 * np][0]     = q[0]; b[2 * np][1]     = q[1];
                b[2 * np + 1][0] = q[2]; b[2 * np + 1][1] = q[3];
            }
#pragma unroll
            for (int mt = 0; mt < 4; mt++)
#pragma unroll
                for (int nt = 0; nt < 8; nt++)
                    mma_bf16(d[mt][nt], a[mt], b[nt]);
        }
    }

#pragma unroll
    for (int mt = 0; mt < 4; mt++) {
        int r0 = m0 + wm + mt * 16 + gq;
        int r1 = r0 + 8;
        if (MODE == 0) {
            __nv_bfloat16* Cb = (__nv_bfloat16*)Cp + (size_t)e * sC;
#pragma unroll
            for (int nt = 0; nt < 8; nt++) {
                int c = n0 + wn + nt * 8 + 2 * tq;
                __nv_bfloat162 u = __float22bfloat162_rn(
                    make_float2(fmaxf(d[mt][nt][0], 0.f), fmaxf(d[mt][nt][1], 0.f)));
                __nv_bfloat162 w = __float22bfloat162_rn(
                    make_float2(fmaxf(d[mt][nt][2], 0.f), fmaxf(d[mt][nt][3], 0.f)));
                *(__nv_bfloat162*)(Cb + (size_t)r0 * N + c) = u;
                *(__nv_bfloat162*)(Cb + (size_t)r1 * N + c) = w;
            }
        } else {
            float* Cf = (float*)Cp + (size_t)e * sC;
            float g0 = gates[r0], g1 = gates[r1];
#pragma unroll
            for (int nt = 0; nt < 8; nt++) {
                int c = n0 + wn + nt * 8 + 2 * tq;
                float2 u, w;
                u.x = d[mt][nt][0] * g0; u.y = d[mt][nt][1] * g0;
                w.x = d[mt][nt][2] * g1; w.y = d[mt][nt][3] * g1;
                *(float2*)(Cf + (size_t)r0 * N + c) = u;
                *(float2*)(Cf + (size_t)r1 * N + c) = w;
            }
        }
    }
}

// ---------------------------------------------------------------------------
// Router (fp32, exact)
// ---------------------------------------------------------------------------
__global__ void __launch_bounds__(256) router_k(const float* __restrict__ xn,
                                                const float* __restrict__ wr,
                                                float* __restrict__ fg,
                                                int* __restrict__ fe) {
    int warp = threadIdx.x >> 5, lane = threadIdx.x & 31;
    int t = blockIdx.x * 8 + warp;
    float acc[8];
#pragma unroll
    for (int e2 = 0; e2 < 8; e2++) acc[e2] = 0.f;
    const float* xr = xn + (size_t)t * Dm;
    for (int d = lane; d < Dm; d += 32) {
        float xv = xr[d];
        const float4* w = (const float4*)(wr + d * En);
        float4 w0 = w[0], w1 = w[1];
        acc[0] = fmaf(xv, w0.x, acc[0]); acc[1] = fmaf(xv, w0.y, acc[1]);
        acc[2] = fmaf(xv, w0.z, acc[2]); acc[3] = fmaf(xv, w0.w, acc[3]);
        acc[4] = fmaf(xv, w1.x, acc[4]); acc[5] = fmaf(xv, w1.y, acc[5]);
        acc[6] = fmaf(xv, w1.z, acc[6]); acc[7] = fmaf(xv, w1.w, acc[7]);
    }
#pragma unroll
    for (int e2 = 0; e2 < 8; e2++)
#pragma unroll
        for (int off = 16; off; off >>= 1)
            acc[e2] += __shfl_down_sync(0xffffffffu, acc[e2], off);
    if (lane == 0) {
        float mx = acc[0];
#pragma unroll
        for (int e2 = 1; e2 < 8; e2++) mx = fmaxf(mx, acc[e2]);
        float p[8], sum = 0.f;
#pragma unroll
        for (int e2 = 0; e2 < 8; e2++) { p[e2] = expf(acc[e2] - mx); sum += p[e2]; }
        float inv = 1.f / sum;
#pragma unroll
        for (int e2 = 0; e2 < 8; e2++) p[e2] *= inv;
        int e0 = 0; float p0 = p[0];
#pragma unroll
        for (int e2 = 1; e2 < 8; e2++) if (p[e2] > p0) { p0 = p[e2]; e0 = e2; }
        int e1 = -1; float p1 = -1.f;
#pragma unroll
        for (int e2 = 0; e2 < 8; e2++)
            if (e2 != e0 && p[e2] > p1) { p1 = p[e2]; e1 = e2; }
        fg[2 * t]     = p0; fe[2 * t]     = e0;
        fg[2 * t + 1] = p1; fe[2 * t + 1] = e1;
    }
}

__global__ void init_etok_k(int* __restrict__ etok) {
    int i = blockIdx.x * blockDim.x + threadIdx.x;
    if (i < En * CAPn) etok[i] = -1;
}

__global__ void __launch_bounds__(256) rank_k(const float* __restrict__ fg,
                                              const int* __restrict__ fe,
                                              int* __restrict__ slot,
                                              int* __restrict__ etok,
                                              float* __restrict__ egate) {
    __shared__ float sg[NA];
    __shared__ unsigned char se[NA];
    for (int i = threadIdx.x; i < NA; i += 256) {
        sg[i] = fg[i];
        se[i] = (unsigned char)fe[i];
    }
    __syncthreads();
    int i = blockIdx.x * 256 + threadIdx.x;
    float gi = sg[i];
    unsigned char ei = se[i];
    int r = 0;
    for (int j = 0; j < NA; j++) {
        bool c = (se[j] == ei) && ((sg[j] > gi) || (sg[j] == gi && j < i));
        r += (int)c;
    }
    if (r < CAPn) {
        slot[i] = r;
        etok[(int)ei * CAPn + r] = i >> 1;
        egate[(int)ei * CAPn + r] = gi;
    } else {
        slot[i] = -1;
    }
}

// ---------------------------------------------------------------------------
// Gather expert inputs -> bf16 (tok<0 -> zeros)
// ---------------------------------------------------------------------------
__global__ void __launch_bounds__(256) xepack_k(const float* __restrict__ xn,
                                                const int* __restrict__ etok,
                                                __nv_bfloat16* __restrict__ xe) {
    int row = blockIdx.x;
    int tok = etok[row];
    int i = threadIdx.x;
    float4 v = make_float4(0.f, 0.f, 0.f, 0.f);
    if (tok >= 0) v = ((const float4*)(xn + (size_t)tok * Dm))[i];
    __nv_bfloat162 lo = __float22bfloat162_rn(make_float2(v.x, v.y));
    __nv_bfloat162 hi = __float22bfloat162_rn(make_float2(v.z, v.w));
    ((uint2*)(xe + (size_t)row * Dm))[i] = make_uint2(*(uint32_t*)&lo, *(uint32_t*)&hi);
}

// ---------------------------------------------------------------------------
// Final combine
// ---------------------------------------------------------------------------
__global__ void __launch_bounds__(256) combine_k(const float* __restrict__ x1,
                                                 const float* __restrict__ ye,
                                                 const int* __restrict__ fe,
                                                 const int* __restrict__ slot,
                                                 float* __restrict__ out) {
    int t = blockIdx.x;
    int d = threadIdx.x;
    float4 v = ((const float4*)(x1 + (size_t)t * Dm))[d];
#pragma unroll
    for (int kk = 0; kk < 2; kk++) {
        int i = 2 * t + kk;
        int sl = slot[i];
        if (sl >= 0) {
            int e = fe[i];
            float4 w = ((const float4*)(ye + ((size_t)e * CAPn + sl) * Dm))[d];
            v.x += w.x; v.y += w.y; v.z += w.z; v.w += w.w;
        }
    }
    ((float4*)(out + (size_t)t * Dm))[d] = v;
}

// ---------------------------------------------------------------------------
// Launch (single stream — stream creation allocates device memory and is
// banned by the harness; all overlap must be intra-launch)
// ---------------------------------------------------------------------------
extern "C" void kernel_launch(void* const* d_in, const int* in_sizes, int n_in,
                              void* d_out, int out_size) {
    (void)in_sizes; (void)n_in; (void)out_size;
    const float* x        = (const float*)d_in[0];
    const float* g1       = (const float*)d_in[1];
    const float* w_qkv    = (const float*)d_in[2];
    const float* w_o      = (const float*)d_in[3];
    const float* g2       = (const float*)d_in[4];
    const float* w_router = (const float*)d_in[5];
    const float* w1       = (const float*)d_in[6];
    const float* w2       = (const float*)d_in[7];
    float* out = (float*)d_out;

    float *p_xn, *p_qkv, *p_q, *p_k, *p_v, *p_attn, *p_x1, *p_cos, *p_sin;
    float *p_fg, *p_egate, *p_ye, *p_wqkvr, *p_wor;
    __nv_bfloat16 *p_xeb, *p_hb, *p_w1b, *p_w2b;
    int *p_fe, *p_slot, *p_etok;
    cudaGetSymbolAddress((void**)&p_xn,   g_xn);
    cudaGetSymbolAddress((void**)&p_qkv,  g_qkv);
    cudaGetSymbolAddress((void**)&p_q,    g_q);
    cudaGetSymbolAddress((void**)&p_k,    g_k);
    cudaGetSymbolAddress((void**)&p_v,    g_v);
    cudaGetSymbolAddress((void**)&p_attn, g_attn);
    cudaGetSymbolAddress((void**)&p_x1,   g_x1);
    cudaGetSymbolAddress((void**)&p_cos,  g_cos);
    cudaGetSymbolAddress((void**)&p_sin,  g_sin);
    cudaGetSymbolAddress((void**)&p_fg,   g_fg);
    cudaGetSymbolAddress((void**)&p_fe,   g_fe);
    cudaGetSymbolAddress((void**)&p_slot, g_slot);
    cudaGetSymbolAddress((void**)&p_etok, g_etok);
    cudaGetSymbolAddress((void**)&p_egate,g_egate);
    cudaGetSymbolAddress((void**)&p_ye,   g_ye);
    cudaGetSymbolAddress((void**)&p_wqkvr,g_wqkvr);
    cudaGetSymbolAddress((void**)&p_wor,  g_wor);
    cudaGetSymbolAddress((void**)&p_xeb,  g_xeb);
    cudaGetSymbolAddress((void**)&p_hb,   g_hb);
    cudaGetSymbolAddress((void**)&p_w1b,  g_w1b);
    cudaGetSymbolAddress((void**)&p_w2b,  g_w2b);

    constexpr int GEMM_SMEM = 4 * 51712;         // tf32 gemm: 206848 bytes
    constexpr int BF16_SMEM = 4 * 24576;         // bf16 gemm: 98304 bytes
    constexpr int ATTN_SMEM = 2 * 8960 * 4;      // 71680 bytes
    cudaFuncSetAttribute(gemm2_k<0>, cudaFuncAttributeMaxDynamicSharedMemorySize, GEMM_SMEM);
    cudaFuncSetAttribute(gemm2_k<1>, cudaFuncAttributeMaxDynamicSharedMemorySize, GEMM_SMEM);
    cudaFuncSetAttribute(gemm_bf16_k<0>, cudaFuncAttributeMaxDynamicSharedMemorySize, BF16_SMEM);
    cudaFuncSetAttribute(gemm_bf16_k<1>, cudaFuncAttributeMaxDynamicSharedMemorySize, BF16_SMEM);
    cudaFuncSetAttribute(attn_tc_k,  cudaFuncAttributeMaxDynamicSharedMemorySize, ATTN_SMEM);

    // Fused precompute: all weight conversions + rope table in ONE launch
    prep_k<<<1184, 256>>>(w_qkv, p_wqkvr, w_o, p_wor,
                          w1, p_w1b, w2, p_w2b, p_cos, p_sin);

    // Attention branch (tf32 — protects routing)
    rmsnorm_k<true><<<Tn, 256>>>(x, g1, p_xn);
    gemm2_k<0><<<dim3(3 * Dm / 256, Tn / 128, 1), 256, GEMM_SMEM>>>(
        p_xn, p_wqkvr, p_qkv, 3 * Dm, Dm, nullptr);
    split_rope_k<<<Tn, 256>>>(p_qkv, p_cos, p_sin, p_q, p_k, p_v);
    attn_tc_k<<<dim3(Sq / 128, Hn, Bz), 256, ATTN_SMEM>>>(p_q, p_k, p_v, p_attn);
    gemm2_k<1><<<dim3(Dm / 256, Tn / 128, 1), 256, GEMM_SMEM>>>(
        p_attn, p_wor, p_x1, Dm, Dm, x);
    rmsnorm_k<false><<<Tn, 256>>>(p_x1, g2, p_xn);

    // Routing (fp32 exact)
    router_k<<<Tn / 8, 256>>>(p_xn, w_router, p_fg, p_fe);
    init_etok_k<<<(En * CAPn + 255) / 256, 256>>>(p_etok);
    rank_k<<<NA / 256, 256>>>(p_fg, p_fe, p_slot, p_etok, p_egate);
    xepack_k<<<En * CAPn, 256>>>(p_xn, p_etok, p_xeb);

    // MoE expert GEMMs (bf16 tensor cores + ldmatrix)
    gemm_bf16_k<0><<<dim3(FFNm / 256, CAPn / 128, En), 256, BF16_SMEM>>>(
        p_xeb, p_w1b, p_hb, FFNm, Dm, nullptr,
        (long)CAPn * Dm, (long)Dm * FFNm, (long)CAPn * FFNm, 0);
    gemm_bf16_k<1><<<dim3(Dm / 256, CAPn / 128, En), 256, BF16_SMEM>>>(
        p_hb, p_w2b, p_ye, Dm, FFNm, p_egate,
        (long)CAPn * FFNm, (long)FFNm * Dm, (long)CAPn * Dm, CAPn);

    // out = x1 + moe
    combine_k<<<Tn, 256>>>(p_x1, p_ye, p_fe, p_slot, out);
}

// round 10
// speedup vs baseline: 5.2225x; 1.0722x over previous
#include <cuda_runtime.h>
#include <cuda_bf16.h>
#include <math.h>
#include <stdint.h>

// ---------------------------------------------------------------------------
// Problem constants
// ---------------------------------------------------------------------------
namespace {
constexpr int Bz   = 2;
constexpr int Sq   = 2048;
constexpr int Dm   = 1024;
constexpr int Hn   = 16;
constexpr int HDm  = 64;
constexpr int FFNm = 2048;
constexpr int En   = 8;
constexpr int Tn   = Bz * Sq;     // 4096 tokens
constexpr int NA   = Tn * 2;      // 8192 flat assignments (top-2)
constexpr int CAPn = 1280;        // ceil(2*2048*2*1.25/8)
// prep_k region sizes (float4 units except rope)
constexpr int NQ4  = Dm * 3 * Dm / 4;        // 786432
constexpr int NO4  = Dm * Dm / 4;            // 262144
constexpr int NW14 = En * Dm * FFNm / 4;     // 4194304
constexpr int NW24 = En * FFNm * Dm / 4;     // 4194304
constexpr int NRP  = Sq * (HDm / 2);         // 65536
}

// ---------------------------------------------------------------------------
// Static scratch (no allocations allowed)
// ---------------------------------------------------------------------------
__device__ float g_xn  [Tn * Dm];
__device__ float g_qkv [Tn * 3 * Dm];
__device__ float g_q   [Tn * Dm];
__device__ float g_k   [Tn * Dm];
__device__ float g_v   [Tn * Dm];
__device__ float g_attn[Tn * Dm];
__device__ float g_x1  [Tn * Dm];
__device__ float g_cos [Sq * (HDm / 2)];
__device__ float g_sin [Sq * (HDm / 2)];
__device__ float g_fg  [NA];
__device__ int   g_fe  [NA];
__device__ int   g_slot[NA];
__device__ int   g_etok [En * CAPn];
__device__ float g_egate[En * CAPn];
__device__ int   g_cnt  [En];               // live rows per expert
__device__ float g_ye[En * CAPn * Dm];
// tf32-rounded weight copies (attention branch)
__device__ float g_wqkvr[Dm * 3 * Dm];
__device__ float g_wor  [Dm * Dm];
// bf16 MoE data
__device__ __nv_bfloat16 g_xeb[En * CAPn * Dm];
__device__ __nv_bfloat16 g_hb [En * CAPn * FFNm];
__device__ __nv_bfloat16 g_w1b[En * Dm * FFNm];
__device__ __nv_bfloat16 g_w2b[En * FFNm * Dm];

// ---------------------------------------------------------------------------
// Helpers
// ---------------------------------------------------------------------------
__device__ __forceinline__ float rnd_tf32(float x) {
    uint32_t u = __float_as_uint(x);
    u = (u + 0x1000u) & 0xFFFFE000u;
    return __uint_as_float(u);
}

__device__ __forceinline__ uint32_t smem_u32(const void* p) {
    uint32_t a;
    asm("{ .reg .u64 t; cvta.to.shared.u64 t, %1; cvt.u32.u64 %0, t; }"
        : "=r"(a) : "l"(p));
    return a;
}

__device__ __forceinline__ void cpasync16(uint32_t dst, const void* src) {
    asm volatile("cp.async.cg.shared.global [%0], [%1], 16;" :: "r"(dst), "l"(src));
}
__device__ __forceinline__ void cp_commit() {
    asm volatile("cp.async.commit_group;" ::: "memory");
}
template <int N>
__device__ __forceinline__ void cp_wait() {
    asm volatile("cp.async.wait_group %0;" :: "n"(N) : "memory");
}

// tf32 m16n8k8 MMA
__device__ __forceinline__ void mma_tf32(float* d, const uint32_t* a, const uint32_t* b) {
    asm volatile(
        "mma.sync.aligned.m16n8k8.row.col.f32.tf32.tf32.f32 "
        "{%0,%1,%2,%3}, {%4,%5,%6,%7}, {%8,%9}, {%0,%1,%2,%3};"
        : "+f"(d[0]), "+f"(d[1]), "+f"(d[2]), "+f"(d[3])
        : "r"(a[0]), "r"(a[1]), "r"(a[2]), "r"(a[3]), "r"(b[0]), "r"(b[1]));
}

// bf16 m16n8k16 MMA
__device__ __forceinline__ void mma_bf16(float* d, const uint32_t* a, const uint32_t* b) {
    asm volatile(
        "mma.sync.aligned.m16n8k16.row.col.f32.bf16.bf16.f32 "
        "{%0,%1,%2,%3}, {%4,%5,%6,%7}, {%8,%9}, {%0,%1,%2,%3};"
        : "+f"(d[0]), "+f"(d[1]), "+f"(d[2]), "+f"(d[3])
        : "r"(a[0]), "r"(a[1]), "r"(a[2]), "r"(a[3]), "r"(b[0]), "r"(b[1]));
}

__device__ __forceinline__ void ldsm_x4(uint32_t* r, uint32_t addr) {
    asm volatile("ldmatrix.sync.aligned.m8n8.x4.shared.b16 {%0,%1,%2,%3}, [%4];"
                 : "=r"(r[0]), "=r"(r[1]), "=r"(r[2]), "=r"(r[3]) : "r"(addr));
}
__device__ __forceinline__ void ldsm_x4_t(uint32_t* r, uint32_t addr) {
    asm volatile("ldmatrix.sync.aligned.m8n8.x4.trans.shared.b16 {%0,%1,%2,%3}, [%4];"
                 : "=r"(r[0]), "=r"(r[1]), "=r"(r[2]), "=r"(r[3]) : "r"(addr));
}

// 2^x for x <= 0, FMA-pipe only.
__device__ __forceinline__ float exp2p(float x) {
    float t = fmaxf(x, -126.f);
    float z = t + 12582912.f;
    float n = z - 12582912.f;
    float f = t - n;
    float p =         1.5353e-4f;
    p = fmaf(p, f, 1.3398886e-3f);
    p = fmaf(p, f, 9.6184372e-3f);
    p = fmaf(p, f, 5.5503327e-2f);
    p = fmaf(p, f, 2.4022648e-1f);
    p = fmaf(p, f, 6.9314718e-1f);
    p = fmaf(p, f, 1.0f);
    int iz = __float_as_int(z) - 0x4B400000;
    return p * __int_as_float((iz + 127) << 23);
}

// ---------------------------------------------------------------------------
// Fused prep: tf32-round w_qkv+w_o, bf16-convert w1+w2, rope table.
// ---------------------------------------------------------------------------
__global__ void prep_k(const float* __restrict__ wqkv, float* __restrict__ wqkvr,
                       const float* __restrict__ wo,   float* __restrict__ wor,
                       const float* __restrict__ w1,   __nv_bfloat16* __restrict__ w1b,
                       const float* __restrict__ w2,   __nv_bfloat16* __restrict__ w2b,
                       float* __restrict__ ct, float* __restrict__ st) {
    const int total = NQ4 + NO4 + NW14 + NW24 + NRP;
    int stride = gridDim.x * blockDim.x;
    for (int i = blockIdx.x * blockDim.x + threadIdx.x; i < total; i += stride) {
        int r = i;
        if (r < NQ4) {
            float4 v = ((const float4*)wqkv)[r];
            v.x = rnd_tf32(v.x); v.y = rnd_tf32(v.y);
            v.z = rnd_tf32(v.z); v.w = rnd_tf32(v.w);
            ((float4*)wqkvr)[r] = v;
            continue;
        }
        r -= NQ4;
        if (r < NO4) {
            float4 v = ((const float4*)wo)[r];
            v.x = rnd_tf32(v.x); v.y = rnd_tf32(v.y);
            v.z = rnd_tf32(v.z); v.w = rnd_tf32(v.w);
            ((float4*)wor)[r] = v;
            continue;
        }
        r -= NO4;
        if (r < NW14) {
            float4 v = ((const float4*)w1)[r];
            __nv_bfloat162 lo = __float22bfloat162_rn(make_float2(v.x, v.y));
            __nv_bfloat162 hi = __float22bfloat162_rn(make_float2(v.z, v.w));
            ((uint2*)w1b)[r] = make_uint2(*(uint32_t*)&lo, *(uint32_t*)&hi);
            continue;
        }
        r -= NW14;
        if (r < NW24) {
            float4 v = ((const float4*)w2)[r];
            __nv_bfloat162 lo = __float22bfloat162_rn(make_float2(v.x, v.y));
            __nv_bfloat162 hi = __float22bfloat162_rn(make_float2(v.z, v.w));
            ((uint2*)w2b)[r] = make_uint2(*(uint32_t*)&lo, *(uint32_t*)&hi);
            continue;
        }
        r -= NW24;
        {
            int s = r >> 5, j = r & 31;
            float th = (float)pow(10000.0, -2.0 * (double)j / (double)HDm);
            double f = (double)s * (double)th;
            ct[r] = (float)cos(f);
            st[r] = (float)sin(f);
        }
    }
}

// ---------------------------------------------------------------------------
// RMSNorm
// ---------------------------------------------------------------------------
template <bool RND>
__global__ void __launch_bounds__(256) rmsnorm_k(const float* __restrict__ x,
                                                 const float* __restrict__ g,
                                                 float* __restrict__ y) {
    int row = blockIdx.x;
    int i = threadIdx.x;
    const float4* xr = (const float4*)(x + (size_t)row * Dm);
    float4 xv = xr[i];
    float ss = xv.x * xv.x + xv.y * xv.y + xv.z * xv.z + xv.w * xv.w;
#pragma unroll
    for (int off = 16; off; off >>= 1) ss += __shfl_down_sync(0xffffffffu, ss, off);
    __shared__ float red[8];
    __shared__ float srms;
    if ((i & 31) == 0) red[i >> 5] = ss;
    __syncthreads();
    if (i == 0) {
        float t = 0.f;
#pragma unroll
        for (int w = 0; w < 8; w++) t += red[w];
        srms = rsqrtf(t * (1.0f / Dm) + 1e-6f);
    }
    __syncthreads();
    float r = srms;
    float4 gv = ((const float4*)g)[i];
    float4 o;
    o.x = gv.x * xv.x * r; o.y = gv.y * xv.y * r;
    o.z = gv.z * xv.z * r; o.w = gv.w * xv.w * r;
    if (RND) {
        o.x = rnd_tf32(o.x); o.y = rnd_tf32(o.y);
        o.z = rnd_tf32(o.z); o.w = rnd_tf32(o.w);
    }
    ((float4*)(y + (size_t)row * Dm))[i] = o;
}

// ---------------------------------------------------------------------------
// Split QKV + RoPE
// ---------------------------------------------------------------------------
__global__ void __launch_bounds__(256) split_rope_k(const float* __restrict__ qkv,
                                                    const float* __restrict__ ct,
                                                    const float* __restrict__ st,
                                                    float* __restrict__ q,
                                                    float* __restrict__ k,
                                                    float* __restrict__ v) {
    int t = blockIdx.x;
    int b = t / Sq, s = t % Sq;
    const float* row = qkv + (size_t)t * (3 * Dm);
    for (int idx = threadIdx.x; idx < Hn * (HDm / 2); idx += blockDim.x) {
        int h = idx >> 5, j = idx & 31;
        float c = ct[s * 32 + j], sn = st[s * 32 + j];
        size_t o = ((size_t)(b * Hn + h) * Sq + s) * HDm;
        float qr = row[h * HDm + 2 * j], qi = row[h * HDm + 2 * j + 1];
        q[o + 2 * j]     = qr * c - qi * sn;
        q[o + 2 * j + 1] = qr * sn + qi * c;
        float kr = row[Dm + h * HDm + 2 * j], ki = row[Dm + h * HDm + 2 * j + 1];
        k[o + 2 * j]     = kr * c - ki * sn;
        k[o + 2 * j + 1] = kr * sn + ki * c;
    }
    for (int idx = threadIdx.x; idx < Dm; idx += blockDim.x) {
        int h = idx >> 6, d = idx & 63;
        v[((size_t)(b * Hn + h) * Sq + s) * HDm + d] = row[2 * Dm + idx];
    }
}

// ---------------------------------------------------------------------------
// Tensor-core causal flash attention (unchanged)
// ---------------------------------------------------------------------------
__global__ void __launch_bounds__(256) attn_tc_k(const float* __restrict__ Q,
                                                 const float* __restrict__ Kt,
                                                 const float* __restrict__ Vt,
                                                 float* __restrict__ Out) {
    extern __shared__ __align__(16) float sm[];
    constexpr float LOG2E = 1.4426950408889634f;
    constexpr int STG = 64 * 68 + 64 * 72;

    int bx = blockIdx.x, h = blockIdx.y, b = blockIdx.z;
    int qt = bx * 128;
    int tid = threadIdx.x, warp = tid >> 5, lane = tid & 31;
    int gq = lane >> 2, tq = lane & 3;
    int wq = qt + warp * 16;
    const size_t base = ((size_t)(b * Hn + h)) * Sq * HDm;
    const float* Qg = Q + base;
    const float* Kg = Kt + base;
    const float* Vg = Vt + base;

    const uint32_t sb = smem_u32(sm);

    uint32_t qf[8][4];
#pragma unroll
    for (int kk = 0; kk < 8; kk++) {
        int c = kk * 8 + tq;
        qf[kk][0] = __float_as_uint(rnd_tf32(Qg[(size_t)(wq + gq) * 64 + c] * 0.125f));
        qf[kk][1] = __float_as_uint(rnd_tf32(Qg[(size_t)(wq + gq + 8) * 64 + c] * 0.125f));
        qf[kk][2] = __float_as_uint(rnd_tf32(Qg[(size_t)(wq + gq) * 64 + c + 4] * 0.125f));
        qf[kk][3] = __float_as_uint(rnd_tf32(Qg[(size_t)(wq + gq + 8) * 64 + c + 4] * 0.125f));
    }

    float O[8][4];
#pragma unroll
    for (int nt = 0; nt < 8; nt++)
#pragma unroll
        for (int c = 0; c < 4; c++) O[nt][c] = 0.f;
    float m0 = -1e30f, m1 = -1e30f, l0 = 0.f, l1 = 0.f;

    int fr = tid >> 2, fs = (tid & 3) * 16;
    auto fill = [&](int stage, int kt) {
        uint32_t kDst = sb + (uint32_t)(stage * STG + fr * 68 + fs) * 4u;
        uint32_t vDst = sb + (uint32_t)(stage * STG + 64 * 68 + fr * 72 + fs) * 4u;
        const float* ks = Kg + (size_t)(kt + fr) * 64 + fs;
        const float* vs = Vg + (size_t)(kt + fr) * 64 + fs;
#pragma unroll
        for (int c = 0; c < 4; c++) {
            cpasync16(kDst + 16u * c, ks + 4 * c);
            cpasync16(vDst + 16u * c, vs + 4 * c);
        }
    };

    int ntiles = 2 * bx + 2;
    fill(0, 0);
    cp_commit();

    for (int it = 0; it < ntiles; it++) {
        if (it + 1 < ntiles) fill((it + 1) & 1, (it + 1) * 64);
        cp_commit();
        cp_wait<1>();
        __syncthreads();

        int kt = it * 64;
        if (kt <= wq + 15) {
            const float* Ks = sm + (it & 1) * STG;
            const float* Vs = Ks + 64 * 68;

            float s[8][4];
#pragma unroll
            for (int nt = 0; nt < 8; nt++)
#pragma unroll
                for (int c = 0; c < 4; c++) s[nt][c] = 0.f;
#pragma unroll
            for (int kk = 0; kk < 8; kk++) {
                uint32_t bf[8][2];
#pragma unroll
                for (int nt = 0; nt < 8; nt++) {
                    int krow = nt * 8 + gq;
                    bf[nt][0] = __float_as_uint(Ks[krow * 68 + kk * 8 + tq]);
                    bf[nt][1] = __float_as_uint(Ks[krow * 68 + kk * 8 + tq + 4]);
                }
#pragma unroll
                for (int nt = 0; nt < 8; nt++) mma_tf32(s[nt], qf[kk], bf[nt]);
            }

            if (kt + 63 > wq) {
                int r0 = wq + gq, r1 = wq + gq + 8;
#pragma unroll
                for (int nt = 0; nt < 8; nt++) {
                    int c0 = kt + nt * 8 + 2 * tq;
                    if (c0 > r0)     s[nt][0] = -3.4e38f;
                    if (c0 + 1 > r0) s[nt][1] = -3.4e38f;
                    if (c0 > r1)     s[nt][2] = -3.4e38f;
                    if (c0 + 1 > r1) s[nt][3] = -3.4e38f;
                }
            }

            float mx0 = -3.4e38f, mx1 = -3.4e38f;
#pragma unroll
            for (int nt = 0; nt < 8; nt++) {
                mx0 = fmaxf(mx0, fmaxf(s[nt][0], s[nt][1]));
                mx1 = fmaxf(mx1, fmaxf(s[nt][2], s[nt][3]));
            }
            mx0 = fmaxf(mx0, __shfl_xor_sync(0xffffffffu, mx0, 1));
            mx0 = fmaxf(mx0, __shfl_xor_sync(0xffffffffu, mx0, 2));
            mx1 = fmaxf(mx1, __shfl_xor_sync(0xffffffffu, mx1, 1));
            mx1 = fmaxf(mx1, __shfl_xor_sync(0xffffffffu, mx1, 2));
            float mn0 = fmaxf(m0, mx0), mn1 = fmaxf(m1, mx1);
            float cr0 = exp2p((m0 - mn0) * LOG2E);
            float cr1 = exp2p((m1 - mn1) * LOG2E);
            float nm0 = mn0 * LOG2E, nm1 = mn1 * LOG2E;

            float sum0 = 0.f, sum1 = 0.f;
#pragma unroll
            for (int nt = 0; nt < 8; nt++) {
                float p0 = rnd_tf32(exp2p(fmaf(s[nt][0], LOG2E, -nm0)));
                float p1 = rnd_tf32(exp2p(fmaf(s[nt][1], LOG2E, -nm0)));
                float p2 = rnd_tf32(exp2p(fmaf(s[nt][2], LOG2E, -nm1)));
                float p3 = rnd_tf32(exp2p(fmaf(s[nt][3], LOG2E, -nm1)));
                s[nt][0] = p0; s[nt][1] = p1; s[nt][2] = p2; s[nt][3] = p3;
                sum0 += p0 + p1; sum1 += p2 + p3;
            }
            sum0 += __shfl_xor_sync(0xffffffffu, sum0, 1);
            sum0 += __shfl_xor_sync(0xffffffffu, sum0, 2);
            sum1 += __shfl_xor_sync(0xffffffffu, sum1, 1);
            sum1 += __shfl_xor_sync(0xffffffffu, sum1, 2);
            l0 = l0 * cr0 + sum0;
            l1 = l1 * cr1 + sum1;
#pragma unroll
            for (int nt = 0; nt < 8; nt++) {
                O[nt][0] *= cr0; O[nt][1] *= cr0;
                O[nt][2] *= cr1; O[nt][3] *= cr1;
            }
            m0 = mn0; m1 = mn1;

            int sl1 = gq * 4 + (tq >> 1);
            int sl2 = sl1 + 2;
            bool odd = (tq & 1);
#pragma unroll
            for (int kk = 0; kk < 8; kk++) {
                float v00 = __shfl_sync(0xffffffffu, s[kk][0], sl1);
                float v01 = __shfl_sync(0xffffffffu, s[kk][1], sl1);
                float v10 = __shfl_sync(0xffffffffu, s[kk][0], sl2);
                float v11 = __shfl_sync(0xffffffffu, s[kk][1], sl2);
                float w00 = __shfl_sync(0xffffffffu, s[kk][2], sl1);
                float w01 = __shfl_sync(0xffffffffu, s[kk][3], sl1);
                float w10 = __shfl_sync(0xffffffffu, s[kk][2], sl2);
                float w11 = __shfl_sync(0xffffffffu, s[kk][3], sl2);
                uint32_t a[4];
                a[0] = __float_as_uint(odd ? v01 : v00);
                a[1] = __float_as_uint(odd ? w01 : w00);
                a[2] = __float_as_uint(odd ? v11 : v10);
                a[3] = __float_as_uint(odd ? w11 : w10);
                uint32_t bf[8][2];
#pragma unroll
                for (int nt = 0; nt < 8; nt++) {
                    int krow = kk * 8 + tq;
                    bf[nt][0] = __float_as_uint(Vs[krow * 72 + nt * 8 + gq]);
                    bf[nt][1] = __float_as_uint(Vs[(krow + 4) * 72 + nt * 8 + gq]);
                }
#pragma unroll
                for (int nt = 0; nt < 8; nt++) mma_tf32(O[nt], a, bf[nt]);
            }
        }
        __syncthreads();
    }

    float i0 = 1.f / l0, i1 = 1.f / l1;
    int r0 = wq + gq, r1 = wq + gq + 8;
    float* o0 = Out + ((size_t)(b * Sq + r0)) * Dm + h * 64 + 2 * tq;
    float* o1 = Out + ((size_t)(b * Sq + r1)) * Dm + h * 64 + 2 * tq;
#pragma unroll
    for (int nt = 0; nt < 8; nt++) {
        float2 u, w;
        u.x = rnd_tf32(O[nt][0] * i0); u.y = rnd_tf32(O[nt][1] * i0);
        w.x = rnd_tf32(O[nt][2] * i1); w.y = rnd_tf32(O[nt][3] * i1);
        *(float2*)(o0 + nt * 8) = u;
        *(float2*)(o1 + nt * 8) = w;
    }
}

// ---------------------------------------------------------------------------
// tf32 GEMM v2b: CTA 128x256, warp 64x64, BK=32, 4-stage cp.async pipeline,
// ONE barrier per K-iter. MODE 0: C = A@B   MODE 1: C = A@B + extra(resid)
// ---------------------------------------------------------------------------
template <int MODE>
__global__ void __launch_bounds__(256, 1)
gemm2_k(const float* __restrict__ A, const float* __restrict__ Bm,
        float* __restrict__ C, int N, int K,
        const float* __restrict__ extra) {
    extern __shared__ __align__(16) float sm[];
    const uint32_t sb = smem_u32(sm);
    constexpr int STGF = 12928;
    constexpr int STGB = STGF * 4;

    int tid = threadIdx.x, warp = tid >> 5, lane = tid & 31;
    int gq = lane >> 2, tq = lane & 3;

    int m0 = blockIdx.y * 128, n0 = blockIdx.x * 256;
    int wm = (warp & 1) * 64, wn = (warp >> 1) * 64;

    int ar = tid >> 1;
    int acf = (tid & 1) * 16;
    int br = tid >> 3;
    int bcf = (tid & 7) * 4;
    const float* aSrc = A + (size_t)(m0 + ar) * K + acf;
    const float* bSrc = Bm + (size_t)br * N + n0 + bcf;
    uint32_t aDst = sb + (uint32_t)(ar * 144 + acf * 4);
    uint32_t bDst = sb + 18432u + (uint32_t)(br * 1040 + bcf * 4);

    auto fetch = [&](int stage, int k0) {
        uint32_t so = (uint32_t)stage * STGB;
        const float* as = aSrc + k0;
#pragma unroll
        for (int i = 0; i < 4; i++) cpasync16(aDst + so + 16u * i, as + 4 * i);
        const float* bs = bSrc + (size_t)k0 * N;
#pragma unroll
        for (int j = 0; j < 8; j++) cpasync16(bDst + so + 128u * j, bs + 32 * j);
    };

    float d[4][8][4];
#pragma unroll
    for (int i = 0; i < 4; i++)
#pragma unroll
        for (int j = 0; j < 8; j++)
#pragma unroll
            for (int c = 0; c < 4; c++) d[i][j][c] = 0.f;

    fetch(0, 0);  cp_commit();
    fetch(1, 32); cp_commit();
    fetch(2, 64); cp_commit();

    int KB = K >> 5;
    for (int it = 0; it < KB; ++it) {
        cp_wait<2>();
        __syncthreads();
        if (it + 3 < KB) fetch((it + 3) & 3, (it + 3) * 32);
        cp_commit();
        const float* As = sm + (it & 3) * STGF;
        const float* Bs = As + 4608;
#pragma unroll
        for (int kk = 0; kk < 4; kk++) {
            uint32_t a[4][4], b[8][2];
#pragma unroll
            for (int mt = 0; mt < 4; mt++) {
                int row = wm + mt * 16 + gq;
                int col = kk * 8 + tq;
                a[mt][0] = __float_as_uint(As[row * 36 + col]);
                a[mt][1] = __float_as_uint(As[(row + 8) * 36 + col]);
                a[mt][2] = __float_as_uint(As[row * 36 + col + 4]);
                a[mt][3] = __float_as_uint(As[(row + 8) * 36 + col + 4]);
            }
#pragma unroll
            for (int nt = 0; nt < 8; nt++) {
                int col = wn + nt * 8 + gq;
                b[nt][0] = __float_as_uint(Bs[(kk * 8 + tq) * 260 + col]);
                b[nt][1] = __float_as_uint(Bs[(kk * 8 + tq + 4) * 260 + col]);
            }
#pragma unroll
            for (int mt = 0; mt < 4; mt++)
#pragma unroll
                for (int nt = 0; nt < 8; nt++)
                    mma_tf32(d[mt][nt], a[mt], b[nt]);
        }
    }

#pragma unroll
    for (int mt = 0; mt < 4; mt++) {
        int r0 = m0 + wm + mt * 16 + gq;
        int r1 = r0 + 8;
#pragma unroll
        for (int nt = 0; nt < 8; nt++) {
            int c = n0 + wn + nt * 8 + 2 * tq;
            float2 v01, v23;
            v01.x = d[mt][nt][0]; v01.y = d[mt][nt][1];
            v23.x = d[mt][nt][2]; v23.y = d[mt][nt][3];
            if (MODE == 1) {
                float2 ra = *(const float2*)(extra + (size_t)r0 * N + c);
                float2 rb = *(const float2*)(extra + (size_t)r1 * N + c);
                v01.x += ra.x; v01.y += ra.y;
                v23.x += rb.x; v23.y += rb.y;
            }
            *(float2*)(C + (size_t)r0 * N + c) = v01;
            *(float2*)(C + (size_t)r1 * N + c) = v23;
        }
    }
}

// ---------------------------------------------------------------------------
// bf16 tensor-core GEMM (MoE experts, grid.z = expert): CTA 128x256,
// warp 64x64, BK=32, 4-stage cp.async, ldmatrix, m16n8k16, ONE barrier/iter.
// CTAs whose M-tile lies entirely beyond cnt[e] (no live capacity rows)
// exit immediately — their outputs are never read by combine.
// MODE 0: C(bf16) = bf16(relu(A@B))   MODE 1: C(f32) = (A@B)*gates[row]
// ---------------------------------------------------------------------------
template <int MODE>
__global__ void __launch_bounds__(256, 1)
gemm_bf16_k(const __nv_bfloat16* __restrict__ A, const __nv_bfloat16* __restrict__ Bm,
            void* __restrict__ Cp, int N, int K,
            const float* __restrict__ gates, const int* __restrict__ cnt,
            long sA, long sB, long sC, int gstride) {
    extern __shared__ __align__(16) float smf[];
    const uint32_t sb = smem_u32(smf);
    constexpr uint32_t STGB = 24576;

    int e = blockIdx.z;
    int m0 = blockIdx.y * 128, n0 = blockIdx.x * 256;
    if (m0 >= cnt[e]) return;   // dead tile: rows never read downstream

    int tid = threadIdx.x, warp = tid >> 5, lane = tid & 31;
    int gq = lane >> 2, tq = lane & 3;
    A  += (size_t)e * sA;
    Bm += (size_t)e * sB;
    if (MODE == 1) gates += (size_t)e * gstride;

    int wm = (warp & 1) * 64, wn = (warp >> 1) * 64;

    int ar = tid >> 1, ah = tid & 1;
    int br2 = tid >> 3, bc0 = (tid & 7) * 4;
    const __nv_bfloat16* aSrc = A + (size_t)(m0 + ar) * K + ah * 16;
    const __nv_bfloat16* bSrc = Bm + (size_t)br2 * N + n0 + bc0 * 8;
    uint32_t aS = (ar >> 1) & 3;
    uint32_t aBase = sb + (uint32_t)ar * 64u;
    uint32_t bBase = sb + 8192u + (uint32_t)br2 * 512u;

    auto fetch = [&](int stage, int k0) {
        uint32_t so = (uint32_t)stage * STGB;
        const __nv_bfloat16* as = aSrc + k0;
        uint32_t c0 = 2u * ah;
        cpasync16(aBase + so + ((c0 ^ aS) * 16u), as);
        cpasync16(aBase + so + (((c0 + 1) ^ aS) * 16u), as + 8);
        const __nv_bfloat16* bs = bSrc + (size_t)k0 * N;
#pragma unroll
        for (int j = 0; j < 4; j++) {
            uint32_t c = bc0 + j;
            cpasync16(bBase + so + ((c ^ (br2 & 7)) * 16u), bs + j * 8);
        }
    };

    float d[4][8][4];
#pragma unroll
    for (int i = 0; i < 4; i++)
#pragma unroll
        for (int j = 0; j < 8; j++)
#pragma unroll
            for (int c = 0; c < 4; c++) d[i][j][c] = 0.f;

    fetch(0, 0);  cp_commit();
    fetch(1, 32); cp_commit();
    fetch(2, 64); cp_commit();

    int lrow = lane & 7, selb = (lane >> 3) & 1, selc = lane >> 4;
    uint32_t aRow = (uint32_t)(wm + lrow + 8 * selb) * 64u;
    uint32_t aSw  = (uint32_t)((lrow >> 1) & 3);
    uint32_t bRow = (uint32_t)(lrow + 8 * selb) * 512u;
    uint32_t bCb  = (uint32_t)((wn >> 3) + selc);

    int KB = K >> 5;
    for (int it = 0; it < KB; ++it) {
        cp_wait<2>();
        __syncthreads();
        if (it + 3 < KB) fetch((it + 3) & 3, (it + 3) * 32);
        cp_commit();

        uint32_t As = sb + (uint32_t)(it & 3) * STGB;
        uint32_t Bs = As + 8192u;
#pragma unroll
        for (int kk = 0; kk < 2; kk++) {
            uint32_t a[4][4], b[8][2];
#pragma unroll
            for (int mt = 0; mt < 4; mt++) {
                uint32_t addr = As + aRow + (uint32_t)mt * 1024u
                              + ((((uint32_t)(2 * kk) + (uint32_t)selc) ^ aSw) * 16u);
                ldsm_x4(a[mt], addr);
            }
#pragma unroll
            for (int np = 0; np < 4; np++) {
                uint32_t q[4];
                uint32_t addr = Bs + bRow + (uint32_t)kk * 8192u
                              + (((bCb + 2u * np) ^ (uint32_t)lrow) * 16u);
                ldsm_x4_t(q, addr);
                b[2 * np][0]     = q[0]; b[2 * np][1]     = q[1];
                b[2 * np + 1][0] = q[2]; b[2 * np + 1][1] = q[3];
            }
#pragma unroll
            for (int mt = 0; mt < 4; mt++)
#pragma unroll
                for (int nt = 0; nt < 8; nt++)
                    mma_bf16(d[mt][nt], a[mt], b[nt]);
        }
    }

#pragma unroll
    for (int mt = 0; mt < 4; mt++) {
        int r0 = m0 + wm + mt * 16 + gq;
        int r1 = r0 + 8;
        if (MODE == 0) {
            __nv_bfloat16* Cb = (__nv_bfloat16*)Cp + (size_t)e * sC;
#pragma unroll
            for (int nt = 0; nt < 8; nt++) {
                int c = n0 + wn + nt * 8 + 2 * tq;
                __nv_bfloat162 u = __float22bfloat162_rn(
                    make_float2(fmaxf(d[mt][nt][0], 0.f), fmaxf(d[mt][nt][1], 0.f)));
                __nv_bfloat162 w = __float22bfloat162_rn(
                    make_float2(fmaxf(d[mt][nt][2], 0.f), fmaxf(d[mt][nt][3], 0.f)));
                *(__nv_bfloat162*)(Cb + (size_t)r0 * N + c) = u;
                *(__nv_bfloat162*)(Cb + (size_t)r1 * N + c) = w;
            }
        } else {
            float* Cf = (float*)Cp + (size_t)e * sC;
            float g0 = gates[r0], g1 = gates[r1];
#pragma unroll
            for (int nt = 0; nt < 8; nt++) {
                int c = n0 + wn + nt * 8 + 2 * tq;
                float2 u, w;
                u.x = d[mt][nt][0] * g0; u.y = d[mt][nt][1] * g0;
                w.x = d[mt][nt][2] * g1; w.y = d[mt][nt][3] * g1;
                *(float2*)(Cf + (size_t)r0 * N + c) = u;
                *(float2*)(Cf + (size_t)r1 * N + c) = w;
            }
        }
    }
}

// ---------------------------------------------------------------------------
// Router (fp32, exact)
// ---------------------------------------------------------------------------
__global__ void __launch_bounds__(256) router_k(const float* __restrict__ xn,
                                                const float* __restrict__ wr,
                                                float* __restrict__ fg,
                                                int* __restrict__ fe) {
    int warp = threadIdx.x >> 5, lane = threadIdx.x & 31;
    int t = blockIdx.x * 8 + warp;
    float acc[8];
#pragma unroll
    for (int e2 = 0; e2 < 8; e2++) acc[e2] = 0.f;
    const float* xr = xn + (size_t)t * Dm;
    for (int d = lane; d < Dm; d += 32) {
        float xv = xr[d];
        const float4* w = (const float4*)(wr + d * En);
        float4 w0 = w[0], w1 = w[1];
        acc[0] = fmaf(xv, w0.x, acc[0]); acc[1] = fmaf(xv, w0.y, acc[1]);
        acc[2] = fmaf(xv, w0.z, acc[2]); acc[3] = fmaf(xv, w0.w, acc[3]);
        acc[4] = fmaf(xv, w1.x, acc[4]); acc[5] = fmaf(xv, w1.y, acc[5]);
        acc[6] = fmaf(xv, w1.z, acc[6]); acc[7] = fmaf(xv, w1.w, acc[7]);
    }
#pragma unroll
    for (int e2 = 0; e2 < 8; e2++)
#pragma unroll
        for (int off = 16; off; off >>= 1)
            acc[e2] += __shfl_down_sync(0xffffffffu, acc[e2], off);
    if (lane == 0) {
        float mx = acc[0];
#pragma unroll
        for (int e2 = 1; e2 < 8; e2++) mx = fmaxf(mx, acc[e2]);
        float p[8], sum = 0.f;
#pragma unroll
        for (int e2 = 0; e2 < 8; e2++) { p[e2] = expf(acc[e2] - mx); sum += p[e2]; }
        float inv = 1.f / sum;
#pragma unroll
        for (int e2 = 0; e2 < 8; e2++) p[e2] *= inv;
        int e0 = 0; float p0 = p[0];
#pragma unroll
        for (int e2 = 1; e2 < 8; e2++) if (p[e2] > p0) { p0 = p[e2]; e0 = e2; }
        int e1 = -1; float p1 = -1.f;
#pragma unroll
        for (int e2 = 0; e2 < 8; e2++)
            if (e2 != e0 && p[e2] > p1) { p1 = p[e2]; e1 = e2; }
        fg[2 * t]     = p0; fe[2 * t]     = e0;
        fg[2 * t + 1] = p1; fe[2 * t + 1] = e1;
    }
}

__global__ void init_etok_k(int* __restrict__ etok, int* __restrict__ cnt) {
    int i = blockIdx.x * blockDim.x + threadIdx.x;
    if (i < En * CAPn) etok[i] = -1;
    if (i < En) cnt[i] = 0;
}

__global__ void __launch_bounds__(256) rank_k(const float* __restrict__ fg,
                                              const int* __restrict__ fe,
                                              int* __restrict__ slot,
                                              int* __restrict__ etok,
                                              float* __restrict__ egate,
                                              int* __restrict__ cnt) {
    __shared__ float sg[NA];
    __shared__ unsigned char se[NA];
    for (int i = threadIdx.x; i < NA; i += 256) {
        sg[i] = fg[i];
        se[i] = (unsigned char)fe[i];
    }
    __syncthreads();
    int i = blockIdx.x * 256 + threadIdx.x;
    float gi = sg[i];
    unsigned char ei = se[i];
    int r = 0;
    for (int j = 0; j < NA; j++) {
        bool c = (se[j] == ei) && ((sg[j] > gi) || (sg[j] == gi && j < i));
        r += (int)c;
    }
    if (r < CAPn) {
        slot[i] = r;
        etok[(int)ei * CAPn + r] = i >> 1;
        egate[(int)ei * CAPn + r] = gi;
        atomicMax(&cnt[(int)ei], r + 1);
    } else {
        slot[i] = -1;
    }
}

// ---------------------------------------------------------------------------
// Gather expert inputs -> bf16 (tok<0 -> zeros)
// ---------------------------------------------------------------------------
__global__ void __launch_bounds__(256) xepack_k(const float* __restrict__ xn,
                                                const int* __restrict__ etok,
                                                __nv_bfloat16* __restrict__ xe) {
    int row = blockIdx.x;
    int tok = etok[row];
    int i = threadIdx.x;
    float4 v = make_float4(0.f, 0.f, 0.f, 0.f);
    if (tok >= 0) v = ((const float4*)(xn + (size_t)tok * Dm))[i];
    __nv_bfloat162 lo = __float22bfloat162_rn(make_float2(v.x, v.y));
    __nv_bfloat162 hi = __float22bfloat162_rn(make_float2(v.z, v.w));
    ((uint2*)(xe + (size_t)row * Dm))[i] = make_uint2(*(uint32_t*)&lo, *(uint32_t*)&hi);
}

// ---------------------------------------------------------------------------
// Final combine
// ---------------------------------------------------------------------------
__global__ void __launch_bounds__(256) combine_k(const float* __restrict__ x1,
                                                 const float* __restrict__ ye,
                                                 const int* __restrict__ fe,
                                                 const int* __restrict__ slot,
                                                 float* __restrict__ out) {
    int t = blockIdx.x;
    int d = threadIdx.x;
    float4 v = ((const float4*)(x1 + (size_t)t * Dm))[d];
#pragma unroll
    for (int kk = 0; kk < 2; kk++) {
        int i = 2 * t + kk;
        int sl = slot[i];
        if (sl >= 0) {
            int e = fe[i];
            float4 w = ((const float4*)(ye + ((size_t)e * CAPn + sl) * Dm))[d];
            v.x += w.x; v.y += w.y; v.z += w.z; v.w += w.w;
        }
    }
    ((float4*)(out + (size_t)t * Dm))[d] = v;
}

// ---------------------------------------------------------------------------
// Launch (single stream)
// ---------------------------------------------------------------------------
extern "C" void kernel_launch(void* const* d_in, const int* in_sizes, int n_in,
                              void* d_out, int out_size) {
    (void)in_sizes; (void)n_in; (void)out_size;
    const float* x        = (const float*)d_in[0];
    const float* g1       = (const float*)d_in[1];
    const float* w_qkv    = (const float*)d_in[2];
    const float* w_o      = (const float*)d_in[3];
    const float* g2       = (const float*)d_in[4];
    const float* w_router = (const float*)d_in[5];
    const float* w1       = (const float*)d_in[6];
    const float* w2       = (const float*)d_in[7];
    float* out = (float*)d_out;

    float *p_xn, *p_qkv, *p_q, *p_k, *p_v, *p_attn, *p_x1, *p_cos, *p_sin;
    float *p_fg, *p_egate, *p_ye, *p_wqkvr, *p_wor;
    __nv_bfloat16 *p_xeb, *p_hb, *p_w1b, *p_w2b;
    int *p_fe, *p_slot, *p_etok, *p_cnt;
    cudaGetSymbolAddress((void**)&p_xn,   g_xn);
    cudaGetSymbolAddress((void**)&p_qkv,  g_qkv);
    cudaGetSymbolAddress((void**)&p_q,    g_q);
    cudaGetSymbolAddress((void**)&p_k,    g_k);
    cudaGetSymbolAddress((void**)&p_v,    g_v);
    cudaGetSymbolAddress((void**)&p_attn, g_attn);
    cudaGetSymbolAddress((void**)&p_x1,   g_x1);
    cudaGetSymbolAddress((void**)&p_cos,  g_cos);
    cudaGetSymbolAddress((void**)&p_sin,  g_sin);
    cudaGetSymbolAddress((void**)&p_fg,   g_fg);
    cudaGetSymbolAddress((void**)&p_fe,   g_fe);
    cudaGetSymbolAddress((void**)&p_slot, g_slot);
    cudaGetSymbolAddress((void**)&p_etok, g_etok);
    cudaGetSymbolAddress((void**)&p_egate,g_egate);
    cudaGetSymbolAddress((void**)&p_cnt,  g_cnt);
    cudaGetSymbolAddress((void**)&p_ye,   g_ye);
    cudaGetSymbolAddress((void**)&p_wqkvr,g_wqkvr);
    cudaGetSymbolAddress((void**)&p_wor,  g_wor);
    cudaGetSymbolAddress((void**)&p_xeb,  g_xeb);
    cudaGetSymbolAddress((void**)&p_hb,   g_hb);
    cudaGetSymbolAddress((void**)&p_w1b,  g_w1b);
    cudaGetSymbolAddress((void**)&p_w2b,  g_w2b);

    constexpr int GEMM_SMEM = 4 * 51712;         // tf32 gemm: 206848 bytes
    constexpr int BF16_SMEM = 4 * 24576;         // bf16 gemm: 98304 bytes
    constexpr int ATTN_SMEM = 2 * 8960 * 4;      // 71680 bytes
    cudaFuncSetAttribute(gemm2_k<0>, cudaFuncAttributeMaxDynamicSharedMemorySize, GEMM_SMEM);
    cudaFuncSetAttribute(gemm2_k<1>, cudaFuncAttributeMaxDynamicSharedMemorySize, GEMM_SMEM);
    cudaFuncSetAttribute(gemm_bf16_k<0>, cudaFuncAttributeMaxDynamicSharedMemorySize, BF16_SMEM);
    cudaFuncSetAttribute(gemm_bf16_k<1>, cudaFuncAttributeMaxDynamicSharedMemorySize, BF16_SMEM);
    cudaFuncSetAttribute(attn_tc_k,  cudaFuncAttributeMaxDynamicSharedMemorySize, ATTN_SMEM);

    // Fused precompute: all weight conversions + rope table in ONE launch
    prep_k<<<1184, 256>>>(w_qkv, p_wqkvr, w_o, p_wor,
                          w1, p_w1b, w2, p_w2b, p_cos, p_sin);

    // Attention branch (tf32 — protects routing)
    rmsnorm_k<true><<<Tn, 256>>>(x, g1, p_xn);
    gemm2_k<0><<<dim3(3 * Dm / 256, Tn / 128, 1), 256, GEMM_SMEM>>>(
        p_xn, p_wqkvr, p_qkv, 3 * Dm, Dm, nullptr);
    split_rope_k<<<Tn, 256>>>(p_qkv, p_cos, p_sin, p_q, p_k, p_v);
    attn_tc_k<<<dim3(Sq / 128, Hn, Bz), 256, ATTN_SMEM>>>(p_q, p_k, p_v, p_attn);
    gemm2_k<1><<<dim3(Dm / 256, Tn / 128, 1), 256, GEMM_SMEM>>>(
        p_attn, p_wor, p_x1, Dm, Dm, x);
    rmsnorm_k<false><<<Tn, 256>>>(p_x1, g2, p_xn);

    // Routing (fp32 exact) + live-row counts
    router_k<<<Tn / 8, 256>>>(p_xn, w_router, p_fg, p_fe);
    init_etok_k<<<(En * CAPn + 255) / 256, 256>>>(p_etok, p_cnt);
    rank_k<<<NA / 256, 256>>>(p_fg, p_fe, p_slot, p_etok, p_egate, p_cnt);
    xepack_k<<<En * CAPn, 256>>>(p_xn, p_etok, p_xeb);

    // MoE expert GEMMs (bf16 tensor cores; dead capacity tiles early-exit)
    gemm_bf16_k<0><<<dim3(FFNm / 256, CAPn / 128, En), 256, BF16_SMEM>>>(
        p_xeb, p_w1b, p_hb, FFNm, Dm, nullptr, p_cnt,
        (long)CAPn * Dm, (long)Dm * FFNm, (long)CAPn * FFNm, 0);
    gemm_bf16_k<1><<<dim3(Dm / 256, CAPn / 128, En), 256, BF16_SMEM>>>(
        p_hb, p_w2b, p_ye, Dm, FFNm, p_egate, p_cnt,
        (long)CAPn * FFNm, (long)FFNm * Dm, (long)CAPn * Dm, CAPn);

    // out = x1 + moe
    combine_k<<<Tn, 256>>>(p_x1, p_ye, p_fe, p_slot, out);
}

// round 11
// speedup vs baseline: 5.7793x; 1.1066x over previous
#include <cuda_runtime.h>
#include <cuda_fp16.h>
#include <math.h>
#include <stdint.h>

// ---------------------------------------------------------------------------
// Problem constants
// ---------------------------------------------------------------------------
namespace {
constexpr int Bz   = 2;
constexpr int Sq   = 2048;
constexpr int Dm   = 1024;
constexpr int Hn   = 16;
constexpr int HDm  = 64;
constexpr int FFNm = 2048;
constexpr int En   = 8;
constexpr int Tn   = Bz * Sq;     // 4096 tokens
constexpr int NA   = Tn * 2;      // 8192 flat assignments (top-2)
constexpr int CAPn = 1280;        // ceil(2*2048*2*1.25/8)
// prep_k region sizes (float4 units except rope)
constexpr int NQ4  = Dm * 3 * Dm / 4;        // 786432
constexpr int NO4  = Dm * Dm / 4;            // 262144
constexpr int NW14 = En * Dm * FFNm / 4;     // 4194304
constexpr int NW24 = En * FFNm * Dm / 4;     // 4194304
constexpr int NRP  = Sq * (HDm / 2);         // 65536
}

// ---------------------------------------------------------------------------
// Static scratch (no allocations allowed)
// ---------------------------------------------------------------------------
__device__ float g_xn  [Tn * Dm];           // rmsnorm2 out (fp32, router path)
__device__ float g_qkv [Tn * 3 * Dm];
__device__ float g_q   [Tn * Dm];
__device__ float g_k   [Tn * Dm];
__device__ float g_v   [Tn * Dm];
__device__ float g_x1  [Tn * Dm];
__device__ float g_cos [Sq * (HDm / 2)];
__device__ float g_sin [Sq * (HDm / 2)];
__device__ float g_fg  [NA];
__device__ int   g_fe  [NA];
__device__ int   g_slot[NA];
__device__ int   g_etok [En * CAPn];
__device__ float g_egate[En * CAPn];
__device__ int   g_cnt  [En];               // live rows per expert
__device__ float g_ye[En * CAPn * Dm];
// fp16 data
__device__ __half g_xnh  [Tn * Dm];         // rmsnorm1 out (qkv GEMM A)
__device__ __half g_attnh[Tn * Dm];         // attention out (o GEMM A)
__device__ __half g_wqkvh[Dm * 3 * Dm];
__device__ __half g_woh  [Dm * Dm];
__device__ __half g_w1h  [En * Dm * FFNm];
__device__ __half g_w2h  [En * FFNm * Dm];
__device__ __half g_xeh  [En * CAPn * Dm];
__device__ __half g_hh   [En * CAPn * FFNm];

// ---------------------------------------------------------------------------
// Helpers
// ---------------------------------------------------------------------------
__device__ __forceinline__ float rnd_tf32(float x) {
    uint32_t u = __float_as_uint(x);
    u = (u + 0x1000u) & 0xFFFFE000u;
    return __uint_as_float(u);
}

__device__ __forceinline__ uint32_t smem_u32(const void* p) {
    uint32_t a;
    asm("{ .reg .u64 t; cvta.to.shared.u64 t, %1; cvt.u32.u64 %0, t; }"
        : "=r"(a) : "l"(p));
    return a;
}

__device__ __forceinline__ void cpasync16(uint32_t dst, const void* src) {
    asm volatile("cp.async.cg.shared.global [%0], [%1], 16;" :: "r"(dst), "l"(src));
}
__device__ __forceinline__ void cp_commit() {
    asm volatile("cp.async.commit_group;" ::: "memory");
}
template <int N>
__device__ __forceinline__ void cp_wait() {
    asm volatile("cp.async.wait_group %0;" :: "n"(N) : "memory");
}

// tf32 m16n8k8 MMA (attention internals)
__device__ __forceinline__ void mma_tf32(float* d, const uint32_t* a, const uint32_t* b) {
    asm volatile(
        "mma.sync.aligned.m16n8k8.row.col.f32.tf32.tf32.f32 "
        "{%0,%1,%2,%3}, {%4,%5,%6,%7}, {%8,%9}, {%0,%1,%2,%3};"
        : "+f"(d[0]), "+f"(d[1]), "+f"(d[2]), "+f"(d[3])
        : "r"(a[0]), "r"(a[1]), "r"(a[2]), "r"(a[3]), "r"(b[0]), "r"(b[1]));
}

// fp16 m16n8k16 MMA, fp32 accumulate
__device__ __forceinline__ void mma_f16(float* d, const uint32_t* a, const uint32_t* b) {
    asm volatile(
        "mma.sync.aligned.m16n8k16.row.col.f32.f16.f16.f32 "
        "{%0,%1,%2,%3}, {%4,%5,%6,%7}, {%8,%9}, {%0,%1,%2,%3};"
        : "+f"(d[0]), "+f"(d[1]), "+f"(d[2]), "+f"(d[3])
        : "r"(a[0]), "r"(a[1]), "r"(a[2]), "r"(a[3]), "r"(b[0]), "r"(b[1]));
}

__device__ __forceinline__ void ldsm_x4(uint32_t* r, uint32_t addr) {
    asm volatile("ldmatrix.sync.aligned.m8n8.x4.shared.b16 {%0,%1,%2,%3}, [%4];"
                 : "=r"(r[0]), "=r"(r[1]), "=r"(r[2]), "=r"(r[3]) : "r"(addr));
}
__device__ __forceinline__ void ldsm_x4_t(uint32_t* r, uint32_t addr) {
    asm volatile("ldmatrix.sync.aligned.m8n8.x4.trans.shared.b16 {%0,%1,%2,%3}, [%4];"
                 : "=r"(r[0]), "=r"(r[1]), "=r"(r[2]), "=r"(r[3]) : "r"(addr));
}

// 2^x for x <= 0, FMA-pipe only.
__device__ __forceinline__ float exp2p(float x) {
    float t = fmaxf(x, -126.f);
    float z = t + 12582912.f;
    float n = z - 12582912.f;
    float f = t - n;
    float p =         1.5353e-4f;
    p = fmaf(p, f, 1.3398886e-3f);
    p = fmaf(p, f, 9.6184372e-3f);
    p = fmaf(p, f, 5.5503327e-2f);
    p = fmaf(p, f, 2.4022648e-1f);
    p = fmaf(p, f, 6.9314718e-1f);
    p = fmaf(p, f, 1.0f);
    int iz = __float_as_int(z) - 0x4B400000;
    return p * __int_as_float((iz + 127) << 23);
}

__device__ __forceinline__ uint32_t h2_bits(float a, float b) {
    __half2 h = __float22half2_rn(make_float2(a, b));
    return *(uint32_t*)&h;
}

// ---------------------------------------------------------------------------
// Fused prep: fp16-convert all four weight tensors + rope table. One launch.
// ---------------------------------------------------------------------------
__global__ void prep_k(const float* __restrict__ wqkv, __half* __restrict__ wqkvh,
                       const float* __restrict__ wo,   __half* __restrict__ woh,
                       const float* __restrict__ w1,   __half* __restrict__ w1h,
                       const float* __restrict__ w2,   __half* __restrict__ w2h,
                       float* __restrict__ ct, float* __restrict__ st) {
    const int total = NQ4 + NO4 + NW14 + NW24 + NRP;
    int stride = gridDim.x * blockDim.x;
    for (int i = blockIdx.x * blockDim.x + threadIdx.x; i < total; i += stride) {
        int r = i;
        if (r < NQ4) {
            float4 v = ((const float4*)wqkv)[r];
            ((uint2*)wqkvh)[r] = make_uint2(h2_bits(v.x, v.y), h2_bits(v.z, v.w));
            continue;
        }
        r -= NQ4;
        if (r < NO4) {
            float4 v = ((const float4*)wo)[r];
            ((uint2*)woh)[r] = make_uint2(h2_bits(v.x, v.y), h2_bits(v.z, v.w));
            continue;
        }
        r -= NO4;
        if (r < NW14) {
            float4 v = ((const float4*)w1)[r];
            ((uint2*)w1h)[r] = make_uint2(h2_bits(v.x, v.y), h2_bits(v.z, v.w));
            continue;
        }
        r -= NW14;
        if (r < NW24) {
            float4 v = ((const float4*)w2)[r];
            ((uint2*)w2h)[r] = make_uint2(h2_bits(v.x, v.y), h2_bits(v.z, v.w));
            continue;
        }
        r -= NW24;
        {
            int s = r >> 5, j = r & 31;
            float th = (float)pow(10000.0, -2.0 * (double)j / (double)HDm);
            double f = (double)s * (double)th;
            ct[r] = (float)cos(f);
            st[r] = (float)sin(f);
        }
    }
}

// ---------------------------------------------------------------------------
// RMSNorm. OUT16: write fp16 (feeds fp16 GEMM A). Else fp32.
// ---------------------------------------------------------------------------
template <bool OUT16>
__global__ void __launch_bounds__(256) rmsnorm_k(const float* __restrict__ x,
                                                 const float* __restrict__ g,
                                                 void* __restrict__ y) {
    int row = blockIdx.x;
    int i = threadIdx.x;
    const float4* xr = (const float4*)(x + (size_t)row * Dm);
    float4 xv = xr[i];
    float ss = xv.x * xv.x + xv.y * xv.y + xv.z * xv.z + xv.w * xv.w;
#pragma unroll
    for (int off = 16; off; off >>= 1) ss += __shfl_down_sync(0xffffffffu, ss, off);
    __shared__ float red[8];
    __shared__ float srms;
    if ((i & 31) == 0) red[i >> 5] = ss;
    __syncthreads();
    if (i == 0) {
        float t = 0.f;
#pragma unroll
        for (int w = 0; w < 8; w++) t += red[w];
        srms = rsqrtf(t * (1.0f / Dm) + 1e-6f);
    }
    __syncthreads();
    float r = srms;
    float4 gv = ((const float4*)g)[i];
    float4 o;
    o.x = gv.x * xv.x * r; o.y = gv.y * xv.y * r;
    o.z = gv.z * xv.z * r; o.w = gv.w * xv.w * r;
    if (OUT16) {
        ((uint2*)((__half*)y + (size_t)row * Dm))[i] =
            make_uint2(h2_bits(o.x, o.y), h2_bits(o.z, o.w));
    } else {
        ((float4*)((float*)y + (size_t)row * Dm))[i] = o;
    }
}

// ---------------------------------------------------------------------------
// Split QKV + RoPE (fp32 in/out, unchanged)
// ---------------------------------------------------------------------------
__global__ void __launch_bounds__(256) split_rope_k(const float* __restrict__ qkv,
                                                    const float* __restrict__ ct,
                                                    const float* __restrict__ st,
                                                    float* __restrict__ q,
                                                    float* __restrict__ k,
                                                    float* __restrict__ v) {
    int t = blockIdx.x;
    int b = t / Sq, s = t % Sq;
    const float* row = qkv + (size_t)t * (3 * Dm);
    for (int idx = threadIdx.x; idx < Hn * (HDm / 2); idx += blockDim.x) {
        int h = idx >> 5, j = idx & 31;
        float c = ct[s * 32 + j], sn = st[s * 32 + j];
        size_t o = ((size_t)(b * Hn + h) * Sq + s) * HDm;
        float qr = row[h * HDm + 2 * j], qi = row[h * HDm + 2 * j + 1];
        q[o + 2 * j]     = qr * c - qi * sn;
        q[o + 2 * j + 1] = qr * sn + qi * c;
        float kr = row[Dm + h * HDm + 2 * j], ki = row[Dm + h * HDm + 2 * j + 1];
        k[o + 2 * j]     = kr * c - ki * sn;
        k[o + 2 * j + 1] = kr * sn + ki * c;
    }
    for (int idx = threadIdx.x; idx < Dm; idx += blockDim.x) {
        int h = idx >> 6, d = idx & 63;
        v[((size_t)(b * Hn + h) * Sq + s) * HDm + d] = row[2 * Dm + idx];
    }
}

// ---------------------------------------------------------------------------
// Tensor-core causal flash attention. fp32 in, fp16 out (feeds o-proj GEMM).
// ---------------------------------------------------------------------------
__global__ void __launch_bounds__(256) attn_tc_k(const float* __restrict__ Q,
                                                 const float* __restrict__ Kt,
                                                 const float* __restrict__ Vt,
                                                 __half* __restrict__ Out) {
    extern __shared__ __align__(16) float sm[];
    constexpr float LOG2E = 1.4426950408889634f;
    constexpr int STG = 64 * 68 + 64 * 72;

    int bx = blockIdx.x, h = blockIdx.y, b = blockIdx.z;
    int qt = bx * 128;
    int tid = threadIdx.x, warp = tid >> 5, lane = tid & 31;
    int gq = lane >> 2, tq = lane & 3;
    int wq = qt + warp * 16;
    const size_t base = ((size_t)(b * Hn + h)) * Sq * HDm;
    const float* Qg = Q + base;
    const float* Kg = Kt + base;
    const float* Vg = Vt + base;

    const uint32_t sb = smem_u32(sm);

    uint32_t qf[8][4];
#pragma unroll
    for (int kk = 0; kk < 8; kk++) {
        int c = kk * 8 + tq;
        qf[kk][0] = __float_as_uint(rnd_tf32(Qg[(size_t)(wq + gq) * 64 + c] * 0.125f));
        qf[kk][1] = __float_as_uint(rnd_tf32(Qg[(size_t)(wq + gq + 8) * 64 + c] * 0.125f));
        qf[kk][2] = __float_as_uint(rnd_tf32(Qg[(size_t)(wq + gq) * 64 + c + 4] * 0.125f));
        qf[kk][3] = __float_as_uint(rnd_tf32(Qg[(size_t)(wq + gq + 8) * 64 + c + 4] * 0.125f));
    }

    float O[8][4];
#pragma unroll
    for (int nt = 0; nt < 8; nt++)
#pragma unroll
        for (int c = 0; c < 4; c++) O[nt][c] = 0.f;
    float m0 = -1e30f, m1 = -1e30f, l0 = 0.f, l1 = 0.f;

    int fr = tid >> 2, fs = (tid & 3) * 16;
    auto fill = [&](int stage, int kt) {
        uint32_t kDst = sb + (uint32_t)(stage * STG + fr * 68 + fs) * 4u;
        uint32_t vDst = sb + (uint32_t)(stage * STG + 64 * 68 + fr * 72 + fs) * 4u;
        const float* ks = Kg + (size_t)(kt + fr) * 64 + fs;
        const float* vs = Vg + (size_t)(kt + fr) * 64 + fs;
#pragma unroll
        for (int c = 0; c < 4; c++) {
            cpasync16(kDst + 16u * c, ks + 4 * c);
            cpasync16(vDst + 16u * c, vs + 4 * c);
        }
    };

    int ntiles = 2 * bx + 2;
    fill(0, 0);
    cp_commit();

    for (int it = 0; it < ntiles; it++) {
        if (it + 1 < ntiles) fill((it + 1) & 1, (it + 1) * 64);
        cp_commit();
        cp_wait<1>();
        __syncthreads();

        int kt = it * 64;
        if (kt <= wq + 15) {
            const float* Ks = sm + (it & 1) * STG;
            const float* Vs = Ks + 64 * 68;

            float s[8][4];
#pragma unroll
            for (int nt = 0; nt < 8; nt++)
#pragma unroll
                for (int c = 0; c < 4; c++) s[nt][c] = 0.f;
#pragma unroll
            for (int kk = 0; kk < 8; kk++) {
                uint32_t bf[8][2];
#pragma unroll
                for (int nt = 0; nt < 8; nt++) {
                    int krow = nt * 8 + gq;
                    bf[nt][0] = __float_as_uint(Ks[krow * 68 + kk * 8 + tq]);
                    bf[nt][1] = __float_as_uint(Ks[krow * 68 + kk * 8 + tq + 4]);
                }
#pragma unroll
                for (int nt = 0; nt < 8; nt++) mma_tf32(s[nt], qf[kk], bf[nt]);
            }

            if (kt + 63 > wq) {
                int r0 = wq + gq, r1 = wq + gq + 8;
#pragma unroll
                for (int nt = 0; nt < 8; nt++) {
                    int c0 = kt + nt * 8 + 2 * tq;
                    if (c0 > r0)     s[nt][0] = -3.4e38f;
                    if (c0 + 1 > r0) s[nt][1] = -3.4e38f;
                    if (c0 > r1)     s[nt][2] = -3.4e38f;
                    if (c0 + 1 > r1) s[nt][3] = -3.4e38f;
                }
            }

            float mx0 = -3.4e38f, mx1 = -3.4e38f;
#pragma unroll
            for (int nt = 0; nt < 8; nt++) {
                mx0 = fmaxf(mx0, fmaxf(s[nt][0], s[nt][1]));
                mx1 = fmaxf(mx1, fmaxf(s[nt][2], s[nt][3]));
            }
            mx0 = fmaxf(mx0, __shfl_xor_sync(0xffffffffu, mx0, 1));
            mx0 = fmaxf(mx0, __shfl_xor_sync(0xffffffffu, mx0, 2));
            mx1 = fmaxf(mx1, __shfl_xor_sync(0xffffffffu, mx1, 1));
            mx1 = fmaxf(mx1, __shfl_xor_sync(0xffffffffu, mx1, 2));
            float mn0 = fmaxf(m0, mx0), mn1 = fmaxf(m1, mx1);
            float cr0 = exp2p((m0 - mn0) * LOG2E);
            float cr1 = exp2p((m1 - mn1) * LOG2E);
            float nm0 = mn0 * LOG2E, nm1 = mn1 * LOG2E;

            float sum0 = 0.f, sum1 = 0.f;
#pragma unroll
            for (int nt = 0; nt < 8; nt++) {
                float p0 = rnd_tf32(exp2p(fmaf(s[nt][0], LOG2E, -nm0)));
                float p1 = rnd_tf32(exp2p(fmaf(s[nt][1], LOG2E, -nm0)));
                float p2 = rnd_tf32(exp2p(fmaf(s[nt][2], LOG2E, -nm1)));
                float p3 = rnd_tf32(exp2p(fmaf(s[nt][3], LOG2E, -nm1)));
                s[nt][0] = p0; s[nt][1] = p1; s[nt][2] = p2; s[nt][3] = p3;
                sum0 += p0 + p1; sum1 += p2 + p3;
            }
            sum0 += __shfl_xor_sync(0xffffffffu, sum0, 1);
            sum0 += __shfl_xor_sync(0xffffffffu, sum0, 2);
            sum1 += __shfl_xor_sync(0xffffffffu, sum1, 1);
            sum1 += __shfl_xor_sync(0xffffffffu, sum1, 2);
            l0 = l0 * cr0 + sum0;
            l1 = l1 * cr1 + sum1;
#pragma unroll
            for (int nt = 0; nt < 8; nt++) {
                O[nt][0] *= cr0; O[nt][1] *= cr0;
                O[nt][2] *= cr1; O[nt][3] *= cr1;
            }
            m0 = mn0; m1 = mn1;

            int sl1 = gq * 4 + (tq >> 1);
            int sl2 = sl1 + 2;
            bool odd = (tq & 1);
#pragma unroll
            for (int kk = 0; kk < 8; kk++) {
                float v00 = __shfl_sync(0xffffffffu, s[kk][0], sl1);
                float v01 = __shfl_sync(0xffffffffu, s[kk][1], sl1);
                float v10 = __shfl_sync(0xffffffffu, s[kk][0], sl2);
                float v11 = __shfl_sync(0xffffffffu, s[kk][1], sl2);
                float w00 = __shfl_sync(0xffffffffu, s[kk][2], sl1);
                float w01 = __shfl_sync(0xffffffffu, s[kk][3], sl1);
                float w10 = __shfl_sync(0xffffffffu, s[kk][2], sl2);
                float w11 = __shfl_sync(0xffffffffu, s[kk][3], sl2);
                uint32_t a[4];
                a[0] = __float_as_uint(odd ? v01 : v00);
                a[1] = __float_as_uint(odd ? w01 : w00);
                a[2] = __float_as_uint(odd ? v11 : v10);
                a[3] = __float_as_uint(odd ? w11 : w10);
                uint32_t bf[8][2];
#pragma unroll
                for (int nt = 0; nt < 8; nt++) {
                    int krow = kk * 8 + tq;
                    bf[nt][0] = __float_as_uint(Vs[krow * 72 + nt * 8 + gq]);
                    bf[nt][1] = __float_as_uint(Vs[(krow + 4) * 72 + nt * 8 + gq]);
                }
#pragma unroll
                for (int nt = 0; nt < 8; nt++) mma_tf32(O[nt], a, bf[nt]);
            }
        }
        __syncthreads();
    }

    float i0 = 1.f / l0, i1 = 1.f / l1;
    int r0 = wq + gq, r1 = wq + gq + 8;
    __half* o0 = Out + ((size_t)(b * Sq + r0)) * Dm + h * 64 + 2 * tq;
    __half* o1 = Out + ((size_t)(b * Sq + r1)) * Dm + h * 64 + 2 * tq;
#pragma unroll
    for (int nt = 0; nt < 8; nt++) {
        *(uint32_t*)(o0 + nt * 8) = h2_bits(O[nt][0] * i0, O[nt][1] * i0);
        *(uint32_t*)(o1 + nt * 8) = h2_bits(O[nt][2] * i1, O[nt][3] * i1);
    }
}

// ---------------------------------------------------------------------------
// fp16 tensor-core GEMM (all four GEMMs): CTA 128x256, warp 64x64, BK=32,
// 4-stage cp.async, ldmatrix, m16n8k16.f16, ONE barrier/iter.
// MODE 0: C(f32) = A@B                 (qkv)
// MODE 1: C(f32) = A@B + extra(resid)  (o-proj)
// MODE 2: C(f16) = relu(A@B)           (moe1)
// MODE 3: C(f32) = (A@B)*gates[row]    (moe2)
// SKIP: early-exit CTAs whose M-tile is past cnt[e] (MoE dead capacity).
// ---------------------------------------------------------------------------
template <int MODE, bool SKIP>
__global__ void __launch_bounds__(256, 1)
gemm_h_k(const __half* __restrict__ A, const __half* __restrict__ Bm,
         void* __restrict__ Cp, int N, int K,
         const float* __restrict__ extra, const int* __restrict__ cnt,
         long sA, long sB, long sC, int gstride) {
    extern __shared__ __align__(16) float smf[];
    const uint32_t sb = smem_u32(smf);
    constexpr uint32_t STGB = 24576;

    int e = blockIdx.z;
    int m0 = blockIdx.y * 128, n0 = blockIdx.x * 256;
    if (SKIP && m0 >= cnt[e]) return;

    int tid = threadIdx.x, warp = tid >> 5, lane = tid & 31;
    int gq = lane >> 2, tq = lane & 3;
    A  += (size_t)e * sA;
    Bm += (size_t)e * sB;
    const float* gates = extra;
    if (MODE == 3) gates += (size_t)e * gstride;

    int wm = (warp & 1) * 64, wn = (warp >> 1) * 64;

    int ar = tid >> 1, ah = tid & 1;
    int br2 = tid >> 3, bc0 = (tid & 7) * 4;
    const __half* aSrc = A + (size_t)(m0 + ar) * K + ah * 16;
    const __half* bSrc = Bm + (size_t)br2 * N + n0 + bc0 * 8;
    uint32_t aS = (ar >> 1) & 3;
    uint32_t aBase = sb + (uint32_t)ar * 64u;
    uint32_t bBase = sb + 8192u + (uint32_t)br2 * 512u;

    auto fetch = [&](int stage, int k0) {
        uint32_t so = (uint32_t)stage * STGB;
        const __half* as = aSrc + k0;
        uint32_t c0 = 2u * ah;
        cpasync16(aBase + so + ((c0 ^ aS) * 16u), as);
        cpasync16(aBase + so + (((c0 + 1) ^ aS) * 16u), as + 8);
        const __half* bs = bSrc + (size_t)k0 * N;
#pragma unroll
        for (int j = 0; j < 4; j++) {
            uint32_t c = bc0 + j;
            cpasync16(bBase + so + ((c ^ (br2 & 7)) * 16u), bs + j * 8);
        }
    };

    float d[4][8][4];
#pragma unroll
    for (int i = 0; i < 4; i++)
#pragma unroll
        for (int j = 0; j < 8; j++)
#pragma unroll
            for (int c = 0; c < 4; c++) d[i][j][c] = 0.f;

    fetch(0, 0);  cp_commit();
    fetch(1, 32); cp_commit();
    fetch(2, 64); cp_commit();

    int lrow = lane & 7, selb = (lane >> 3) & 1, selc = lane >> 4;
    uint32_t aRow = (uint32_t)(wm + lrow + 8 * selb) * 64u;
    uint32_t aSw  = (uint32_t)((lrow >> 1) & 3);
    uint32_t bRow = (uint32_t)(lrow + 8 * selb) * 512u;
    uint32_t bCb  = (uint32_t)((wn >> 3) + selc);

    int KB = K >> 5;
    for (int it = 0; it < KB; ++it) {
        cp_wait<2>();
        __syncthreads();
        if (it + 3 < KB) fetch((it + 3) & 3, (it + 3) * 32);
        cp_commit();

        uint32_t As = sb + (uint32_t)(it & 3) * STGB;
        uint32_t Bs = As + 8192u;
#pragma unroll
        for (int kk = 0; kk < 2; kk++) {
            uint32_t a[4][4], b[8][2];
#pragma unroll
            for (int mt = 0; mt < 4; mt++) {
                uint32_t addr = As + aRow + (uint32_t)mt * 1024u
                              + ((((uint32_t)(2 * kk) + (uint32_t)selc) ^ aSw) * 16u);
                ldsm_x4(a[mt], addr);
            }
#pragma unroll
            for (int np = 0; np < 4; np++) {
                uint32_t q[4];
                uint32_t addr = Bs + bRow + (uint32_t)kk * 8192u
                              + (((bCb + 2u * np) ^ (uint32_t)lrow) * 16u);
                ldsm_x4_t(q, addr);
                b[2 * np][0]     = q[0]; b[2 * np][1]     = q[1];
                b[2 * np + 1][0] = q[2]; b[2 * np + 1][1] = q[3];
            }
#pragma unroll
            for (int mt = 0; mt < 4; mt++)
#pragma unroll
                for (int nt = 0; nt < 8; nt++)
                    mma_f16(d[mt][nt], a[mt], b[nt]);
        }
    }

#pragma unroll
    for (int mt = 0; mt < 4; mt++) {
        int r0 = m0 + wm + mt * 16 + gq;
        int r1 = r0 + 8;
        if (MODE == 2) {
            __half* Cb = (__half*)Cp + (size_t)e * sC;
#pragma unroll
            for (int nt = 0; nt < 8; nt++) {
                int c = n0 + wn + nt * 8 + 2 * tq;
                *(uint32_t*)(Cb + (size_t)r0 * N + c) =
                    h2_bits(fmaxf(d[mt][nt][0], 0.f), fmaxf(d[mt][nt][1], 0.f));
                *(uint32_t*)(Cb + (size_t)r1 * N + c) =
                    h2_bits(fmaxf(d[mt][nt][2], 0.f), fmaxf(d[mt][nt][3], 0.f));
            }
        } else {
            float* Cf = (float*)Cp + (size_t)e * sC;
            float g0 = 1.f, g1 = 1.f;
            if (MODE == 3) { g0 = gates[r0]; g1 = gates[r1]; }
#pragma unroll
            for (int nt = 0; nt < 8; nt++) {
                int c = n0 + wn + nt * 8 + 2 * tq;
                float2 u, w;
                u.x = d[mt][nt][0]; u.y = d[mt][nt][1];
                w.x = d[mt][nt][2]; w.y = d[mt][nt][3];
                if (MODE == 1) {
                    float2 ra = *(const float2*)(extra + (size_t)r0 * N + c);
                    float2 rb = *(const float2*)(extra + (size_t)r1 * N + c);
                    u.x += ra.x; u.y += ra.y;
                    w.x += rb.x; w.y += rb.y;
                }
                if (MODE == 3) {
                    u.x *= g0; u.y *= g0;
                    w.x *= g1; w.y *= g1;
                }
                *(float2*)(Cf + (size_t)r0 * N + c) = u;
                *(float2*)(Cf + (size_t)r1 * N + c) = w;
            }
        }
    }
}

// ---------------------------------------------------------------------------
// Router (fp32, exact). Block 0 also zeroes cnt[] for the later rank pass.
// ---------------------------------------------------------------------------
__global__ void __launch_bounds__(256) router_k(const float* __restrict__ xn,
                                                const float* __restrict__ wr,
                                                float* __restrict__ fg,
                                                int* __restrict__ fe,
                                                int* __restrict__ cnt) {
    if (blockIdx.x == 0 && threadIdx.x < En) cnt[threadIdx.x] = 0;
    int warp = threadIdx.x >> 5, lane = threadIdx.x & 31;
    int t = blockIdx.x * 8 + warp;
    float acc[8];
#pragma unroll
    for (int e2 = 0; e2 < 8; e2++) acc[e2] = 0.f;
    const float* xr = xn + (size_t)t * Dm;
    for (int d = lane; d < Dm; d += 32) {
        float xv = xr[d];
        const float4* w = (const float4*)(wr + d * En);
        float4 w0 = w[0], w1 = w[1];
        acc[0] = fmaf(xv, w0.x, acc[0]); acc[1] = fmaf(xv, w0.y, acc[1]);
        acc[2] = fmaf(xv, w0.z, acc[2]); acc[3] = fmaf(xv, w0.w, acc[3]);
        acc[4] = fmaf(xv, w1.x, acc[4]); acc[5] = fmaf(xv, w1.y, acc[5]);
        acc[6] = fmaf(xv, w1.z, acc[6]); acc[7] = fmaf(xv, w1.w, acc[7]);
    }
#pragma unroll
    for (int e2 = 0; e2 < 8; e2++)
#pragma unroll
        for (int off = 16; off; off >>= 1)
            acc[e2] += __shfl_down_sync(0xffffffffu, acc[e2], off);
    if (lane == 0) {
        float mx = acc[0];
#pragma unroll
        for (int e2 = 1; e2 < 8; e2++) mx = fmaxf(mx, acc[e2]);
        float p[8], sum = 0.f;
#pragma unroll
        for (int e2 = 0; e2 < 8; e2++) { p[e2] = expf(acc[e2] - mx); sum += p[e2]; }
        float inv = 1.f / sum;
#pragma unroll
        for (int e2 = 0; e2 < 8; e2++) p[e2] *= inv;
        int e0 = 0; float p0 = p[0];
#pragma unroll
        for (int e2 = 1; e2 < 8; e2++) if (p[e2] > p0) { p0 = p[e2]; e0 = e2; }
        int e1 = -1; float p1 = -1.f;
#pragma unroll
        for (int e2 = 0; e2 < 8; e2++)
            if (e2 != e0 && p[e2] > p1) { p1 = p[e2]; e1 = e2; }
        fg[2 * t]     = p0; fe[2 * t]     = e0;
        fg[2 * t + 1] = p1; fe[2 * t + 1] = e1;
    }
}

// ---------------------------------------------------------------------------
// Exact capacity ranking. Slots [0, cnt_e) are filled densely, so etok needs
// no initialization; cnt tracks the live row count per expert.
// ---------------------------------------------------------------------------
__global__ void __launch_bounds__(256) rank_k(const float* __restrict__ fg,
                                              const int* __restrict__ fe,
                                              int* __restrict__ slot,
                                              int* __restrict__ etok,
                                              float* __restrict__ egate,
                                              int* __restrict__ cnt) {
    __shared__ float sg[NA];
    __shared__ unsigned char se[NA];
    for (int i = threadIdx.x; i < NA; i += 256) {
        sg[i] = fg[i];
        se[i] = (unsigned char)fe[i];
    }
    __syncthreads();
    int i = blockIdx.x * 256 + threadIdx.x;
    float gi = sg[i];
    unsigned char ei = se[i];
    int r = 0;
    for (int j = 0; j < NA; j++) {
        bool c = (se[j] == ei) && ((sg[j] > gi) || (sg[j] == gi && j < i));
        r += (int)c;
    }
    if (r < CAPn) {
        slot[i] = r;
        etok[(int)ei * CAPn + r] = i >> 1;
        egate[(int)ei * CAPn + r] = gi;
        atomicMax(&cnt[(int)ei], r + 1);
    } else {
        slot[i] = -1;
    }
}

// ---------------------------------------------------------------------------
// Gather expert inputs -> fp16 (rows >= cnt[e]: zeros; etok valid below cnt)
// ---------------------------------------------------------------------------
__global__ void __launch_bounds__(256) xepack_k(const float* __restrict__ xn,
                                                const int* __restrict__ etok,
                                                const int* __restrict__ cnt,
                                                __half* __restrict__ xe) {
    int row = blockIdx.x;
    int e = row / CAPn, r = row - e * CAPn;
    int i = threadIdx.x;
    float4 v = make_float4(0.f, 0.f, 0.f, 0.f);
    if (r < cnt[e]) {
        int tok = etok[row];
        v = ((const float4*)(xn + (size_t)tok * Dm))[i];
    }
    ((uint2*)(xe + (size_t)row * Dm))[i] =
        make_uint2(h2_bits(v.x, v.y), h2_bits(v.z, v.w));
}

// ---------------------------------------------------------------------------
// Final combine
// ---------------------------------------------------------------------------
__global__ void __launch_bounds__(256) combine_k(const float* __restrict__ x1,
                                                 const float* __restrict__ ye,
                                                 const int* __restrict__ fe,
                                                 const int* __restrict__ slot,
                                                 float* __restrict__ out) {
    int t = blockIdx.x;
    int d = threadIdx.x;
    float4 v = ((const float4*)(x1 + (size_t)t * Dm))[d];
#pragma unroll
    for (int kk = 0; kk < 2; kk++) {
        int i = 2 * t + kk;
        int sl = slot[i];
        if (sl >= 0) {
            int e = fe[i];
            float4 w = ((const float4*)(ye + ((size_t)e * CAPn + sl) * Dm))[d];
            v.x += w.x; v.y += w.y; v.z += w.z; v.w += w.w;
        }
    }
    ((float4*)(out + (size_t)t * Dm))[d] = v;
}

// ---------------------------------------------------------------------------
// Launch (single stream)
// ---------------------------------------------------------------------------
extern "C" void kernel_launch(void* const* d_in, const int* in_sizes, int n_in,
                              void* d_out, int out_size) {
    (void)in_sizes; (void)n_in; (void)out_size;
    const float* x        = (const float*)d_in[0];
    const float* g1       = (const float*)d_in[1];
    const float* w_qkv    = (const float*)d_in[2];
    const float* w_o      = (const float*)d_in[3];
    const float* g2       = (const float*)d_in[4];
    const float* w_router = (const float*)d_in[5];
    const float* w1       = (const float*)d_in[6];
    const float* w2       = (const float*)d_in[7];
    float* out = (float*)d_out;

    float *p_xn, *p_qkv, *p_q, *p_k, *p_v, *p_x1, *p_cos, *p_sin;
    float *p_fg, *p_egate, *p_ye;
    __half *p_xnh, *p_attnh, *p_wqkvh, *p_woh, *p_w1h, *p_w2h, *p_xeh, *p_hh;
    int *p_fe, *p_slot, *p_etok, *p_cnt;
    cudaGetSymbolAddress((void**)&p_xn,    g_xn);
    cudaGetSymbolAddress((void**)&p_qkv,   g_qkv);
    cudaGetSymbolAddress((void**)&p_q,     g_q);
    cudaGetSymbolAddress((void**)&p_k,     g_k);
    cudaGetSymbolAddress((void**)&p_v,     g_v);
    cudaGetSymbolAddress((void**)&p_x1,    g_x1);
    cudaGetSymbolAddress((void**)&p_cos,   g_cos);
    cudaGetSymbolAddress((void**)&p_sin,   g_sin);
    cudaGetSymbolAddress((void**)&p_fg,    g_fg);
    cudaGetSymbolAddress((void**)&p_fe,    g_fe);
    cudaGetSymbolAddress((void**)&p_slot,  g_slot);
    cudaGetSymbolAddress((void**)&p_etok,  g_etok);
    cudaGetSymbolAddress((void**)&p_egate, g_egate);
    cudaGetSymbolAddress((void**)&p_cnt,   g_cnt);
    cudaGetSymbolAddress((void**)&p_ye,    g_ye);
    cudaGetSymbolAddress((void**)&p_xnh,   g_xnh);
    cudaGetSymbolAddress((void**)&p_attnh, g_attnh);
    cudaGetSymbolAddress((void**)&p_wqkvh, g_wqkvh);
    cudaGetSymbolAddress((void**)&p_woh,   g_woh);
    cudaGetSymbolAddress((void**)&p_w1h,   g_w1h);
    cudaGetSymbolAddress((void**)&p_w2h,   g_w2h);
    cudaGetSymbolAddress((void**)&p_xeh,   g_xeh);
    cudaGetSymbolAddress((void**)&p_hh,    g_hh);

    constexpr int H_SMEM    = 4 * 24576;        // fp16 gemm: 98304 bytes
    constexpr int ATTN_SMEM = 2 * 8960 * 4;     // 71680 bytes
    cudaFuncSetAttribute(gemm_h_k<0, false>, cudaFuncAttributeMaxDynamicSharedMemorySize, H_SMEM);
    cudaFuncSetAttribute(gemm_h_k<1, false>, cudaFuncAttributeMaxDynamicSharedMemorySize, H_SMEM);
    cudaFuncSetAttribute(gemm_h_k<2, true>,  cudaFuncAttributeMaxDynamicSharedMemorySize, H_SMEM);
    cudaFuncSetAttribute(gemm_h_k<3, true>,  cudaFuncAttributeMaxDynamicSharedMemorySize, H_SMEM);
    cudaFuncSetAttribute(attn_tc_k, cudaFuncAttributeMaxDynamicSharedMemorySize, ATTN_SMEM);

    // Fused precompute: fp16 weight conversions + rope table in ONE launch
    prep_k<<<1184, 256>>>(w_qkv, p_wqkvh, w_o, p_woh,
                          w1, p_w1h, w2, p_w2h, p_cos, p_sin);

    // Attention branch (fp16 GEMMs, tf32-grade precision — protects routing)
    rmsnorm_k<true><<<Tn, 256>>>(x, g1, p_xnh);
    gemm_h_k<0, false><<<dim3(3 * Dm / 256, Tn / 128, 1), 256, H_SMEM>>>(
        p_xnh, p_wqkvh, p_qkv, 3 * Dm, Dm, nullptr, nullptr, 0, 0, 0, 0);
    split_rope_k<<<Tn, 256>>>(p_qkv, p_cos, p_sin, p_q, p_k, p_v);
    attn_tc_k<<<dim3(Sq / 128, Hn, Bz), 256, ATTN_SMEM>>>(p_q, p_k, p_v, p_attnh);
    gemm_h_k<1, false><<<dim3(Dm / 256, Tn / 128, 1), 256, H_SMEM>>>(
        p_attnh, p_woh, p_x1, Dm, Dm, x, nullptr, 0, 0, 0, 0);
    rmsnorm_k<false><<<Tn, 256>>>(p_x1, g2, p_xn);

    // Routing (fp32 exact) + live-row counts
    router_k<<<Tn / 8, 256>>>(p_xn, w_router, p_fg, p_fe, p_cnt);
    rank_k<<<NA / 256, 256>>>(p_fg, p_fe, p_slot, p_etok, p_egate, p_cnt);
    xepack_k<<<En * CAPn, 256>>>(p_xn, p_etok, p_cnt, p_xeh);

    // MoE expert GEMMs (fp16 tensor cores; dead capacity tiles early-exit)
    gemm_h_k<2, true><<<dim3(FFNm / 256, CAPn / 128, En), 256, H_SMEM>>>(
        p_xeh, p_w1h, p_hh, FFNm, Dm, nullptr, p_cnt,
        (long)CAPn * Dm, (long)Dm * FFNm, (long)CAPn * FFNm, 0);
    gemm_h_k<3, true><<<dim3(Dm / 256, CAPn / 128, En), 256, H_SMEM>>>(
        p_hh, p_w2h, p_ye, Dm, FFNm, p_egate, p_cnt,
        (long)CAPn * FFNm, (long)FFNm * Dm, (long)CAPn * Dm, CAPn);

    // out = x1 + moe
    combine_k<<<Tn, 256>>>(p_x1, p_ye, p_fe, p_slot, out);
}

// round 12
// speedup vs baseline: 5.9968x; 1.0376x over previous
#include <cuda_runtime.h>
#include <cuda_fp16.h>
#include <math.h>
#include <stdint.h>

// ---------------------------------------------------------------------------
// Problem constants
// ---------------------------------------------------------------------------
namespace {
constexpr int Bz   = 2;
constexpr int Sq   = 2048;
constexpr int Dm   = 1024;
constexpr int Hn   = 16;
constexpr int HDm  = 64;
constexpr int FFNm = 2048;
constexpr int En   = 8;
constexpr int Tn   = Bz * Sq;     // 4096 tokens
constexpr int NA   = Tn * 2;      // 8192 flat assignments (top-2)
constexpr int CAPn = 1280;        // ceil(2*2048*2*1.25/8)
// prep_k region sizes (float4 units except rope)
constexpr int NQ4  = Dm * 3 * Dm / 4;        // 786432
constexpr int NO4  = Dm * Dm / 4;            // 262144
constexpr int NW14 = En * Dm * FFNm / 4;     // 4194304
constexpr int NW24 = En * FFNm * Dm / 4;     // 4194304
constexpr int NRP  = Sq * (HDm / 2);         // 65536
}

// ---------------------------------------------------------------------------
// Static scratch (no allocations allowed)
// ---------------------------------------------------------------------------
__device__ float g_xn  [Tn * Dm];           // rmsnorm2 out (fp32, xepack path)
__device__ float g_qkv [Tn * 3 * Dm];
__device__ float g_v   [Tn * Dm];
__device__ float g_x1  [Tn * Dm];
__device__ float g_cos [Sq * (HDm / 2)];
__device__ float g_sin [Sq * (HDm / 2)];
__device__ float g_fg  [NA];
__device__ int   g_fe  [NA];
__device__ int   g_slot[NA];
__device__ int   g_etok [En * CAPn];
__device__ float g_egate[En * CAPn];
__device__ int   g_cnt  [En];               // live rows per expert
__device__ float g_ye[En * CAPn * Dm];
// fp16 data
__device__ __half g_qh   [Tn * Dm];         // rope'd Q, pre-scaled 1/8
__device__ __half g_kh   [Tn * Dm];         // rope'd K
__device__ __half g_xnh  [Tn * Dm];         // rmsnorm1 out (qkv GEMM A)
__device__ __half g_attnh[Tn * Dm];         // attention out (o GEMM A)
__device__ __half g_wqkvh[Dm * 3 * Dm];
__device__ __half g_woh  [Dm * Dm];
__device__ __half g_w1h  [En * Dm * FFNm];
__device__ __half g_w2h  [En * FFNm * Dm];
__device__ __half g_xeh  [En * CAPn * Dm];
__device__ __half g_hh   [En * CAPn * FFNm];

// ---------------------------------------------------------------------------
// Helpers
// ---------------------------------------------------------------------------
__device__ __forceinline__ float rnd_tf32(float x) {
    uint32_t u = __float_as_uint(x);
    u = (u + 0x1000u) & 0xFFFFE000u;
    return __uint_as_float(u);
}

__device__ __forceinline__ uint32_t smem_u32(const void* p) {
    uint32_t a;
    asm("{ .reg .u64 t; cvta.to.shared.u64 t, %1; cvt.u32.u64 %0, t; }"
        : "=r"(a) : "l"(p));
    return a;
}

__device__ __forceinline__ void cpasync16(uint32_t dst, const void* src) {
    asm volatile("cp.async.cg.shared.global [%0], [%1], 16;" :: "r"(dst), "l"(src));
}
__device__ __forceinline__ void cp_commit() {
    asm volatile("cp.async.commit_group;" ::: "memory");
}
template <int N>
__device__ __forceinline__ void cp_wait() {
    asm volatile("cp.async.wait_group %0;" :: "n"(N) : "memory");
}

// tf32 m16n8k8 MMA (attention PV stage)
__device__ __forceinline__ void mma_tf32(float* d, const uint32_t* a, const uint32_t* b) {
    asm volatile(
        "mma.sync.aligned.m16n8k8.row.col.f32.tf32.tf32.f32 "
        "{%0,%1,%2,%3}, {%4,%5,%6,%7}, {%8,%9}, {%0,%1,%2,%3};"
        : "+f"(d[0]), "+f"(d[1]), "+f"(d[2]), "+f"(d[3])
        : "r"(a[0]), "r"(a[1]), "r"(a[2]), "r"(a[3]), "r"(b[0]), "r"(b[1]));
}

// fp16 m16n8k16 MMA, fp32 accumulate
__device__ __forceinline__ void mma_f16(float* d, const uint32_t* a, const uint32_t* b) {
    asm volatile(
        "mma.sync.aligned.m16n8k16.row.col.f32.f16.f16.f32 "
        "{%0,%1,%2,%3}, {%4,%5,%6,%7}, {%8,%9}, {%0,%1,%2,%3};"
        : "+f"(d[0]), "+f"(d[1]), "+f"(d[2]), "+f"(d[3])
        : "r"(a[0]), "r"(a[1]), "r"(a[2]), "r"(a[3]), "r"(b[0]), "r"(b[1]));
}

__device__ __forceinline__ void ldsm_x4(uint32_t* r, uint32_t addr) {
    asm volatile("ldmatrix.sync.aligned.m8n8.x4.shared.b16 {%0,%1,%2,%3}, [%4];"
                 : "=r"(r[0]), "=r"(r[1]), "=r"(r[2]), "=r"(r[3]) : "r"(addr));
}
__device__ __forceinline__ void ldsm_x4_t(uint32_t* r, uint32_t addr) {
    asm volatile("ldmatrix.sync.aligned.m8n8.x4.trans.shared.b16 {%0,%1,%2,%3}, [%4];"
                 : "=r"(r[0]), "=r"(r[1]), "=r"(r[2]), "=r"(r[3]) : "r"(addr));
}

// 2^x for x <= 0, FMA-pipe only.
__device__ __forceinline__ float exp2p(float x) {
    float t = fmaxf(x, -126.f);
    float z = t + 12582912.f;
    float n = z - 12582912.f;
    float f = t - n;
    float p =         1.5353e-4f;
    p = fmaf(p, f, 1.3398886e-3f);
    p = fmaf(p, f, 9.6184372e-3f);
    p = fmaf(p, f, 5.5503327e-2f);
    p = fmaf(p, f, 2.4022648e-1f);
    p = fmaf(p, f, 6.9314718e-1f);
    p = fmaf(p, f, 1.0f);
    int iz = __float_as_int(z) - 0x4B400000;
    return p * __int_as_float((iz + 127) << 23);
}

__device__ __forceinline__ uint32_t h2_bits(float a, float b) {
    __half2 h = __float22half2_rn(make_float2(a, b));
    return *(uint32_t*)&h;
}

// ---------------------------------------------------------------------------
// Fused prep: fp16-convert all four weight tensors + rope table. One launch.
// ---------------------------------------------------------------------------
__global__ void prep_k(const float* __restrict__ wqkv, __half* __restrict__ wqkvh,
                       const float* __restrict__ wo,   __half* __restrict__ woh,
                       const float* __restrict__ w1,   __half* __restrict__ w1h,
                       const float* __restrict__ w2,   __half* __restrict__ w2h,
                       float* __restrict__ ct, float* __restrict__ st) {
    const int total = NQ4 + NO4 + NW14 + NW24 + NRP;
    int stride = gridDim.x * blockDim.x;
    for (int i = blockIdx.x * blockDim.x + threadIdx.x; i < total; i += stride) {
        int r = i;
        if (r < NQ4) {
            float4 v = ((const float4*)wqkv)[r];
            ((uint2*)wqkvh)[r] = make_uint2(h2_bits(v.x, v.y), h2_bits(v.z, v.w));
            continue;
        }
        r -= NQ4;
        if (r < NO4) {
            float4 v = ((const float4*)wo)[r];
            ((uint2*)woh)[r] = make_uint2(h2_bits(v.x, v.y), h2_bits(v.z, v.w));
            continue;
        }
        r -= NO4;
        if (r < NW14) {
            float4 v = ((const float4*)w1)[r];
            ((uint2*)w1h)[r] = make_uint2(h2_bits(v.x, v.y), h2_bits(v.z, v.w));
            continue;
        }
        r -= NW14;
        if (r < NW24) {
            float4 v = ((const float4*)w2)[r];
            ((uint2*)w2h)[r] = make_uint2(h2_bits(v.x, v.y), h2_bits(v.z, v.w));
            continue;
        }
        r -= NW24;
        {
            int s = r >> 5, j = r & 31;
            float th = (float)pow(10000.0, -2.0 * (double)j / (double)HDm);
            double f = (double)s * (double)th;
            ct[r] = (float)cos(f);
            st[r] = (float)sin(f);
        }
    }
}

// ---------------------------------------------------------------------------
// RMSNorm (fp16 out; feeds qkv GEMM)
// ---------------------------------------------------------------------------
__global__ void __launch_bounds__(256) rmsnorm_k(const float* __restrict__ x,
                                                 const float* __restrict__ g,
                                                 __half* __restrict__ y) {
    int row = blockIdx.x;
    int i = threadIdx.x;
    const float4* xr = (const float4*)(x + (size_t)row * Dm);
    float4 xv = xr[i];
    float ss = xv.x * xv.x + xv.y * xv.y + xv.z * xv.z + xv.w * xv.w;
#pragma unroll
    for (int off = 16; off; off >>= 1) ss += __shfl_down_sync(0xffffffffu, ss, off);
    __shared__ float red[8];
    __shared__ float srms;
    if ((i & 31) == 0) red[i >> 5] = ss;
    __syncthreads();
    if (i == 0) {
        float t = 0.f;
#pragma unroll
        for (int w = 0; w < 8; w++) t += red[w];
        srms = rsqrtf(t * (1.0f / Dm) + 1e-6f);
    }
    __syncthreads();
    float r = srms;
    float4 gv = ((const float4*)g)[i];
    ((uint2*)(y + (size_t)row * Dm))[i] =
        make_uint2(h2_bits(gv.x * xv.x * r, gv.y * xv.y * r),
                   h2_bits(gv.z * xv.z * r, gv.w * xv.w * r));
}

// ---------------------------------------------------------------------------
// Fused RMSNorm2 + router: norm -> xn (fp32), 8 logits, softmax, top-2.
// One block per token.
// ---------------------------------------------------------------------------
__global__ void __launch_bounds__(256) rmsrouter_k(const float* __restrict__ x,
                                                   const float* __restrict__ g,
                                                   const float* __restrict__ wr,
                                                   float* __restrict__ xn,
                                                   float* __restrict__ fg,
                                                   int* __restrict__ fe,
                                                   int* __restrict__ cnt) {
    int row = blockIdx.x;
    int i = threadIdx.x;
    if (row == 0 && i < En) cnt[i] = 0;
    const float4* xr = (const float4*)(x + (size_t)row * Dm);
    float4 xv = xr[i];
    float ss = xv.x * xv.x + xv.y * xv.y + xv.z * xv.z + xv.w * xv.w;
#pragma unroll
    for (int off = 16; off; off >>= 1) ss += __shfl_down_sync(0xffffffffu, ss, off);
    __shared__ float red[8];
    __shared__ float srms;
    if ((i & 31) == 0) red[i >> 5] = ss;
    __syncthreads();
    if (i == 0) {
        float t = 0.f;
#pragma unroll
        for (int w = 0; w < 8; w++) t += red[w];
        srms = rsqrtf(t * (1.0f / Dm) + 1e-6f);
    }
    __syncthreads();
    float r = srms;
    float4 gv = ((const float4*)g)[i];
    float o[4];
    o[0] = gv.x * xv.x * r; o[1] = gv.y * xv.y * r;
    o[2] = gv.z * xv.z * r; o[3] = gv.w * xv.w * r;
    float4 ov;
    ov.x = o[0]; ov.y = o[1]; ov.z = o[2]; ov.w = o[3];
    ((float4*)(xn + (size_t)row * Dm))[i] = ov;

    // logits: thread i covers dims 4i..4i+3
    float acc[8];
#pragma unroll
    for (int e = 0; e < 8; e++) acc[e] = 0.f;
#pragma unroll
    for (int c = 0; c < 4; c++) {
        const float4* w = (const float4*)(wr + (size_t)(4 * i + c) * En);
        float4 w0 = w[0], w1 = w[1];
        acc[0] = fmaf(o[c], w0.x, acc[0]); acc[1] = fmaf(o[c], w0.y, acc[1]);
        acc[2] = fmaf(o[c], w0.z, acc[2]); acc[3] = fmaf(o[c], w0.w, acc[3]);
        acc[4] = fmaf(o[c], w1.x, acc[4]); acc[5] = fmaf(o[c], w1.y, acc[5]);
        acc[6] = fmaf(o[c], w1.z, acc[6]); acc[7] = fmaf(o[c], w1.w, acc[7]);
    }
#pragma unroll
    for (int e = 0; e < 8; e++)
#pragma unroll
        for (int off = 16; off; off >>= 1)
            acc[e] += __shfl_down_sync(0xffffffffu, acc[e], off);
    __shared__ float lred[8][8];
    if ((i & 31) == 0)
#pragma unroll
        for (int e = 0; e < 8; e++) lred[i >> 5][e] = acc[e];
    __syncthreads();
    if (i == 0) {
        float p[8];
#pragma unroll
        for (int e = 0; e < 8; e++) {
            float s = 0.f;
#pragma unroll
            for (int w = 0; w < 8; w++) s += lred[w][e];
            p[e] = s;
        }
        float mx = p[0];
#pragma unroll
        for (int e = 1; e < 8; e++) mx = fmaxf(mx, p[e]);
        float sum = 0.f;
#pragma unroll
        for (int e = 0; e < 8; e++) { p[e] = expf(p[e] - mx); sum += p[e]; }
        float inv = 1.f / sum;
#pragma unroll
        for (int e = 0; e < 8; e++) p[e] *= inv;
        int e0 = 0; float p0 = p[0];
#pragma unroll
        for (int e = 1; e < 8; e++) if (p[e] > p0) { p0 = p[e]; e0 = e; }
        int e1 = -1; float p1 = -1.f;
#pragma unroll
        for (int e = 0; e < 8; e++)
            if (e != e0 && p[e] > p1) { p1 = p[e]; e1 = e; }
        fg[2 * row]     = p0; fe[2 * row]     = e0;
        fg[2 * row + 1] = p1; fe[2 * row + 1] = e1;
    }
}

// ---------------------------------------------------------------------------
// Split QKV + RoPE: q (pre-scaled 1/8) and k as fp16, v as fp32.
// ---------------------------------------------------------------------------
__global__ void __launch_bounds__(256) split_rope_k(const float* __restrict__ qkv,
                                                    const float* __restrict__ ct,
                                                    const float* __restrict__ st,
                                                    __half* __restrict__ q,
                                                    __half* __restrict__ k,
                                                    float* __restrict__ v) {
    int t = blockIdx.x;
    int b = t / Sq, s = t % Sq;
    const float* row = qkv + (size_t)t * (3 * Dm);
    for (int idx = threadIdx.x; idx < Hn * (HDm / 2); idx += blockDim.x) {
        int h = idx >> 5, j = idx & 31;
        float c = ct[s * 32 + j], sn = st[s * 32 + j];
        size_t o = ((size_t)(b * Hn + h) * Sq + s) * HDm;
        float qr = row[h * HDm + 2 * j], qi = row[h * HDm + 2 * j + 1];
        *(uint32_t*)(q + o + 2 * j) =
            h2_bits((qr * c - qi * sn) * 0.125f, (qr * sn + qi * c) * 0.125f);
        float kr = row[Dm + h * HDm + 2 * j], ki = row[Dm + h * HDm + 2 * j + 1];
        *(uint32_t*)(k + o + 2 * j) =
            h2_bits(kr * c - ki * sn, kr * sn + ki * c);
    }
    for (int idx = threadIdx.x; idx < Dm; idx += blockDim.x) {
        int h = idx >> 6, d = idx & 63;
        v[((size_t)(b * Hn + h) * Sq + s) * HDm + d] = row[2 * Dm + idx];
    }
}

// ---------------------------------------------------------------------------
// Tensor-core causal flash attention.
// QK^T: fp16 m16n8k16 (Q/K fp16, K smem stride 72 halves, conflict-free).
// PV: tf32 (P tf32-rounded fp32, V fp32 smem stride 72).
// fp16 output (feeds o-proj GEMM).
// ---------------------------------------------------------------------------
__global__ void __launch_bounds__(256) attn_tc_k(const __half* __restrict__ Q,
                                                 const __half* __restrict__ Kt,
                                                 const float* __restrict__ Vt,
                                                 __half* __restrict__ Out) {
    extern __shared__ __align__(16) char smc[];
    constexpr float LOG2E = 1.4426950408889634f;
    constexpr int STGB = 64 * 144 + 64 * 288;   // K tile 9216B + V tile 18432B

    int bx = blockIdx.x, h = blockIdx.y, b = blockIdx.z;
    int qt = bx * 128;
    int tid = threadIdx.x, warp = tid >> 5, lane = tid & 31;
    int gq = lane >> 2, tq = lane & 3;
    int wq = qt + warp * 16;
    const size_t base = ((size_t)(b * Hn + h)) * Sq * HDm;
    const __half* Qg = Q + base;
    const __half* Kg = Kt + base;
    const float* Vg = Vt + base;

    const uint32_t sb = smem_u32(smc);

    // Q fragments for m16n8k16: qf[kk][0..3], kk over 4 k-chunks of 16 dims
    uint32_t qf[4][4];
#pragma unroll
    for (int kk = 0; kk < 4; kk++) {
        const __half* q0 = Qg + (size_t)(wq + gq) * 64 + kk * 16 + 2 * tq;
        const __half* q1 = Qg + (size_t)(wq + gq + 8) * 64 + kk * 16 + 2 * tq;
        qf[kk][0] = *(const uint32_t*)q0;
        qf[kk][1] = *(const uint32_t*)q1;
        qf[kk][2] = *(const uint32_t*)(q0 + 8);
        qf[kk][3] = *(const uint32_t*)(q1 + 8);
    }

    float O[8][4];
#pragma unroll
    for (int nt = 0; nt < 8; nt++)
#pragma unroll
        for (int c = 0; c < 4; c++) O[nt][c] = 0.f;
    float m0 = -1e30f, m1 = -1e30f, l0 = 0.f, l1 = 0.f;

    int fr = tid >> 2;                 // row 0..63
    int fsK = (tid & 3) * 16;          // halves
    int fsV = (tid & 3) * 16;          // floats
    auto fill = [&](int stage, int kt) {
        uint32_t kDst = sb + (uint32_t)(stage * STGB + fr * 144 + fsK * 2);
        uint32_t vDst = sb + (uint32_t)(stage * STGB + 9216 + fr * 288 + fsV * 4);
        const __half* ks = Kg + (size_t)(kt + fr) * 64 + fsK;
        const float* vs = Vg + (size_t)(kt + fr) * 64 + fsV;
        cpasync16(kDst, ks);
        cpasync16(kDst + 16u, ks + 8);
#pragma unroll
        for (int c = 0; c < 4; c++) cpasync16(vDst + 16u * c, vs + 4 * c);
    };

    int ntiles = 2 * bx + 2;
    fill(0, 0);
    cp_commit();

    for (int it = 0; it < ntiles; it++) {
        if (it + 1 < ntiles) fill((it + 1) & 1, (it + 1) * 64);
        cp_commit();
        cp_wait<1>();
        __syncthreads();

        int kt = it * 64;
        if (kt <= wq + 15) {
            const __half* Ks = (const __half*)(smc + (it & 1) * STGB);
            const float* Vs = (const float*)(smc + (it & 1) * STGB + 9216);

            // ---- S = Q K^T (fp16 MMA) ----
            float s[8][4];
#pragma unroll
            for (int nt = 0; nt < 8; nt++)
#pragma unroll
                for (int c = 0; c < 4; c++) s[nt][c] = 0.f;
#pragma unroll
            for (int kk = 0; kk < 4; kk++) {
                uint32_t bf[8][2];
#pragma unroll
                for (int nt = 0; nt < 8; nt++) {
                    const __half* kr = Ks + (nt * 8 + gq) * 72 + kk * 16 + 2 * tq;
                    bf[nt][0] = *(const uint32_t*)kr;
                    bf[nt][1] = *(const uint32_t*)(kr + 8);
                }
#pragma unroll
                for (int nt = 0; nt < 8; nt++) mma_f16(s[nt], qf[kk], bf[nt]);
            }

            if (kt + 63 > wq) {
                int r0 = wq + gq, r1 = wq + gq + 8;
#pragma unroll
                for (int nt = 0; nt < 8; nt++) {
                    int c0 = kt + nt * 8 + 2 * tq;
                    if (c0 > r0)     s[nt][0] = -3.4e38f;
                    if (c0 + 1 > r0) s[nt][1] = -3.4e38f;
                    if (c0 > r1)     s[nt][2] = -3.4e38f;
                    if (c0 + 1 > r1) s[nt][3] = -3.4e38f;
                }
            }

            float mx0 = -3.4e38f, mx1 = -3.4e38f;
#pragma unroll
            for (int nt = 0; nt < 8; nt++) {
                mx0 = fmaxf(mx0, fmaxf(s[nt][0], s[nt][1]));
                mx1 = fmaxf(mx1, fmaxf(s[nt][2], s[nt][3]));
            }
            mx0 = fmaxf(mx0, __shfl_xor_sync(0xffffffffu, mx0, 1));
            mx0 = fmaxf(mx0, __shfl_xor_sync(0xffffffffu, mx0, 2));
            mx1 = fmaxf(mx1, __shfl_xor_sync(0xffffffffu, mx1, 1));
            mx1 = fmaxf(mx1, __shfl_xor_sync(0xffffffffu, mx1, 2));
            float mn0 = fmaxf(m0, mx0), mn1 = fmaxf(m1, mx1);
            float cr0 = exp2p((m0 - mn0) * LOG2E);
            float cr1 = exp2p((m1 - mn1) * LOG2E);
            float nm0 = mn0 * LOG2E, nm1 = mn1 * LOG2E;

            float sum0 = 0.f, sum1 = 0.f;
#pragma unroll
            for (int nt = 0; nt < 8; nt++) {
                float p0 = rnd_tf32(exp2p(fmaf(s[nt][0], LOG2E, -nm0)));
                float p1 = rnd_tf32(exp2p(fmaf(s[nt][1], LOG2E, -nm0)));
                float p2 = rnd_tf32(exp2p(fmaf(s[nt][2], LOG2E, -nm1)));
                float p3 = rnd_tf32(exp2p(fmaf(s[nt][3], LOG2E, -nm1)));
                s[nt][0] = p0; s[nt][1] = p1; s[nt][2] = p2; s[nt][3] = p3;
                sum0 += p0 + p1; sum1 += p2 + p3;
            }
            sum0 += __shfl_xor_sync(0xffffffffu, sum0, 1);
            sum0 += __shfl_xor_sync(0xffffffffu, sum0, 2);
            sum1 += __shfl_xor_sync(0xffffffffu, sum1, 1);
            sum1 += __shfl_xor_sync(0xffffffffu, sum1, 2);
            l0 = l0 * cr0 + sum0;
            l1 = l1 * cr1 + sum1;
#pragma unroll
            for (int nt = 0; nt < 8; nt++) {
                O[nt][0] *= cr0; O[nt][1] *= cr0;
                O[nt][2] *= cr1; O[nt][3] *= cr1;
            }
            m0 = mn0; m1 = mn1;

            // ---- O += P V (tf32 path, unchanged) ----
            int sl1 = gq * 4 + (tq >> 1);
            int sl2 = sl1 + 2;
            bool odd = (tq & 1);
#pragma unroll
            for (int kk = 0; kk < 8; kk++) {
                float v00 = __shfl_sync(0xffffffffu, s[kk][0], sl1);
                float v01 = __shfl_sync(0xffffffffu, s[kk][1], sl1);
                float v10 = __shfl_sync(0xffffffffu, s[kk][0], sl2);
                float v11 = __shfl_sync(0xffffffffu, s[kk][1], sl2);
                float w00 = __shfl_sync(0xffffffffu, s[kk][2], sl1);
                float w01 = __shfl_sync(0xffffffffu, s[kk][3], sl1);
                float w10 = __shfl_sync(0xffffffffu, s[kk][2], sl2);
                float w11 = __shfl_sync(0xffffffffu, s[kk][3], sl2);
                uint32_t a[4];
                a[0] = __float_as_uint(odd ? v01 : v00);
                a[1] = __float_as_uint(odd ? w01 : w00);
                a[2] = __float_as_uint(odd ? v11 : v10);
                a[3] = __float_as_uint(odd ? w11 : w10);
                uint32_t bf[8][2];
#pragma unroll
                for (int nt = 0; nt < 8; nt++) {
                    int krow = kk * 8 + tq;
                    bf[nt][0] = __float_as_uint(Vs[krow * 72 + nt * 8 + gq]);
                    bf[nt][1] = __float_as_uint(Vs[(krow + 4) * 72 + nt * 8 + gq]);
                }
#pragma unroll
                for (int nt = 0; nt < 8; nt++) mma_tf32(O[nt], a, bf[nt]);
            }
        }
        __syncthreads();
    }

    float i0 = 1.f / l0, i1 = 1.f / l1;
    int r0 = wq + gq, r1 = wq + gq + 8;
    __half* o0 = Out + ((size_t)(b * Sq + r0)) * Dm + h * 64 + 2 * tq;
    __half* o1 = Out + ((size_t)(b * Sq + r1)) * Dm + h * 64 + 2 * tq;
#pragma unroll
    for (int nt = 0; nt < 8; nt++) {
        *(uint32_t*)(o0 + nt * 8) = h2_bits(O[nt][0] * i0, O[nt][1] * i0);
        *(uint32_t*)(o1 + nt * 8) = h2_bits(O[nt][2] * i1, O[nt][3] * i1);
    }
}

// ---------------------------------------------------------------------------
// fp16 tensor-core GEMM (all four GEMMs): CTA 128x256, warp 64x64, BK=32,
// 4-stage cp.async, ldmatrix, m16n8k16.f16, ONE barrier/iter.
// MODE 0: C(f32) = A@B                 (qkv)
// MODE 1: C(f32) = A@B + extra(resid)  (o-proj)
// MODE 2: C(f16) = relu(A@B)           (moe1)
// MODE 3: C(f32) = (A@B)*gates[row]    (moe2)
// SKIP: early-exit CTAs whose M-tile is past cnt[e] (MoE dead capacity).
// ---------------------------------------------------------------------------
template <int MODE, bool SKIP>
__global__ void __launch_bounds__(256, 1)
gemm_h_k(const __half* __restrict__ A, const __half* __restrict__ Bm,
         void* __restrict__ Cp, int N, int K,
         const float* __restrict__ extra, const int* __restrict__ cnt,
         long sA, long sB, long sC, int gstride) {
    extern __shared__ __align__(16) float smf[];
    const uint32_t sb = smem_u32(smf);
    constexpr uint32_t STGB = 24576;

    int e = blockIdx.z;
    int m0 = blockIdx.y * 128, n0 = blockIdx.x * 256;
    if (SKIP && m0 >= cnt[e]) return;

    int tid = threadIdx.x, warp = tid >> 5, lane = tid & 31;
    int gq = lane >> 2, tq = lane & 3;
    A  += (size_t)e * sA;
    Bm += (size_t)e * sB;
    const float* gates = extra;
    if (MODE == 3) gates += (size_t)e * gstride;

    int wm = (warp & 1) * 64, wn = (warp >> 1) * 64;

    int ar = tid >> 1, ah = tid & 1;
    int br2 = tid >> 3, bc0 = (tid & 7) * 4;
    const __half* aSrc = A + (size_t)(m0 + ar) * K + ah * 16;
    const __half* bSrc = Bm + (size_t)br2 * N + n0 + bc0 * 8;
    uint32_t aS = (ar >> 1) & 3;
    uint32_t aBase = sb + (uint32_t)ar * 64u;
    uint32_t bBase = sb + 8192u + (uint32_t)br2 * 512u;

    auto fetch = [&](int stage, int k0) {
        uint32_t so = (uint32_t)stage * STGB;
        const __half* as = aSrc + k0;
        uint32_t c0 = 2u * ah;
        cpasync16(aBase + so + ((c0 ^ aS) * 16u), as);
        cpasync16(aBase + so + (((c0 + 1) ^ aS) * 16u), as + 8);
        const __half* bs = bSrc + (size_t)k0 * N;
#pragma unroll
        for (int j = 0; j < 4; j++) {
            uint32_t c = bc0 + j;
            cpasync16(bBase + so + ((c ^ (br2 & 7)) * 16u), bs + j * 8);
        }
    };

    float d[4][8][4];
#pragma unroll
    for (int i = 0; i < 4; i++)
#pragma unroll
        for (int j = 0; j < 8; j++)
#pragma unroll
            for (int c = 0; c < 4; c++) d[i][j][c] = 0.f;

    fetch(0, 0);  cp_commit();
    fetch(1, 32); cp_commit();
    fetch(2, 64); cp_commit();

    int lrow = lane & 7, selb = (lane >> 3) & 1, selc = lane >> 4;
    uint32_t aRow = (uint32_t)(wm + lrow + 8 * selb) * 64u;
    uint32_t aSw  = (uint32_t)((lrow >> 1) & 3);
    uint32_t bRow = (uint32_t)(lrow + 8 * selb) * 512u;
    uint32_t bCb  = (uint32_t)((wn >> 3) + selc);

    int KB = K >> 5;
    for (int it = 0; it < KB; ++it) {
        cp_wait<2>();
        __syncthreads();
        if (it + 3 < KB) fetch((it + 3) & 3, (it + 3) * 32);
        cp_commit();

        uint32_t As = sb + (uint32_t)(it & 3) * STGB;
        uint32_t Bs = As + 8192u;
#pragma unroll
        for (int kk = 0; kk < 2; kk++) {
            uint32_t a[4][4], b[8][2];
#pragma unroll
            for (int mt = 0; mt < 4; mt++) {
                uint32_t addr = As + aRow + (uint32_t)mt * 1024u
                              + ((((uint32_t)(2 * kk) + (uint32_t)selc) ^ aSw) * 16u);
                ldsm_x4(a[mt], addr);
            }
#pragma unroll
            for (int np = 0; np < 4; np++) {
                uint32_t q[4];
                uint32_t addr = Bs + bRow + (uint32_t)kk * 8192u
                              + (((bCb + 2u * np) ^ (uint32_t)lrow) * 16u);
                ldsm_x4_t(q, addr);
                b[2 * np][0]     = q[0]; b[2 * np][1]     = q[1];
                b[2 * np + 1][0] = q[2]; b[2 * np + 1][1] = q[3];
            }
#pragma unroll
            for (int mt = 0; mt < 4; mt++)
#pragma unroll
                for (int nt = 0; nt < 8; nt++)
                    mma_f16(d[mt][nt], a[mt], b[nt]);
        }
    }

#pragma unroll
    for (int mt = 0; mt < 4; mt++) {
        int r0 = m0 + wm + mt * 16 + gq;
        int r1 = r0 + 8;
        if (MODE == 2) {
            __half* Cb = (__half*)Cp + (size_t)e * sC;
#pragma unroll
            for (int nt = 0; nt < 8; nt++) {
                int c = n0 + wn + nt * 8 + 2 * tq;
                *(uint32_t*)(Cb + (size_t)r0 * N + c) =
                    h2_bits(fmaxf(d[mt][nt][0], 0.f), fmaxf(d[mt][nt][1], 0.f));
                *(uint32_t*)(Cb + (size_t)r1 * N + c) =
                    h2_bits(fmaxf(d[mt][nt][2], 0.f), fmaxf(d[mt][nt][3], 0.f));
            }
        } else {
            float* Cf = (float*)Cp + (size_t)e * sC;
            float g0 = 1.f, g1 = 1.f;
            if (MODE == 3) { g0 = gates[r0]; g1 = gates[r1]; }
#pragma unroll
            for (int nt = 0; nt < 8; nt++) {
                int c = n0 + wn + nt * 8 + 2 * tq;
                float2 u, w;
                u.x = d[mt][nt][0]; u.y = d[mt][nt][1];
                w.x = d[mt][nt][2]; w.y = d[mt][nt][3];
                if (MODE == 1) {
                    float2 ra = *(const float2*)(extra + (size_t)r0 * N + c);
                    float2 rb = *(const float2*)(extra + (size_t)r1 * N + c);
                    u.x += ra.x; u.y += ra.y;
                    w.x += rb.x; w.y += rb.y;
                }
                if (MODE == 3) {
                    u.x *= g0; u.y *= g0;
                    w.x *= g1; w.y *= g1;
                }
                *(float2*)(Cf + (size_t)r0 * N + c) = u;
                *(float2*)(Cf + (size_t)r1 * N + c) = w;
            }
        }
    }
}

// ---------------------------------------------------------------------------
// Exact capacity ranking. Slots [0, cnt_e) are filled densely, so etok needs
// no initialization; cnt tracks the live row count per expert.
// ---------------------------------------------------------------------------
__global__ void __launch_bounds__(256) rank_k(const float* __restrict__ fg,
                                              const int* __restrict__ fe,
                                              int* __restrict__ slot,
                                              int* __restrict__ etok,
                                              float* __restrict__ egate,
                                              int* __restrict__ cnt) {
    __shared__ float sg[NA];
    __shared__ unsigned char se[NA];
    for (int i = threadIdx.x; i < NA; i += 256) {
        sg[i] = fg[i];
        se[i] = (unsigned char)fe[i];
    }
    __syncthreads();
    int i = blockIdx.x * 256 + threadIdx.x;
    float gi = sg[i];
    unsigned char ei = se[i];
    int r = 0;
    for (int j = 0; j < NA; j++) {
        bool c = (se[j] == ei) && ((sg[j] > gi) || (sg[j] == gi && j < i));
        r += (int)c;
    }
    if (r < CAPn) {
        slot[i] = r;
        etok[(int)ei * CAPn + r] = i >> 1;
        egate[(int)ei * CAPn + r] = gi;
        atomicMax(&cnt[(int)ei], r + 1);
    } else {
        slot[i] = -1;
    }
}

// ---------------------------------------------------------------------------
// Gather expert inputs -> fp16 (rows >= cnt[e]: zeros)
// ---------------------------------------------------------------------------
__global__ void __launch_bounds__(256) xepack_k(const float* __restrict__ xn,
                                                const int* __restrict__ etok,
                                                const int* __restrict__ cnt,
                                                __half* __restrict__ xe) {
    int row = blockIdx.x;
    int e = row / CAPn, r = row - e * CAPn;
    int i = threadIdx.x;
    float4 v = make_float4(0.f, 0.f, 0.f, 0.f);
    if (r < cnt[e]) {
        int tok = etok[row];
        v = ((const float4*)(xn + (size_t)tok * Dm))[i];
    }
    ((uint2*)(xe + (size_t)row * Dm))[i] =
        make_uint2(h2_bits(v.x, v.y), h2_bits(v.z, v.w));
}

// ---------------------------------------------------------------------------
// Final combine
// ---------------------------------------------------------------------------
__global__ void __launch_bounds__(256) combine_k(const float* __restrict__ x1,
                                                 const float* __restrict__ ye,
                                                 const int* __restrict__ fe,
                                                 const int* __restrict__ slot,
                                                 float* __restrict__ out) {
    int t = blockIdx.x;
    int d = threadIdx.x;
    float4 v = ((const float4*)(x1 + (size_t)t * Dm))[d];
#pragma unroll
    for (int kk = 0; kk < 2; kk++) {
        int i = 2 * t + kk;
        int sl = slot[i];
        if (sl >= 0) {
            int e = fe[i];
            float4 w = ((const float4*)(ye + ((size_t)e * CAPn + sl) * Dm))[d];
            v.x += w.x; v.y += w.y; v.z += w.z; v.w += w.w;
        }
    }
    ((float4*)(out + (size_t)t * Dm))[d] = v;
}

// ---------------------------------------------------------------------------
// Launch (single stream)
// ---------------------------------------------------------------------------
extern "C" void kernel_launch(void* const* d_in, const int* in_sizes, int n_in,
                              void* d_out, int out_size) {
    (void)in_sizes; (void)n_in; (void)out_size;
    const float* x        = (const float*)d_in[0];
    const float* g1       = (const float*)d_in[1];
    const float* w_qkv    = (const float*)d_in[2];
    const float* w_o      = (const float*)d_in[3];
    const float* g2       = (const float*)d_in[4];
    const float* w_router = (const float*)d_in[5];
    const float* w1       = (const float*)d_in[6];
    const float* w2       = (const float*)d_in[7];
    float* out = (float*)d_out;

    float *p_xn, *p_qkv, *p_v, *p_x1, *p_cos, *p_sin;
    float *p_fg, *p_egate, *p_ye;
    __half *p_qh, *p_kh, *p_xnh, *p_attnh, *p_wqkvh, *p_woh, *p_w1h, *p_w2h, *p_xeh, *p_hh;
    int *p_fe, *p_slot, *p_etok, *p_cnt;
    cudaGetSymbolAddress((void**)&p_xn,    g_xn);
    cudaGetSymbolAddress((void**)&p_qkv,   g_qkv);
    cudaGetSymbolAddress((void**)&p_v,     g_v);
    cudaGetSymbolAddress((void**)&p_x1,    g_x1);
    cudaGetSymbolAddress((void**)&p_cos,   g_cos);
    cudaGetSymbolAddress((void**)&p_sin,   g_sin);
    cudaGetSymbolAddress((void**)&p_fg,    g_fg);
    cudaGetSymbolAddress((void**)&p_fe,    g_fe);
    cudaGetSymbolAddress((void**)&p_slot,  g_slot);
    cudaGetSymbolAddress((void**)&p_etok,  g_etok);
    cudaGetSymbolAddress((void**)&p_egate, g_egate);
    cudaGetSymbolAddress((void**)&p_cnt,   g_cnt);
    cudaGetSymbolAddress((void**)&p_ye,    g_ye);
    cudaGetSymbolAddress((void**)&p_qh,    g_qh);
    cudaGetSymbolAddress((void**)&p_kh,    g_kh);
    cudaGetSymbolAddress((void**)&p_xnh,   g_xnh);
    cudaGetSymbolAddress((void**)&p_attnh, g_attnh);
    cudaGetSymbolAddress((void**)&p_wqkvh, g_wqkvh);
    cudaGetSymbolAddress((void**)&p_woh,   g_woh);
    cudaGetSymbolAddress((void**)&p_w1h,   g_w1h);
    cudaGetSymbolAddress((void**)&p_w2h,   g_w2h);
    cudaGetSymbolAddress((void**)&p_xeh,   g_xeh);
    cudaGetSymbolAddress((void**)&p_hh,    g_hh);

    constexpr int H_SMEM    = 4 * 24576;              // fp16 gemm: 98304 bytes
    constexpr int ATTN_SMEM = 2 * (64 * 144 + 64 * 288);  // 55296 bytes
    cudaFuncSetAttribute(gemm_h_k<0, false>, cudaFuncAttributeMaxDynamicSharedMemorySize, H_SMEM);
    cudaFuncSetAttribute(gemm_h_k<1, false>, cudaFuncAttributeMaxDynamicSharedMemorySize, H_SMEM);
    cudaFuncSetAttribute(gemm_h_k<2, true>,  cudaFuncAttributeMaxDynamicSharedMemorySize, H_SMEM);
    cudaFuncSetAttribute(gemm_h_k<3, true>,  cudaFuncAttributeMaxDynamicSharedMemorySize, H_SMEM);
    cudaFuncSetAttribute(attn_tc_k, cudaFuncAttributeMaxDynamicSharedMemorySize, ATTN_SMEM);

    // Fused precompute: fp16 weight conversions + rope table in ONE launch
    prep_k<<<1184, 256>>>(w_qkv, p_wqkvh, w_o, p_woh,
                          w1, p_w1h, w2, p_w2h, p_cos, p_sin);

    // Attention branch
    rmsnorm_k<<<Tn, 256>>>(x, g1, p_xnh);
    gemm_h_k<0, false><<<dim3(3 * Dm / 256, Tn / 128, 1), 256, H_SMEM>>>(
        p_xnh, p_wqkvh, p_qkv, 3 * Dm, Dm, nullptr, nullptr, 0, 0, 0, 0);
    split_rope_k<<<Tn, 256>>>(p_qkv, p_cos, p_sin, p_qh, p_kh, p_v);
    attn_tc_k<<<dim3(Sq / 128, Hn, Bz), 256, ATTN_SMEM>>>(p_qh, p_kh, p_v, p_attnh);
    gemm_h_k<1, false><<<dim3(Dm / 256, Tn / 128, 1), 256, H_SMEM>>>(
        p_attnh, p_woh, p_x1, Dm, Dm, x, nullptr, 0, 0, 0, 0);

    // Fused rmsnorm2 + routing (fp32 exact)
    rmsrouter_k<<<Tn, 256>>>(p_x1, g2, w_router, p_xn, p_fg, p_fe, p_cnt);
    rank_k<<<NA / 256, 256>>>(p_fg, p_fe, p_slot, p_etok, p_egate, p_cnt);
    xepack_k<<<En * CAPn, 256>>>(p_xn, p_etok, p_cnt, p_xeh);

    // MoE expert GEMMs (fp16 tensor cores; dead capacity tiles early-exit)
    gemm_h_k<2, true><<<dim3(FFNm / 256, CAPn / 128, En), 256, H_SMEM>>>(
        p_xeh, p_w1h, p_hh, FFNm, Dm, nullptr, p_cnt,
        (long)CAPn * Dm, (long)Dm * FFNm, (long)CAPn * FFNm, 0);
    gemm_h_k<3, true><<<dim3(Dm / 256, CAPn / 128, En), 256, H_SMEM>>>(
        p_hh, p_w2h, p_ye, Dm, FFNm, p_egate, p_cnt,
        (long)CAPn * FFNm, (long)FFNm * Dm, (long)CAPn * Dm, CAPn);

    // out = x1 + moe
    combine_k<<<Tn, 256>>>(p_x1, p_ye, p_fe, p_slot, out);
}

// round 13
// speedup vs baseline: 6.1690x; 1.0287x over previous
#include <cuda_runtime.h>
#include <cuda_fp16.h>
#include <math.h>
#include <stdint.h>

// ---------------------------------------------------------------------------
// Problem constants
// ---------------------------------------------------------------------------
namespace {
constexpr int Bz   = 2;
constexpr int Sq   = 2048;
constexpr int Dm   = 1024;
constexpr int Hn   = 16;
constexpr int HDm  = 64;
constexpr int FFNm = 2048;
constexpr int En   = 8;
constexpr int Tn   = Bz * Sq;     // 4096 tokens
constexpr int NA   = Tn * 2;      // 8192 flat assignments (top-2)
constexpr int CAPn = 1280;        // ceil(2*2048*2*1.25/8)
// prep_k region sizes (float4 units except rope)
constexpr int NQ4  = Dm * 3 * Dm / 4;        // 786432
constexpr int NO4  = Dm * Dm / 4;            // 262144
constexpr int NW14 = En * Dm * FFNm / 4;     // 4194304
constexpr int NW24 = En * FFNm * Dm / 4;     // 4194304
constexpr int NRP  = Sq * (HDm / 2);         // 65536
}

// ---------------------------------------------------------------------------
// Static scratch (no allocations allowed)
// ---------------------------------------------------------------------------
__device__ float g_xn  [Tn * Dm];           // rmsnorm2 out (fp32, xepack path)
__device__ float g_qkv [Tn * 3 * Dm];
__device__ float g_x1  [Tn * Dm];
__device__ float g_cos [Sq * (HDm / 2)];
__device__ float g_sin [Sq * (HDm / 2)];
__device__ float g_fg  [NA];
__device__ int   g_fe  [NA];
__device__ int   g_slot[NA];
__device__ int   g_etok [En * CAPn];
__device__ float g_egate[En * CAPn];
__device__ int   g_cnt  [En];               // live rows per expert
__device__ float g_ye[En * CAPn * Dm];
// fp16 data
__device__ __half g_qh   [Tn * Dm];         // rope'd Q, pre-scaled 1/8
__device__ __half g_kh   [Tn * Dm];         // rope'd K
__device__ __half g_vh   [Tn * Dm];         // V
__device__ __half g_xnh  [Tn * Dm];         // rmsnorm1 out (qkv GEMM A)
__device__ __half g_attnh[Tn * Dm];         // attention out (o GEMM A)
__device__ __half g_wqkvh[Dm * 3 * Dm];
__device__ __half g_woh  [Dm * Dm];
__device__ __half g_w1h  [En * Dm * FFNm];
__device__ __half g_w2h  [En * FFNm * Dm];
__device__ __half g_xeh  [En * CAPn * Dm];
__device__ __half g_hh   [En * CAPn * FFNm];

// ---------------------------------------------------------------------------
// Helpers
// ---------------------------------------------------------------------------
__device__ __forceinline__ uint32_t smem_u32(const void* p) {
    uint32_t a;
    asm("{ .reg .u64 t; cvta.to.shared.u64 t, %1; cvt.u32.u64 %0, t; }"
        : "=r"(a) : "l"(p));
    return a;
}

__device__ __forceinline__ void cpasync16(uint32_t dst, const void* src) {
    asm volatile("cp.async.cg.shared.global [%0], [%1], 16;" :: "r"(dst), "l"(src));
}
__device__ __forceinline__ void cp_commit() {
    asm volatile("cp.async.commit_group;" ::: "memory");
}
template <int N>
__device__ __forceinline__ void cp_wait() {
    asm volatile("cp.async.wait_group %0;" :: "n"(N) : "memory");
}

// fp16 m16n8k16 MMA, fp32 accumulate
__device__ __forceinline__ void mma_f16(float* d, const uint32_t* a, const uint32_t* b) {
    asm volatile(
        "mma.sync.aligned.m16n8k16.row.col.f32.f16.f16.f32 "
        "{%0,%1,%2,%3}, {%4,%5,%6,%7}, {%8,%9}, {%0,%1,%2,%3};"
        : "+f"(d[0]), "+f"(d[1]), "+f"(d[2]), "+f"(d[3])
        : "r"(a[0]), "r"(a[1]), "r"(a[2]), "r"(a[3]), "r"(b[0]), "r"(b[1]));
}

__device__ __forceinline__ void ldsm_x4(uint32_t* r, uint32_t addr) {
    asm volatile("ldmatrix.sync.aligned.m8n8.x4.shared.b16 {%0,%1,%2,%3}, [%4];"
                 : "=r"(r[0]), "=r"(r[1]), "=r"(r[2]), "=r"(r[3]) : "r"(addr));
}
__device__ __forceinline__ void ldsm_x4_t(uint32_t* r, uint32_t addr) {
    asm volatile("ldmatrix.sync.aligned.m8n8.x4.trans.shared.b16 {%0,%1,%2,%3}, [%4];"
                 : "=r"(r[0]), "=r"(r[1]), "=r"(r[2]), "=r"(r[3]) : "r"(addr));
}

// 2^x for x <= 0, FMA-pipe only.
__device__ __forceinline__ float exp2p(float x) {
    float t = fmaxf(x, -126.f);
    float z = t + 12582912.f;
    float n = z - 12582912.f;
    float f = t - n;
    float p =         1.5353e-4f;
    p = fmaf(p, f, 1.3398886e-3f);
    p = fmaf(p, f, 9.6184372e-3f);
    p = fmaf(p, f, 5.5503327e-2f);
    p = fmaf(p, f, 2.4022648e-1f);
    p = fmaf(p, f, 6.9314718e-1f);
    p = fmaf(p, f, 1.0f);
    int iz = __float_as_int(z) - 0x4B400000;
    return p * __int_as_float((iz + 127) << 23);
}

__device__ __forceinline__ uint32_t h2_bits(float a, float b) {
    __half2 h = __float22half2_rn(make_float2(a, b));
    return *(uint32_t*)&h;
}

// ---------------------------------------------------------------------------
// Fused prep: fp16-convert all four weight tensors + rope table. One launch.
// ---------------------------------------------------------------------------
__global__ void prep_k(const float* __restrict__ wqkv, __half* __restrict__ wqkvh,
                       const float* __restrict__ wo,   __half* __restrict__ woh,
                       const float* __restrict__ w1,   __half* __restrict__ w1h,
                       const float* __restrict__ w2,   __half* __restrict__ w2h,
                       float* __restrict__ ct, float* __restrict__ st) {
    const int total = NQ4 + NO4 + NW14 + NW24 + NRP;
    int stride = gridDim.x * blockDim.x;
    for (int i = blockIdx.x * blockDim.x + threadIdx.x; i < total; i += stride) {
        int r = i;
        if (r < NQ4) {
            float4 v = ((const float4*)wqkv)[r];
            ((uint2*)wqkvh)[r] = make_uint2(h2_bits(v.x, v.y), h2_bits(v.z, v.w));
            continue;
        }
        r -= NQ4;
        if (r < NO4) {
            float4 v = ((const float4*)wo)[r];
            ((uint2*)woh)[r] = make_uint2(h2_bits(v.x, v.y), h2_bits(v.z, v.w));
            continue;
        }
        r -= NO4;
        if (r < NW14) {
            float4 v = ((const float4*)w1)[r];
            ((uint2*)w1h)[r] = make_uint2(h2_bits(v.x, v.y), h2_bits(v.z, v.w));
            continue;
        }
        r -= NW14;
        if (r < NW24) {
            float4 v = ((const float4*)w2)[r];
            ((uint2*)w2h)[r] = make_uint2(h2_bits(v.x, v.y), h2_bits(v.z, v.w));
            continue;
        }
        r -= NW24;
        {
            int s = r >> 5, j = r & 31;
            float th = (float)pow(10000.0, -2.0 * (double)j / (double)HDm);
            double f = (double)s * (double)th;
            ct[r] = (float)cos(f);
            st[r] = (float)sin(f);
        }
    }
}

// ---------------------------------------------------------------------------
// RMSNorm (fp16 out; feeds qkv GEMM)
// ---------------------------------------------------------------------------
__global__ void __launch_bounds__(256) rmsnorm_k(const float* __restrict__ x,
                                                 const float* __restrict__ g,
                                                 __half* __restrict__ y) {
    int row = blockIdx.x;
    int i = threadIdx.x;
    const float4* xr = (const float4*)(x + (size_t)row * Dm);
    float4 xv = xr[i];
    float ss = xv.x * xv.x + xv.y * xv.y + xv.z * xv.z + xv.w * xv.w;
#pragma unroll
    for (int off = 16; off; off >>= 1) ss += __shfl_down_sync(0xffffffffu, ss, off);
    __shared__ float red[8];
    __shared__ float srms;
    if ((i & 31) == 0) red[i >> 5] = ss;
    __syncthreads();
    if (i == 0) {
        float t = 0.f;
#pragma unroll
        for (int w = 0; w < 8; w++) t += red[w];
        srms = rsqrtf(t * (1.0f / Dm) + 1e-6f);
    }
    __syncthreads();
    float r = srms;
    float4 gv = ((const float4*)g)[i];
    ((uint2*)(y + (size_t)row * Dm))[i] =
        make_uint2(h2_bits(gv.x * xv.x * r, gv.y * xv.y * r),
                   h2_bits(gv.z * xv.z * r, gv.w * xv.w * r));
}

// ---------------------------------------------------------------------------
// Fused RMSNorm2 + router: norm -> xn (fp32), 8 logits, softmax, top-2.
// ---------------------------------------------------------------------------
__global__ void __launch_bounds__(256) rmsrouter_k(const float* __restrict__ x,
                                                   const float* __restrict__ g,
                                                   const float* __restrict__ wr,
                                                   float* __restrict__ xn,
                                                   float* __restrict__ fg,
                                                   int* __restrict__ fe,
                                                   int* __restrict__ cnt) {
    int row = blockIdx.x;
    int i = threadIdx.x;
    if (row == 0 && i < En) cnt[i] = 0;
    const float4* xr = (const float4*)(x + (size_t)row * Dm);
    float4 xv = xr[i];
    float ss = xv.x * xv.x + xv.y * xv.y + xv.z * xv.z + xv.w * xv.w;
#pragma unroll
    for (int off = 16; off; off >>= 1) ss += __shfl_down_sync(0xffffffffu, ss, off);
    __shared__ float red[8];
    __shared__ float srms;
    if ((i & 31) == 0) red[i >> 5] = ss;
    __syncthreads();
    if (i == 0) {
        float t = 0.f;
#pragma unroll
        for (int w = 0; w < 8; w++) t += red[w];
        srms = rsqrtf(t * (1.0f / Dm) + 1e-6f);
    }
    __syncthreads();
    float r = srms;
    float4 gv = ((const float4*)g)[i];
    float o[4];
    o[0] = gv.x * xv.x * r; o[1] = gv.y * xv.y * r;
    o[2] = gv.z * xv.z * r; o[3] = gv.w * xv.w * r;
    float4 ov;
    ov.x = o[0]; ov.y = o[1]; ov.z = o[2]; ov.w = o[3];
    ((float4*)(xn + (size_t)row * Dm))[i] = ov;

    float acc[8];
#pragma unroll
    for (int e = 0; e < 8; e++) acc[e] = 0.f;
#pragma unroll
    for (int c = 0; c < 4; c++) {
        const float4* w = (const float4*)(wr + (size_t)(4 * i + c) * En);
        float4 w0 = w[0], w1 = w[1];
        acc[0] = fmaf(o[c], w0.x, acc[0]); acc[1] = fmaf(o[c], w0.y, acc[1]);
        acc[2] = fmaf(o[c], w0.z, acc[2]); acc[3] = fmaf(o[c], w0.w, acc[3]);
        acc[4] = fmaf(o[c], w1.x, acc[4]); acc[5] = fmaf(o[c], w1.y, acc[5]);
        acc[6] = fmaf(o[c], w1.z, acc[6]); acc[7] = fmaf(o[c], w1.w, acc[7]);
    }
#pragma unroll
    for (int e = 0; e < 8; e++)
#pragma unroll
        for (int off = 16; off; off >>= 1)
            acc[e] += __shfl_down_sync(0xffffffffu, acc[e], off);
    __shared__ float lred[8][8];
    if ((i & 31) == 0)
#pragma unroll
        for (int e = 0; e < 8; e++) lred[i >> 5][e] = acc[e];
    __syncthreads();
    if (i == 0) {
        float p[8];
#pragma unroll
        for (int e = 0; e < 8; e++) {
            float s = 0.f;
#pragma unroll
            for (int w = 0; w < 8; w++) s += lred[w][e];
            p[e] = s;
        }
        float mx = p[0];
#pragma unroll
        for (int e = 1; e < 8; e++) mx = fmaxf(mx, p[e]);
        float sum = 0.f;
#pragma unroll
        for (int e = 0; e < 8; e++) { p[e] = expf(p[e] - mx); sum += p[e]; }
        float inv = 1.f / sum;
#pragma unroll
        for (int e = 0; e < 8; e++) p[e] *= inv;
        int e0 = 0; float p0 = p[0];
#pragma unroll
        for (int e = 1; e < 8; e++) if (p[e] > p0) { p0 = p[e]; e0 = e; }
        int e1 = -1; float p1 = -1.f;
#pragma unroll
        for (int e = 0; e < 8; e++)
            if (e != e0 && p[e] > p1) { p1 = p[e]; e1 = e; }
        fg[2 * row]     = p0; fe[2 * row]     = e0;
        fg[2 * row + 1] = p1; fe[2 * row + 1] = e1;
    }
}

// ---------------------------------------------------------------------------
// Split QKV + RoPE: q (pre-scaled 1/8), k, v all fp16.
// ---------------------------------------------------------------------------
__global__ void __launch_bounds__(256) split_rope_k(const float* __restrict__ qkv,
                                                    const float* __restrict__ ct,
                                                    const float* __restrict__ st,
                                                    __half* __restrict__ q,
                                                    __half* __restrict__ k,
                                                    __half* __restrict__ v) {
    int t = blockIdx.x;
    int b = t / Sq, s = t % Sq;
    const float* row = qkv + (size_t)t * (3 * Dm);
    for (int idx = threadIdx.x; idx < Hn * (HDm / 2); idx += blockDim.x) {
        int h = idx >> 5, j = idx & 31;
        float c = ct[s * 32 + j], sn = st[s * 32 + j];
        size_t o = ((size_t)(b * Hn + h) * Sq + s) * HDm;
        float qr = row[h * HDm + 2 * j], qi = row[h * HDm + 2 * j + 1];
        *(uint32_t*)(q + o + 2 * j) =
            h2_bits((qr * c - qi * sn) * 0.125f, (qr * sn + qi * c) * 0.125f);
        float kr = row[Dm + h * HDm + 2 * j], ki = row[Dm + h * HDm + 2 * j + 1];
        *(uint32_t*)(k + o + 2 * j) =
            h2_bits(kr * c - ki * sn, kr * sn + ki * c);
    }
    for (int idx = threadIdx.x; idx < Dm / 2; idx += blockDim.x) {
        int d2 = 2 * idx;
        int h = d2 >> 6, d = d2 & 63;
        *(uint32_t*)(v + ((size_t)(b * Hn + h) * Sq + s) * HDm + d) =
            h2_bits(row[2 * Dm + d2], row[2 * Dm + d2 + 1]);
    }
}

// ---------------------------------------------------------------------------
// Tensor-core causal flash attention, all-fp16 MMAs.
// QK^T: fp16 (K smem stride 72 halves). PV: fp16, P re-fragmented directly
// from the S accumulator layout (C frag == A frag for m16n8k16 — no shfl),
// V fp16 in smem with the same ldsm_x4_t pattern as the GEMM B tiles.
// ---------------------------------------------------------------------------
__global__ void __launch_bounds__(256) attn_tc_k(const __half* __restrict__ Q,
                                                 const __half* __restrict__ Kt,
                                                 const __half* __restrict__ Vt,
                                                 __half* __restrict__ Out) {
    extern __shared__ __align__(16) char smc[];
    constexpr float LOG2E = 1.4426950408889634f;
    constexpr int KBYTES = 64 * 144;            // 9216
    constexpr int STGB = KBYTES + 64 * 128;     // + V 8192 = 17408

    int bx = blockIdx.x, h = blockIdx.y, b = blockIdx.z;
    int qt = bx * 128;
    int tid = threadIdx.x, warp = tid >> 5, lane = tid & 31;
    int gq = lane >> 2, tq = lane & 3;
    int wq = qt + warp * 16;
    const size_t base = ((size_t)(b * Hn + h)) * Sq * HDm;
    const __half* Qg = Q + base;
    const __half* Kg = Kt + base;
    const __half* Vg = Vt + base;

    const uint32_t sb = smem_u32(smc);

    uint32_t qf[4][4];
#pragma unroll
    for (int kk = 0; kk < 4; kk++) {
        const __half* q0 = Qg + (size_t)(wq + gq) * 64 + kk * 16 + 2 * tq;
        const __half* q1 = Qg + (size_t)(wq + gq + 8) * 64 + kk * 16 + 2 * tq;
        qf[kk][0] = *(const uint32_t*)q0;
        qf[kk][1] = *(const uint32_t*)q1;
        qf[kk][2] = *(const uint32_t*)(q0 + 8);
        qf[kk][3] = *(const uint32_t*)(q1 + 8);
    }

    float O[8][4];
#pragma unroll
    for (int nt = 0; nt < 8; nt++)
#pragma unroll
        for (int c = 0; c < 4; c++) O[nt][c] = 0.f;
    float m0 = -1e30f, m1 = -1e30f, l0 = 0.f, l1 = 0.f;

    int fr = tid >> 2;                 // row 0..63
    int fc = tid & 3;
    auto fill = [&](int stage, int kt) {
        // K: 144B rows, 2 chunks/thread
        uint32_t kDst = sb + (uint32_t)(stage * STGB + fr * 144 + fc * 32);
        const __half* ks = Kg + (size_t)(kt + fr) * 64 + fc * 16;
        cpasync16(kDst, ks);
        cpasync16(kDst + 16u, ks + 8);
        // V: 128B rows, chunk-swizzled (c ^ (row & 7)), 2 chunks/thread
        uint32_t vBase = sb + (uint32_t)(stage * STGB + KBYTES + fr * 128);
        const __half* vs = Vg + (size_t)(kt + fr) * 64;
        uint32_t sw = (uint32_t)(fr & 7);
#pragma unroll
        for (int j = 0; j < 2; j++) {
            uint32_t c = (uint32_t)(fc * 2 + j);
            cpasync16(vBase + ((c ^ sw) * 16u), vs + c * 8);
        }
    };

    int ntiles = 2 * bx + 2;
    fill(0, 0);
    cp_commit();

    int lrow = lane & 7, selb = (lane >> 3) & 1, selc = lane >> 4;

    for (int it = 0; it < ntiles; it++) {
        if (it + 1 < ntiles) fill((it + 1) & 1, (it + 1) * 64);
        cp_commit();
        cp_wait<1>();
        __syncthreads();

        int kt = it * 64;
        if (kt <= wq + 15) {
            const __half* Ks = (const __half*)(smc + (it & 1) * STGB);
            const uint32_t Vsb = sb + (uint32_t)((it & 1) * STGB + KBYTES);

            // ---- S = Q K^T (fp16 MMA) ----
            float s[8][4];
#pragma unroll
            for (int nt = 0; nt < 8; nt++)
#pragma unroll
                for (int c = 0; c < 4; c++) s[nt][c] = 0.f;
#pragma unroll
            for (int kk = 0; kk < 4; kk++) {
                uint32_t bf[8][2];
#pragma unroll
                for (int nt = 0; nt < 8; nt++) {
                    const __half* kr = Ks + (nt * 8 + gq) * 72 + kk * 16 + 2 * tq;
                    bf[nt][0] = *(const uint32_t*)kr;
                    bf[nt][1] = *(const uint32_t*)(kr + 8);
                }
#pragma unroll
                for (int nt = 0; nt < 8; nt++) mma_f16(s[nt], qf[kk], bf[nt]);
            }

            if (kt + 63 > wq) {
                int r0 = wq + gq, r1 = wq + gq + 8;
#pragma unroll
                for (int nt = 0; nt < 8; nt++) {
                    int c0 = kt + nt * 8 + 2 * tq;
                    if (c0 > r0)     s[nt][0] = -3.4e38f;
                    if (c0 + 1 > r0) s[nt][1] = -3.4e38f;
                    if (c0 > r1)     s[nt][2] = -3.4e38f;
                    if (c0 + 1 > r1) s[nt][3] = -3.4e38f;
                }
            }

            float mx0 = -3.4e38f, mx1 = -3.4e38f;
#pragma unroll
            for (int nt = 0; nt < 8; nt++) {
                mx0 = fmaxf(mx0, fmaxf(s[nt][0], s[nt][1]));
                mx1 = fmaxf(mx1, fmaxf(s[nt][2], s[nt][3]));
            }
            mx0 = fmaxf(mx0, __shfl_xor_sync(0xffffffffu, mx0, 1));
            mx0 = fmaxf(mx0, __shfl_xor_sync(0xffffffffu, mx0, 2));
            mx1 = fmaxf(mx1, __shfl_xor_sync(0xffffffffu, mx1, 1));
            mx1 = fmaxf(mx1, __shfl_xor_sync(0xffffffffu, mx1, 2));
            float mn0 = fmaxf(m0, mx0), mn1 = fmaxf(m1, mx1);
            float cr0 = exp2p((m0 - mn0) * LOG2E);
            float cr1 = exp2p((m1 - mn1) * LOG2E);
            float nm0 = mn0 * LOG2E, nm1 = mn1 * LOG2E;

            float sum0 = 0.f, sum1 = 0.f;
#pragma unroll
            for (int nt = 0; nt < 8; nt++) {
                float p0 = exp2p(fmaf(s[nt][0], LOG2E, -nm0));
                float p1 = exp2p(fmaf(s[nt][1], LOG2E, -nm0));
                float p2 = exp2p(fmaf(s[nt][2], LOG2E, -nm1));
                float p3 = exp2p(fmaf(s[nt][3], LOG2E, -nm1));
                s[nt][0] = p0; s[nt][1] = p1; s[nt][2] = p2; s[nt][3] = p3;
                sum0 += p0 + p1; sum1 += p2 + p3;
            }
            sum0 += __shfl_xor_sync(0xffffffffu, sum0, 1);
            sum0 += __shfl_xor_sync(0xffffffffu, sum0, 2);
            sum1 += __shfl_xor_sync(0xffffffffu, sum1, 1);
            sum1 += __shfl_xor_sync(0xffffffffu, sum1, 2);
            l0 = l0 * cr0 + sum0;
            l1 = l1 * cr1 + sum1;
#pragma unroll
            for (int nt = 0; nt < 8; nt++) {
                O[nt][0] *= cr0; O[nt][1] *= cr0;
                O[nt][2] *= cr1; O[nt][3] *= cr1;
            }
            m0 = mn0; m1 = mn1;

            // ---- O += P V (fp16 MMA; C frag -> A frag direct, no shfl) ----
#pragma unroll
            for (int kk = 0; kk < 4; kk++) {
                uint32_t a[4];
                a[0] = h2_bits(s[2 * kk][0],     s[2 * kk][1]);
                a[1] = h2_bits(s[2 * kk][2],     s[2 * kk][3]);
                a[2] = h2_bits(s[2 * kk + 1][0], s[2 * kk + 1][1]);
                a[3] = h2_bits(s[2 * kk + 1][2], s[2 * kk + 1][3]);
                uint32_t bvv[8][2];
#pragma unroll
                for (int np = 0; np < 4; np++) {
                    uint32_t qd[4];
                    uint32_t addr = Vsb + (uint32_t)((lrow + 8 * selb) * 128)
                                  + (uint32_t)(kk * 2048)
                                  + ((((uint32_t)(selc + 2 * np)) ^ (uint32_t)lrow) * 16u);
                    ldsm_x4_t(qd, addr);
                    bvv[2 * np][0]     = qd[0]; bvv[2 * np][1]     = qd[1];
                    bvv[2 * np + 1][0] = qd[2]; bvv[2 * np + 1][1] = qd[3];
                }
#pragma unroll
                for (int nt = 0; nt < 8; nt++) mma_f16(O[nt], a, bvv[nt]);
            }
        }
        __syncthreads();
    }

    float i0 = 1.f / l0, i1 = 1.f / l1;
    int r0 = wq + gq, r1 = wq + gq + 8;
    __half* o0 = Out + ((size_t)(b * Sq + r0)) * Dm + h * 64 + 2 * tq;
    __half* o1 = Out + ((size_t)(b * Sq + r1)) * Dm + h * 64 + 2 * tq;
#pragma unroll
    for (int nt = 0; nt < 8; nt++) {
        *(uint32_t*)(o0 + nt * 8) = h2_bits(O[nt][0] * i0, O[nt][1] * i0);
        *(uint32_t*)(o1 + nt * 8) = h2_bits(O[nt][2] * i1, O[nt][3] * i1);
    }
}

// ---------------------------------------------------------------------------
// fp16 tensor-core GEMM: CTA 128xNT (NT=256 or 128), 8 warps, BK=32,
// 4-stage cp.async, ldmatrix, m16n8k16.f16, ONE barrier/iter.
// MODE 0: C(f32)=A@B  1: +resid  2: C(f16)=relu  3: C(f32)=*gates[row]
// SKIP: early-exit CTAs whose M-tile is past cnt[e].
// ---------------------------------------------------------------------------
template <int MODE, bool SKIP, int NT>
__global__ void __launch_bounds__(256, 1)
gemm_h_k(const __half* __restrict__ A, const __half* __restrict__ Bm,
         void* __restrict__ Cp, int N, int K,
         const float* __restrict__ extra, const int* __restrict__ cnt,
         long sA, long sB, long sC, int gstride) {
    extern __shared__ __align__(16) float smf[];
    const uint32_t sb = smem_u32(smf);
    constexpr int NTW  = NT / 32;        // n-tiles per warp (8 or 4)
    constexpr int CPT  = NT / 64;        // B fill chunks per thread (4 or 2)
    constexpr uint32_t BROW = NT * 2;    // B smem row bytes
    constexpr uint32_t STGB = 8192u + 32u * BROW;

    int e = blockIdx.z;
    int m0 = blockIdx.y * 128, n0 = blockIdx.x * NT;
    if (SKIP && m0 >= cnt[e]) return;

    int tid = threadIdx.x, warp = tid >> 5, lane = tid & 31;
    int gq = lane >> 2, tq = lane & 3;
    A  += (size_t)e * sA;
    Bm += (size_t)e * sB;
    const float* gates = extra;
    if (MODE == 3) gates += (size_t)e * gstride;

    int wm = (warp & 1) * 64, wn = (warp >> 1) * (NT / 4);

    int ar = tid >> 1, ah = tid & 1;
    int br2 = tid >> 3, bc0 = (tid & 7) * CPT;
    const __half* aSrc = A + (size_t)(m0 + ar) * K + ah * 16;
    const __half* bSrc = Bm + (size_t)br2 * N + n0 + bc0 * 8;
    uint32_t aS = (ar >> 1) & 3;
    uint32_t aBase = sb + (uint32_t)ar * 64u;
    uint32_t bBase = sb + 8192u + (uint32_t)br2 * BROW;

    auto fetch = [&](int stage, int k0) {
        uint32_t so = (uint32_t)stage * STGB;
        const __half* as = aSrc + k0;
        uint32_t c0 = 2u * ah;
        cpasync16(aBase + so + ((c0 ^ aS) * 16u), as);
        cpasync16(aBase + so + (((c0 + 1) ^ aS) * 16u), as + 8);
        const __half* bs = bSrc + (size_t)k0 * N;
#pragma unroll
        for (int j = 0; j < CPT; j++) {
            uint32_t c = (uint32_t)(bc0 + j);
            cpasync16(bBase + so + ((c ^ (uint32_t)(br2 & 7)) * 16u), bs + j * 8);
        }
    };

    float d[4][NTW][4];
#pragma unroll
    for (int i = 0; i < 4; i++)
#pragma unroll
        for (int j = 0; j < NTW; j++)
#pragma unroll
            for (int c = 0; c < 4; c++) d[i][j][c] = 0.f;

    fetch(0, 0);  cp_commit();
    fetch(1, 32); cp_commit();
    fetch(2, 64); cp_commit();

    int lrow = lane & 7, selb = (lane >> 3) & 1, selc = lane >> 4;
    uint32_t aRow = (uint32_t)(wm + lrow + 8 * selb) * 64u;
    uint32_t aSw  = (uint32_t)((lrow >> 1) & 3);
    uint32_t bRow = (uint32_t)(lrow + 8 * selb) * BROW;
    uint32_t bCb  = (uint32_t)((wn >> 3) + selc);

    int KB = K >> 5;
    for (int it = 0; it < KB; ++it) {
        cp_wait<2>();
        __syncthreads();
        if (it + 3 < KB) fetch((it + 3) & 3, (it + 3) * 32);
        cp_commit();

        uint32_t As = sb + (uint32_t)(it & 3) * STGB;
        uint32_t Bs = As + 8192u;
#pragma unroll
        for (int kk = 0; kk < 2; kk++) {
            uint32_t a[4][4], b[NTW][2];
#pragma unroll
            for (int mt = 0; mt < 4; mt++) {
                uint32_t addr = As + aRow + (uint32_t)mt * 1024u
                              + ((((uint32_t)(2 * kk) + (uint32_t)selc) ^ aSw) * 16u);
                ldsm_x4(a[mt], addr);
            }
#pragma unroll
            for (int np = 0; np < NTW / 2; np++) {
                uint32_t q[4];
                uint32_t addr = Bs + bRow + (uint32_t)kk * 16u * BROW
                              + (((bCb + 2u * np) ^ (uint32_t)lrow) * 16u);
                ldsm_x4_t(q, addr);
                b[2 * np][0]     = q[0]; b[2 * np][1]     = q[1];
                b[2 * np + 1][0] = q[2]; b[2 * np + 1][1] = q[3];
            }
#pragma unroll
            for (int mt = 0; mt < 4; mt++)
#pragma unroll
                for (int nt = 0; nt < NTW; nt++)
                    mma_f16(d[mt][nt], a[mt], b[nt]);
        }
    }

#pragma unroll
    for (int mt = 0; mt < 4; mt++) {
        int r0 = m0 + wm + mt * 16 + gq;
        int r1 = r0 + 8;
        if (MODE == 2) {
            __half* Cb = (__half*)Cp + (size_t)e * sC;
#pragma unroll
            for (int nt = 0; nt < NTW; nt++) {
                int c = n0 + wn + nt * 8 + 2 * tq;
                *(uint32_t*)(Cb + (size_t)r0 * N + c) =
                    h2_bits(fmaxf(d[mt][nt][0], 0.f), fmaxf(d[mt][nt][1], 0.f));
                *(uint32_t*)(Cb + (size_t)r1 * N + c) =
                    h2_bits(fmaxf(d[mt][nt][2], 0.f), fmaxf(d[mt][nt][3], 0.f));
            }
        } else {
            float* Cf = (float*)Cp + (size_t)e * sC;
            float g0 = 1.f, g1 = 1.f;
            if (MODE == 3) { g0 = gates[r0]; g1 = gates[r1]; }
#pragma unroll
            for (int nt = 0; nt < NTW; nt++) {
                int c = n0 + wn + nt * 8 + 2 * tq;
                float2 u, w;
                u.x = d[mt][nt][0]; u.y = d[mt][nt][1];
                w.x = d[mt][nt][2]; w.y = d[mt][nt][3];
                if (MODE == 1) {
                    float2 ra = *(const float2*)(extra + (size_t)r0 * N + c);
                    float2 rb = *(const float2*)(extra + (size_t)r1 * N + c);
                    u.x += ra.x; u.y += ra.y;
                    w.x += rb.x; w.y += rb.y;
                }
                if (MODE == 3) {
                    u.x *= g0; u.y *= g0;
                    w.x *= g1; w.y *= g1;
                }
                *(float2*)(Cf + (size_t)r0 * N + c) = u;
                *(float2*)(Cf + (size_t)r1 * N + c) = w;
            }
        }
    }
}

// ---------------------------------------------------------------------------
// Exact capacity ranking.
// ---------------------------------------------------------------------------
__global__ void __launch_bounds__(256) rank_k(const float* __restrict__ fg,
                                              const int* __restrict__ fe,
                                              int* __restrict__ slot,
                                              int* __restrict__ etok,
                                              float* __restrict__ egate,
                                              int* __restrict__ cnt) {
    __shared__ float sg[NA];
    __shared__ unsigned char se[NA];
    for (int i = threadIdx.x; i < NA; i += 256) {
        sg[i] = fg[i];
        se[i] = (unsigned char)fe[i];
    }
    __syncthreads();
    int i = blockIdx.x * 256 + threadIdx.x;
    float gi = sg[i];
    unsigned char ei = se[i];
    int r = 0;
    for (int j = 0; j < NA; j++) {
        bool c = (se[j] == ei) && ((sg[j] > gi) || (sg[j] == gi && j < i));
        r += (int)c;
    }
    if (r < CAPn) {
        slot[i] = r;
        etok[(int)ei * CAPn + r] = i >> 1;
        egate[(int)ei * CAPn + r] = gi;
        atomicMax(&cnt[(int)ei], r + 1);
    } else {
        slot[i] = -1;
    }
}

// ---------------------------------------------------------------------------
// Gather expert inputs -> fp16 (rows >= cnt[e]: zeros)
// ---------------------------------------------------------------------------
__global__ void __launch_bounds__(256) xepack_k(const float* __restrict__ xn,
                                                const int* __restrict__ etok,
                                                const int* __restrict__ cnt,
                                                __half* __restrict__ xe) {
    int row = blockIdx.x;
    int e = row / CAPn, r = row - e * CAPn;
    int i = threadIdx.x;
    float4 v = make_float4(0.f, 0.f, 0.f, 0.f);
    if (r < cnt[e]) {
        int tok = etok[row];
        v = ((const float4*)(xn + (size_t)tok * Dm))[i];
    }
    ((uint2*)(xe + (size_t)row * Dm))[i] =
        make_uint2(h2_bits(v.x, v.y), h2_bits(v.z, v.w));
}

// ---------------------------------------------------------------------------
// Final combine
// ---------------------------------------------------------------------------
__global__ void __launch_bounds__(256) combine_k(const float* __restrict__ x1,
                                                 const float* __restrict__ ye,
                                                 const int* __restrict__ fe,
                                                 const int* __restrict__ slot,
                                                 float* __restrict__ out) {
    int t = blockIdx.x;
    int d = threadIdx.x;
    float4 v = ((const float4*)(x1 + (size_t)t * Dm))[d];
#pragma unroll
    for (int kk = 0; kk < 2; kk++) {
        int i = 2 * t + kk;
        int sl = slot[i];
        if (sl >= 0) {
            int e = fe[i];
            float4 w = ((const float4*)(ye + ((size_t)e * CAPn + sl) * Dm))[d];
            v.x += w.x; v.y += w.y; v.z += w.z; v.w += w.w;
        }
    }
    ((float4*)(out + (size_t)t * Dm))[d] = v;
}

// ---------------------------------------------------------------------------
// Launch (single stream)
// ---------------------------------------------------------------------------
extern "C" void kernel_launch(void* const* d_in, const int* in_sizes, int n_in,
                              void* d_out, int out_size) {
    (void)in_sizes; (void)n_in; (void)out_size;
    const float* x        = (const float*)d_in[0];
    const float* g1       = (const float*)d_in[1];
    const float* w_qkv    = (const float*)d_in[2];
    const float* w_o      = (const float*)d_in[3];
    const float* g2       = (const float*)d_in[4];
    const float* w_router = (const float*)d_in[5];
    const float* w1       = (const float*)d_in[6];
    const float* w2       = (const float*)d_in[7];
    float* out = (float*)d_out;

    float *p_xn, *p_qkv, *p_x1, *p_cos, *p_sin, *p_fg, *p_egate, *p_ye;
    __half *p_qh, *p_kh, *p_vh, *p_xnh, *p_attnh;
    __half *p_wqkvh, *p_woh, *p_w1h, *p_w2h, *p_xeh, *p_hh;
    int *p_fe, *p_slot, *p_etok, *p_cnt;
    cudaGetSymbolAddress((void**)&p_xn,    g_xn);
    cudaGetSymbolAddress((void**)&p_qkv,   g_qkv);
    cudaGetSymbolAddress((void**)&p_x1,    g_x1);
    cudaGetSymbolAddress((void**)&p_cos,   g_cos);
    cudaGetSymbolAddress((void**)&p_sin,   g_sin);
    cudaGetSymbolAddress((void**)&p_fg,    g_fg);
    cudaGetSymbolAddress((void**)&p_fe,    g_fe);
    cudaGetSymbolAddress((void**)&p_slot,  g_slot);
    cudaGetSymbolAddress((void**)&p_etok,  g_etok);
    cudaGetSymbolAddress((void**)&p_egate, g_egate);
    cudaGetSymbolAddress((void**)&p_cnt,   g_cnt);
    cudaGetSymbolAddress((void**)&p_ye,    g_ye);
    cudaGetSymbolAddress((void**)&p_qh,    g_qh);
    cudaGetSymbolAddress((void**)&p_kh,    g_kh);
    cudaGetSymbolAddress((void**)&p_vh,    g_vh);
    cudaGetSymbolAddress((void**)&p_xnh,   g_xnh);
    cudaGetSymbolAddress((void**)&p_attnh, g_attnh);
    cudaGetSymbolAddress((void**)&p_wqkvh, g_wqkvh);
    cudaGetSymbolAddress((void**)&p_woh,   g_woh);
    cudaGetSymbolAddress((void**)&p_w1h,   g_w1h);
    cudaGetSymbolAddress((void**)&p_w2h,   g_w2h);
    cudaGetSymbolAddress((void**)&p_xeh,   g_xeh);
    cudaGetSymbolAddress((void**)&p_hh,    g_hh);

    constexpr int H_SMEM256 = 4 * 24576;        // 98304 bytes
    constexpr int H_SMEM128 = 4 * 16384;        // 65536 bytes
    constexpr int ATTN_SMEM = 2 * 17408;        // 34816 bytes
    cudaFuncSetAttribute(gemm_h_k<0, false, 256>, cudaFuncAttributeMaxDynamicSharedMemorySize, H_SMEM256);
    cudaFuncSetAttribute(gemm_h_k<1, false, 256>, cudaFuncAttributeMaxDynamicSharedMemorySize, H_SMEM256);
    cudaFuncSetAttribute(gemm_h_k<2, true, 128>,  cudaFuncAttributeMaxDynamicSharedMemorySize, H_SMEM128);
    cudaFuncSetAttribute(gemm_h_k<3, true, 128>,  cudaFuncAttributeMaxDynamicSharedMemorySize, H_SMEM128);
    cudaFuncSetAttribute(attn_tc_k, cudaFuncAttributeMaxDynamicSharedMemorySize, ATTN_SMEM);

    // Fused precompute: fp16 weight conversions + rope table in ONE launch
    prep_k<<<1184, 256>>>(w_qkv, p_wqkvh, w_o, p_woh,
                          w1, p_w1h, w2, p_w2h, p_cos, p_sin);

    // Attention branch
    rmsnorm_k<<<Tn, 256>>>(x, g1, p_xnh);
    gemm_h_k<0, false, 256><<<dim3(3 * Dm / 256, Tn / 128, 1), 256, H_SMEM256>>>(
        p_xnh, p_wqkvh, p_qkv, 3 * Dm, Dm, nullptr, nullptr, 0, 0, 0, 0);
    split_rope_k<<<Tn, 256>>>(p_qkv, p_cos, p_sin, p_qh, p_kh, p_vh);
    attn_tc_k<<<dim3(Sq / 128, Hn, Bz), 256, ATTN_SMEM>>>(p_qh, p_kh, p_vh, p_attnh);
    gemm_h_k<1, false, 256><<<dim3(Dm / 256, Tn / 128, 1), 256, H_SMEM256>>>(
        p_attnh, p_woh, p_x1, Dm, Dm, x, nullptr, 0, 0, 0, 0);

    // Fused rmsnorm2 + routing (fp32 exact)
    rmsrouter_k<<<Tn, 256>>>(p_x1, g2, w_router, p_xn, p_fg, p_fe, p_cnt);
    rank_k<<<NA / 256, 256>>>(p_fg, p_fe, p_slot, p_etok, p_egate, p_cnt);
    xepack_k<<<En * CAPn, 256>>>(p_xn, p_etok, p_cnt, p_xeh);

    // MoE expert GEMMs (fp16, 128x128 tiles to kill wave quantization)
    gemm_h_k<2, true, 128><<<dim3(FFNm / 128, CAPn / 128, En), 256, H_SMEM128>>>(
        p_xeh, p_w1h, p_hh, FFNm, Dm, nullptr, p_cnt,
        (long)CAPn * Dm, (long)Dm * FFNm, (long)CAPn * FFNm, 0);
    gemm_h_k<3, true, 128><<<dim3(Dm / 128, CAPn / 128, En), 256, H_SMEM128>>>(
        p_hh, p_w2h, p_ye, Dm, FFNm, p_egate, p_cnt,
        (long)CAPn * FFNm, (long)FFNm * Dm, (long)CAPn * Dm, CAPn);

    // out = x1 + moe
    combine_k<<<Tn, 256>>>(p_x1, p_ye, p_fe, p_slot, out);
}

// round 14
// speedup vs baseline: 6.2240x; 1.0089x over previous
#include <cuda_runtime.h>
#include <cuda_fp16.h>
#include <math.h>
#include <stdint.h>

// ---------------------------------------------------------------------------
// Problem constants
// ---------------------------------------------------------------------------
namespace {
constexpr int Bz   = 2;
constexpr int Sq   = 2048;
constexpr int Dm   = 1024;
constexpr int Hn   = 16;
constexpr int HDm  = 64;
constexpr int FFNm = 2048;
constexpr int En   = 8;
constexpr int Tn   = Bz * Sq;     // 4096 tokens
constexpr int NA   = Tn * 2;      // 8192 flat assignments (top-2)
constexpr int CAPn = 1280;        // ceil(2*2048*2*1.25/8)
// prep_k region sizes (float4 units except rope)
constexpr int NQ4  = Dm * 3 * Dm / 4;        // 786432
constexpr int NO4  = Dm * Dm / 4;            // 262144
constexpr int NW14 = En * Dm * FFNm / 4;     // 4194304
constexpr int NW24 = En * FFNm * Dm / 4;     // 4194304
constexpr int NRP  = Sq * (HDm / 2);         // 65536
}

// ---------------------------------------------------------------------------
// Static scratch (no allocations allowed)
// ---------------------------------------------------------------------------
__device__ float g_x1  [Tn * Dm];
__device__ float g_cos [Sq * (HDm / 2)];
__device__ float g_sin [Sq * (HDm / 2)];
__device__ float g_fg  [NA];
__device__ int   g_fe  [NA];
__device__ int   g_slot[NA];
__device__ int   g_etok [En * CAPn];
__device__ float g_egate[En * CAPn];
__device__ int   g_cnt  [En];               // live rows per expert
__device__ float g_ye[En * CAPn * Dm];
// fp16 data
__device__ __half g_qh   [Tn * Dm];         // rope'd Q, pre-scaled 1/8
__device__ __half g_kh   [Tn * Dm];         // rope'd K
__device__ __half g_vh   [Tn * Dm];         // V
__device__ __half g_xnh  [Tn * Dm];         // rmsnorm1 out (qkv GEMM A)
__device__ __half g_xn2h [Tn * Dm];         // rmsnorm2 out (MoE gather src)
__device__ __half g_attnh[Tn * Dm];         // attention out (o GEMM A)
__device__ __half g_wqkvh[Dm * 3 * Dm];
__device__ __half g_woh  [Dm * Dm];
__device__ __half g_w1h  [En * Dm * FFNm];
__device__ __half g_w2h  [En * FFNm * Dm];
__device__ __half g_hh   [En * CAPn * FFNm];

// ---------------------------------------------------------------------------
// Helpers
// ---------------------------------------------------------------------------
__device__ __forceinline__ uint32_t smem_u32(const void* p) {
    uint32_t a;
    asm("{ .reg .u64 t; cvta.to.shared.u64 t, %1; cvt.u32.u64 %0, t; }"
        : "=r"(a) : "l"(p));
    return a;
}

__device__ __forceinline__ void cpasync16(uint32_t dst, const void* src) {
    asm volatile("cp.async.cg.shared.global [%0], [%1], 16;" :: "r"(dst), "l"(src));
}
// Zero-fill variant: src-size 0 -> smem dst gets zeros, no global read.
__device__ __forceinline__ void cpasync16z(uint32_t dst, const void* src, uint32_t ssz) {
    asm volatile("cp.async.cg.shared.global [%0], [%1], 16, %2;"
                 :: "r"(dst), "l"(src), "r"(ssz));
}
__device__ __forceinline__ void cp_commit() {
    asm volatile("cp.async.commit_group;" ::: "memory");
}
template <int N>
__device__ __forceinline__ void cp_wait() {
    asm volatile("cp.async.wait_group %0;" :: "n"(N) : "memory");
}

// fp16 m16n8k16 MMA, fp32 accumulate
__device__ __forceinline__ void mma_f16(float* d, const uint32_t* a, const uint32_t* b) {
    asm volatile(
        "mma.sync.aligned.m16n8k16.row.col.f32.f16.f16.f32 "
        "{%0,%1,%2,%3}, {%4,%5,%6,%7}, {%8,%9}, {%0,%1,%2,%3};"
        : "+f"(d[0]), "+f"(d[1]), "+f"(d[2]), "+f"(d[3])
        : "r"(a[0]), "r"(a[1]), "r"(a[2]), "r"(a[3]), "r"(b[0]), "r"(b[1]));
}

__device__ __forceinline__ void ldsm_x4(uint32_t* r, uint32_t addr) {
    asm volatile("ldmatrix.sync.aligned.m8n8.x4.shared.b16 {%0,%1,%2,%3}, [%4];"
                 : "=r"(r[0]), "=r"(r[1]), "=r"(r[2]), "=r"(r[3]) : "r"(addr));
}
__device__ __forceinline__ void ldsm_x4_t(uint32_t* r, uint32_t addr) {
    asm volatile("ldmatrix.sync.aligned.m8n8.x4.trans.shared.b16 {%0,%1,%2,%3}, [%4];"
                 : "=r"(r[0]), "=r"(r[1]), "=r"(r[2]), "=r"(r[3]) : "r"(addr));
}

// 2^x for x <= 0, FMA-pipe only.
__device__ __forceinline__ float exp2p(float x) {
    float t = fmaxf(x, -126.f);
    float z = t + 12582912.f;
    float n = z - 12582912.f;
    float f = t - n;
    float p =         1.5353e-4f;
    p = fmaf(p, f, 1.3398886e-3f);
    p = fmaf(p, f, 9.6184372e-3f);
    p = fmaf(p, f, 5.5503327e-2f);
    p = fmaf(p, f, 2.4022648e-1f);
    p = fmaf(p, f, 6.9314718e-1f);
    p = fmaf(p, f, 1.0f);
    int iz = __float_as_int(z) - 0x4B400000;
    return p * __int_as_float((iz + 127) << 23);
}

__device__ __forceinline__ uint32_t h2_bits(float a, float b) {
    __half2 h = __float22half2_rn(make_float2(a, b));
    return *(uint32_t*)&h;
}

// ---------------------------------------------------------------------------
// Fused prep: fp16-convert all four weight tensors + rope table. One launch.
// ---------------------------------------------------------------------------
__global__ void prep_k(const float* __restrict__ wqkv, __half* __restrict__ wqkvh,
                       const float* __restrict__ wo,   __half* __restrict__ woh,
                       const float* __restrict__ w1,   __half* __restrict__ w1h,
                       const float* __restrict__ w2,   __half* __restrict__ w2h,
                       float* __restrict__ ct, float* __restrict__ st) {
    const int total = NQ4 + NO4 + NW14 + NW24 + NRP;
    int stride = gridDim.x * blockDim.x;
    for (int i = blockIdx.x * blockDim.x + threadIdx.x; i < total; i += stride) {
        int r = i;
        if (r < NQ4) {
            float4 v = ((const float4*)wqkv)[r];
            ((uint2*)wqkvh)[r] = make_uint2(h2_bits(v.x, v.y), h2_bits(v.z, v.w));
            continue;
        }
        r -= NQ4;
        if (r < NO4) {
            float4 v = ((const float4*)wo)[r];
            ((uint2*)woh)[r] = make_uint2(h2_bits(v.x, v.y), h2_bits(v.z, v.w));
            continue;
        }
        r -= NO4;
        if (r < NW14) {
            float4 v = ((const float4*)w1)[r];
            ((uint2*)w1h)[r] = make_uint2(h2_bits(v.x, v.y), h2_bits(v.z, v.w));
            continue;
        }
        r -= NW14;
        if (r < NW24) {
            float4 v = ((const float4*)w2)[r];
            ((uint2*)w2h)[r] = make_uint2(h2_bits(v.x, v.y), h2_bits(v.z, v.w));
            continue;
        }
        r -= NW24;
        {
            int s = r >> 5, j = r & 31;
            float th = (float)pow(10000.0, -2.0 * (double)j / (double)HDm);
            double f = (double)s * (double)th;
            ct[r] = (float)cos(f);
            st[r] = (float)sin(f);
        }
    }
}

// ---------------------------------------------------------------------------
// RMSNorm (fp16 out; feeds qkv GEMM)
// ---------------------------------------------------------------------------
__global__ void __launch_bounds__(256) rmsnorm_k(const float* __restrict__ x,
                                                 const float* __restrict__ g,
                                                 __half* __restrict__ y) {
    int row = blockIdx.x;
    int i = threadIdx.x;
    const float4* xr = (const float4*)(x + (size_t)row * Dm);
    float4 xv = xr[i];
    float ss = xv.x * xv.x + xv.y * xv.y + xv.z * xv.z + xv.w * xv.w;
#pragma unroll
    for (int off = 16; off; off >>= 1) ss += __shfl_down_sync(0xffffffffu, ss, off);
    __shared__ float red[8];
    __shared__ float srms;
    if ((i & 31) == 0) red[i >> 5] = ss;
    __syncthreads();
    if (i == 0) {
        float t = 0.f;
#pragma unroll
        for (int w = 0; w < 8; w++) t += red[w];
        srms = rsqrtf(t * (1.0f / Dm) + 1e-6f);
    }
    __syncthreads();
    float r = srms;
    float4 gv = ((const float4*)g)[i];
    ((uint2*)(y + (size_t)row * Dm))[i] =
        make_uint2(h2_bits(gv.x * xv.x * r, gv.y * xv.y * r),
                   h2_bits(gv.z * xv.z * r, gv.w * xv.w * r));
}

// ---------------------------------------------------------------------------
// Fused RMSNorm2 + router: norm -> xn (fp16, MoE gather source), 8 logits,
// softmax, top-2. One block per token.
// ---------------------------------------------------------------------------
__global__ void __launch_bounds__(256) rmsrouter_k(const float* __restrict__ x,
                                                   const float* __restrict__ g,
                                                   const float* __restrict__ wr,
                                                   __half* __restrict__ xnh,
                                                   float* __restrict__ fg,
                                                   int* __restrict__ fe,
                                                   int* __restrict__ cnt) {
    int row = blockIdx.x;
    int i = threadIdx.x;
    if (row == 0 && i < En) cnt[i] = 0;
    const float4* xr = (const float4*)(x + (size_t)row * Dm);
    float4 xv = xr[i];
    float ss = xv.x * xv.x + xv.y * xv.y + xv.z * xv.z + xv.w * xv.w;
#pragma unroll
    for (int off = 16; off; off >>= 1) ss += __shfl_down_sync(0xffffffffu, ss, off);
    __shared__ float red[8];
    __shared__ float srms;
    if ((i & 31) == 0) red[i >> 5] = ss;
    __syncthreads();
    if (i == 0) {
        float t = 0.f;
#pragma unroll
        for (int w = 0; w < 8; w++) t += red[w];
        srms = rsqrtf(t * (1.0f / Dm) + 1e-6f);
    }
    __syncthreads();
    float r = srms;
    float4 gv = ((const float4*)g)[i];
    float o[4];
    o[0] = gv.x * xv.x * r; o[1] = gv.y * xv.y * r;
    o[2] = gv.z * xv.z * r; o[3] = gv.w * xv.w * r;
    ((uint2*)(xnh + (size_t)row * Dm))[i] =
        make_uint2(h2_bits(o[0], o[1]), h2_bits(o[2], o[3]));

    float acc[8];
#pragma unroll
    for (int e = 0; e < 8; e++) acc[e] = 0.f;
#pragma unroll
    for (int c = 0; c < 4; c++) {
        const float4* w = (const float4*)(wr + (size_t)(4 * i + c) * En);
        float4 w0 = w[0], w1 = w[1];
        acc[0] = fmaf(o[c], w0.x, acc[0]); acc[1] = fmaf(o[c], w0.y, acc[1]);
        acc[2] = fmaf(o[c], w0.z, acc[2]); acc[3] = fmaf(o[c], w0.w, acc[3]);
        acc[4] = fmaf(o[c], w1.x, acc[4]); acc[5] = fmaf(o[c], w1.y, acc[5]);
        acc[6] = fmaf(o[c], w1.z, acc[6]); acc[7] = fmaf(o[c], w1.w, acc[7]);
    }
#pragma unroll
    for (int e = 0; e < 8; e++)
#pragma unroll
        for (int off = 16; off; off >>= 1)
            acc[e] += __shfl_down_sync(0xffffffffu, acc[e], off);
    __shared__ float lred[8][8];
    if ((i & 31) == 0)
#pragma unroll
        for (int e = 0; e < 8; e++) lred[i >> 5][e] = acc[e];
    __syncthreads();
    if (i == 0) {
        float p[8];
#pragma unroll
        for (int e = 0; e < 8; e++) {
            float s = 0.f;
#pragma unroll
            for (int w = 0; w < 8; w++) s += lred[w][e];
            p[e] = s;
        }
        float mx = p[0];
#pragma unroll
        for (int e = 1; e < 8; e++) mx = fmaxf(mx, p[e]);
        float sum = 0.f;
#pragma unroll
        for (int e = 0; e < 8; e++) { p[e] = expf(p[e] - mx); sum += p[e]; }
        float inv = 1.f / sum;
#pragma unroll
        for (int e = 0; e < 8; e++) p[e] *= inv;
        int e0 = 0; float p0 = p[0];
#pragma unroll
        for (int e = 1; e < 8; e++) if (p[e] > p0) { p0 = p[e]; e0 = e; }
        int e1 = -1; float p1 = -1.f;
#pragma unroll
        for (int e = 0; e < 8; e++)
            if (e != e0 && p[e] > p1) { p1 = p[e]; e1 = e; }
        fg[2 * row]     = p0; fe[2 * row]     = e0;
        fg[2 * row + 1] = p1; fe[2 * row + 1] = e1;
    }
}

// ---------------------------------------------------------------------------
// Tensor-core causal flash attention, all-fp16 MMAs (unchanged from R13).
// ---------------------------------------------------------------------------
__global__ void __launch_bounds__(256) attn_tc_k(const __half* __restrict__ Q,
                                                 const __half* __restrict__ Kt,
                                                 const __half* __restrict__ Vt,
                                                 __half* __restrict__ Out) {
    extern __shared__ __align__(16) char smc[];
    constexpr float LOG2E = 1.4426950408889634f;
    constexpr int KBYTES = 64 * 144;            // 9216
    constexpr int STGB = KBYTES + 64 * 128;     // + V 8192 = 17408

    int bx = blockIdx.x, h = blockIdx.y, b = blockIdx.z;
    int qt = bx * 128;
    int tid = threadIdx.x, warp = tid >> 5, lane = tid & 31;
    int gq = lane >> 2, tq = lane & 3;
    int wq = qt + warp * 16;
    const size_t base = ((size_t)(b * Hn + h)) * Sq * HDm;
    const __half* Qg = Q + base;
    const __half* Kg = Kt + base;
    const __half* Vg = Vt + base;

    const uint32_t sb = smem_u32(smc);

    uint32_t qf[4][4];
#pragma unroll
    for (int kk = 0; kk < 4; kk++) {
        const __half* q0 = Qg + (size_t)(wq + gq) * 64 + kk * 16 + 2 * tq;
        const __half* q1 = Qg + (size_t)(wq + gq + 8) * 64 + kk * 16 + 2 * tq;
        qf[kk][0] = *(const uint32_t*)q0;
        qf[kk][1] = *(const uint32_t*)q1;
        qf[kk][2] = *(const uint32_t*)(q0 + 8);
        qf[kk][3] = *(const uint32_t*)(q1 + 8);
    }

    float O[8][4];
#pragma unroll
    for (int nt = 0; nt < 8; nt++)
#pragma unroll
        for (int c = 0; c < 4; c++) O[nt][c] = 0.f;
    float m0 = -1e30f, m1 = -1e30f, l0 = 0.f, l1 = 0.f;

    int fr = tid >> 2;
    int fc = tid & 3;
    auto fill = [&](int stage, int kt) {
        uint32_t kDst = sb + (uint32_t)(stage * STGB + fr * 144 + fc * 32);
        const __half* ks = Kg + (size_t)(kt + fr) * 64 + fc * 16;
        cpasync16(kDst, ks);
        cpasync16(kDst + 16u, ks + 8);
        uint32_t vBase = sb + (uint32_t)(stage * STGB + KBYTES + fr * 128);
        const __half* vs = Vg + (size_t)(kt + fr) * 64;
        uint32_t sw = (uint32_t)(fr & 7);
#pragma unroll
        for (int j = 0; j < 2; j++) {
            uint32_t c = (uint32_t)(fc * 2 + j);
            cpasync16(vBase + ((c ^ sw) * 16u), vs + c * 8);
        }
    };

    int ntiles = 2 * bx + 2;
    fill(0, 0);
    cp_commit();

    int lrow = lane & 7, selb = (lane >> 3) & 1, selc = lane >> 4;

    for (int it = 0; it < ntiles; it++) {
        if (it + 1 < ntiles) fill((it + 1) & 1, (it + 1) * 64);
        cp_commit();
        cp_wait<1>();
        __syncthreads();

        int kt = it * 64;
        if (kt <= wq + 15) {
            const __half* Ks = (const __half*)(smc + (it & 1) * STGB);
            const uint32_t Vsb = sb + (uint32_t)((it & 1) * STGB + KBYTES);

            float s[8][4];
#pragma unroll
            for (int nt = 0; nt < 8; nt++)
#pragma unroll
                for (int c = 0; c < 4; c++) s[nt][c] = 0.f;
#pragma unroll
            for (int kk = 0; kk < 4; kk++) {
                uint32_t bf[8][2];
#pragma unroll
                for (int nt = 0; nt < 8; nt++) {
                    const __half* kr = Ks + (nt * 8 + gq) * 72 + kk * 16 + 2 * tq;
                    bf[nt][0] = *(const uint32_t*)kr;
                    bf[nt][1] = *(const uint32_t*)(kr + 8);
                }
#pragma unroll
                for (int nt = 0; nt < 8; nt++) mma_f16(s[nt], qf[kk], bf[nt]);
            }

            if (kt + 63 > wq) {
                int r0 = wq + gq, r1 = wq + gq + 8;
#pragma unroll
                for (int nt = 0; nt < 8; nt++) {
                    int c0 = kt + nt * 8 + 2 * tq;
                    if (c0 > r0)     s[nt][0] = -3.4e38f;
                    if (c0 + 1 > r0) s[nt][1] = -3.4e38f;
                    if (c0 > r1)     s[nt][2] = -3.4e38f;
                    if (c0 + 1 > r1) s[nt][3] = -3.4e38f;
                }
            }

            float mx0 = -3.4e38f, mx1 = -3.4e38f;
#pragma unroll
            for (int nt = 0; nt < 8; nt++) {
                mx0 = fmaxf(mx0, fmaxf(s[nt][0], s[nt][1]));
                mx1 = fmaxf(mx1, fmaxf(s[nt][2], s[nt][3]));
            }
            mx0 = fmaxf(mx0, __shfl_xor_sync(0xffffffffu, mx0, 1));
            mx0 = fmaxf(mx0, __shfl_xor_sync(0xffffffffu, mx0, 2));
            mx1 = fmaxf(mx1, __shfl_xor_sync(0xffffffffu, mx1, 1));
            mx1 = fmaxf(mx1, __shfl_xor_sync(0xffffffffu, mx1, 2));
            float mn0 = fmaxf(m0, mx0), mn1 = fmaxf(m1, mx1);
            float cr0 = exp2p((m0 - mn0) * LOG2E);
            float cr1 = exp2p((m1 - mn1) * LOG2E);
            float nm0 = mn0 * LOG2E, nm1 = mn1 * LOG2E;

            float sum0 = 0.f, sum1 = 0.f;
#pragma unroll
            for (int nt = 0; nt < 8; nt++) {
                float p0 = exp2p(fmaf(s[nt][0], LOG2E, -nm0));
                float p1 = exp2p(fmaf(s[nt][1], LOG2E, -nm0));
                float p2 = exp2p(fmaf(s[nt][2], LOG2E, -nm1));
                float p3 = exp2p(fmaf(s[nt][3], LOG2E, -nm1));
                s[nt][0] = p0; s[nt][1] = p1; s[nt][2] = p2; s[nt][3] = p3;
                sum0 += p0 + p1; sum1 += p2 + p3;
            }
            sum0 += __shfl_xor_sync(0xffffffffu, sum0, 1);
            sum0 += __shfl_xor_sync(0xffffffffu, sum0, 2);
            sum1 += __shfl_xor_sync(0xffffffffu, sum1, 1);
            sum1 += __shfl_xor_sync(0xffffffffu, sum1, 2);
            l0 = l0 * cr0 + sum0;
            l1 = l1 * cr1 + sum1;
#pragma unroll
            for (int nt = 0; nt < 8; nt++) {
                O[nt][0] *= cr0; O[nt][1] *= cr0;
                O[nt][2] *= cr1; O[nt][3] *= cr1;
            }
            m0 = mn0; m1 = mn1;

#pragma unroll
            for (int kk = 0; kk < 4; kk++) {
                uint32_t a[4];
                a[0] = h2_bits(s[2 * kk][0],     s[2 * kk][1]);
                a[1] = h2_bits(s[2 * kk][2],     s[2 * kk][3]);
                a[2] = h2_bits(s[2 * kk + 1][0], s[2 * kk + 1][1]);
                a[3] = h2_bits(s[2 * kk + 1][2], s[2 * kk + 1][3]);
                uint32_t bvv[8][2];
#pragma unroll
                for (int np = 0; np < 4; np++) {
                    uint32_t qd[4];
                    uint32_t addr = Vsb + (uint32_t)((lrow + 8 * selb) * 128)
                                  + (uint32_t)(kk * 2048)
                                  + ((((uint32_t)(selc + 2 * np)) ^ (uint32_t)lrow) * 16u);
                    ldsm_x4_t(qd, addr);
                    bvv[2 * np][0]     = qd[0]; bvv[2 * np][1]     = qd[1];
                    bvv[2 * np + 1][0] = qd[2]; bvv[2 * np + 1][1] = qd[3];
                }
#pragma unroll
                for (int nt = 0; nt < 8; nt++) mma_f16(O[nt], a, bvv[nt]);
            }
        }
        __syncthreads();
    }

    float i0 = 1.f / l0, i1 = 1.f / l1;
    int r0 = wq + gq, r1 = wq + gq + 8;
    __half* o0 = Out + ((size_t)(b * Sq + r0)) * Dm + h * 64 + 2 * tq;
    __half* o1 = Out + ((size_t)(b * Sq + r1)) * Dm + h * 64 + 2 * tq;
#pragma unroll
    for (int nt = 0; nt < 8; nt++) {
        *(uint32_t*)(o0 + nt * 8) = h2_bits(O[nt][0] * i0, O[nt][1] * i0);
        *(uint32_t*)(o1 + nt * 8) = h2_bits(O[nt][2] * i1, O[nt][3] * i1);
    }
}

// ---------------------------------------------------------------------------
// fp16 tensor-core GEMM: CTA 128xNT, 8 warps, BK=32, 4-stage cp.async,
// ldmatrix, m16n8k16.f16, ONE barrier/iter.
// MODE 0: C(f32)=A@B            1: +resid
// MODE 2: C(f16)=relu(A@B)      3: C(f32)=(A@B)*gates[row]
// MODE 4: rope+split epilogue -> q(x1/8)/k/v fp16 (qkv projection)
// SKIP: early-exit CTAs past cnt[e]. GATHER: A rows via etok (zero-fill dead).
// ---------------------------------------------------------------------------
template <int MODE, bool SKIP, bool GATHER, int NT>
__global__ void __launch_bounds__(256, 1)
gemm_h_k(const __half* __restrict__ A, const __half* __restrict__ Bm,
         void* __restrict__ Cp, int N, int K,
         const float* __restrict__ extra, const int* __restrict__ cnt,
         const int* __restrict__ etok,
         const float* __restrict__ ct, const float* __restrict__ st,
         __half* __restrict__ kOut, __half* __restrict__ vOut,
         long sA, long sB, long sC, int gstride) {
    extern __shared__ __align__(16) float smf[];
    const uint32_t sb = smem_u32(smf);
    constexpr int NTW  = NT / 32;
    constexpr int CPT  = NT / 64;
    constexpr uint32_t BROW = NT * 2;
    constexpr uint32_t STGB = 8192u + 32u * BROW;

    int e = blockIdx.z;
    int m0 = blockIdx.y * 128, n0 = blockIdx.x * NT;
    int cntE = 0;
    if (SKIP) {
        cntE = cnt[e];
        if (m0 >= cntE) return;
    }

    int tid = threadIdx.x, warp = tid >> 5, lane = tid & 31;
    int gq = lane >> 2, tq = lane & 3;
    if (!GATHER) A += (size_t)e * sA;
    Bm += (size_t)e * sB;
    const float* gates = extra;
    if (MODE == 3) gates += (size_t)e * gstride;

    int wm = (warp & 1) * 64, wn = (warp >> 1) * (NT / 4);

    int ar = tid >> 1, ah = tid & 1;
    int br2 = tid >> 3, bc0 = (tid & 7) * CPT;
    const __half* aSrc;
    uint32_t aLive = 16u;
    if (GATHER) {
        int rr = m0 + ar;
        bool live = rr < cntE;
        int tok = live ? etok[e * CAPn + rr] : 0;
        aLive = live ? 16u : 0u;
        aSrc = A + (size_t)tok * K + ah * 16;
    } else {
        aSrc = A + (size_t)(m0 + ar) * K + ah * 16;
    }
    const __half* bSrc = Bm + (size_t)br2 * N + n0 + bc0 * 8;
    uint32_t aS = (ar >> 1) & 3;
    uint32_t aBase = sb + (uint32_t)ar * 64u;
    uint32_t bBase = sb + 8192u + (uint32_t)br2 * BROW;

    auto fetch = [&](int stage, int k0) {
        uint32_t so = (uint32_t)stage * STGB;
        const __half* as = aSrc + k0;
        uint32_t c0 = 2u * ah;
        if (GATHER) {
            cpasync16z(aBase + so + ((c0 ^ aS) * 16u), as, aLive);
            cpasync16z(aBase + so + (((c0 + 1) ^ aS) * 16u), as + 8, aLive);
        } else {
            cpasync16(aBase + so + ((c0 ^ aS) * 16u), as);
            cpasync16(aBase + so + (((c0 + 1) ^ aS) * 16u), as + 8);
        }
        const __half* bs = bSrc + (size_t)k0 * N;
#pragma unroll
        for (int j = 0; j < CPT; j++) {
            uint32_t c = (uint32_t)(bc0 + j);
            cpasync16(bBase + so + ((c ^ (uint32_t)(br2 & 7)) * 16u), bs + j * 8);
        }
    };

    float d[4][NTW][4];
#pragma unroll
    for (int i = 0; i < 4; i++)
#pragma unroll
        for (int j = 0; j < NTW; j++)
#pragma unroll
            for (int c = 0; c < 4; c++) d[i][j][c] = 0.f;

    fetch(0, 0);  cp_commit();
    fetch(1, 32); cp_commit();
    fetch(2, 64); cp_commit();

    int lrow = lane & 7, selb = (lane >> 3) & 1, selc = lane >> 4;
    uint32_t aRow = (uint32_t)(wm + lrow + 8 * selb) * 64u;
    uint32_t aSw  = (uint32_t)((lrow >> 1) & 3);
    uint32_t bRow = (uint32_t)(lrow + 8 * selb) * BROW;
    uint32_t bCb  = (uint32_t)((wn >> 3) + selc);

    int KB = K >> 5;
    for (int it = 0; it < KB; ++it) {
        cp_wait<2>();
        __syncthreads();
        if (it + 3 < KB) fetch((it + 3) & 3, (it + 3) * 32);
        cp_commit();

        uint32_t As = sb + (uint32_t)(it & 3) * STGB;
        uint32_t Bs = As + 8192u;
#pragma unroll
        for (int kk = 0; kk < 2; kk++) {
            uint32_t a[4][4], b[NTW][2];
#pragma unroll
            for (int mt = 0; mt < 4; mt++) {
                uint32_t addr = As + aRow + (uint32_t)mt * 1024u
                              + ((((uint32_t)(2 * kk) + (uint32_t)selc) ^ aSw) * 16u);
                ldsm_x4(a[mt], addr);
            }
#pragma unroll
            for (int np = 0; np < NTW / 2; np++) {
                uint32_t q[4];
                uint32_t addr = Bs + bRow + (uint32_t)kk * 16u * BROW
                              + (((bCb + 2u * np) ^ (uint32_t)lrow) * 16u);
                ldsm_x4_t(q, addr);
                b[2 * np][0]     = q[0]; b[2 * np][1]     = q[1];
                b[2 * np + 1][0] = q[2]; b[2 * np + 1][1] = q[3];
            }
#pragma unroll
            for (int mt = 0; mt < 4; mt++)
#pragma unroll
                for (int nt = 0; nt < NTW; nt++)
                    mma_f16(d[mt][nt], a[mt], b[nt]);
        }
    }

    if (MODE == 4) {
        // region constant per N-tile: 0=Q, 1=K, 2=V (NT=256 divides 1024)
        int region = n0 >> 10;
        __half* q0v[3] = { (__half*)Cp, kOut, vOut };
        __half* outb = q0v[region];
#pragma unroll
        for (int mt = 0; mt < 4; mt++) {
#pragma unroll
            for (int half = 0; half < 2; half++) {
                int row = m0 + wm + mt * 16 + gq + 8 * half;
                int bb = row >> 11, s = row & (Sq - 1);
                float va = 0.f, vb = 0.f;
#pragma unroll
                for (int nt = 0; nt < NTW; nt++) {
                    int c = n0 + wn + nt * 8 + 2 * tq;
                    va = d[mt][nt][2 * half];
                    vb = d[mt][nt][2 * half + 1];
                    int cc = c & 1023;
                    int hh = cc >> 6, dd = cc & 63;
                    size_t off = ((size_t)(bb * Hn + hh) * Sq + s) * HDm + dd;
                    uint32_t bits;
                    if (region == 2) {
                        bits = h2_bits(va, vb);
                    } else {
                        int j = dd >> 1;
                        float cs = ct[s * 32 + j], sn = st[s * 32 + j];
                        float orr = va * cs - vb * sn;
                        float oii = va * sn + vb * cs;
                        if (region == 0) { orr *= 0.125f; oii *= 0.125f; }
                        bits = h2_bits(orr, oii);
                    }
                    *(uint32_t*)(outb + off) = bits;
                }
            }
        }
        return;
    }

#pragma unroll
    for (int mt = 0; mt < 4; mt++) {
        int r0 = m0 + wm + mt * 16 + gq;
        int r1 = r0 + 8;
        if (MODE == 2) {
            __half* Cb = (__half*)Cp + (size_t)e * sC;
#pragma unroll
            for (int nt = 0; nt < NTW; nt++) {
                int c = n0 + wn + nt * 8 + 2 * tq;
                *(uint32_t*)(Cb + (size_t)r0 * N + c) =
                    h2_bits(fmaxf(d[mt][nt][0], 0.f), fmaxf(d[mt][nt][1], 0.f));
                *(uint32_t*)(Cb + (size_t)r1 * N + c) =
                    h2_bits(fmaxf(d[mt][nt][2], 0.f), fmaxf(d[mt][nt][3], 0.f));
            }
        } else if (MODE != 4) {
            float* Cf = (float*)Cp + (size_t)e * sC;
            float g0 = 1.f, g1 = 1.f;
            if (MODE == 3) { g0 = gates[r0]; g1 = gates[r1]; }
#pragma unroll
            for (int nt = 0; nt < NTW; nt++) {
                int c = n0 + wn + nt * 8 + 2 * tq;
                float2 u, w;
                u.x = d[mt][nt][0]; u.y = d[mt][nt][1];
                w.x = d[mt][nt][2]; w.y = d[mt][nt][3];
                if (MODE == 1) {
                    float2 ra = *(const float2*)(extra + (size_t)r0 * N + c);
                    float2 rb = *(const float2*)(extra + (size_t)r1 * N + c);
                    u.x += ra.x; u.y += ra.y;
                    w.x += rb.x; w.y += rb.y;
                }
                if (MODE == 3) {
                    u.x *= g0; u.y *= g0;
                    w.x *= g1; w.y *= g1;
                }
                *(float2*)(Cf + (size_t)r0 * N + c) = u;
                *(float2*)(Cf + (size_t)r1 * N + c) = w;
            }
        }
    }
}

// ---------------------------------------------------------------------------
// Exact capacity ranking.
// ---------------------------------------------------------------------------
__global__ void __launch_bounds__(256) rank_k(const float* __restrict__ fg,
                                              const int* __restrict__ fe,
                                              int* __restrict__ slot,
                                              int* __restrict__ etok,
                                              float* __restrict__ egate,
                                              int* __restrict__ cnt) {
    __shared__ float sg[NA];
    __shared__ unsigned char se[NA];
    for (int i = threadIdx.x; i < NA; i += 256) {
        sg[i] = fg[i];
        se[i] = (unsigned char)fe[i];
    }
    __syncthreads();
    int i = blockIdx.x * 256 + threadIdx.x;
    float gi = sg[i];
    unsigned char ei = se[i];
    int r = 0;
    for (int j = 0; j < NA; j++) {
        bool c = (se[j] == ei) && ((sg[j] > gi) || (sg[j] == gi && j < i));
        r += (int)c;
    }
    if (r < CAPn) {
        slot[i] = r;
        etok[(int)ei * CAPn + r] = i >> 1;
        egate[(int)ei * CAPn + r] = gi;
        atomicMax(&cnt[(int)ei], r + 1);
    } else {
        slot[i] = -1;
    }
}

// ---------------------------------------------------------------------------
// Final combine
// ---------------------------------------------------------------------------
__global__ void __launch_bounds__(256) combine_k(const float* __restrict__ x1,
                                                 const float* __restrict__ ye,
                                                 const int* __restrict__ fe,
                                                 const int* __restrict__ slot,
                                                 float* __restrict__ out) {
    int t = blockIdx.x;
    int d = threadIdx.x;
    float4 v = ((const float4*)(x1 + (size_t)t * Dm))[d];
#pragma unroll
    for (int kk = 0; kk < 2; kk++) {
        int i = 2 * t + kk;
        int sl = slot[i];
        if (sl >= 0) {
            int e = fe[i];
            float4 w = ((const float4*)(ye + ((size_t)e * CAPn + sl) * Dm))[d];
            v.x += w.x; v.y += w.y; v.z += w.z; v.w += w.w;
        }
    }
    ((float4*)(out + (size_t)t * Dm))[d] = v;
}

// ---------------------------------------------------------------------------
// Launch (single stream)
// ---------------------------------------------------------------------------
extern "C" void kernel_launch(void* const* d_in, const int* in_sizes, int n_in,
                              void* d_out, int out_size) {
    (void)in_sizes; (void)n_in; (void)out_size;
    const float* x        = (const float*)d_in[0];
    const float* g1       = (const float*)d_in[1];
    const float* w_qkv    = (const float*)d_in[2];
    const float* w_o      = (const float*)d_in[3];
    const float* g2       = (const float*)d_in[4];
    const float* w_router = (const float*)d_in[5];
    const float* w1       = (const float*)d_in[6];
    const float* w2       = (const float*)d_in[7];
    float* out = (float*)d_out;

    float *p_x1, *p_cos, *p_sin, *p_fg, *p_egate, *p_ye;
    __half *p_qh, *p_kh, *p_vh, *p_xnh, *p_xn2h, *p_attnh;
    __half *p_wqkvh, *p_woh, *p_w1h, *p_w2h, *p_hh;
    int *p_fe, *p_slot, *p_etok, *p_cnt;
    cudaGetSymbolAddress((void**)&p_x1,    g_x1);
    cudaGetSymbolAddress((void**)&p_cos,   g_cos);
    cudaGetSymbolAddress((void**)&p_sin,   g_sin);
    cudaGetSymbolAddress((void**)&p_fg,    g_fg);
    cudaGetSymbolAddress((void**)&p_fe,    g_fe);
    cudaGetSymbolAddress((void**)&p_slot,  g_slot);
    cudaGetSymbolAddress((void**)&p_etok,  g_etok);
    cudaGetSymbolAddress((void**)&p_egate, g_egate);
    cudaGetSymbolAddress((void**)&p_cnt,   g_cnt);
    cudaGetSymbolAddress((void**)&p_ye,    g_ye);
    cudaGetSymbolAddress((void**)&p_qh,    g_qh);
    cudaGetSymbolAddress((void**)&p_kh,    g_kh);
    cudaGetSymbolAddress((void**)&p_vh,    g_vh);
    cudaGetSymbolAddress((void**)&p_xnh,   g_xnh);
    cudaGetSymbolAddress((void**)&p_xn2h,  g_xn2h);
    cudaGetSymbolAddress((void**)&p_attnh, g_attnh);
    cudaGetSymbolAddress((void**)&p_wqkvh, g_wqkvh);
    cudaGetSymbolAddress((void**)&p_woh,   g_woh);
    cudaGetSymbolAddress((void**)&p_w1h,   g_w1h);
    cudaGetSymbolAddress((void**)&p_w2h,   g_w2h);
    cudaGetSymbolAddress((void**)&p_hh,    g_hh);

    constexpr int H_SMEM256 = 4 * 24576;        // 98304 bytes
    constexpr int H_SMEM128 = 4 * 16384;        // 65536 bytes
    constexpr int ATTN_SMEM = 2 * 17408;        // 34816 bytes
    cudaFuncSetAttribute((const void*)gemm_h_k<4, false, false, 256>,
                         cudaFuncAttributeMaxDynamicSharedMemorySize, H_SMEM256);
    cudaFuncSetAttribute((const void*)gemm_h_k<1, false, false, 256>,
                         cudaFuncAttributeMaxDynamicSharedMemorySize, H_SMEM256);
    cudaFuncSetAttribute((const void*)gemm_h_k<2, true, true, 128>,
                         cudaFuncAttributeMaxDynamicSharedMemorySize, H_SMEM128);
    cudaFuncSetAttribute((const void*)gemm_h_k<3, true, false, 128>,
                         cudaFuncAttributeMaxDynamicSharedMemorySize, H_SMEM128);
    cudaFuncSetAttribute((const void*)attn_tc_k,
                         cudaFuncAttributeMaxDynamicSharedMemorySize, ATTN_SMEM);

    // Fused precompute: fp16 weight conversions + rope table in ONE launch
    prep_k<<<1184, 256>>>(w_qkv, p_wqkvh, w_o, p_woh,
                          w1, p_w1h, w2, p_w2h, p_cos, p_sin);

    // Attention branch: qkv GEMM with fused rope/split epilogue
    rmsnorm_k<<<Tn, 256>>>(x, g1, p_xnh);
    gemm_h_k<4, false, false, 256><<<dim3(3 * Dm / 256, Tn / 128, 1), 256, H_SMEM256>>>(
        p_xnh, p_wqkvh, p_qh, 3 * Dm, Dm, nullptr, nullptr, nullptr,
        p_cos, p_sin, p_kh, p_vh, 0, 0, 0, 0);
    attn_tc_k<<<dim3(Sq / 128, Hn, Bz), 256, ATTN_SMEM>>>(p_qh, p_kh, p_vh, p_attnh);
    gemm_h_k<1, false, false, 256><<<dim3(Dm / 256, Tn / 128, 1), 256, H_SMEM256>>>(
        p_attnh, p_woh, p_x1, Dm, Dm, x, nullptr, nullptr,
        nullptr, nullptr, nullptr, nullptr, 0, 0, 0, 0);

    // Fused rmsnorm2 + routing (fp32 exact; xn emitted fp16 for MoE gather)
    rmsrouter_k<<<Tn, 256>>>(p_x1, g2, w_router, p_xn2h, p_fg, p_fe, p_cnt);
    rank_k<<<NA / 256, 256>>>(p_fg, p_fe, p_slot, p_etok, p_egate, p_cnt);

    // MoE expert GEMMs (fp16; gemm1 gathers A rows via etok, zero-fill dead)
    gemm_h_k<2, true, true, 128><<<dim3(FFNm / 128, CAPn / 128, En), 256, H_SMEM128>>>(
        p_xn2h, p_w1h, p_hh, FFNm, Dm, nullptr, p_cnt, p_etok,
        nullptr, nullptr, nullptr, nullptr,
        0, (long)Dm * FFNm, (long)CAPn * FFNm, 0);
    gemm_h_k<3, true, false, 128><<<dim3(Dm / 128, CAPn / 128, En), 256, H_SMEM128>>>(
        p_hh, p_w2h, p_ye, Dm, FFNm, p_egate, p_cnt, nullptr,
        nullptr, nullptr, nullptr, nullptr,
        (long)CAPn * FFNm, (long)FFNm * Dm, (long)CAPn * Dm, CAPn);

    // out = x1 + moe
    combine_k<<<Tn, 256>>>(p_x1, p_ye, p_fe, p_slot, out);
}